// round 6
// baseline (speedup 1.0000x reference)
#include <cuda_runtime.h>
#include <cuda_bf16.h>
#include <math.h>
#include <stdint.h>

#define Bsz 2
#define Tn  1024
#define Dm  1024
#define Hn  16
#define DHn 64
#define BHn (Bsz*Hn)
#define MAXP 64

// ---------------- scratch (static device arrays; no allocation) ----------------
__device__ float g_Qf[BHn*Tn*DHn];           // fp32 Q (for qpe)
__device__ float g_QPE[BHn*Tn*MAXP];
__device__ float g_S[(long)BHn*Tn*Tn];       // qk scores fp32, 128MB
__device__ __nv_bfloat16 g_Ph[(long)BHn*Tn*Tn], g_Pl[(long)BHn*Tn*Tn];  // probs hi/lo
__device__ __nv_bfloat16 g_Vth[BHn*DHn*Tn], g_Vtl[BHn*DHn*Tn];          // V^T hi/lo
__device__ __nv_bfloat16 g_xh[Bsz*Tn*Dm],  g_xl[Bsz*Tn*Dm];
__device__ __nv_bfloat16 g_Wqh[Dm*Dm], g_Wql[Dm*Dm];
__device__ __nv_bfloat16 g_Wkh[Dm*Dm], g_Wkl[Dm*Dm];
__device__ __nv_bfloat16 g_Wvh[Dm*Dm], g_Wvl[Dm*Dm];
__device__ __nv_bfloat16 g_Woh[Dm*Dm], g_Wol[Dm*Dm];
__device__ __nv_bfloat16 g_Qh[BHn*Tn*DHn], g_Ql[BHn*Tn*DHn];
__device__ __nv_bfloat16 g_Kh[BHn*Tn*DHn], g_Kl[BHn*Tn*DHn];
__device__ __nv_bfloat16 g_AOh[Bsz*Tn*Dm], g_AOl[Bsz*Tn*Dm];

// ---------------- helpers ----------------
__device__ __forceinline__ uint32_t smem_u32(const void* p) {
    uint32_t a;
    asm("{ .reg .u64 t; cvta.to.shared.u64 t, %1; cvt.u32.u64 %0, t; }" : "=r"(a) : "l"(p));
    return a;
}
__device__ __forceinline__ void cpa16(uint32_t dst, const void* src) {
    asm volatile("cp.async.cg.shared.global [%0], [%1], 16;" :: "r"(dst), "l"(src));
}
#define CPA_COMMIT() asm volatile("cp.async.commit_group;" ::: "memory")
#define CPA_WAIT2()  asm volatile("cp.async.wait_group 2;" ::: "memory")
#define CPA_WAIT1()  asm volatile("cp.async.wait_group 1;" ::: "memory")
#define CPA_WAIT0()  asm volatile("cp.async.wait_group 0;" ::: "memory")

#define LDSM4(r, a) \
    asm volatile("ldmatrix.sync.aligned.m8n8.x4.shared.b16 {%0,%1,%2,%3}, [%4];" \
        : "=r"((r)[0]), "=r"((r)[1]), "=r"((r)[2]), "=r"((r)[3]) : "r"(a))

#define MMA_BF16(c, a, b0v, b1v) \
    asm volatile("mma.sync.aligned.m16n8k16.row.col.f32.bf16.bf16.f32 " \
        "{%0,%1,%2,%3},{%4,%5,%6,%7},{%8,%9},{%0,%1,%2,%3};" \
        : "+f"((c)[0]), "+f"((c)[1]), "+f"((c)[2]), "+f"((c)[3]) \
        : "r"((a)[0]), "r"((a)[1]), "r"((a)[2]), "r"((a)[3]), "r"(b0v), "r"(b1v))

// ---------------- split fp32 -> bf16 hi/lo ----------------
__device__ __forceinline__ void split_store4(const float* s, __nv_bfloat16* h,
                                             __nv_bfloat16* l, int i)
{
    float4 v = *(const float4*)(s + i);
    __nv_bfloat16 h0 = __float2bfloat16(v.x), h1 = __float2bfloat16(v.y);
    __nv_bfloat16 h2 = __float2bfloat16(v.z), h3 = __float2bfloat16(v.w);
    __nv_bfloat162 H0; H0.x = h0; H0.y = h1;
    __nv_bfloat162 H1; H1.x = h2; H1.y = h3;
    __nv_bfloat162 L0, L1;
    L0.x = __float2bfloat16(v.x - __bfloat162float(h0));
    L0.y = __float2bfloat16(v.y - __bfloat162float(h1));
    L1.x = __float2bfloat16(v.z - __bfloat162float(h2));
    L1.y = __float2bfloat16(v.w - __bfloat162float(h3));
    *(__nv_bfloat162*)(h + i)     = H0;
    *(__nv_bfloat162*)(h + i + 2) = H1;
    *(__nv_bfloat162*)(l + i)     = L0;
    *(__nv_bfloat162*)(l + i + 2) = L1;
}

__global__ __launch_bounds__(256) void splitk(const float* __restrict__ s,
                                              __nv_bfloat16* __restrict__ h,
                                              __nv_bfloat16* __restrict__ l, int n)
{
    int i = (blockIdx.x * 256 + threadIdx.x) * 4;
    if (i >= n) return;
    split_store4(s, h, l, i);
}

// merged weight split: z selects Wq/Wk/Wv/Wo
__global__ __launch_bounds__(256) void splitW4(
    const float* __restrict__ Wq, const float* __restrict__ Wk,
    const float* __restrict__ Wv, const float* __restrict__ Wo,
    __nv_bfloat16* __restrict__ Wqh, __nv_bfloat16* __restrict__ Wql,
    __nv_bfloat16* __restrict__ Wkh, __nv_bfloat16* __restrict__ Wkl,
    __nv_bfloat16* __restrict__ Wvh, __nv_bfloat16* __restrict__ Wvl,
    __nv_bfloat16* __restrict__ Woh, __nv_bfloat16* __restrict__ Wol)
{
    const int z = blockIdx.z;
    const float* s = (z == 0) ? Wq : (z == 1) ? Wk : (z == 2) ? Wv : Wo;
    __nv_bfloat16* h = (z == 0) ? Wqh : (z == 1) ? Wkh : (z == 2) ? Wvh : Woh;
    __nv_bfloat16* l = (z == 0) ? Wql : (z == 1) ? Wkl : (z == 2) ? Wvl : Wol;
    int i = (blockIdx.x * 256 + threadIdx.x) * 4;
    split_store4(s, h, l, i);
}

// ---------------- common GEMM tile params ----------------
#define NS   3
#define PITCH 80
#define MATB (128*PITCH)
#define STG  (4*MATB)
#define MM_SMEM (NS*STG)

// ---------------- merged QKV projection GEMM, z = blockIdx.z selects Q/K/V ------
__global__ __launch_bounds__(256, 1) void qkv_hmma(
    const __nv_bfloat16* __restrict__ xh, const __nv_bfloat16* __restrict__ xl,
    const __nv_bfloat16* __restrict__ Wqh, const __nv_bfloat16* __restrict__ Wql,
    const __nv_bfloat16* __restrict__ Wkh, const __nv_bfloat16* __restrict__ Wkl,
    const __nv_bfloat16* __restrict__ Wvh, const __nv_bfloat16* __restrict__ Wvl,
    const float* __restrict__ bq, const float* __restrict__ bk, const float* __restrict__ bv,
    float* __restrict__ Qf,
    __nv_bfloat16* __restrict__ Qh, __nv_bfloat16* __restrict__ Ql,
    __nv_bfloat16* __restrict__ Kh, __nv_bfloat16* __restrict__ Kl,
    __nv_bfloat16* __restrict__ Vth, __nv_bfloat16* __restrict__ Vtl)
{
    extern __shared__ char dsm[];
    const uint32_t sbase = smem_u32(dsm);

    const int tid  = threadIdx.x;
    const int wid  = tid >> 5;
    const int lane = tid & 31;
    const int wm   = wid & 1;
    const int wn   = wid >> 1;
    const int z    = blockIdx.z;
    const int bm   = blockIdx.y * 128;
    const int bn   = blockIdx.x * 128;
    const int K    = 1024;

    const __nv_bfloat16* Bh_ = (z == 0) ? Wqh : (z == 1) ? Wkh : Wvh;
    const __nv_bfloat16* Bl_ = (z == 0) ? Wql : (z == 1) ? Wkl : Wvl;
    const float* bias = (z == 0) ? bq : (z == 1) ? bk : bv;

    const __nv_bfloat16* Ah = xh + (long)bm * K;
    const __nv_bfloat16* Al = xl + (long)bm * K;
    const __nv_bfloat16* Bh = Bh_ + (long)bn * K;
    const __nv_bfloat16* Bl = Bl_ + (long)bn * K;

    float acc[4][4][4];
#pragma unroll
    for (int i = 0; i < 4; i++)
#pragma unroll
        for (int j = 0; j < 4; j++)
#pragma unroll
            for (int c = 0; c < 4; c++) acc[i][j][c] = 0.f;

    const int KS = K >> 5;

    auto load_stage = [&](int slot, int ks) {
        const uint32_t base = sbase + slot * STG;
        const int k0 = ks * 32;
#pragma unroll
        for (int c = tid; c < 512; c += 256) {
            const int r = c >> 2, seg = c & 3;
            const uint32_t d = base + r * PITCH + seg * 16;
            const long off = (long)r * K + k0 + seg * 8;
            cpa16(d,            Ah + off);
            cpa16(d + MATB,     Al + off);
            cpa16(d + 2*MATB,   Bh + off);
            cpa16(d + 3*MATB,   Bl + off);
        }
    };

#pragma unroll
    for (int s = 0; s < NS - 1; s++) {
        load_stage(s, s);
        CPA_COMMIT();
    }

    const uint32_t a_row = (uint32_t)(wm * 64 + (lane & 15)) * PITCH;
    const uint32_t b_row = (uint32_t)(wn * 32 + (lane & 15)) * PITCH;
    const uint32_t lcol  = (uint32_t)((lane >> 4) * 16);

    for (int k = 0; k < KS; k++) {
        const int kl = k + NS - 1;
        if (kl < KS) load_stage(kl % NS, kl);
        CPA_COMMIT();
        CPA_WAIT2();
        __syncthreads();

        const uint32_t st = sbase + (k % NS) * STG;
#pragma unroll
        for (int kc = 0; kc < 2; kc++) {
            const uint32_t col = kc * 32 + lcol;
            uint32_t ah[4][4], al[4][4], bh[2][4], bl[2][4];
#pragma unroll
            for (int mt = 0; mt < 4; mt++) {
                const uint32_t ad = st + a_row + (uint32_t)(mt * 16 * PITCH) + col;
                LDSM4(ah[mt], ad);
                LDSM4(al[mt], ad + MATB);
            }
#pragma unroll
            for (int np = 0; np < 2; np++) {
                const uint32_t bd = st + 2*MATB + b_row + (uint32_t)(np * 16 * PITCH) + col;
                LDSM4(bh[np], bd);
                LDSM4(bl[np], bd + MATB);
            }
#pragma unroll
            for (int mt = 0; mt < 4; mt++)
#pragma unroll
                for (int nt = 0; nt < 4; nt++) {
                    const int np = nt >> 1, i = nt & 1;
                    MMA_BF16(acc[mt][nt], ah[mt], bh[np][i], bh[np][i + 2]);
                    MMA_BF16(acc[mt][nt], ah[mt], bl[np][i], bl[np][i + 2]);
                    MMA_BF16(acc[mt][nt], al[mt], bh[np][i], bh[np][i + 2]);
                }
        }
        __syncthreads();
    }

#pragma unroll
    for (int mt = 0; mt < 4; mt++)
#pragma unroll
        for (int nt = 0; nt < 4; nt++) {
            const int m0 = bm + wm * 64 + mt * 16 + (lane >> 2);
            const int n0 = bn + wn * 32 + nt * 8 + (lane & 3) * 2;
            const float b0 = bias[n0], b1 = bias[n0 + 1];
            const int h = n0 >> 6, dh0 = n0 & 63;
#pragma unroll
            for (int half = 0; half < 2; half++) {
                const int m = m0 + half * 8;
                const float v0 = acc[mt][nt][half * 2 + 0] + b0;
                const float v1 = acc[mt][nt][half * 2 + 1] + b1;
                const int b = m >> 10, t = m & 1023;
                __nv_bfloat16 hh0 = __float2bfloat16(v0);
                __nv_bfloat16 hh1 = __float2bfloat16(v1);
                __nv_bfloat16 ll0 = __float2bfloat16(v0 - __bfloat162float(hh0));
                __nv_bfloat16 ll1 = __float2bfloat16(v1 - __bfloat162float(hh1));
                if (z == 2) {
                    const long tb = (((long)(b * Hn + h) * DHn + dh0) * Tn) + t;
                    Vth[tb]      = hh0;  Vtl[tb]      = ll0;
                    Vth[tb + Tn] = hh1;  Vtl[tb + Tn] = ll1;
                } else {
                    const long base = (((long)(b * Hn + h) * Tn + t) * DHn) + dh0;
                    if (z == 0) {
                        Qf[base] = v0; Qf[base + 1] = v1;
                        Qh[base] = hh0; Qh[base + 1] = hh1;
                        Ql[base] = ll0; Ql[base + 1] = ll1;
                    } else {
                        Kh[base] = hh0; Kh[base + 1] = hh1;
                        Kl[base] = ll0; Kl[base + 1] = ll1;
                    }
                }
            }
        }
}

// ---------------- HMMA split-bf16 GEMM: C = (Ahi+Alo)(Bhi+Blo)^T + bias --------
__global__ __launch_bounds__(256, 1) void mm_hmma(
    const __nv_bfloat16* __restrict__ Ahi, const __nv_bfloat16* __restrict__ Alo,
    const __nv_bfloat16* __restrict__ Bhi, const __nv_bfloat16* __restrict__ Blo,
    const float* __restrict__ bias,
    float* __restrict__ Cf,
    int M, int N, int K, long sA, long sB, long sC, int causal)
{
    if (causal && blockIdx.x > blockIdx.y) return;

    extern __shared__ char dsm[];
    const uint32_t sbase = smem_u32(dsm);

    const int tid  = threadIdx.x;
    const int wid  = tid >> 5;
    const int lane = tid & 31;
    const int wm   = wid & 1;
    const int wn   = wid >> 1;
    const int z    = blockIdx.z;
    const int bm   = blockIdx.y * 128;
    const int bn   = blockIdx.x * 128;

    const __nv_bfloat16* Ah = Ahi + (long)z * sA + (long)bm * K;
    const __nv_bfloat16* Al = Alo + (long)z * sA + (long)bm * K;
    const __nv_bfloat16* Bh = Bhi + (long)z * sB + (long)bn * K;
    const __nv_bfloat16* Bl = Blo + (long)z * sB + (long)bn * K;

    float acc[4][4][4];
#pragma unroll
    for (int i = 0; i < 4; i++)
#pragma unroll
        for (int j = 0; j < 4; j++)
#pragma unroll
            for (int c = 0; c < 4; c++) acc[i][j][c] = 0.f;

    const int KS = K >> 5;

    auto load_stage = [&](int slot, int ks) {
        const uint32_t base = sbase + slot * STG;
        const int k0 = ks * 32;
#pragma unroll
        for (int c = tid; c < 512; c += 256) {
            const int r = c >> 2, seg = c & 3;
            const uint32_t d = base + r * PITCH + seg * 16;
            const long off = (long)r * K + k0 + seg * 8;
            cpa16(d,            Ah + off);
            cpa16(d + MATB,     Al + off);
            cpa16(d + 2*MATB,   Bh + off);
            cpa16(d + 3*MATB,   Bl + off);
        }
    };

#pragma unroll
    for (int s = 0; s < NS - 1; s++) {
        if (s < KS) load_stage(s, s);
        CPA_COMMIT();
    }

    const uint32_t a_row = (uint32_t)(wm * 64 + (lane & 15)) * PITCH;
    const uint32_t b_row = (uint32_t)(wn * 32 + (lane & 15)) * PITCH;
    const uint32_t lcol  = (uint32_t)((lane >> 4) * 16);

    for (int k = 0; k < KS; k++) {
        const int kl = k + NS - 1;
        if (kl < KS) load_stage(kl % NS, kl);
        CPA_COMMIT();
        CPA_WAIT2();
        __syncthreads();

        const uint32_t st = sbase + (k % NS) * STG;
#pragma unroll
        for (int kc = 0; kc < 2; kc++) {
            const uint32_t col = kc * 32 + lcol;
            uint32_t ah[4][4], al[4][4], bh[2][4], bl[2][4];
#pragma unroll
            for (int mt = 0; mt < 4; mt++) {
                const uint32_t ad = st + a_row + (uint32_t)(mt * 16 * PITCH) + col;
                LDSM4(ah[mt], ad);
                LDSM4(al[mt], ad + MATB);
            }
#pragma unroll
            for (int np = 0; np < 2; np++) {
                const uint32_t bd = st + 2*MATB + b_row + (uint32_t)(np * 16 * PITCH) + col;
                LDSM4(bh[np], bd);
                LDSM4(bl[np], bd + MATB);
            }
#pragma unroll
            for (int mt = 0; mt < 4; mt++)
#pragma unroll
                for (int nt = 0; nt < 4; nt++) {
                    const int np = nt >> 1, i = nt & 1;
                    MMA_BF16(acc[mt][nt], ah[mt], bh[np][i], bh[np][i + 2]);
                    MMA_BF16(acc[mt][nt], ah[mt], bl[np][i], bl[np][i + 2]);
                    MMA_BF16(acc[mt][nt], al[mt], bh[np][i], bh[np][i + 2]);
                }
        }
        __syncthreads();
    }

#pragma unroll
    for (int mt = 0; mt < 4; mt++)
#pragma unroll
        for (int nt = 0; nt < 4; nt++) {
            const int m0 = bm + wm * 64 + mt * 16 + (lane >> 2);
            const int n0 = bn + wn * 32 + nt * 8 + (lane & 3) * 2;
            float b0 = 0.f, b1 = 0.f;
            if (bias) { b0 = bias[n0]; b1 = bias[n0 + 1]; }
#pragma unroll
            for (int half = 0; half < 2; half++) {
                const int m = m0 + half * 8;
                float* cp = Cf + (long)z * sC + (long)m * N + n0;
                cp[0] = acc[mt][nt][half * 2 + 0] + b0;
                cp[1] = acc[mt][nt][half * 2 + 1] + b1;
            }
        }
}

// ---------------- qpe table ----------------
__global__ __launch_bounds__(256) void qpe_kernel(const float* __restrict__ PE,
                                                  const float* __restrict__ Q,
                                                  float* __restrict__ QPE)
{
    const int it = blockIdx.x, bh = blockIdx.y, h = bh & (Hn - 1);
    const float* Aq = Q + ((long)bh * Tn + it * 64) * DHn;
    const float* Bp = PE + (long)h * MAXP * DHn;

    __shared__ float Qs[64][65];
    __shared__ float Ps[64][65];

    const int tid = threadIdx.x;
    const int rowb = tid >> 4, c4 = (tid & 15) << 2;
#pragma unroll
    for (int r = 0; r < 4; r++) {
        int row = rowb + r * 16;
        float4 q4 = *(const float4*)(Aq + (long)row * DHn + c4);
        Qs[row][c4] = q4.x; Qs[row][c4 + 1] = q4.y;
        Qs[row][c4 + 2] = q4.z; Qs[row][c4 + 3] = q4.w;
        float4 p4 = *(const float4*)(Bp + (long)row * DHn + c4);
        Ps[row][c4] = p4.x; Ps[row][c4 + 1] = p4.y;
        Ps[row][c4 + 2] = p4.z; Ps[row][c4 + 3] = p4.w;
    }
    __syncthreads();

    const int tx = tid & 15, ty = tid >> 4;
    float acc[4][4];
#pragma unroll
    for (int i = 0; i < 4; i++)
#pragma unroll
        for (int j = 0; j < 4; j++) acc[i][j] = 0.f;

#pragma unroll 16
    for (int kk = 0; kk < 64; kk++) {
        float a0 = Qs[ty * 4 + 0][kk], a1 = Qs[ty * 4 + 1][kk];
        float a2 = Qs[ty * 4 + 2][kk], a3 = Qs[ty * 4 + 3][kk];
        float b0 = Ps[tx * 4 + 0][kk], b1 = Ps[tx * 4 + 1][kk];
        float b2 = Ps[tx * 4 + 2][kk], b3 = Ps[tx * 4 + 3][kk];
        acc[0][0] = fmaf(a0, b0, acc[0][0]); acc[0][1] = fmaf(a0, b1, acc[0][1]);
        acc[0][2] = fmaf(a0, b2, acc[0][2]); acc[0][3] = fmaf(a0, b3, acc[0][3]);
        acc[1][0] = fmaf(a1, b0, acc[1][0]); acc[1][1] = fmaf(a1, b1, acc[1][1]);
        acc[1][2] = fmaf(a1, b2, acc[1][2]); acc[1][3] = fmaf(a1, b3, acc[1][3]);
        acc[2][0] = fmaf(a2, b0, acc[2][0]); acc[2][1] = fmaf(a2, b1, acc[2][1]);
        acc[2][2] = fmaf(a2, b2, acc[2][2]); acc[2][3] = fmaf(a2, b3, acc[2][3]);
        acc[3][0] = fmaf(a3, b0, acc[3][0]); acc[3][1] = fmaf(a3, b1, acc[3][1]);
        acc[3][2] = fmaf(a3, b2, acc[3][2]); acc[3][3] = fmaf(a3, b3, acc[3][3]);
    }

    float* out = QPE + ((long)bh * Tn + it * 64) * MAXP;
#pragma unroll
    for (int ii = 0; ii < 4; ii++) {
        float4 o4 = make_float4(acc[ii][0], acc[ii][1], acc[ii][2], acc[ii][3]);
        *(float4*)(out + (long)(ty * 4 + ii) * MAXP + tx * 4) = o4;
    }
}

// ---------------- CoPE warp-per-row: gates + suffix-sum + interp + softmax ------------
// 8 warps/block, warp w owns row i = blockIdx.x*8 + w of (bh = blockIdx.y).
// Reverse chunk iteration computes pos[j] = sum_{k>j,k<=i} g[k] directly (suffix sum).
__global__ __launch_bounds__(256) void cope_kernel(const float* __restrict__ S,
                                                   const float* __restrict__ QPE,
                                                   __nv_bfloat16* __restrict__ Ph,
                                                   __nv_bfloat16* __restrict__ Pl)
{
    const int warp = threadIdx.x >> 5, lane = threadIdx.x & 31;
    const int i  = blockIdx.x * 8 + warp;
    const int bh = blockIdx.y;
    const float* row = S + ((long)bh * Tn + i) * Tn;
    const long prow  = ((long)bh * Tn + i) * Tn;

    __shared__ float qpes[8][64];
    {
        const float* qpe = QPE + ((long)bh * Tn + i) * MAXP;
        float2 q2 = *(const float2*)(qpe + lane * 2);
        qpes[warp][lane * 2]     = q2.x;
        qpes[warp][lane * 2 + 1] = q2.y;
    }
    __syncwarp();

    const int cmax = i >> 5;                 // last chunk with valid j
    float score[32];
    float carry = 0.f;                       // suffix sum of chunks > c

    // pass 1: reverse chunks — gates, per-chunk suffix scan, pos, interp, raw score
#pragma unroll
    for (int cc = 0; cc < 32; cc++) {
        const int c = 31 - cc;
        if (c > cmax) continue;              // warp-uniform
        const int j = c * 32 + lane;
        const float qk = row[j];             // coalesced 128B
        const bool valid = (j <= i);
        float g = 0.f;
        if (valid)
            g = __fdividef(1.f, 1.f + __expf(-0.125f * qk));
        // inclusive suffix scan within chunk: s[lane] = sum_{l>=lane} g[l]
        float s = g;
#pragma unroll
        for (int o = 1; o < 32; o <<= 1) {
            float t = __shfl_down_sync(0xffffffffu, s, o);
            if (lane + o < 32) s += t;
        }
        float pos = carry + (s - g);         // sum over k > j within row
        carry += __shfl_sync(0xffffffffu, s, 0);   // chunk total
        float sc = -INFINITY;
        if (valid) {
            pos = fminf(fmaxf(pos, 0.f), 63.f);
            float pf = floorf(pos);
            int fi = (int)pf;
            float al = pos - pf;
            int ci = (fi < 63) ? fi + 1 : 63;
            float qf = qpes[warp][fi], qc = qpes[warp][ci];
            sc = 0.125f * (qk + (qf + al * (qc - qf)));
        }
        score[c] = sc;
    }

    // pass 2: row max
    float mx = -INFINITY;
#pragma unroll
    for (int c = 0; c < 32; c++) {
        if (c > cmax) continue;
        mx = fmaxf(mx, score[c]);
    }
#pragma unroll
    for (int o = 16; o; o >>= 1) mx = fmaxf(mx, __shfl_xor_sync(0xffffffffu, mx, o));

    // pass 3: exp (overwrite score) + sum
    float ssum = 0.f;
#pragma unroll
    for (int c = 0; c < 32; c++) {
        if (c > cmax) continue;
        float e = (score[c] == -INFINITY) ? 0.f : __expf(score[c] - mx);
        score[c] = e;
        ssum += e;
    }
#pragma unroll
    for (int o = 16; o; o >>= 1) ssum += __shfl_xor_sync(0xffffffffu, ssum, o);
    const float inv = __fdividef(1.f, ssum);

    // pass 4: store probs (hi/lo) out to the 128-block causal extent; zeros beyond i
    const int cstore = ((i >> 7) + 1) * 4;   // chunks of 32 within blockend
#pragma unroll
    for (int c = 0; c < 32; c++) {
        if (c >= cstore) continue;
        const int j = c * 32 + lane;
        float p = (c <= cmax) ? score[c] * inv : 0.f;
        __nv_bfloat16 hh = __float2bfloat16(p);
        Ph[prow + j] = hh;
        Pl[prow + j] = __float2bfloat16(p - __bfloat162float(hh));
    }
}

// ---------------- pv HMMA: AO = P @ V ----------------
#define PPITCH 144
#define PMATB (128*PPITCH)
#define VMATB (64*PPITCH)
#define PVSTG (2*PMATB + 2*VMATB)
#define PV_SMEM (2*PVSTG)

__global__ __launch_bounds__(256, 1) void pv_hmma(
    const __nv_bfloat16* __restrict__ Ph, const __nv_bfloat16* __restrict__ Pl,
    const __nv_bfloat16* __restrict__ Vth, const __nv_bfloat16* __restrict__ Vtl,
    __nv_bfloat16* __restrict__ AOh, __nv_bfloat16* __restrict__ AOl)
{
    extern __shared__ char dsm[];
    const uint32_t sbase = smem_u32(dsm);

    const int tid  = threadIdx.x;
    const int wid  = tid >> 5;
    const int lane = tid & 31;
    const int wm   = wid & 1;
    const int wn   = wid >> 1;
    const int it   = blockIdx.x;
    const int bh   = blockIdx.y;
    const int b    = bh >> 4, h = bh & 15;

    const __nv_bfloat16* Pr_h = Ph + ((long)bh * Tn + it * 128) * Tn;
    const __nv_bfloat16* Pr_l = Pl + ((long)bh * Tn + it * 128) * Tn;
    const __nv_bfloat16* Vh_  = Vth + (long)bh * DHn * Tn;
    const __nv_bfloat16* Vl_  = Vtl + (long)bh * DHn * Tn;

    float acc[4][2][4];
#pragma unroll
    for (int i = 0; i < 4; i++)
#pragma unroll
        for (int j = 0; j < 2; j++)
#pragma unroll
            for (int c = 0; c < 4; c++) acc[i][j][c] = 0.f;

    const int KS = 2 * (it + 1);

    auto load_stage = [&](int slot, int ks) {
        const uint32_t base = sbase + slot * PVSTG;
        const int k0 = ks * 64;
#pragma unroll
        for (int c = tid; c < 1024; c += 256) {
            const int r = c >> 3, seg = c & 7;
            const uint32_t d = base + r * PPITCH + seg * 16;
            const long off = (long)r * Tn + k0 + seg * 8;
            cpa16(d,         Pr_h + off);
            cpa16(d + PMATB, Pr_l + off);
        }
#pragma unroll
        for (int c = tid; c < 512; c += 256) {
            const int r = c >> 3, seg = c & 7;
            const uint32_t d = base + 2*PMATB + r * PPITCH + seg * 16;
            const long off = (long)r * Tn + k0 + seg * 8;
            cpa16(d,         Vh_ + off);
            cpa16(d + VMATB, Vl_ + off);
        }
        CPA_COMMIT();
    };

    load_stage(0, 0);

    const uint32_t a_row = (uint32_t)(wm * 64 + (lane & 15)) * PPITCH;
    const uint32_t b_row = (uint32_t)(wn * 16 + (lane & 15)) * PPITCH;
    const uint32_t lcol  = (uint32_t)((lane >> 4) * 16);

    for (int k = 0; k < KS; k++) {
        if (k + 1 < KS) load_stage((k + 1) & 1, k + 1);
        if (k + 1 < KS) { CPA_WAIT1(); } else { CPA_WAIT0(); }
        __syncthreads();

        const uint32_t st = sbase + (k & 1) * PVSTG;
#pragma unroll
        for (int kc = 0; kc < 4; kc++) {
            const uint32_t col = kc * 32 + lcol;
            uint32_t ah[4][4], al[4][4], bh4[4], bl4[4];
#pragma unroll
            for (int mt = 0; mt < 4; mt++) {
                const uint32_t ad = st + a_row + (uint32_t)(mt * 16 * PPITCH) + col;
                LDSM4(ah[mt], ad);
                LDSM4(al[mt], ad + PMATB);
            }
            {
                const uint32_t bd = st + 2*PMATB + b_row + col;
                LDSM4(bh4, bd);
                LDSM4(bl4, bd + VMATB);
            }
#pragma unroll
            for (int mt = 0; mt < 4; mt++)
#pragma unroll
                for (int nt = 0; nt < 2; nt++) {
                    MMA_BF16(acc[mt][nt], ah[mt], bh4[nt], bh4[nt + 2]);
                    MMA_BF16(acc[mt][nt], ah[mt], bl4[nt], bl4[nt + 2]);
                    MMA_BF16(acc[mt][nt], al[mt], bh4[nt], bh4[nt + 2]);
                }
        }
        __syncthreads();
    }

#pragma unroll
    for (int mt = 0; mt < 4; mt++)
#pragma unroll
        for (int nt = 0; nt < 2; nt++) {
            const int i0 = it * 128 + wm * 64 + mt * 16 + (lane >> 2);
            const int dh = wn * 16 + nt * 8 + (lane & 3) * 2;
#pragma unroll
            for (int half = 0; half < 2; half++) {
                const int t = i0 + half * 8;
                const float v0 = acc[mt][nt][half * 2 + 0];
                const float v1 = acc[mt][nt][half * 2 + 1];
                const long base = ((long)b * Tn + t) * Dm + h * 64 + dh;
                __nv_bfloat16 h0 = __float2bfloat16(v0);
                __nv_bfloat16 h1 = __float2bfloat16(v1);
                __nv_bfloat162 H; H.x = h0; H.y = h1;
                __nv_bfloat162 L;
                L.x = __float2bfloat16(v0 - __bfloat162float(h0));
                L.y = __float2bfloat16(v1 - __bfloat162float(h1));
                *(__nv_bfloat162*)(AOh + base) = H;
                *(__nv_bfloat162*)(AOl + base) = L;
            }
        }
}

// ---------------- launcher ----------------
extern "C" void kernel_launch(void* const* d_in, const int* in_sizes, int n_in,
                              void* d_out, int out_size)
{
    (void)in_sizes; (void)n_in; (void)out_size;
    const float* x  = (const float*)d_in[0];
    const float* Wq = (const float*)d_in[1];
    const float* bq = (const float*)d_in[2];
    const float* Wk = (const float*)d_in[3];
    const float* bk = (const float*)d_in[4];
    const float* Wv = (const float*)d_in[5];
    const float* bv = (const float*)d_in[6];
    const float* Wo = (const float*)d_in[7];
    const float* bo = (const float*)d_in[8];
    const float* pe = (const float*)d_in[9];
    float* out = (float*)d_out;

    float *Qf, *QPEd, *Sd;
    __nv_bfloat16 *xh, *xl, *Wqh, *Wql, *Wkh, *Wkl, *Wvh, *Wvl, *Woh, *Wol;
    __nv_bfloat16 *Qh, *Ql, *Kh, *Kl, *AOh, *AOl, *Phd, *Pld, *Vth, *Vtl;
    cudaGetSymbolAddress((void**)&Qf, g_Qf);
    cudaGetSymbolAddress((void**)&QPEd, g_QPE);
    cudaGetSymbolAddress((void**)&Sd, g_S);
    cudaGetSymbolAddress((void**)&xh, g_xh);   cudaGetSymbolAddress((void**)&xl, g_xl);
    cudaGetSymbolAddress((void**)&Wqh, g_Wqh); cudaGetSymbolAddress((void**)&Wql, g_Wql);
    cudaGetSymbolAddress((void**)&Wkh, g_Wkh); cudaGetSymbolAddress((void**)&Wkl, g_Wkl);
    cudaGetSymbolAddress((void**)&Wvh, g_Wvh); cudaGetSymbolAddress((void**)&Wvl, g_Wvl);
    cudaGetSymbolAddress((void**)&Woh, g_Woh); cudaGetSymbolAddress((void**)&Wol, g_Wol);
    cudaGetSymbolAddress((void**)&Qh, g_Qh);   cudaGetSymbolAddress((void**)&Ql, g_Ql);
    cudaGetSymbolAddress((void**)&Kh, g_Kh);   cudaGetSymbolAddress((void**)&Kl, g_Kl);
    cudaGetSymbolAddress((void**)&AOh, g_AOh); cudaGetSymbolAddress((void**)&AOl, g_AOl);
    cudaGetSymbolAddress((void**)&Phd, g_Ph);  cudaGetSymbolAddress((void**)&Pld, g_Pl);
    cudaGetSymbolAddress((void**)&Vth, g_Vth); cudaGetSymbolAddress((void**)&Vtl, g_Vtl);

    static int smem_set = 0;
    if (!smem_set) {
        cudaFuncSetAttribute(mm_hmma, cudaFuncAttributeMaxDynamicSharedMemorySize, MM_SMEM);
        cudaFuncSetAttribute(qkv_hmma, cudaFuncAttributeMaxDynamicSharedMemorySize, MM_SMEM);
        cudaFuncSetAttribute(pv_hmma, cudaFuncAttributeMaxDynamicSharedMemorySize, PV_SMEM);
        smem_set = 1;
    }

    dim3 blk(256);

    splitk<<<2048, blk>>>(x, xh, xl, Bsz * Tn * Dm);
    splitW4<<<dim3(1024, 1, 4), blk>>>(Wq, Wk, Wv, Wo, Wqh, Wql, Wkh, Wkl,
                                       Wvh, Wvl, Woh, Wol);

    qkv_hmma<<<dim3(8, 16, 3), blk, MM_SMEM>>>(xh, xl, Wqh, Wql, Wkh, Wkl, Wvh, Wvl,
                                               bq, bk, bv, Qf, Qh, Ql, Kh, Kl, Vth, Vtl);

    mm_hmma<<<dim3(8, 8, 32), blk, MM_SMEM>>>(Qh, Ql, Kh, Kl, nullptr,
                                              Sd, 1024, 1024, 64,
                                              (long)Tn * DHn, (long)Tn * DHn, (long)Tn * Tn, 1);

    qpe_kernel<<<dim3(16, 32), blk>>>(pe, Qf, QPEd);

    cope_kernel<<<dim3(128, 32), blk>>>(Sd, QPEd, Phd, Pld);

    pv_hmma<<<dim3(8, 32), blk, PV_SMEM>>>(Phd, Pld, Vth, Vtl, AOh, AOl);

    mm_hmma<<<dim3(8, 16, 1), blk, MM_SMEM>>>(AOh, AOl, Woh, Wol, bo,
                                              out, 2048, 1024, 1024, 0, 0, 0, 0);
}

// round 7
// speedup vs baseline: 1.0869x; 1.0869x over previous
#include <cuda_runtime.h>
#include <cuda_bf16.h>
#include <math.h>
#include <stdint.h>

#define Bsz 2
#define Tn  1024
#define Dm  1024
#define Hn  16
#define DHn 64
#define BHn (Bsz*Hn)
#define MAXP 64

// ---------------- scratch ----------------
__device__ float g_Qf[BHn*Tn*DHn];
__device__ float g_QPE[BHn*Tn*MAXP];
__device__ float g_S[(long)BHn*Tn*Tn];
__device__ __nv_bfloat16 g_Ph[(long)BHn*Tn*Tn], g_Pl[(long)BHn*Tn*Tn];
__device__ __nv_bfloat16 g_Vth[BHn*DHn*Tn], g_Vtl[BHn*DHn*Tn];
__device__ __nv_bfloat16 g_xh[Bsz*Tn*Dm],  g_xl[Bsz*Tn*Dm];
__device__ __nv_bfloat16 g_Wqh[Dm*Dm], g_Wql[Dm*Dm];
__device__ __nv_bfloat16 g_Wkh[Dm*Dm], g_Wkl[Dm*Dm];
__device__ __nv_bfloat16 g_Wvh[Dm*Dm], g_Wvl[Dm*Dm];
__device__ __nv_bfloat16 g_Woh[Dm*Dm], g_Wol[Dm*Dm];
__device__ __nv_bfloat16 g_Qh[BHn*Tn*DHn], g_Ql[BHn*Tn*DHn];
__device__ __nv_bfloat16 g_Kh[BHn*Tn*DHn], g_Kl[BHn*Tn*DHn];
__device__ __nv_bfloat16 g_AOh[Bsz*Tn*Dm], g_AOl[Bsz*Tn*Dm];

// ---------------- helpers ----------------
__device__ __forceinline__ uint32_t smem_u32(const void* p) {
    uint32_t a;
    asm("{ .reg .u64 t; cvta.to.shared.u64 t, %1; cvt.u32.u64 %0, t; }" : "=r"(a) : "l"(p));
    return a;
}
__device__ __forceinline__ void cpa16(uint32_t dst, const void* src) {
    asm volatile("cp.async.cg.shared.global [%0], [%1], 16;" :: "r"(dst), "l"(src));
}
#define CPA_COMMIT() asm volatile("cp.async.commit_group;" ::: "memory")
#define CPA_WAIT2()  asm volatile("cp.async.wait_group 2;" ::: "memory")
#define CPA_WAIT1()  asm volatile("cp.async.wait_group 1;" ::: "memory")
#define CPA_WAIT0()  asm volatile("cp.async.wait_group 0;" ::: "memory")

#define LDSM4(r, a) \
    asm volatile("ldmatrix.sync.aligned.m8n8.x4.shared.b16 {%0,%1,%2,%3}, [%4];" \
        : "=r"((r)[0]), "=r"((r)[1]), "=r"((r)[2]), "=r"((r)[3]) : "r"(a))

#define MMA_BF16(c, a, b0v, b1v) \
    asm volatile("mma.sync.aligned.m16n8k16.row.col.f32.bf16.bf16.f32 " \
        "{%0,%1,%2,%3},{%4,%5,%6,%7},{%8,%9},{%0,%1,%2,%3};" \
        : "+f"((c)[0]), "+f"((c)[1]), "+f"((c)[2]), "+f"((c)[3]) \
        : "r"((a)[0]), "r"((a)[1]), "r"((a)[2]), "r"((a)[3]), "r"(b0v), "r"(b1v))

// ---------------- split fp32 -> bf16 hi/lo ----------------
__device__ __forceinline__ void split_store4(const float* s, __nv_bfloat16* h,
                                             __nv_bfloat16* l, int i)
{
    float4 v = *(const float4*)(s + i);
    __nv_bfloat16 h0 = __float2bfloat16(v.x), h1 = __float2bfloat16(v.y);
    __nv_bfloat16 h2 = __float2bfloat16(v.z), h3 = __float2bfloat16(v.w);
    __nv_bfloat162 H0; H0.x = h0; H0.y = h1;
    __nv_bfloat162 H1; H1.x = h2; H1.y = h3;
    __nv_bfloat162 L0, L1;
    L0.x = __float2bfloat16(v.x - __bfloat162float(h0));
    L0.y = __float2bfloat16(v.y - __bfloat162float(h1));
    L1.x = __float2bfloat16(v.z - __bfloat162float(h2));
    L1.y = __float2bfloat16(v.w - __bfloat162float(h3));
    *(__nv_bfloat162*)(h + i)     = H0;
    *(__nv_bfloat162*)(h + i + 2) = H1;
    *(__nv_bfloat162*)(l + i)     = L0;
    *(__nv_bfloat162*)(l + i + 2) = L1;
}

__global__ __launch_bounds__(256) void splitk(const float* __restrict__ s,
                                              __nv_bfloat16* __restrict__ h,
                                              __nv_bfloat16* __restrict__ l, int n)
{
    int i = (blockIdx.x * 256 + threadIdx.x) * 4;
    if (i >= n) return;
    split_store4(s, h, l, i);
}

__global__ __launch_bounds__(256) void splitW4(
    const float* __restrict__ Wq, const float* __restrict__ Wk,
    const float* __restrict__ Wv, const float* __restrict__ Wo,
    __nv_bfloat16* __restrict__ Wqh, __nv_bfloat16* __restrict__ Wql,
    __nv_bfloat16* __restrict__ Wkh, __nv_bfloat16* __restrict__ Wkl,
    __nv_bfloat16* __restrict__ Wvh, __nv_bfloat16* __restrict__ Wvl,
    __nv_bfloat16* __restrict__ Woh, __nv_bfloat16* __restrict__ Wol)
{
    const int z = blockIdx.z;
    const float* s = (z == 0) ? Wq : (z == 1) ? Wk : (z == 2) ? Wv : Wo;
    __nv_bfloat16* h = (z == 0) ? Wqh : (z == 1) ? Wkh : (z == 2) ? Wvh : Woh;
    __nv_bfloat16* l = (z == 0) ? Wql : (z == 1) ? Wkl : (z == 2) ? Wvl : Wol;
    int i = (blockIdx.x * 256 + threadIdx.x) * 4;
    split_store4(s, h, l, i);
}

// ---------------- common GEMM tile params (512 threads, 16 warps) ----------------
#define NS   3
#define PITCH 80
#define MATB (128*PITCH)
#define STG  (4*MATB)
#define MM_SMEM (NS*STG)

// ---------------- merged QKV projection GEMM (512 thr), z selects Q/K/V ------
__global__ __launch_bounds__(512, 1) void qkv_hmma(
    const __nv_bfloat16* __restrict__ xh, const __nv_bfloat16* __restrict__ xl,
    const __nv_bfloat16* __restrict__ Wqh, const __nv_bfloat16* __restrict__ Wql,
    const __nv_bfloat16* __restrict__ Wkh, const __nv_bfloat16* __restrict__ Wkl,
    const __nv_bfloat16* __restrict__ Wvh, const __nv_bfloat16* __restrict__ Wvl,
    const float* __restrict__ bq, const float* __restrict__ bk, const float* __restrict__ bv,
    float* __restrict__ Qf,
    __nv_bfloat16* __restrict__ Qh, __nv_bfloat16* __restrict__ Ql,
    __nv_bfloat16* __restrict__ Kh, __nv_bfloat16* __restrict__ Kl,
    __nv_bfloat16* __restrict__ Vth, __nv_bfloat16* __restrict__ Vtl)
{
    extern __shared__ char dsm[];
    const uint32_t sbase = smem_u32(dsm);

    const int tid  = threadIdx.x;
    const int wid  = tid >> 5;
    const int lane = tid & 31;
    const int wm   = wid & 3;      // 4 m-slices of 32
    const int wn   = wid >> 2;     // 4 n-slices of 32
    const int z    = blockIdx.z;
    const int bm   = blockIdx.y * 128;
    const int bn   = blockIdx.x * 128;
    const int K    = 1024;

    const __nv_bfloat16* Bh_ = (z == 0) ? Wqh : (z == 1) ? Wkh : Wvh;
    const __nv_bfloat16* Bl_ = (z == 0) ? Wql : (z == 1) ? Wkl : Wvl;
    const float* bias = (z == 0) ? bq : (z == 1) ? bk : bv;

    const __nv_bfloat16* Ah = xh + (long)bm * K;
    const __nv_bfloat16* Al = xl + (long)bm * K;
    const __nv_bfloat16* Bh = Bh_ + (long)bn * K;
    const __nv_bfloat16* Bl = Bl_ + (long)bn * K;

    float acc[2][4][4];
#pragma unroll
    for (int i = 0; i < 2; i++)
#pragma unroll
        for (int j = 0; j < 4; j++)
#pragma unroll
            for (int c = 0; c < 4; c++) acc[i][j][c] = 0.f;

    const int KS = K >> 5;

    auto load_stage = [&](int slot, int ks) {
        const uint32_t base = sbase + slot * STG;
        const int k0 = ks * 32;
        const int r = tid >> 2, seg = tid & 3;   // 512 chunks, one per thread
        const uint32_t d = base + r * PITCH + seg * 16;
        const long off = (long)r * K + k0 + seg * 8;
        cpa16(d,            Ah + off);
        cpa16(d + MATB,     Al + off);
        cpa16(d + 2*MATB,   Bh + off);
        cpa16(d + 3*MATB,   Bl + off);
    };

#pragma unroll
    for (int s = 0; s < NS - 1; s++) {
        load_stage(s, s);
        CPA_COMMIT();
    }

    const uint32_t a_row = (uint32_t)(wm * 32 + (lane & 15)) * PITCH;
    const uint32_t b_row = (uint32_t)(wn * 32 + (lane & 15)) * PITCH;
    const uint32_t lcol  = (uint32_t)((lane >> 4) * 16);

    for (int k = 0; k < KS; k++) {
        const int kl = k + NS - 1;
        if (kl < KS) load_stage(kl % NS, kl);
        CPA_COMMIT();
        CPA_WAIT2();
        __syncthreads();

        const uint32_t st = sbase + (k % NS) * STG;
#pragma unroll
        for (int kc = 0; kc < 2; kc++) {
            const uint32_t col = kc * 32 + lcol;
            uint32_t ah[2][4], al[2][4], bh[2][4], bl[2][4];
#pragma unroll
            for (int mt = 0; mt < 2; mt++) {
                const uint32_t ad = st + a_row + (uint32_t)(mt * 16 * PITCH) + col;
                LDSM4(ah[mt], ad);
                LDSM4(al[mt], ad + MATB);
            }
#pragma unroll
            for (int np = 0; np < 2; np++) {
                const uint32_t bd = st + 2*MATB + b_row + (uint32_t)(np * 16 * PITCH) + col;
                LDSM4(bh[np], bd);
                LDSM4(bl[np], bd + MATB);
            }
#pragma unroll
            for (int mt = 0; mt < 2; mt++)
#pragma unroll
                for (int nt = 0; nt < 4; nt++) {
                    const int np = nt >> 1, i = nt & 1;
                    MMA_BF16(acc[mt][nt], ah[mt], bh[np][i], bh[np][i + 2]);
                    MMA_BF16(acc[mt][nt], ah[mt], bl[np][i], bl[np][i + 2]);
                    MMA_BF16(acc[mt][nt], al[mt], bh[np][i], bh[np][i + 2]);
                }
        }
        __syncthreads();
    }

#pragma unroll
    for (int mt = 0; mt < 2; mt++)
#pragma unroll
        for (int nt = 0; nt < 4; nt++) {
            const int m0 = bm + wm * 32 + mt * 16 + (lane >> 2);
            const int n0 = bn + wn * 32 + nt * 8 + (lane & 3) * 2;
            const float b0 = bias[n0], b1 = bias[n0 + 1];
            const int h = n0 >> 6, dh0 = n0 & 63;
#pragma unroll
            for (int half = 0; half < 2; half++) {
                const int m = m0 + half * 8;
                const float v0 = acc[mt][nt][half * 2 + 0] + b0;
                const float v1 = acc[mt][nt][half * 2 + 1] + b1;
                const int b = m >> 10, t = m & 1023;
                __nv_bfloat16 hh0 = __float2bfloat16(v0);
                __nv_bfloat16 hh1 = __float2bfloat16(v1);
                __nv_bfloat16 ll0 = __float2bfloat16(v0 - __bfloat162float(hh0));
                __nv_bfloat16 ll1 = __float2bfloat16(v1 - __bfloat162float(hh1));
                if (z == 2) {
                    const long tb = (((long)(b * Hn + h) * DHn + dh0) * Tn) + t;
                    Vth[tb]      = hh0;  Vtl[tb]      = ll0;
                    Vth[tb + Tn] = hh1;  Vtl[tb + Tn] = ll1;
                } else {
                    const long base = (((long)(b * Hn + h) * Tn + t) * DHn) + dh0;
                    if (z == 0) {
                        Qf[base] = v0; Qf[base + 1] = v1;
                        Qh[base] = hh0; Qh[base + 1] = hh1;
                        Ql[base] = ll0; Ql[base + 1] = ll1;
                    } else {
                        Kh[base] = hh0; Kh[base + 1] = hh1;
                        Kl[base] = ll0; Kl[base + 1] = ll1;
                    }
                }
            }
        }
}

// ---------------- generic HMMA GEMM (512 thr): C = (Ahi+Alo)(Bhi+Blo)^T + bias ----
__global__ __launch_bounds__(512, 1) void mm_hmma(
    const __nv_bfloat16* __restrict__ Ahi, const __nv_bfloat16* __restrict__ Alo,
    const __nv_bfloat16* __restrict__ Bhi, const __nv_bfloat16* __restrict__ Blo,
    const float* __restrict__ bias,
    float* __restrict__ Cf,
    int M, int N, int K, long sA, long sB, long sC, int causal)
{
    if (causal && blockIdx.x > blockIdx.y) return;

    extern __shared__ char dsm[];
    const uint32_t sbase = smem_u32(dsm);

    const int tid  = threadIdx.x;
    const int wid  = tid >> 5;
    const int lane = tid & 31;
    const int wm   = wid & 3;
    const int wn   = wid >> 2;
    const int z    = blockIdx.z;
    const int bm   = blockIdx.y * 128;
    const int bn   = blockIdx.x * 128;

    const __nv_bfloat16* Ah = Ahi + (long)z * sA + (long)bm * K;
    const __nv_bfloat16* Al = Alo + (long)z * sA + (long)bm * K;
    const __nv_bfloat16* Bh = Bhi + (long)z * sB + (long)bn * K;
    const __nv_bfloat16* Bl = Blo + (long)z * sB + (long)bn * K;

    float acc[2][4][4];
#pragma unroll
    for (int i = 0; i < 2; i++)
#pragma unroll
        for (int j = 0; j < 4; j++)
#pragma unroll
            for (int c = 0; c < 4; c++) acc[i][j][c] = 0.f;

    const int KS = K >> 5;

    auto load_stage = [&](int slot, int ks) {
        const uint32_t base = sbase + slot * STG;
        const int k0 = ks * 32;
        const int r = tid >> 2, seg = tid & 3;
        const uint32_t d = base + r * PITCH + seg * 16;
        const long off = (long)r * K + k0 + seg * 8;
        cpa16(d,            Ah + off);
        cpa16(d + MATB,     Al + off);
        cpa16(d + 2*MATB,   Bh + off);
        cpa16(d + 3*MATB,   Bl + off);
    };

#pragma unroll
    for (int s = 0; s < NS - 1; s++) {
        if (s < KS) load_stage(s, s);
        CPA_COMMIT();
    }

    const uint32_t a_row = (uint32_t)(wm * 32 + (lane & 15)) * PITCH;
    const uint32_t b_row = (uint32_t)(wn * 32 + (lane & 15)) * PITCH;
    const uint32_t lcol  = (uint32_t)((lane >> 4) * 16);

    for (int k = 0; k < KS; k++) {
        const int kl = k + NS - 1;
        if (kl < KS) load_stage(kl % NS, kl);
        CPA_COMMIT();
        CPA_WAIT2();
        __syncthreads();

        const uint32_t st = sbase + (k % NS) * STG;
#pragma unroll
        for (int kc = 0; kc < 2; kc++) {
            const uint32_t col = kc * 32 + lcol;
            uint32_t ah[2][4], al[2][4], bh[2][4], bl[2][4];
#pragma unroll
            for (int mt = 0; mt < 2; mt++) {
                const uint32_t ad = st + a_row + (uint32_t)(mt * 16 * PITCH) + col;
                LDSM4(ah[mt], ad);
                LDSM4(al[mt], ad + MATB);
            }
#pragma unroll
            for (int np = 0; np < 2; np++) {
                const uint32_t bd = st + 2*MATB + b_row + (uint32_t)(np * 16 * PITCH) + col;
                LDSM4(bh[np], bd);
                LDSM4(bl[np], bd + MATB);
            }
#pragma unroll
            for (int mt = 0; mt < 2; mt++)
#pragma unroll
                for (int nt = 0; nt < 4; nt++) {
                    const int np = nt >> 1, i = nt & 1;
                    MMA_BF16(acc[mt][nt], ah[mt], bh[np][i], bh[np][i + 2]);
                    MMA_BF16(acc[mt][nt], ah[mt], bl[np][i], bl[np][i + 2]);
                    MMA_BF16(acc[mt][nt], al[mt], bh[np][i], bh[np][i + 2]);
                }
        }
        __syncthreads();
    }

#pragma unroll
    for (int mt = 0; mt < 2; mt++)
#pragma unroll
        for (int nt = 0; nt < 4; nt++) {
            const int m0 = bm + wm * 32 + mt * 16 + (lane >> 2);
            const int n0 = bn + wn * 32 + nt * 8 + (lane & 3) * 2;
            float b0 = 0.f, b1 = 0.f;
            if (bias) { b0 = bias[n0]; b1 = bias[n0 + 1]; }
#pragma unroll
            for (int half = 0; half < 2; half++) {
                const int m = m0 + half * 8;
                float* cp = Cf + (long)z * sC + (long)m * N + n0;
                cp[0] = acc[mt][nt][half * 2 + 0] + b0;
                cp[1] = acc[mt][nt][half * 2 + 1] + b1;
            }
        }
}

// ---------------- qpe table ----------------
__global__ __launch_bounds__(256) void qpe_kernel(const float* __restrict__ PE,
                                                  const float* __restrict__ Q,
                                                  float* __restrict__ QPE)
{
    const int it = blockIdx.x, bh = blockIdx.y, h = bh & (Hn - 1);
    const float* Aq = Q + ((long)bh * Tn + it * 64) * DHn;
    const float* Bp = PE + (long)h * MAXP * DHn;

    __shared__ float Qs[64][65];
    __shared__ float Ps[64][65];

    const int tid = threadIdx.x;
    const int rowb = tid >> 4, c4 = (tid & 15) << 2;
#pragma unroll
    for (int r = 0; r < 4; r++) {
        int row = rowb + r * 16;
        float4 q4 = *(const float4*)(Aq + (long)row * DHn + c4);
        Qs[row][c4] = q4.x; Qs[row][c4 + 1] = q4.y;
        Qs[row][c4 + 2] = q4.z; Qs[row][c4 + 3] = q4.w;
        float4 p4 = *(const float4*)(Bp + (long)row * DHn + c4);
        Ps[row][c4] = p4.x; Ps[row][c4 + 1] = p4.y;
        Ps[row][c4 + 2] = p4.z; Ps[row][c4 + 3] = p4.w;
    }
    __syncthreads();

    const int tx = tid & 15, ty = tid >> 4;
    float acc[4][4];
#pragma unroll
    for (int i = 0; i < 4; i++)
#pragma unroll
        for (int j = 0; j < 4; j++) acc[i][j] = 0.f;

#pragma unroll 16
    for (int kk = 0; kk < 64; kk++) {
        float a0 = Qs[ty * 4 + 0][kk], a1 = Qs[ty * 4 + 1][kk];
        float a2 = Qs[ty * 4 + 2][kk], a3 = Qs[ty * 4 + 3][kk];
        float b0 = Ps[tx * 4 + 0][kk], b1 = Ps[tx * 4 + 1][kk];
        float b2 = Ps[tx * 4 + 2][kk], b3 = Ps[tx * 4 + 3][kk];
        acc[0][0] = fmaf(a0, b0, acc[0][0]); acc[0][1] = fmaf(a0, b1, acc[0][1]);
        acc[0][2] = fmaf(a0, b2, acc[0][2]); acc[0][3] = fmaf(a0, b3, acc[0][3]);
        acc[1][0] = fmaf(a1, b0, acc[1][0]); acc[1][1] = fmaf(a1, b1, acc[1][1]);
        acc[1][2] = fmaf(a1, b2, acc[1][2]); acc[1][3] = fmaf(a1, b3, acc[1][3]);
        acc[2][0] = fmaf(a2, b0, acc[2][0]); acc[2][1] = fmaf(a2, b1, acc[2][1]);
        acc[2][2] = fmaf(a2, b2, acc[2][2]); acc[2][3] = fmaf(a2, b3, acc[2][3]);
        acc[3][0] = fmaf(a3, b0, acc[3][0]); acc[3][1] = fmaf(a3, b1, acc[3][1]);
        acc[3][2] = fmaf(a3, b2, acc[3][2]); acc[3][3] = fmaf(a3, b3, acc[3][3]);
    }

    float* out = QPE + ((long)bh * Tn + it * 64) * MAXP;
#pragma unroll
    for (int ii = 0; ii < 4; ii++) {
        float4 o4 = make_float4(acc[ii][0], acc[ii][1], acc[ii][2], acc[ii][3]);
        *(float4*)(out + (long)(ty * 4 + ii) * MAXP + tx * 4) = o4;
    }
}

// ---------------- CoPE (round-5 block-per-row version, measured fastest) ---------------
__global__ __launch_bounds__(256) void cope_kernel(const float* __restrict__ S,
                                                   const float* __restrict__ QPE,
                                                   __nv_bfloat16* __restrict__ Ph,
                                                   __nv_bfloat16* __restrict__ Pl)
{
    const int i = blockIdx.x, bh = blockIdx.y;
    const float* row = S + ((long)bh * Tn + i) * Tn;
    const long prow = ((long)bh * Tn + i) * Tn;
    const float* qpe = QPE + ((long)bh * Tn + i) * MAXP;
    const int blockend = ((i >> 7) + 1) << 7;

    __shared__ float qpes[64];
    __shared__ float wred[8];
    __shared__ float wred2[8];

    const int tid = threadIdx.x, lane = tid & 31, wid = tid >> 5;
    if (tid < 64) qpes[tid] = qpe[tid];

    const int j0 = tid << 2;
    float qk[4] = {0.f, 0.f, 0.f, 0.f};
    if (j0 <= i) {
        float4 s4 = *(const float4*)(row + j0);
        qk[0] = s4.x; qk[1] = s4.y; qk[2] = s4.z; qk[3] = s4.w;
    }

    float lpre[4];
    float run = 0.f;
#pragma unroll
    for (int q = 0; q < 4; q++) {
        float gg = 0.f;
        if (j0 + q <= i)
            gg = __fdividef(1.f, 1.f + __expf(-0.125f * qk[q]));
        run += gg;
        lpre[q] = run;
    }

    float v = run;
#pragma unroll
    for (int o = 1; o < 32; o <<= 1) {
        float t = __shfl_up_sync(0xffffffffu, v, o);
        if (lane >= o) v += t;
    }
    if (lane == 31) wred[wid] = v;
    __syncthreads();
    if (tid < 8) {
        float w = wred[tid];
#pragma unroll
        for (int o = 1; o < 8; o <<= 1) {
            float t = __shfl_up_sync(0x000000ffu, w, o);
            if (tid >= o) w += t;
        }
        wred[tid] = w;
    }
    __syncthreads();
    const float base  = (v - run) + (wid ? wred[wid - 1] : 0.f);
    const float total = wred[7];

    float sc[4];
    float mx = -INFINITY;
#pragma unroll
    for (int q = 0; q < 4; q++) {
        float s_ = -INFINITY;
        if (j0 + q <= i) {
            float pos = total - (base + lpre[q]);
            pos = fminf(fmaxf(pos, 0.f), 63.f);
            float pf = floorf(pos);
            int fi = (int)pf;
            float al = pos - pf;
            int ci = (fi < 63) ? fi + 1 : 63;
            float qf = qpes[fi], qc = qpes[ci];
            float qv = qf + al * (qc - qf);
            s_ = 0.125f * (qk[q] + qv);
        }
        sc[q] = s_;
        mx = fmaxf(mx, s_);
    }
#pragma unroll
    for (int o = 16; o; o >>= 1) mx = fmaxf(mx, __shfl_xor_sync(0xffffffffu, mx, o));
    if (lane == 0) wred2[wid] = mx;
    __syncthreads();
    float bmax = wred2[0];
#pragma unroll
    for (int k = 1; k < 8; k++) bmax = fmaxf(bmax, wred2[k]);

    float p[4];
    float ssum = 0.f;
#pragma unroll
    for (int q = 0; q < 4; q++) {
        float e = (j0 + q <= i) ? __expf(sc[q] - bmax) : 0.f;
        p[q] = e;
        ssum += e;
    }
#pragma unroll
    for (int o = 16; o; o >>= 1) ssum += __shfl_xor_sync(0xffffffffu, ssum, o);
    __syncthreads();
    if (lane == 0) wred2[wid] = ssum;
    __syncthreads();
    float tot = 0.f;
#pragma unroll
    for (int k = 0; k < 8; k++) tot += wred2[k];
    const float inv = __fdividef(1.f, tot);

    if (j0 < blockend) {
        float v0 = p[0] * inv, v1 = p[1] * inv, v2 = p[2] * inv, v3 = p[3] * inv;
        __nv_bfloat16 h0 = __float2bfloat16(v0), h1 = __float2bfloat16(v1);
        __nv_bfloat16 h2 = __float2bfloat16(v2), h3 = __float2bfloat16(v3);
        __nv_bfloat162 H0; H0.x = h0; H0.y = h1;
        __nv_bfloat162 H1; H1.x = h2; H1.y = h3;
        __nv_bfloat162 L0, L1;
        L0.x = __float2bfloat16(v0 - __bfloat162float(h0));
        L0.y = __float2bfloat16(v1 - __bfloat162float(h1));
        L1.x = __float2bfloat16(v2 - __bfloat162float(h2));
        L1.y = __float2bfloat16(v3 - __bfloat162float(h3));
        *(__nv_bfloat162*)(Ph + prow + j0)     = H0;
        *(__nv_bfloat162*)(Ph + prow + j0 + 2) = H1;
        *(__nv_bfloat162*)(Pl + prow + j0)     = L0;
        *(__nv_bfloat162*)(Pl + prow + j0 + 2) = L1;
    }
}

// ---------------- pv HMMA (512 thr): AO = P @ V ----------------
#define PPITCH 144
#define PMATB (128*PPITCH)
#define VMATB (64*PPITCH)
#define PVSTG (2*PMATB + 2*VMATB)
#define PV_SMEM (2*PVSTG)

__global__ __launch_bounds__(512, 1) void pv_hmma(
    const __nv_bfloat16* __restrict__ Ph, const __nv_bfloat16* __restrict__ Pl,
    const __nv_bfloat16* __restrict__ Vth, const __nv_bfloat16* __restrict__ Vtl,
    __nv_bfloat16* __restrict__ AOh, __nv_bfloat16* __restrict__ AOl)
{
    extern __shared__ char dsm[];
    const uint32_t sbase = smem_u32(dsm);

    const int tid  = threadIdx.x;
    const int wid  = tid >> 5;
    const int lane = tid & 31;
    const int wm   = wid & 3;      // 4 m-slices of 32
    const int wn   = wid >> 2;     // 4 n-slices of 16
    const int it   = blockIdx.x;
    const int bh   = blockIdx.y;
    const int b    = bh >> 4, h = bh & 15;

    const __nv_bfloat16* Pr_h = Ph + ((long)bh * Tn + it * 128) * Tn;
    const __nv_bfloat16* Pr_l = Pl + ((long)bh * Tn + it * 128) * Tn;
    const __nv_bfloat16* Vh_  = Vth + (long)bh * DHn * Tn;
    const __nv_bfloat16* Vl_  = Vtl + (long)bh * DHn * Tn;

    float acc[2][2][4];
#pragma unroll
    for (int i = 0; i < 2; i++)
#pragma unroll
        for (int j = 0; j < 2; j++)
#pragma unroll
            for (int c = 0; c < 4; c++) acc[i][j][c] = 0.f;

    const int KS = 2 * (it + 1);

    auto load_stage = [&](int slot, int ks) {
        const uint32_t base = sbase + slot * PVSTG;
        const int k0 = ks * 64;
#pragma unroll
        for (int c = tid; c < 1024; c += 512) {
            const int r = c >> 3, seg = c & 7;
            const uint32_t d = base + r * PPITCH + seg * 16;
            const long off = (long)r * Tn + k0 + seg * 8;
            cpa16(d,         Pr_h + off);
            cpa16(d + PMATB, Pr_l + off);
        }
        if (tid < 512) {
            const int r = tid >> 3, seg = tid & 7;
            if (r < 64) {
                const uint32_t d = base + 2*PMATB + r * PPITCH + seg * 16;
                const long off = (long)r * Tn + k0 + seg * 8;
                cpa16(d,         Vh_ + off);
                cpa16(d + VMATB, Vl_ + off);
            }
        }
        CPA_COMMIT();
    };

    load_stage(0, 0);

    const uint32_t a_row = (uint32_t)(wm * 32 + (lane & 15)) * PPITCH;
    const uint32_t b_row = (uint32_t)(wn * 16 + (lane & 15)) * PPITCH;
    const uint32_t lcol  = (uint32_t)((lane >> 4) * 16);

    for (int k = 0; k < KS; k++) {
        if (k + 1 < KS) load_stage((k + 1) & 1, k + 1);
        if (k + 1 < KS) { CPA_WAIT1(); } else { CPA_WAIT0(); }
        __syncthreads();

        const uint32_t st = sbase + (k & 1) * PVSTG;
#pragma unroll
        for (int kc = 0; kc < 4; kc++) {
            const uint32_t col = kc * 32 + lcol;
            uint32_t ah[2][4], al[2][4], bh4[4], bl4[4];
#pragma unroll
            for (int mt = 0; mt < 2; mt++) {
                const uint32_t ad = st + a_row + (uint32_t)(mt * 16 * PPITCH) + col;
                LDSM4(ah[mt], ad);
                LDSM4(al[mt], ad + PMATB);
            }
            {
                const uint32_t bd = st + 2*PMATB + b_row + col;
                LDSM4(bh4, bd);
                LDSM4(bl4, bd + VMATB);
            }
#pragma unroll
            for (int mt = 0; mt < 2; mt++)
#pragma unroll
                for (int nt = 0; nt < 2; nt++) {
                    MMA_BF16(acc[mt][nt], ah[mt], bh4[nt], bh4[nt + 2]);
                    MMA_BF16(acc[mt][nt], ah[mt], bl4[nt], bl4[nt + 2]);
                    MMA_BF16(acc[mt][nt], al[mt], bh4[nt], bh4[nt + 2]);
                }
        }
        __syncthreads();
    }

#pragma unroll
    for (int mt = 0; mt < 2; mt++)
#pragma unroll
        for (int nt = 0; nt < 2; nt++) {
            const int i0 = it * 128 + wm * 32 + mt * 16 + (lane >> 2);
            const int dh = wn * 16 + nt * 8 + (lane & 3) * 2;
#pragma unroll
            for (int half = 0; half < 2; half++) {
                const int t = i0 + half * 8;
                const float v0 = acc[mt][nt][half * 2 + 0];
                const float v1 = acc[mt][nt][half * 2 + 1];
                const long base = ((long)b * Tn + t) * Dm + h * 64 + dh;
                __nv_bfloat16 h0 = __float2bfloat16(v0);
                __nv_bfloat16 h1 = __float2bfloat16(v1);
                __nv_bfloat162 H; H.x = h0; H.y = h1;
                __nv_bfloat162 L;
                L.x = __float2bfloat16(v0 - __bfloat162float(h0));
                L.y = __float2bfloat16(v1 - __bfloat162float(h1));
                *(__nv_bfloat162*)(AOh + base) = H;
                *(__nv_bfloat162*)(AOl + base) = L;
            }
        }
}

// ---------------- launcher ----------------
extern "C" void kernel_launch(void* const* d_in, const int* in_sizes, int n_in,
                              void* d_out, int out_size)
{
    (void)in_sizes; (void)n_in; (void)out_size;
    const float* x  = (const float*)d_in[0];
    const float* Wq = (const float*)d_in[1];
    const float* bq = (const float*)d_in[2];
    const float* Wk = (const float*)d_in[3];
    const float* bk = (const float*)d_in[4];
    const float* Wv = (const float*)d_in[5];
    const float* bv = (const float*)d_in[6];
    const float* Wo = (const float*)d_in[7];
    const float* bo = (const float*)d_in[8];
    const float* pe = (const float*)d_in[9];
    float* out = (float*)d_out;

    float *Qf, *QPEd, *Sd;
    __nv_bfloat16 *xh, *xl, *Wqh, *Wql, *Wkh, *Wkl, *Wvh, *Wvl, *Woh, *Wol;
    __nv_bfloat16 *Qh, *Ql, *Kh, *Kl, *AOh, *AOl, *Phd, *Pld, *Vth, *Vtl;
    cudaGetSymbolAddress((void**)&Qf, g_Qf);
    cudaGetSymbolAddress((void**)&QPEd, g_QPE);
    cudaGetSymbolAddress((void**)&Sd, g_S);
    cudaGetSymbolAddress((void**)&xh, g_xh);   cudaGetSymbolAddress((void**)&xl, g_xl);
    cudaGetSymbolAddress((void**)&Wqh, g_Wqh); cudaGetSymbolAddress((void**)&Wql, g_Wql);
    cudaGetSymbolAddress((void**)&Wkh, g_Wkh); cudaGetSymbolAddress((void**)&Wkl, g_Wkl);
    cudaGetSymbolAddress((void**)&Wvh, g_Wvh); cudaGetSymbolAddress((void**)&Wvl, g_Wvl);
    cudaGetSymbolAddress((void**)&Woh, g_Woh); cudaGetSymbolAddress((void**)&Wol, g_Wol);
    cudaGetSymbolAddress((void**)&Qh, g_Qh);   cudaGetSymbolAddress((void**)&Ql, g_Ql);
    cudaGetSymbolAddress((void**)&Kh, g_Kh);   cudaGetSymbolAddress((void**)&Kl, g_Kl);
    cudaGetSymbolAddress((void**)&AOh, g_AOh); cudaGetSymbolAddress((void**)&AOl, g_AOl);
    cudaGetSymbolAddress((void**)&Phd, g_Ph);  cudaGetSymbolAddress((void**)&Pld, g_Pl);
    cudaGetSymbolAddress((void**)&Vth, g_Vth); cudaGetSymbolAddress((void**)&Vtl, g_Vtl);

    static int smem_set = 0;
    if (!smem_set) {
        cudaFuncSetAttribute(mm_hmma, cudaFuncAttributeMaxDynamicSharedMemorySize, MM_SMEM);
        cudaFuncSetAttribute(qkv_hmma, cudaFuncAttributeMaxDynamicSharedMemorySize, MM_SMEM);
        cudaFuncSetAttribute(pv_hmma, cudaFuncAttributeMaxDynamicSharedMemorySize, PV_SMEM);
        smem_set = 1;
    }

    dim3 blk(256), blk512(512);

    splitk<<<2048, blk>>>(x, xh, xl, Bsz * Tn * Dm);
    splitW4<<<dim3(1024, 1, 4), blk>>>(Wq, Wk, Wv, Wo, Wqh, Wql, Wkh, Wkl,
                                       Wvh, Wvl, Woh, Wol);

    qkv_hmma<<<dim3(8, 16, 3), blk512, MM_SMEM>>>(xh, xl, Wqh, Wql, Wkh, Wkl, Wvh, Wvl,
                                                  bq, bk, bv, Qf, Qh, Ql, Kh, Kl, Vth, Vtl);

    mm_hmma<<<dim3(8, 8, 32), blk512, MM_SMEM>>>(Qh, Ql, Kh, Kl, nullptr,
                                                 Sd, 1024, 1024, 64,
                                                 (long)Tn * DHn, (long)Tn * DHn, (long)Tn * Tn, 1);

    qpe_kernel<<<dim3(16, 32), blk>>>(pe, Qf, QPEd);

    cope_kernel<<<dim3(1024, 32), blk>>>(Sd, QPEd, Phd, Pld);

    pv_hmma<<<dim3(8, 32), blk512, PV_SMEM>>>(Phd, Pld, Vth, Vtl, AOh, AOl);

    mm_hmma<<<dim3(8, 16, 1), blk512, MM_SMEM>>>(AOh, AOl, Woh, Wol, bo,
                                                 out, 2048, 1024, 1024, 0, 0, 0, 0);
}

// round 8
// speedup vs baseline: 1.1026x; 1.0144x over previous
#include <cuda_runtime.h>
#include <cuda_bf16.h>
#include <math.h>
#include <stdint.h>

#define Bsz 2
#define Tn  1024
#define Dm  1024
#define Hn  16
#define DHn 64
#define BHn (Bsz*Hn)
#define MAXP 64

// ---------------- scratch ----------------
__device__ float g_Qf[BHn*Tn*DHn];
__device__ float g_QPE[BHn*Tn*MAXP];
__device__ float g_S[(long)BHn*Tn*Tn];
__device__ __nv_bfloat16 g_Ph[(long)BHn*Tn*Tn], g_Pl[(long)BHn*Tn*Tn];
__device__ __nv_bfloat16 g_Vth[BHn*DHn*Tn], g_Vtl[BHn*DHn*Tn];
__device__ __nv_bfloat16 g_xh[Bsz*Tn*Dm],  g_xl[Bsz*Tn*Dm];
__device__ __nv_bfloat16 g_Wqh[Dm*Dm], g_Wql[Dm*Dm];
__device__ __nv_bfloat16 g_Wkh[Dm*Dm], g_Wkl[Dm*Dm];
__device__ __nv_bfloat16 g_Wvh[Dm*Dm], g_Wvl[Dm*Dm];
__device__ __nv_bfloat16 g_Woh[Dm*Dm], g_Wol[Dm*Dm];
__device__ __nv_bfloat16 g_Qh[BHn*Tn*DHn], g_Ql[BHn*Tn*DHn];
__device__ __nv_bfloat16 g_Kh[BHn*Tn*DHn], g_Kl[BHn*Tn*DHn];
__device__ __nv_bfloat16 g_AOh[Bsz*Tn*Dm], g_AOl[Bsz*Tn*Dm];

// ---------------- helpers ----------------
__device__ __forceinline__ uint32_t smem_u32(const void* p) {
    uint32_t a;
    asm("{ .reg .u64 t; cvta.to.shared.u64 t, %1; cvt.u32.u64 %0, t; }" : "=r"(a) : "l"(p));
    return a;
}
__device__ __forceinline__ void cpa16(uint32_t dst, const void* src) {
    asm volatile("cp.async.cg.shared.global [%0], [%1], 16;" :: "r"(dst), "l"(src));
}
#define CPA_COMMIT() asm volatile("cp.async.commit_group;" ::: "memory")
#define CPA_WAIT1()  asm volatile("cp.async.wait_group 1;" ::: "memory")

#define LDSM4(r, a) \
    asm volatile("ldmatrix.sync.aligned.m8n8.x4.shared.b16 {%0,%1,%2,%3}, [%4];" \
        : "=r"((r)[0]), "=r"((r)[1]), "=r"((r)[2]), "=r"((r)[3]) : "r"(a))

#define MMA_BF16(c, a, b0v, b1v) \
    asm volatile("mma.sync.aligned.m16n8k16.row.col.f32.bf16.bf16.f32 " \
        "{%0,%1,%2,%3},{%4,%5,%6,%7},{%8,%9},{%0,%1,%2,%3};" \
        : "+f"((c)[0]), "+f"((c)[1]), "+f"((c)[2]), "+f"((c)[3]) \
        : "r"((a)[0]), "r"((a)[1]), "r"((a)[2]), "r"((a)[3]), "r"(b0v), "r"(b1v))

// ---------------- split fp32 -> bf16 hi/lo ----------------
__device__ __forceinline__ void split_store4(const float* s, __nv_bfloat16* h,
                                             __nv_bfloat16* l, int i)
{
    float4 v = *(const float4*)(s + i);
    __nv_bfloat16 h0 = __float2bfloat16(v.x), h1 = __float2bfloat16(v.y);
    __nv_bfloat16 h2 = __float2bfloat16(v.z), h3 = __float2bfloat16(v.w);
    __nv_bfloat162 H0; H0.x = h0; H0.y = h1;
    __nv_bfloat162 H1; H1.x = h2; H1.y = h3;
    __nv_bfloat162 L0, L1;
    L0.x = __float2bfloat16(v.x - __bfloat162float(h0));
    L0.y = __float2bfloat16(v.y - __bfloat162float(h1));
    L1.x = __float2bfloat16(v.z - __bfloat162float(h2));
    L1.y = __float2bfloat16(v.w - __bfloat162float(h3));
    *(__nv_bfloat162*)(h + i)     = H0;
    *(__nv_bfloat162*)(h + i + 2) = H1;
    *(__nv_bfloat162*)(l + i)     = L0;
    *(__nv_bfloat162*)(l + i + 2) = L1;
}

__global__ __launch_bounds__(256) void splitk(const float* __restrict__ s,
                                              __nv_bfloat16* __restrict__ h,
                                              __nv_bfloat16* __restrict__ l, int n)
{
    int i = (blockIdx.x * 256 + threadIdx.x) * 4;
    if (i >= n) return;
    split_store4(s, h, l, i);
}

__global__ __launch_bounds__(256) void splitW4(
    const float* __restrict__ Wq, const float* __restrict__ Wk,
    const float* __restrict__ Wv, const float* __restrict__ Wo,
    __nv_bfloat16* __restrict__ Wqh, __nv_bfloat16* __restrict__ Wql,
    __nv_bfloat16* __restrict__ Wkh, __nv_bfloat16* __restrict__ Wkl,
    __nv_bfloat16* __restrict__ Wvh, __nv_bfloat16* __restrict__ Wvl,
    __nv_bfloat16* __restrict__ Woh, __nv_bfloat16* __restrict__ Wol)
{
    const int z = blockIdx.z;
    const float* s = (z == 0) ? Wq : (z == 1) ? Wk : (z == 2) ? Wv : Wo;
    __nv_bfloat16* h = (z == 0) ? Wqh : (z == 1) ? Wkh : (z == 2) ? Wvh : Woh;
    __nv_bfloat16* l = (z == 0) ? Wql : (z == 1) ? Wkl : (z == 2) ? Wvl : Wol;
    int i = (blockIdx.x * 256 + threadIdx.x) * 4;
    split_store4(s, h, l, i);
}

// ---------------- GEMM tile engine: BM=128, BN=64, BK=32, 256 thr, NS=2 --------
// smem stage: [Ah 128x80B][Al][Bh 64x80B][Bl] = 30720B; NS=2 -> 61440B -> 2 CTA/SM
#define PITCH 80
#define AMAT  (128*PITCH)          // 10240
#define BMAT  (64*PITCH)           // 5120
#define STG   (2*AMAT + 2*BMAT)    // 30720
#define MM_SMEM (2*STG)            // 61440

// generic: C(fp32) = (Ahi+Alo)(Bhi+Blo)^T + bias ; causal: skip bx >= 2*by+2
__global__ __launch_bounds__(256, 2) void mm_hmma(
    const __nv_bfloat16* __restrict__ Ahi, const __nv_bfloat16* __restrict__ Alo,
    const __nv_bfloat16* __restrict__ Bhi, const __nv_bfloat16* __restrict__ Blo,
    const float* __restrict__ bias,
    float* __restrict__ Cf,
    int M, int N, int K, long sA, long sB, long sC, int causal)
{
    if (causal && (int)blockIdx.x >= 2 * (int)blockIdx.y + 2) return;

    extern __shared__ char dsm[];
    const uint32_t sbase = smem_u32(dsm);

    const int tid  = threadIdx.x;
    const int wid  = tid >> 5;
    const int lane = tid & 31;
    const int wm   = wid & 3;        // 4 slices of 32 rows
    const int wn   = wid >> 2;       // 2 slices of 32 cols
    const int z    = blockIdx.z;
    const int bm   = blockIdx.y * 128;
    const int bn   = blockIdx.x * 64;

    const __nv_bfloat16* Ah = Ahi + (long)z * sA + (long)bm * K;
    const __nv_bfloat16* Al = Alo + (long)z * sA + (long)bm * K;
    const __nv_bfloat16* Bh = Bhi + (long)z * sB + (long)bn * K;
    const __nv_bfloat16* Bl = Blo + (long)z * sB + (long)bn * K;

    float acc[2][4][4];
#pragma unroll
    for (int i = 0; i < 2; i++)
#pragma unroll
        for (int j = 0; j < 4; j++)
#pragma unroll
            for (int c = 0; c < 4; c++) acc[i][j][c] = 0.f;

    const int KS = K >> 5;

    auto load_stage = [&](int slot, int ks) {
        const uint32_t base = sbase + slot * STG;
        const int k0 = ks * 32;
#pragma unroll
        for (int c = tid; c < 512; c += 256) {      // A: 128 rows x 4 segs
            const int r = c >> 2, seg = c & 3;
            const uint32_t d = base + r * PITCH + seg * 16;
            const long off = (long)r * K + k0 + seg * 8;
            cpa16(d,        Ah + off);
            cpa16(d + AMAT, Al + off);
        }
        {                                            // B: 64 rows x 4 segs
            const int r = tid >> 2, seg = tid & 3;   // tid<256 covers exactly
            const uint32_t d = base + 2*AMAT + r * PITCH + seg * 16;
            const long off = (long)r * K + k0 + seg * 8;
            cpa16(d,        Bh + off);
            cpa16(d + BMAT, Bl + off);
        }
    };

    load_stage(0, 0);
    CPA_COMMIT();

    const uint32_t a_row = (uint32_t)(wm * 32 + (lane & 15)) * PITCH;
    const uint32_t b_row = (uint32_t)(wn * 32 + (lane & 15)) * PITCH;
    const uint32_t lcol  = (uint32_t)((lane >> 4) * 16);

    for (int k = 0; k < KS; k++) {
        if (k + 1 < KS) load_stage((k + 1) & 1, k + 1);
        CPA_COMMIT();
        CPA_WAIT1();
        __syncthreads();

        const uint32_t st = sbase + (k & 1) * STG;
#pragma unroll
        for (int kc = 0; kc < 2; kc++) {
            const uint32_t col = kc * 32 + lcol;
            uint32_t ah[2][4], al[2][4], bh[2][4], bl[2][4];
#pragma unroll
            for (int mt = 0; mt < 2; mt++) {
                const uint32_t ad = st + a_row + (uint32_t)(mt * 16 * PITCH) + col;
                LDSM4(ah[mt], ad);
                LDSM4(al[mt], ad + AMAT);
            }
#pragma unroll
            for (int np = 0; np < 2; np++) {
                const uint32_t bd = st + 2*AMAT + b_row + (uint32_t)(np * 16 * PITCH) + col;
                LDSM4(bh[np], bd);
                LDSM4(bl[np], bd + BMAT);
            }
#pragma unroll
            for (int mt = 0; mt < 2; mt++)
#pragma unroll
                for (int nt = 0; nt < 4; nt++) {
                    const int np = nt >> 1, i = nt & 1;
                    MMA_BF16(acc[mt][nt], ah[mt], bh[np][i], bh[np][i + 2]);
                    MMA_BF16(acc[mt][nt], ah[mt], bl[np][i], bl[np][i + 2]);
                    MMA_BF16(acc[mt][nt], al[mt], bh[np][i], bh[np][i + 2]);
                }
        }
        __syncthreads();
    }

#pragma unroll
    for (int mt = 0; mt < 2; mt++)
#pragma unroll
        for (int nt = 0; nt < 4; nt++) {
            const int m0 = bm + wm * 32 + mt * 16 + (lane >> 2);
            const int n0 = bn + wn * 32 + nt * 8 + (lane & 3) * 2;
            float b0 = 0.f, b1 = 0.f;
            if (bias) { b0 = bias[n0]; b1 = bias[n0 + 1]; }
#pragma unroll
            for (int half = 0; half < 2; half++) {
                const int m = m0 + half * 8;
                float* cp = Cf + (long)z * sC + (long)m * N + n0;
                cp[0] = acc[mt][nt][half * 2 + 0] + b0;
                cp[1] = acc[mt][nt][half * 2 + 1] + b1;
            }
        }
}

// ---------------- merged QKV projection (same engine, scatter epilogue) --------
__global__ __launch_bounds__(256, 2) void qkv_hmma(
    const __nv_bfloat16* __restrict__ xh, const __nv_bfloat16* __restrict__ xl,
    const __nv_bfloat16* __restrict__ Wqh, const __nv_bfloat16* __restrict__ Wql,
    const __nv_bfloat16* __restrict__ Wkh, const __nv_bfloat16* __restrict__ Wkl,
    const __nv_bfloat16* __restrict__ Wvh, const __nv_bfloat16* __restrict__ Wvl,
    const float* __restrict__ bq, const float* __restrict__ bk, const float* __restrict__ bv,
    float* __restrict__ Qf,
    __nv_bfloat16* __restrict__ Qh, __nv_bfloat16* __restrict__ Ql,
    __nv_bfloat16* __restrict__ Kh, __nv_bfloat16* __restrict__ Kl,
    __nv_bfloat16* __restrict__ Vth, __nv_bfloat16* __restrict__ Vtl)
{
    extern __shared__ char dsm[];
    const uint32_t sbase = smem_u32(dsm);

    const int tid  = threadIdx.x;
    const int wid  = tid >> 5;
    const int lane = tid & 31;
    const int wm   = wid & 3;
    const int wn   = wid >> 2;
    const int z    = blockIdx.z;
    const int bm   = blockIdx.y * 128;
    const int bn   = blockIdx.x * 64;
    const int K    = 1024;

    const __nv_bfloat16* Bh_ = (z == 0) ? Wqh : (z == 1) ? Wkh : Wvh;
    const __nv_bfloat16* Bl_ = (z == 0) ? Wql : (z == 1) ? Wkl : Wvl;
    const float* bias = (z == 0) ? bq : (z == 1) ? bk : bv;

    const __nv_bfloat16* Ah = xh + (long)bm * K;
    const __nv_bfloat16* Al = xl + (long)bm * K;
    const __nv_bfloat16* Bh = Bh_ + (long)bn * K;
    const __nv_bfloat16* Bl = Bl_ + (long)bn * K;

    float acc[2][4][4];
#pragma unroll
    for (int i = 0; i < 2; i++)
#pragma unroll
        for (int j = 0; j < 4; j++)
#pragma unroll
            for (int c = 0; c < 4; c++) acc[i][j][c] = 0.f;

    const int KS = K >> 5;

    auto load_stage = [&](int slot, int ks) {
        const uint32_t base = sbase + slot * STG;
        const int k0 = ks * 32;
#pragma unroll
        for (int c = tid; c < 512; c += 256) {
            const int r = c >> 2, seg = c & 3;
            const uint32_t d = base + r * PITCH + seg * 16;
            const long off = (long)r * K + k0 + seg * 8;
            cpa16(d,        Ah + off);
            cpa16(d + AMAT, Al + off);
        }
        {
            const int r = tid >> 2, seg = tid & 3;
            const uint32_t d = base + 2*AMAT + r * PITCH + seg * 16;
            const long off = (long)r * K + k0 + seg * 8;
            cpa16(d,        Bh + off);
            cpa16(d + BMAT, Bl + off);
        }
    };

    load_stage(0, 0);
    CPA_COMMIT();

    const uint32_t a_row = (uint32_t)(wm * 32 + (lane & 15)) * PITCH;
    const uint32_t b_row = (uint32_t)(wn * 32 + (lane & 15)) * PITCH;
    const uint32_t lcol  = (uint32_t)((lane >> 4) * 16);

    for (int k = 0; k < KS; k++) {
        if (k + 1 < KS) load_stage((k + 1) & 1, k + 1);
        CPA_COMMIT();
        CPA_WAIT1();
        __syncthreads();

        const uint32_t st = sbase + (k & 1) * STG;
#pragma unroll
        for (int kc = 0; kc < 2; kc++) {
            const uint32_t col = kc * 32 + lcol;
            uint32_t ah[2][4], al[2][4], bh[2][4], bl[2][4];
#pragma unroll
            for (int mt = 0; mt < 2; mt++) {
                const uint32_t ad = st + a_row + (uint32_t)(mt * 16 * PITCH) + col;
                LDSM4(ah[mt], ad);
                LDSM4(al[mt], ad + AMAT);
            }
#pragma unroll
            for (int np = 0; np < 2; np++) {
                const uint32_t bd = st + 2*AMAT + b_row + (uint32_t)(np * 16 * PITCH) + col;
                LDSM4(bh[np], bd);
                LDSM4(bl[np], bd + BMAT);
            }
#pragma unroll
            for (int mt = 0; mt < 2; mt++)
#pragma unroll
                for (int nt = 0; nt < 4; nt++) {
                    const int np = nt >> 1, i = nt & 1;
                    MMA_BF16(acc[mt][nt], ah[mt], bh[np][i], bh[np][i + 2]);
                    MMA_BF16(acc[mt][nt], ah[mt], bl[np][i], bl[np][i + 2]);
                    MMA_BF16(acc[mt][nt], al[mt], bh[np][i], bh[np][i + 2]);
                }
        }
        __syncthreads();
    }

#pragma unroll
    for (int mt = 0; mt < 2; mt++)
#pragma unroll
        for (int nt = 0; nt < 4; nt++) {
            const int m0 = bm + wm * 32 + mt * 16 + (lane >> 2);
            const int n0 = bn + wn * 32 + nt * 8 + (lane & 3) * 2;
            const float b0 = bias[n0], b1 = bias[n0 + 1];
            const int h = n0 >> 6, dh0 = n0 & 63;
#pragma unroll
            for (int half = 0; half < 2; half++) {
                const int m = m0 + half * 8;
                const float v0 = acc[mt][nt][half * 2 + 0] + b0;
                const float v1 = acc[mt][nt][half * 2 + 1] + b1;
                const int b = m >> 10, t = m & 1023;
                __nv_bfloat16 hh0 = __float2bfloat16(v0);
                __nv_bfloat16 hh1 = __float2bfloat16(v1);
                __nv_bfloat16 ll0 = __float2bfloat16(v0 - __bfloat162float(hh0));
                __nv_bfloat16 ll1 = __float2bfloat16(v1 - __bfloat162float(hh1));
                if (z == 2) {
                    const long tb = (((long)(b * Hn + h) * DHn + dh0) * Tn) + t;
                    Vth[tb]      = hh0;  Vtl[tb]      = ll0;
                    Vth[tb + Tn] = hh1;  Vtl[tb + Tn] = ll1;
                } else {
                    const long base = (((long)(b * Hn + h) * Tn + t) * DHn) + dh0;
                    if (z == 0) {
                        Qf[base] = v0; Qf[base + 1] = v1;
                        Qh[base] = hh0; Qh[base + 1] = hh1;
                        Ql[base] = ll0; Ql[base + 1] = ll1;
                    } else {
                        Kh[base] = hh0; Kh[base + 1] = hh1;
                        Kl[base] = ll0; Kl[base + 1] = ll1;
                    }
                }
            }
        }
}

// ---------------- pv: AO = P @ V (same engine; P=A rows, Vt=B rows; causal KS) -
__global__ __launch_bounds__(256, 2) void pv_hmma(
    const __nv_bfloat16* __restrict__ Ph, const __nv_bfloat16* __restrict__ Pl,
    const __nv_bfloat16* __restrict__ Vth, const __nv_bfloat16* __restrict__ Vtl,
    __nv_bfloat16* __restrict__ AOh, __nv_bfloat16* __restrict__ AOl)
{
    extern __shared__ char dsm[];
    const uint32_t sbase = smem_u32(dsm);

    const int tid  = threadIdx.x;
    const int wid  = tid >> 5;
    const int lane = tid & 31;
    const int wm   = wid & 3;
    const int wn   = wid >> 2;
    const int it   = blockIdx.x;
    const int bh   = blockIdx.y;
    const int b    = bh >> 4, h = bh & 15;

    const __nv_bfloat16* Ah = Ph + ((long)bh * Tn + it * 128) * Tn;
    const __nv_bfloat16* Al = Pl + ((long)bh * Tn + it * 128) * Tn;
    const __nv_bfloat16* Bh = Vth + (long)bh * DHn * Tn;
    const __nv_bfloat16* Bl = Vtl + (long)bh * DHn * Tn;

    float acc[2][4][4];
#pragma unroll
    for (int i = 0; i < 2; i++)
#pragma unroll
        for (int j = 0; j < 4; j++)
#pragma unroll
            for (int c = 0; c < 4; c++) acc[i][j][c] = 0.f;

    const int KS = 4 * (it + 1);          // 32-wide k chunks over causal extent

    auto load_stage = [&](int slot, int ks) {
        const uint32_t base = sbase + slot * STG;
        const int k0 = ks * 32;
#pragma unroll
        for (int c = tid; c < 512; c += 256) {
            const int r = c >> 2, seg = c & 3;
            const uint32_t d = base + r * PITCH + seg * 16;
            const long off = (long)r * Tn + k0 + seg * 8;
            cpa16(d,        Ah + off);
            cpa16(d + AMAT, Al + off);
        }
        {
            const int r = tid >> 2, seg = tid & 3;
            const uint32_t d = base + 2*AMAT + r * PITCH + seg * 16;
            const long off = (long)r * Tn + k0 + seg * 8;
            cpa16(d,        Bh + off);
            cpa16(d + BMAT, Bl + off);
        }
    };

    load_stage(0, 0);
    CPA_COMMIT();

    const uint32_t a_row = (uint32_t)(wm * 32 + (lane & 15)) * PITCH;
    const uint32_t b_row = (uint32_t)(wn * 32 + (lane & 15)) * PITCH;
    const uint32_t lcol  = (uint32_t)((lane >> 4) * 16);

    for (int k = 0; k < KS; k++) {
        if (k + 1 < KS) load_stage((k + 1) & 1, k + 1);
        CPA_COMMIT();
        CPA_WAIT1();
        __syncthreads();

        const uint32_t st = sbase + (k & 1) * STG;
#pragma unroll
        for (int kc = 0; kc < 2; kc++) {
            const uint32_t col = kc * 32 + lcol;
            uint32_t ah[2][4], al[2][4], bh[2][4], bl[2][4];
#pragma unroll
            for (int mt = 0; mt < 2; mt++) {
                const uint32_t ad = st + a_row + (uint32_t)(mt * 16 * PITCH) + col;
                LDSM4(ah[mt], ad);
                LDSM4(al[mt], ad + AMAT);
            }
#pragma unroll
            for (int np = 0; np < 2; np++) {
                const uint32_t bd = st + 2*AMAT + b_row + (uint32_t)(np * 16 * PITCH) + col;
                LDSM4(bh[np], bd);
                LDSM4(bl[np], bd + BMAT);
            }
#pragma unroll
            for (int mt = 0; mt < 2; mt++)
#pragma unroll
                for (int nt = 0; nt < 4; nt++) {
                    const int np = nt >> 1, i = nt & 1;
                    MMA_BF16(acc[mt][nt], ah[mt], bh[np][i], bh[np][i + 2]);
                    MMA_BF16(acc[mt][nt], ah[mt], bl[np][i], bl[np][i + 2]);
                    MMA_BF16(acc[mt][nt], al[mt], bh[np][i], bh[np][i + 2]);
                }
        }
        __syncthreads();
    }

#pragma unroll
    for (int mt = 0; mt < 2; mt++)
#pragma unroll
        for (int nt = 0; nt < 4; nt++) {
            const int t0 = it * 128 + wm * 32 + mt * 16 + (lane >> 2);
            const int dh = wn * 32 + nt * 8 + (lane & 3) * 2;
#pragma unroll
            for (int half = 0; half < 2; half++) {
                const int t = t0 + half * 8;
                const float v0 = acc[mt][nt][half * 2 + 0];
                const float v1 = acc[mt][nt][half * 2 + 1];
                const long base = ((long)b * Tn + t) * Dm + h * 64 + dh;
                __nv_bfloat16 h0 = __float2bfloat16(v0);
                __nv_bfloat16 h1 = __float2bfloat16(v1);
                __nv_bfloat162 H; H.x = h0; H.y = h1;
                __nv_bfloat162 L;
                L.x = __float2bfloat16(v0 - __bfloat162float(h0));
                L.y = __float2bfloat16(v1 - __bfloat162float(h1));
                *(__nv_bfloat162*)(AOh + base) = H;
                *(__nv_bfloat162*)(AOl + base) = L;
            }
        }
}

// ---------------- qpe table ----------------
__global__ __launch_bounds__(256) void qpe_kernel(const float* __restrict__ PE,
                                                  const float* __restrict__ Q,
                                                  float* __restrict__ QPE)
{
    const int it = blockIdx.x, bh = blockIdx.y, h = bh & (Hn - 1);
    const float* Aq = Q + ((long)bh * Tn + it * 64) * DHn;
    const float* Bp = PE + (long)h * MAXP * DHn;

    __shared__ float Qs[64][65];
    __shared__ float Ps[64][65];

    const int tid = threadIdx.x;
    const int rowb = tid >> 4, c4 = (tid & 15) << 2;
#pragma unroll
    for (int r = 0; r < 4; r++) {
        int row = rowb + r * 16;
        float4 q4 = *(const float4*)(Aq + (long)row * DHn + c4);
        Qs[row][c4] = q4.x; Qs[row][c4 + 1] = q4.y;
        Qs[row][c4 + 2] = q4.z; Qs[row][c4 + 3] = q4.w;
        float4 p4 = *(const float4*)(Bp + (long)row * DHn + c4);
        Ps[row][c4] = p4.x; Ps[row][c4 + 1] = p4.y;
        Ps[row][c4 + 2] = p4.z; Ps[row][c4 + 3] = p4.w;
    }
    __syncthreads();

    const int tx = tid & 15, ty = tid >> 4;
    float acc[4][4];
#pragma unroll
    for (int i = 0; i < 4; i++)
#pragma unroll
        for (int j = 0; j < 4; j++) acc[i][j] = 0.f;

#pragma unroll 16
    for (int kk = 0; kk < 64; kk++) {
        float a0 = Qs[ty * 4 + 0][kk], a1 = Qs[ty * 4 + 1][kk];
        float a2 = Qs[ty * 4 + 2][kk], a3 = Qs[ty * 4 + 3][kk];
        float b0 = Ps[tx * 4 + 0][kk], b1 = Ps[tx * 4 + 1][kk];
        float b2 = Ps[tx * 4 + 2][kk], b3 = Ps[tx * 4 + 3][kk];
        acc[0][0] = fmaf(a0, b0, acc[0][0]); acc[0][1] = fmaf(a0, b1, acc[0][1]);
        acc[0][2] = fmaf(a0, b2, acc[0][2]); acc[0][3] = fmaf(a0, b3, acc[0][3]);
        acc[1][0] = fmaf(a1, b0, acc[1][0]); acc[1][1] = fmaf(a1, b1, acc[1][1]);
        acc[1][2] = fmaf(a1, b2, acc[1][2]); acc[1][3] = fmaf(a1, b3, acc[1][3]);
        acc[2][0] = fmaf(a2, b0, acc[2][0]); acc[2][1] = fmaf(a2, b1, acc[2][1]);
        acc[2][2] = fmaf(a2, b2, acc[2][2]); acc[2][3] = fmaf(a2, b3, acc[2][3]);
        acc[3][0] = fmaf(a3, b0, acc[3][0]); acc[3][1] = fmaf(a3, b1, acc[3][1]);
        acc[3][2] = fmaf(a3, b2, acc[3][2]); acc[3][3] = fmaf(a3, b3, acc[3][3]);
    }

    float* out = QPE + ((long)bh * Tn + it * 64) * MAXP;
#pragma unroll
    for (int ii = 0; ii < 4; ii++) {
        float4 o4 = make_float4(acc[ii][0], acc[ii][1], acc[ii][2], acc[ii][3]);
        *(float4*)(out + (long)(ty * 4 + ii) * MAXP + tx * 4) = o4;
    }
}

// ---------------- CoPE (block-per-row, validated) ----------------
__global__ __launch_bounds__(256) void cope_kernel(const float* __restrict__ S,
                                                   const float* __restrict__ QPE,
                                                   __nv_bfloat16* __restrict__ Ph,
                                                   __nv_bfloat16* __restrict__ Pl)
{
    const int i = blockIdx.x, bh = blockIdx.y;
    const float* row = S + ((long)bh * Tn + i) * Tn;
    const long prow = ((long)bh * Tn + i) * Tn;
    const float* qpe = QPE + ((long)bh * Tn + i) * MAXP;
    const int blockend = ((i >> 7) + 1) << 7;

    __shared__ float qpes[64];
    __shared__ float wred[8];
    __shared__ float wred2[8];

    const int tid = threadIdx.x, lane = tid & 31, wid = tid >> 5;
    if (tid < 64) qpes[tid] = qpe[tid];

    const int j0 = tid << 2;
    float qk[4] = {0.f, 0.f, 0.f, 0.f};
    if (j0 <= i) {
        float4 s4 = *(const float4*)(row + j0);
        qk[0] = s4.x; qk[1] = s4.y; qk[2] = s4.z; qk[3] = s4.w;
    }

    float lpre[4];
    float run = 0.f;
#pragma unroll
    for (int q = 0; q < 4; q++) {
        float gg = 0.f;
        if (j0 + q <= i)
            gg = __fdividef(1.f, 1.f + __expf(-0.125f * qk[q]));
        run += gg;
        lpre[q] = run;
    }

    float v = run;
#pragma unroll
    for (int o = 1; o < 32; o <<= 1) {
        float t = __shfl_up_sync(0xffffffffu, v, o);
        if (lane >= o) v += t;
    }
    if (lane == 31) wred[wid] = v;
    __syncthreads();
    if (tid < 8) {
        float w = wred[tid];
#pragma unroll
        for (int o = 1; o < 8; o <<= 1) {
            float t = __shfl_up_sync(0x000000ffu, w, o);
            if (tid >= o) w += t;
        }
        wred[tid] = w;
    }
    __syncthreads();
    const float base  = (v - run) + (wid ? wred[wid - 1] : 0.f);
    const float total = wred[7];

    float sc[4];
    float mx = -INFINITY;
#pragma unroll
    for (int q = 0; q < 4; q++) {
        float s_ = -INFINITY;
        if (j0 + q <= i) {
            float pos = total - (base + lpre[q]);
            pos = fminf(fmaxf(pos, 0.f), 63.f);
            float pf = floorf(pos);
            int fi = (int)pf;
            float al = pos - pf;
            int ci = (fi < 63) ? fi + 1 : 63;
            float qf = qpes[fi], qc = qpes[ci];
            float qv = qf + al * (qc - qf);
            s_ = 0.125f * (qk[q] + qv);
        }
        sc[q] = s_;
        mx = fmaxf(mx, s_);
    }
#pragma unroll
    for (int o = 16; o; o >>= 1) mx = fmaxf(mx, __shfl_xor_sync(0xffffffffu, mx, o));
    if (lane == 0) wred2[wid] = mx;
    __syncthreads();
    float bmax = wred2[0];
#pragma unroll
    for (int k = 1; k < 8; k++) bmax = fmaxf(bmax, wred2[k]);

    float p[4];
    float ssum = 0.f;
#pragma unroll
    for (int q = 0; q < 4; q++) {
        float e = (j0 + q <= i) ? __expf(sc[q] - bmax) : 0.f;
        p[q] = e;
        ssum += e;
    }
#pragma unroll
    for (int o = 16; o; o >>= 1) ssum += __shfl_xor_sync(0xffffffffu, ssum, o);
    __syncthreads();
    if (lane == 0) wred2[wid] = ssum;
    __syncthreads();
    float tot = 0.f;
#pragma unroll
    for (int k = 0; k < 8; k++) tot += wred2[k];
    const float inv = __fdividef(1.f, tot);

    if (j0 < blockend) {
        float v0 = p[0] * inv, v1 = p[1] * inv, v2 = p[2] * inv, v3 = p[3] * inv;
        __nv_bfloat16 h0 = __float2bfloat16(v0), h1 = __float2bfloat16(v1);
        __nv_bfloat16 h2 = __float2bfloat16(v2), h3 = __float2bfloat16(v3);
        __nv_bfloat162 H0; H0.x = h0; H0.y = h1;
        __nv_bfloat162 H1; H1.x = h2; H1.y = h3;
        __nv_bfloat162 L0, L1;
        L0.x = __float2bfloat16(v0 - __bfloat162float(h0));
        L0.y = __float2bfloat16(v1 - __bfloat162float(h1));
        L1.x = __float2bfloat16(v2 - __bfloat162float(h2));
        L1.y = __float2bfloat16(v3 - __bfloat162float(h3));
        *(__nv_bfloat162*)(Ph + prow + j0)     = H0;
        *(__nv_bfloat162*)(Ph + prow + j0 + 2) = H1;
        *(__nv_bfloat162*)(Pl + prow + j0)     = L0;
        *(__nv_bfloat162*)(Pl + prow + j0 + 2) = L1;
    }
}

// ---------------- launcher ----------------
extern "C" void kernel_launch(void* const* d_in, const int* in_sizes, int n_in,
                              void* d_out, int out_size)
{
    (void)in_sizes; (void)n_in; (void)out_size;
    const float* x  = (const float*)d_in[0];
    const float* Wq = (const float*)d_in[1];
    const float* bq = (const float*)d_in[2];
    const float* Wk = (const float*)d_in[3];
    const float* bk = (const float*)d_in[4];
    const float* Wv = (const float*)d_in[5];
    const float* bv = (const float*)d_in[6];
    const float* Wo = (const float*)d_in[7];
    const float* bo = (const float*)d_in[8];
    const float* pe = (const float*)d_in[9];
    float* out = (float*)d_out;

    float *Qf, *QPEd, *Sd;
    __nv_bfloat16 *xh, *xl, *Wqh, *Wql, *Wkh, *Wkl, *Wvh, *Wvl, *Woh, *Wol;
    __nv_bfloat16 *Qh, *Ql, *Kh, *Kl, *AOh, *AOl, *Phd, *Pld, *Vth, *Vtl;
    cudaGetSymbolAddress((void**)&Qf, g_Qf);
    cudaGetSymbolAddress((void**)&QPEd, g_QPE);
    cudaGetSymbolAddress((void**)&Sd, g_S);
    cudaGetSymbolAddress((void**)&xh, g_xh);   cudaGetSymbolAddress((void**)&xl, g_xl);
    cudaGetSymbolAddress((void**)&Wqh, g_Wqh); cudaGetSymbolAddress((void**)&Wql, g_Wql);
    cudaGetSymbolAddress((void**)&Wkh, g_Wkh); cudaGetSymbolAddress((void**)&Wkl, g_Wkl);
    cudaGetSymbolAddress((void**)&Wvh, g_Wvh); cudaGetSymbolAddress((void**)&Wvl, g_Wvl);
    cudaGetSymbolAddress((void**)&Woh, g_Woh); cudaGetSymbolAddress((void**)&Wol, g_Wol);
    cudaGetSymbolAddress((void**)&Qh, g_Qh);   cudaGetSymbolAddress((void**)&Ql, g_Ql);
    cudaGetSymbolAddress((void**)&Kh, g_Kh);   cudaGetSymbolAddress((void**)&Kl, g_Kl);
    cudaGetSymbolAddress((void**)&AOh, g_AOh); cudaGetSymbolAddress((void**)&AOl, g_AOl);
    cudaGetSymbolAddress((void**)&Phd, g_Ph);  cudaGetSymbolAddress((void**)&Pld, g_Pl);
    cudaGetSymbolAddress((void**)&Vth, g_Vth); cudaGetSymbolAddress((void**)&Vtl, g_Vtl);

    static int smem_set = 0;
    if (!smem_set) {
        cudaFuncSetAttribute(mm_hmma, cudaFuncAttributeMaxDynamicSharedMemorySize, MM_SMEM);
        cudaFuncSetAttribute(qkv_hmma, cudaFuncAttributeMaxDynamicSharedMemorySize, MM_SMEM);
        cudaFuncSetAttribute(pv_hmma, cudaFuncAttributeMaxDynamicSharedMemorySize, MM_SMEM);
        smem_set = 1;
    }

    dim3 blk(256);

    splitk<<<2048, blk>>>(x, xh, xl, Bsz * Tn * Dm);
    splitW4<<<dim3(1024, 1, 4), blk>>>(Wq, Wk, Wv, Wo, Wqh, Wql, Wkh, Wkl,
                                       Wvh, Wvl, Woh, Wol);

    // merged QKV projection: (2048x1024)@W^T, tiles 128x64
    qkv_hmma<<<dim3(16, 16, 3), blk, MM_SMEM>>>(xh, xl, Wqh, Wql, Wkh, Wkl, Wvh, Wvl,
                                                bq, bk, bv, Qf, Qh, Ql, Kh, Kl, Vth, Vtl);

    // qk = Q @ K^T per (b,h): M=1024(128-tiles), N=1024(64-tiles), causal skip
    mm_hmma<<<dim3(16, 8, 32), blk, MM_SMEM>>>(Qh, Ql, Kh, Kl, nullptr,
                                               Sd, 1024, 1024, 64,
                                               (long)Tn * DHn, (long)Tn * DHn, (long)Tn * Tn, 1);

    qpe_kernel<<<dim3(16, 32), blk>>>(pe, Qf, QPEd);

    cope_kernel<<<dim3(1024, 32), blk>>>(Sd, QPEd, Phd, Pld);

    pv_hmma<<<dim3(8, 32), blk, MM_SMEM>>>(Phd, Pld, Vth, Vtl, AOh, AOl);

    // output projection
    mm_hmma<<<dim3(16, 16, 1), blk, MM_SMEM>>>(AOh, AOl, Woh, Wol, bo,
                                               out, 2048, 1024, 1024, 0, 0, 0, 0);
}

// round 9
// speedup vs baseline: 1.1125x; 1.0090x over previous
#include <cuda_runtime.h>
#include <cuda_bf16.h>
#include <math.h>
#include <stdint.h>

#define Bsz 2
#define Tn  1024
#define Dm  1024
#define Hn  16
#define DHn 64
#define BHn (Bsz*Hn)
#define MAXP 64

// ---------------- scratch ----------------
__device__ float g_Qf[BHn*Tn*DHn];
__device__ float g_QPE[BHn*Tn*MAXP];
__device__ float g_S[(long)BHn*Tn*Tn];
__device__ __nv_bfloat16 g_Ph[(long)BHn*Tn*Tn], g_Pl[(long)BHn*Tn*Tn];
__device__ __nv_bfloat16 g_Vth[BHn*DHn*Tn], g_Vtl[BHn*DHn*Tn];
__device__ __nv_bfloat16 g_xh[Bsz*Tn*Dm],  g_xl[Bsz*Tn*Dm];
__device__ __nv_bfloat16 g_Wqh[Dm*Dm], g_Wql[Dm*Dm];
__device__ __nv_bfloat16 g_Wkh[Dm*Dm], g_Wkl[Dm*Dm];
__device__ __nv_bfloat16 g_Wvh[Dm*Dm], g_Wvl[Dm*Dm];
__device__ __nv_bfloat16 g_Woh[Dm*Dm], g_Wol[Dm*Dm];
__device__ __nv_bfloat16 g_Qh[BHn*Tn*DHn], g_Ql[BHn*Tn*DHn];
__device__ __nv_bfloat16 g_Kh[BHn*Tn*DHn], g_Kl[BHn*Tn*DHn];
__device__ __nv_bfloat16 g_AOh[Bsz*Tn*Dm], g_AOl[Bsz*Tn*Dm];

// ---------------- helpers ----------------
__device__ __forceinline__ uint32_t smem_u32(const void* p) {
    uint32_t a;
    asm("{ .reg .u64 t; cvta.to.shared.u64 t, %1; cvt.u32.u64 %0, t; }" : "=r"(a) : "l"(p));
    return a;
}
__device__ __forceinline__ void cpa16(uint32_t dst, const void* src) {
    asm volatile("cp.async.cg.shared.global [%0], [%1], 16;" :: "r"(dst), "l"(src));
}
#define CPA_COMMIT() asm volatile("cp.async.commit_group;" ::: "memory")
#define CPA_WAIT1()  asm volatile("cp.async.wait_group 1;" ::: "memory")
#define CPA_WAIT0()  asm volatile("cp.async.wait_group 0;" ::: "memory")

#define LDSM4(r, a) \
    asm volatile("ldmatrix.sync.aligned.m8n8.x4.shared.b16 {%0,%1,%2,%3}, [%4];" \
        : "=r"((r)[0]), "=r"((r)[1]), "=r"((r)[2]), "=r"((r)[3]) : "r"(a))

#define MMA_BF16(c, a, b0v, b1v) \
    asm volatile("mma.sync.aligned.m16n8k16.row.col.f32.bf16.bf16.f32 " \
        "{%0,%1,%2,%3},{%4,%5,%6,%7},{%8,%9},{%0,%1,%2,%3};" \
        : "+f"((c)[0]), "+f"((c)[1]), "+f"((c)[2]), "+f"((c)[3]) \
        : "r"((a)[0]), "r"((a)[1]), "r"((a)[2]), "r"((a)[3]), "r"(b0v), "r"(b1v))

// ---------------- split fp32 -> bf16 hi/lo ----------------
__device__ __forceinline__ void split_store4(const float* s, __nv_bfloat16* h,
                                             __nv_bfloat16* l, int i)
{
    float4 v = *(const float4*)(s + i);
    __nv_bfloat16 h0 = __float2bfloat16(v.x), h1 = __float2bfloat16(v.y);
    __nv_bfloat16 h2 = __float2bfloat16(v.z), h3 = __float2bfloat16(v.w);
    __nv_bfloat162 H0; H0.x = h0; H0.y = h1;
    __nv_bfloat162 H1; H1.x = h2; H1.y = h3;
    __nv_bfloat162 L0, L1;
    L0.x = __float2bfloat16(v.x - __bfloat162float(h0));
    L0.y = __float2bfloat16(v.y - __bfloat162float(h1));
    L1.x = __float2bfloat16(v.z - __bfloat162float(h2));
    L1.y = __float2bfloat16(v.w - __bfloat162float(h3));
    *(__nv_bfloat162*)(h + i)     = H0;
    *(__nv_bfloat162*)(h + i + 2) = H1;
    *(__nv_bfloat162*)(l + i)     = L0;
    *(__nv_bfloat162*)(l + i + 2) = L1;
}

__global__ __launch_bounds__(256) void splitk(const float* __restrict__ s,
                                              __nv_bfloat16* __restrict__ h,
                                              __nv_bfloat16* __restrict__ l, int n)
{
    int i = (blockIdx.x * 256 + threadIdx.x) * 4;
    if (i >= n) return;
    split_store4(s, h, l, i);
}

__global__ __launch_bounds__(256) void splitW4(
    const float* __restrict__ Wq, const float* __restrict__ Wk,
    const float* __restrict__ Wv, const float* __restrict__ Wo,
    __nv_bfloat16* __restrict__ Wqh, __nv_bfloat16* __restrict__ Wql,
    __nv_bfloat16* __restrict__ Wkh, __nv_bfloat16* __restrict__ Wkl,
    __nv_bfloat16* __restrict__ Wvh, __nv_bfloat16* __restrict__ Wvl,
    __nv_bfloat16* __restrict__ Woh, __nv_bfloat16* __restrict__ Wol)
{
    const int z = blockIdx.z;
    const float* s = (z == 0) ? Wq : (z == 1) ? Wk : (z == 2) ? Wv : Wo;
    __nv_bfloat16* h = (z == 0) ? Wqh : (z == 1) ? Wkh : (z == 2) ? Wvh : Woh;
    __nv_bfloat16* l = (z == 0) ? Wql : (z == 1) ? Wkl : (z == 2) ? Wvl : Wol;
    int i = (blockIdx.x * 256 + threadIdx.x) * 4;
    split_store4(s, h, l, i);
}

// ---------------- GEMM tile params: BM=128, BN=64, BK=32, 256 thr, NS=3 --------
#define PITCH 80
#define AMAT  (128*PITCH)          // 10240
#define BMAT  (64*PITCH)           // 5120
#define STG   (2*AMAT + 2*BMAT)    // 30720
#define MM_SMEM (3*STG)            // 92160 -> 2 CTA/SM (184320 <= 228KB)

// shared compute macro body: fragments + 3-pass MMA for one 32-wide k chunk pair
#define GEMM_COMPUTE(st)                                                          \
    _Pragma("unroll")                                                             \
    for (int kc = 0; kc < 2; kc++) {                                              \
        const uint32_t col = kc * 32 + lcol;                                      \
        uint32_t ah[2][4], al[2][4], bh[2][4], bl[2][4];                          \
        _Pragma("unroll")                                                         \
        for (int mt = 0; mt < 2; mt++) {                                          \
            const uint32_t ad = (st) + a_row + (uint32_t)(mt * 16 * PITCH) + col; \
            LDSM4(ah[mt], ad);                                                    \
            LDSM4(al[mt], ad + AMAT);                                             \
        }                                                                         \
        _Pragma("unroll")                                                         \
        for (int np = 0; np < 2; np++) {                                          \
            const uint32_t bd = (st) + 2*AMAT + b_row + (uint32_t)(np * 16 * PITCH) + col; \
            LDSM4(bh[np], bd);                                                    \
            LDSM4(bl[np], bd + BMAT);                                             \
        }                                                                         \
        _Pragma("unroll")                                                         \
        for (int mt = 0; mt < 2; mt++)                                            \
            _Pragma("unroll")                                                     \
            for (int nt = 0; nt < 4; nt++) {                                      \
                const int np = nt >> 1, i = nt & 1;                               \
                MMA_BF16(acc[mt][nt], ah[mt], bh[np][i], bh[np][i + 2]);          \
                MMA_BF16(acc[mt][nt], ah[mt], bl[np][i], bl[np][i + 2]);          \
                MMA_BF16(acc[mt][nt], al[mt], bh[np][i], bh[np][i + 2]);          \
            }                                                                     \
    }

// generic: C(fp32) = (Ahi+Alo)(Bhi+Blo)^T + bias
__global__ __launch_bounds__(256, 2) void mm_hmma(
    const __nv_bfloat16* __restrict__ Ahi, const __nv_bfloat16* __restrict__ Alo,
    const __nv_bfloat16* __restrict__ Bhi, const __nv_bfloat16* __restrict__ Blo,
    const float* __restrict__ bias,
    float* __restrict__ Cf,
    int M, int N, int K, long sA, long sB, long sC)
{
    extern __shared__ char dsm[];
    const uint32_t sbase = smem_u32(dsm);

    const int tid  = threadIdx.x;
    const int wid  = tid >> 5;
    const int lane = tid & 31;
    const int wm   = wid & 3;
    const int wn   = wid >> 2;
    const int z    = blockIdx.z;
    const int bm   = blockIdx.y * 128;
    const int bn   = blockIdx.x * 64;

    const __nv_bfloat16* Ah = Ahi + (long)z * sA + (long)bm * K;
    const __nv_bfloat16* Al = Alo + (long)z * sA + (long)bm * K;
    const __nv_bfloat16* Bh = Bhi + (long)z * sB + (long)bn * K;
    const __nv_bfloat16* Bl = Blo + (long)z * sB + (long)bn * K;

    float acc[2][4][4];
#pragma unroll
    for (int i = 0; i < 2; i++)
#pragma unroll
        for (int j = 0; j < 4; j++)
#pragma unroll
            for (int c = 0; c < 4; c++) acc[i][j][c] = 0.f;

    const int KS = K >> 5;

    auto load_stage = [&](int slot, int ks) {
        const uint32_t base = sbase + slot * STG;
        const int k0 = ks * 32;
#pragma unroll
        for (int c = tid; c < 512; c += 256) {
            const int r = c >> 2, seg = c & 3;
            const uint32_t d = base + r * PITCH + seg * 16;
            const long off = (long)r * K + k0 + seg * 8;
            cpa16(d,        Ah + off);
            cpa16(d + AMAT, Al + off);
        }
        {
            const int r = tid >> 2, seg = tid & 3;
            const uint32_t d = base + 2*AMAT + r * PITCH + seg * 16;
            const long off = (long)r * K + k0 + seg * 8;
            cpa16(d,        Bh + off);
            cpa16(d + BMAT, Bl + off);
        }
        CPA_COMMIT();
    };

    load_stage(0, 0);
    if (KS > 1) load_stage(1, 1);

    const uint32_t a_row = (uint32_t)(wm * 32 + (lane & 15)) * PITCH;
    const uint32_t b_row = (uint32_t)(wn * 32 + (lane & 15)) * PITCH;
    const uint32_t lcol  = (uint32_t)((lane >> 4) * 16);

    for (int k = 0; k < KS; k++) {
        if (k + 1 < KS) { CPA_WAIT1(); } else { CPA_WAIT0(); }
        __syncthreads();
        if (k + 2 < KS) load_stage((k + 2) % 3, k + 2);
        const uint32_t st = sbase + (k % 3) * STG;
        GEMM_COMPUTE(st)
    }

#pragma unroll
    for (int mt = 0; mt < 2; mt++)
#pragma unroll
        for (int nt = 0; nt < 4; nt++) {
            const int m0 = bm + wm * 32 + mt * 16 + (lane >> 2);
            const int n0 = bn + wn * 32 + nt * 8 + (lane & 3) * 2;
            float b0 = 0.f, b1 = 0.f;
            if (bias) { b0 = bias[n0]; b1 = bias[n0 + 1]; }
#pragma unroll
            for (int half = 0; half < 2; half++) {
                const int m = m0 + half * 8;
                float* cp = Cf + (long)z * sC + (long)m * N + n0;
                cp[0] = acc[mt][nt][half * 2 + 0] + b0;
                cp[1] = acc[mt][nt][half * 2 + 1] + b1;
            }
        }
}

// ---------------- QK specialized: K=64 single-stage, causal tile skip ----------
#define QPITCH 144
#define QAMAT  (128*QPITCH)   // 18432
#define QBMAT  (64*QPITCH)    // 9216
#define QK_SMEM (2*QAMAT + 2*QBMAT)   // 55296

__global__ __launch_bounds__(256, 2) void qk_hmma(
    const __nv_bfloat16* __restrict__ Qh, const __nv_bfloat16* __restrict__ Ql,
    const __nv_bfloat16* __restrict__ Kh, const __nv_bfloat16* __restrict__ Kl,
    float* __restrict__ S)
{
    if ((int)blockIdx.x >= 2 * (int)blockIdx.y + 2) return;

    extern __shared__ char dsm[];
    const uint32_t sbase = smem_u32(dsm);

    const int tid  = threadIdx.x;
    const int wid  = tid >> 5;
    const int lane = tid & 31;
    const int wm   = wid & 3;
    const int wn   = wid >> 2;
    const int z    = blockIdx.z;
    const int bm   = blockIdx.y * 128;
    const int bn   = blockIdx.x * 64;

    const __nv_bfloat16* Ah = Qh + (long)z * Tn * DHn + (long)bm * DHn;
    const __nv_bfloat16* Al = Ql + (long)z * Tn * DHn + (long)bm * DHn;
    const __nv_bfloat16* Bh = Kh + (long)z * Tn * DHn + (long)bn * DHn;
    const __nv_bfloat16* Bl = Kl + (long)z * Tn * DHn + (long)bn * DHn;

    // load everything once: A 128 rows x 8 segs, B 64 rows x 8 segs
#pragma unroll
    for (int c = tid; c < 1024; c += 256) {
        const int r = c >> 3, seg = c & 7;
        const uint32_t d = sbase + r * QPITCH + seg * 16;
        const long off = (long)r * DHn + seg * 8;
        cpa16(d,         Ah + off);
        cpa16(d + QAMAT, Al + off);
    }
#pragma unroll
    for (int c = tid; c < 512; c += 256) {
        const int r = c >> 3, seg = c & 7;
        const uint32_t d = sbase + 2*QAMAT + r * QPITCH + seg * 16;
        const long off = (long)r * DHn + seg * 8;
        cpa16(d,         Bh + off);
        cpa16(d + QBMAT, Bl + off);
    }
    CPA_COMMIT();
    CPA_WAIT0();
    __syncthreads();

    float acc[2][4][4];
#pragma unroll
    for (int i = 0; i < 2; i++)
#pragma unroll
        for (int j = 0; j < 4; j++)
#pragma unroll
            for (int c = 0; c < 4; c++) acc[i][j][c] = 0.f;

    const uint32_t a_row = (uint32_t)(wm * 32 + (lane & 15)) * QPITCH;
    const uint32_t b_row = (uint32_t)(wn * 32 + (lane & 15)) * QPITCH;
    const uint32_t lcol  = (uint32_t)((lane >> 4) * 16);

#pragma unroll
    for (int kc = 0; kc < 4; kc++) {
        const uint32_t col = kc * 32 + lcol;
        uint32_t ah[2][4], al[2][4], bh[2][4], bl[2][4];
#pragma unroll
        for (int mt = 0; mt < 2; mt++) {
            const uint32_t ad = sbase + a_row + (uint32_t)(mt * 16 * QPITCH) + col;
            LDSM4(ah[mt], ad);
            LDSM4(al[mt], ad + QAMAT);
        }
#pragma unroll
        for (int np = 0; np < 2; np++) {
            const uint32_t bd = sbase + 2*QAMAT + b_row + (uint32_t)(np * 16 * QPITCH) + col;
            LDSM4(bh[np], bd);
            LDSM4(bl[np], bd + QBMAT);
        }
#pragma unroll
        for (int mt = 0; mt < 2; mt++)
#pragma unroll
            for (int nt = 0; nt < 4; nt++) {
                const int np = nt >> 1, i = nt & 1;
                MMA_BF16(acc[mt][nt], ah[mt], bh[np][i], bh[np][i + 2]);
                MMA_BF16(acc[mt][nt], ah[mt], bl[np][i], bl[np][i + 2]);
                MMA_BF16(acc[mt][nt], al[mt], bh[np][i], bh[np][i + 2]);
            }
    }

#pragma unroll
    for (int mt = 0; mt < 2; mt++)
#pragma unroll
        for (int nt = 0; nt < 4; nt++) {
            const int m0 = bm + wm * 32 + mt * 16 + (lane >> 2);
            const int n0 = bn + wn * 32 + nt * 8 + (lane & 3) * 2;
#pragma unroll
            for (int half = 0; half < 2; half++) {
                const int m = m0 + half * 8;
                float* cp = S + (long)z * Tn * Tn + (long)m * Tn + n0;
                cp[0] = acc[mt][nt][half * 2 + 0];
                cp[1] = acc[mt][nt][half * 2 + 1];
            }
        }
}

// ---------------- merged QKV projection (NS=3; V via coalesced smem transpose) --
#define VTP 272   // bytes per staged Vt row (128 els * 2B + 16 pad), 16B aligned

__global__ __launch_bounds__(256, 2) void qkv_hmma(
    const __nv_bfloat16* __restrict__ xh, const __nv_bfloat16* __restrict__ xl,
    const __nv_bfloat16* __restrict__ Wqh, const __nv_bfloat16* __restrict__ Wql,
    const __nv_bfloat16* __restrict__ Wkh, const __nv_bfloat16* __restrict__ Wkl,
    const __nv_bfloat16* __restrict__ Wvh, const __nv_bfloat16* __restrict__ Wvl,
    const float* __restrict__ bq, const float* __restrict__ bk, const float* __restrict__ bv,
    float* __restrict__ Qf,
    __nv_bfloat16* __restrict__ Qh, __nv_bfloat16* __restrict__ Ql,
    __nv_bfloat16* __restrict__ Kh, __nv_bfloat16* __restrict__ Kl,
    __nv_bfloat16* __restrict__ Vth, __nv_bfloat16* __restrict__ Vtl)
{
    extern __shared__ char dsm[];
    const uint32_t sbase = smem_u32(dsm);

    const int tid  = threadIdx.x;
    const int wid  = tid >> 5;
    const int lane = tid & 31;
    const int wm   = wid & 3;
    const int wn   = wid >> 2;
    const int z    = blockIdx.z;
    const int bm   = blockIdx.y * 128;
    const int bn   = blockIdx.x * 64;
    const int K    = 1024;

    const __nv_bfloat16* Bh_ = (z == 0) ? Wqh : (z == 1) ? Wkh : Wvh;
    const __nv_bfloat16* Bl_ = (z == 0) ? Wql : (z == 1) ? Wkl : Wvl;
    const float* bias = (z == 0) ? bq : (z == 1) ? bk : bv;

    const __nv_bfloat16* Ah = xh + (long)bm * K;
    const __nv_bfloat16* Al = xl + (long)bm * K;
    const __nv_bfloat16* Bh = Bh_ + (long)bn * K;
    const __nv_bfloat16* Bl = Bl_ + (long)bn * K;

    float acc[2][4][4];
#pragma unroll
    for (int i = 0; i < 2; i++)
#pragma unroll
        for (int j = 0; j < 4; j++)
#pragma unroll
            for (int c = 0; c < 4; c++) acc[i][j][c] = 0.f;

    const int KS = K >> 5;

    auto load_stage = [&](int slot, int ks) {
        const uint32_t base = sbase + slot * STG;
        const int k0 = ks * 32;
#pragma unroll
        for (int c = tid; c < 512; c += 256) {
            const int r = c >> 2, seg = c & 3;
            const uint32_t d = base + r * PITCH + seg * 16;
            const long off = (long)r * K + k0 + seg * 8;
            cpa16(d,        Ah + off);
            cpa16(d + AMAT, Al + off);
        }
        {
            const int r = tid >> 2, seg = tid & 3;
            const uint32_t d = base + 2*AMAT + r * PITCH + seg * 16;
            const long off = (long)r * K + k0 + seg * 8;
            cpa16(d,        Bh + off);
            cpa16(d + BMAT, Bl + off);
        }
        CPA_COMMIT();
    };

    load_stage(0, 0);
    load_stage(1, 1);

    const uint32_t a_row = (uint32_t)(wm * 32 + (lane & 15)) * PITCH;
    const uint32_t b_row = (uint32_t)(wn * 32 + (lane & 15)) * PITCH;
    const uint32_t lcol  = (uint32_t)((lane >> 4) * 16);

    for (int k = 0; k < KS; k++) {
        if (k + 1 < KS) { CPA_WAIT1(); } else { CPA_WAIT0(); }
        __syncthreads();
        if (k + 2 < KS) load_stage((k + 2) % 3, k + 2);
        const uint32_t st = sbase + (k % 3) * STG;
        GEMM_COMPUTE(st)
    }

    const int h = bn >> 6;
    const int b = bm >> 10, t0 = bm & 1023;

    if (z == 2) {
        // stage transposed tile in smem, then coalesced writes
        __syncthreads();   // all compute done before smem reuse
#pragma unroll
        for (int mt = 0; mt < 2; mt++)
#pragma unroll
            for (int nt = 0; nt < 4; nt++) {
                const int dh = wn * 32 + nt * 8 + (lane & 3) * 2;
                const float b0 = bias[bn + dh], b1 = bias[bn + dh + 1];
#pragma unroll
                for (int half = 0; half < 2; half++) {
                    const int tl = wm * 32 + mt * 16 + (lane >> 2) + half * 8;
                    const float v0 = acc[mt][nt][half * 2 + 0] + b0;
                    const float v1 = acc[mt][nt][half * 2 + 1] + b1;
                    __nv_bfloat16 hh0 = __float2bfloat16(v0);
                    __nv_bfloat16 hh1 = __float2bfloat16(v1);
                    __nv_bfloat16 ll0 = __float2bfloat16(v0 - __bfloat162float(hh0));
                    __nv_bfloat16 ll1 = __float2bfloat16(v1 - __bfloat162float(hh1));
                    *(__nv_bfloat16*)(dsm + dh * VTP + tl * 2)               = hh0;
                    *(__nv_bfloat16*)(dsm + (dh + 1) * VTP + tl * 2)         = hh1;
                    *(__nv_bfloat16*)(dsm + 17408 + dh * VTP + tl * 2)       = ll0;
                    *(__nv_bfloat16*)(dsm + 17408 + (dh + 1) * VTP + tl * 2) = ll1;
                }
            }
        __syncthreads();
        {
            const int dh = tid >> 2, seg = tid & 3;   // 64 rows x 4 segs of 64B
            const long gb = (((long)(b * Hn + h) * DHn + dh) * Tn) + t0 + seg * 32;
            const char* srh = dsm + dh * VTP + seg * 64;
            const char* srl = dsm + 17408 + dh * VTP + seg * 64;
#pragma unroll
            for (int i = 0; i < 4; i++) {
                *(float4*)(Vth + gb + i * 8) = *(const float4*)(srh + i * 16);
                *(float4*)(Vtl + gb + i * 8) = *(const float4*)(srl + i * 16);
            }
        }
        return;
    }

#pragma unroll
    for (int mt = 0; mt < 2; mt++)
#pragma unroll
        for (int nt = 0; nt < 4; nt++) {
            const int m0 = bm + wm * 32 + mt * 16 + (lane >> 2);
            const int n0 = bn + wn * 32 + nt * 8 + (lane & 3) * 2;
            const float b0 = bias[n0], b1 = bias[n0 + 1];
            const int dh0 = n0 & 63;
#pragma unroll
            for (int half = 0; half < 2; half++) {
                const int m = m0 + half * 8;
                const float v0 = acc[mt][nt][half * 2 + 0] + b0;
                const float v1 = acc[mt][nt][half * 2 + 1] + b1;
                const int bb = m >> 10, t = m & 1023;
                __nv_bfloat16 hh0 = __float2bfloat16(v0);
                __nv_bfloat16 hh1 = __float2bfloat16(v1);
                __nv_bfloat16 ll0 = __float2bfloat16(v0 - __bfloat162float(hh0));
                __nv_bfloat16 ll1 = __float2bfloat16(v1 - __bfloat162float(hh1));
                const long base = (((long)(bb * Hn + h) * Tn + t) * DHn) + dh0;
                if (z == 0) {
                    Qf[base] = v0; Qf[base + 1] = v1;
                    Qh[base] = hh0; Qh[base + 1] = hh1;
                    Ql[base] = ll0; Ql[base + 1] = ll1;
                } else {
                    Kh[base] = hh0; Kh[base + 1] = hh1;
                    Kl[base] = ll0; Kl[base + 1] = ll1;
                }
            }
        }
}

// ---------------- pv: AO = P @ V (NS=3, causal KS) ----------------
__global__ __launch_bounds__(256, 2) void pv_hmma(
    const __nv_bfloat16* __restrict__ Ph, const __nv_bfloat16* __restrict__ Pl,
    const __nv_bfloat16* __restrict__ Vth, const __nv_bfloat16* __restrict__ Vtl,
    __nv_bfloat16* __restrict__ AOh, __nv_bfloat16* __restrict__ AOl)
{
    extern __shared__ char dsm[];
    const uint32_t sbase = smem_u32(dsm);

    const int tid  = threadIdx.x;
    const int wid  = tid >> 5;
    const int lane = tid & 31;
    const int wm   = wid & 3;
    const int wn   = wid >> 2;
    const int it   = blockIdx.x;
    const int bh   = blockIdx.y;
    const int b    = bh >> 4, h = bh & 15;

    const __nv_bfloat16* Ah = Ph + ((long)bh * Tn + it * 128) * Tn;
    const __nv_bfloat16* Al = Pl + ((long)bh * Tn + it * 128) * Tn;
    const __nv_bfloat16* Bh = Vth + (long)bh * DHn * Tn;
    const __nv_bfloat16* Bl = Vtl + (long)bh * DHn * Tn;

    float acc[2][4][4];
#pragma unroll
    for (int i = 0; i < 2; i++)
#pragma unroll
        for (int j = 0; j < 4; j++)
#pragma unroll
            for (int c = 0; c < 4; c++) acc[i][j][c] = 0.f;

    const int KS = 4 * (it + 1);

    auto load_stage = [&](int slot, int ks) {
        const uint32_t base = sbase + slot * STG;
        const int k0 = ks * 32;
#pragma unroll
        for (int c = tid; c < 512; c += 256) {
            const int r = c >> 2, seg = c & 3;
            const uint32_t d = base + r * PITCH + seg * 16;
            const long off = (long)r * Tn + k0 + seg * 8;
            cpa16(d,        Ah + off);
            cpa16(d + AMAT, Al + off);
        }
        {
            const int r = tid >> 2, seg = tid & 3;
            const uint32_t d = base + 2*AMAT + r * PITCH + seg * 16;
            const long off = (long)r * Tn + k0 + seg * 8;
            cpa16(d,        Bh + off);
            cpa16(d + BMAT, Bl + off);
        }
        CPA_COMMIT();
    };

    load_stage(0, 0);
    load_stage(1, 1);

    const uint32_t a_row = (uint32_t)(wm * 32 + (lane & 15)) * PITCH;
    const uint32_t b_row = (uint32_t)(wn * 32 + (lane & 15)) * PITCH;
    const uint32_t lcol  = (uint32_t)((lane >> 4) * 16);

    for (int k = 0; k < KS; k++) {
        if (k + 1 < KS) { CPA_WAIT1(); } else { CPA_WAIT0(); }
        __syncthreads();
        if (k + 2 < KS) load_stage((k + 2) % 3, k + 2);
        const uint32_t st = sbase + (k % 3) * STG;
        GEMM_COMPUTE(st)
    }

#pragma unroll
    for (int mt = 0; mt < 2; mt++)
#pragma unroll
        for (int nt = 0; nt < 4; nt++) {
            const int t0 = it * 128 + wm * 32 + mt * 16 + (lane >> 2);
            const int dh = wn * 32 + nt * 8 + (lane & 3) * 2;
#pragma unroll
            for (int half = 0; half < 2; half++) {
                const int t = t0 + half * 8;
                const float v0 = acc[mt][nt][half * 2 + 0];
                const float v1 = acc[mt][nt][half * 2 + 1];
                const long base = ((long)b * Tn + t) * Dm + h * 64 + dh;
                __nv_bfloat16 h0 = __float2bfloat16(v0);
                __nv_bfloat16 h1 = __float2bfloat16(v1);
                __nv_bfloat162 H; H.x = h0; H.y = h1;
                __nv_bfloat162 L;
                L.x = __float2bfloat16(v0 - __bfloat162float(h0));
                L.y = __float2bfloat16(v1 - __bfloat162float(h1));
                *(__nv_bfloat162*)(AOh + base) = H;
                *(__nv_bfloat162*)(AOl + base) = L;
            }
        }
}

// ---------------- qpe table ----------------
__global__ __launch_bounds__(256) void qpe_kernel(const float* __restrict__ PE,
                                                  const float* __restrict__ Q,
                                                  float* __restrict__ QPE)
{
    const int it = blockIdx.x, bh = blockIdx.y, h = bh & (Hn - 1);
    const float* Aq = Q + ((long)bh * Tn + it * 64) * DHn;
    const float* Bp = PE + (long)h * MAXP * DHn;

    __shared__ float Qs[64][65];
    __shared__ float Ps[64][65];

    const int tid = threadIdx.x;
    const int rowb = tid >> 4, c4 = (tid & 15) << 2;
#pragma unroll
    for (int r = 0; r < 4; r++) {
        int row = rowb + r * 16;
        float4 q4 = *(const float4*)(Aq + (long)row * DHn + c4);
        Qs[row][c4] = q4.x; Qs[row][c4 + 1] = q4.y;
        Qs[row][c4 + 2] = q4.z; Qs[row][c4 + 3] = q4.w;
        float4 p4 = *(const float4*)(Bp + (long)row * DHn + c4);
        Ps[row][c4] = p4.x; Ps[row][c4 + 1] = p4.y;
        Ps[row][c4 + 2] = p4.z; Ps[row][c4 + 3] = p4.w;
    }
    __syncthreads();

    const int tx = tid & 15, ty = tid >> 4;
    float acc[4][4];
#pragma unroll
    for (int i = 0; i < 4; i++)
#pragma unroll
        for (int j = 0; j < 4; j++) acc[i][j] = 0.f;

#pragma unroll 16
    for (int kk = 0; kk < 64; kk++) {
        float a0 = Qs[ty * 4 + 0][kk], a1 = Qs[ty * 4 + 1][kk];
        float a2 = Qs[ty * 4 + 2][kk], a3 = Qs[ty * 4 + 3][kk];
        float b0 = Ps[tx * 4 + 0][kk], b1 = Ps[tx * 4 + 1][kk];
        float b2 = Ps[tx * 4 + 2][kk], b3 = Ps[tx * 4 + 3][kk];
        acc[0][0] = fmaf(a0, b0, acc[0][0]); acc[0][1] = fmaf(a0, b1, acc[0][1]);
        acc[0][2] = fmaf(a0, b2, acc[0][2]); acc[0][3] = fmaf(a0, b3, acc[0][3]);
        acc[1][0] = fmaf(a1, b0, acc[1][0]); acc[1][1] = fmaf(a1, b1, acc[1][1]);
        acc[1][2] = fmaf(a1, b2, acc[1][2]); acc[1][3] = fmaf(a1, b3, acc[1][3]);
        acc[2][0] = fmaf(a2, b0, acc[2][0]); acc[2][1] = fmaf(a2, b1, acc[2][1]);
        acc[2][2] = fmaf(a2, b2, acc[2][2]); acc[2][3] = fmaf(a2, b3, acc[2][3]);
        acc[3][0] = fmaf(a3, b0, acc[3][0]); acc[3][1] = fmaf(a3, b1, acc[3][1]);
        acc[3][2] = fmaf(a3, b2, acc[3][2]); acc[3][3] = fmaf(a3, b3, acc[3][3]);
    }

    float* out = QPE + ((long)bh * Tn + it * 64) * MAXP;
#pragma unroll
    for (int ii = 0; ii < 4; ii++) {
        float4 o4 = make_float4(acc[ii][0], acc[ii][1], acc[ii][2], acc[ii][3]);
        *(float4*)(out + (long)(ty * 4 + ii) * MAXP + tx * 4) = o4;
    }
}

// ---------------- CoPE (block-per-row, validated) ----------------
__global__ __launch_bounds__(256) void cope_kernel(const float* __restrict__ S,
                                                   const float* __restrict__ QPE,
                                                   __nv_bfloat16* __restrict__ Ph,
                                                   __nv_bfloat16* __restrict__ Pl)
{
    const int i = blockIdx.x, bh = blockIdx.y;
    const float* row = S + ((long)bh * Tn + i) * Tn;
    const long prow = ((long)bh * Tn + i) * Tn;
    const float* qpe = QPE + ((long)bh * Tn + i) * MAXP;
    const int blockend = ((i >> 7) + 1) << 7;

    __shared__ float qpes[64];
    __shared__ float wred[8];
    __shared__ float wred2[8];

    const int tid = threadIdx.x, lane = tid & 31, wid = tid >> 5;
    if (tid < 64) qpes[tid] = qpe[tid];

    const int j0 = tid << 2;
    float qk[4] = {0.f, 0.f, 0.f, 0.f};
    if (j0 <= i) {
        float4 s4 = *(const float4*)(row + j0);
        qk[0] = s4.x; qk[1] = s4.y; qk[2] = s4.z; qk[3] = s4.w;
    }

    float lpre[4];
    float run = 0.f;
#pragma unroll
    for (int q = 0; q < 4; q++) {
        float gg = 0.f;
        if (j0 + q <= i)
            gg = __fdividef(1.f, 1.f + __expf(-0.125f * qk[q]));
        run += gg;
        lpre[q] = run;
    }

    float v = run;
#pragma unroll
    for (int o = 1; o < 32; o <<= 1) {
        float t = __shfl_up_sync(0xffffffffu, v, o);
        if (lane >= o) v += t;
    }
    if (lane == 31) wred[wid] = v;
    __syncthreads();
    if (tid < 8) {
        float w = wred[tid];
#pragma unroll
        for (int o = 1; o < 8; o <<= 1) {
            float t = __shfl_up_sync(0x000000ffu, w, o);
            if (tid >= o) w += t;
        }
        wred[tid] = w;
    }
    __syncthreads();
    const float base  = (v - run) + (wid ? wred[wid - 1] : 0.f);
    const float total = wred[7];

    float sc[4];
    float mx = -INFINITY;
#pragma unroll
    for (int q = 0; q < 4; q++) {
        float s_ = -INFINITY;
        if (j0 + q <= i) {
            float pos = total - (base + lpre[q]);
            pos = fminf(fmaxf(pos, 0.f), 63.f);
            float pf = floorf(pos);
            int fi = (int)pf;
            float al = pos - pf;
            int ci = (fi < 63) ? fi + 1 : 63;
            float qf = qpes[fi], qc = qpes[ci];
            float qv = qf + al * (qc - qf);
            s_ = 0.125f * (qk[q] + qv);
        }
        sc[q] = s_;
        mx = fmaxf(mx, s_);
    }
#pragma unroll
    for (int o = 16; o; o >>= 1) mx = fmaxf(mx, __shfl_xor_sync(0xffffffffu, mx, o));
    if (lane == 0) wred2[wid] = mx;
    __syncthreads();
    float bmax = wred2[0];
#pragma unroll
    for (int k = 1; k < 8; k++) bmax = fmaxf(bmax, wred2[k]);

    float p[4];
    float ssum = 0.f;
#pragma unroll
    for (int q = 0; q < 4; q++) {
        float e = (j0 + q <= i) ? __expf(sc[q] - bmax) : 0.f;
        p[q] = e;
        ssum += e;
    }
#pragma unroll
    for (int o = 16; o; o >>= 1) ssum += __shfl_xor_sync(0xffffffffu, ssum, o);
    __syncthreads();
    if (lane == 0) wred2[wid] = ssum;
    __syncthreads();
    float tot = 0.f;
#pragma unroll
    for (int k = 0; k < 8; k++) tot += wred2[k];
    const float inv = __fdividef(1.f, tot);

    if (j0 < blockend) {
        float v0 = p[0] * inv, v1 = p[1] * inv, v2 = p[2] * inv, v3 = p[3] * inv;
        __nv_bfloat16 h0 = __float2bfloat16(v0), h1 = __float2bfloat16(v1);
        __nv_bfloat16 h2 = __float2bfloat16(v2), h3 = __float2bfloat16(v3);
        __nv_bfloat162 H0; H0.x = h0; H0.y = h1;
        __nv_bfloat162 H1; H1.x = h2; H1.y = h3;
        __nv_bfloat162 L0, L1;
        L0.x = __float2bfloat16(v0 - __bfloat162float(h0));
        L0.y = __float2bfloat16(v1 - __bfloat162float(h1));
        L1.x = __float2bfloat16(v2 - __bfloat162float(h2));
        L1.y = __float2bfloat16(v3 - __bfloat162float(h3));
        *(__nv_bfloat162*)(Ph + prow + j0)     = H0;
        *(__nv_bfloat162*)(Ph + prow + j0 + 2) = H1;
        *(__nv_bfloat162*)(Pl + prow + j0)     = L0;
        *(__nv_bfloat162*)(Pl + prow + j0 + 2) = L1;
    }
}

// ---------------- launcher ----------------
extern "C" void kernel_launch(void* const* d_in, const int* in_sizes, int n_in,
                              void* d_out, int out_size)
{
    (void)in_sizes; (void)n_in; (void)out_size;
    const float* x  = (const float*)d_in[0];
    const float* Wq = (const float*)d_in[1];
    const float* bq = (const float*)d_in[2];
    const float* Wk = (const float*)d_in[3];
    const float* bk = (const float*)d_in[4];
    const float* Wv = (const float*)d_in[5];
    const float* bv = (const float*)d_in[6];
    const float* Wo = (const float*)d_in[7];
    const float* bo = (const float*)d_in[8];
    const float* pe = (const float*)d_in[9];
    float* out = (float*)d_out;

    float *Qf, *QPEd, *Sd;
    __nv_bfloat16 *xh, *xl, *Wqh, *Wql, *Wkh, *Wkl, *Wvh, *Wvl, *Woh, *Wol;
    __nv_bfloat16 *Qh, *Ql, *Kh, *Kl, *AOh, *AOl, *Phd, *Pld, *Vth, *Vtl;
    cudaGetSymbolAddress((void**)&Qf, g_Qf);
    cudaGetSymbolAddress((void**)&QPEd, g_QPE);
    cudaGetSymbolAddress((void**)&Sd, g_S);
    cudaGetSymbolAddress((void**)&xh, g_xh);   cudaGetSymbolAddress((void**)&xl, g_xl);
    cudaGetSymbolAddress((void**)&Wqh, g_Wqh); cudaGetSymbolAddress((void**)&Wql, g_Wql);
    cudaGetSymbolAddress((void**)&Wkh, g_Wkh); cudaGetSymbolAddress((void**)&Wkl, g_Wkl);
    cudaGetSymbolAddress((void**)&Wvh, g_Wvh); cudaGetSymbolAddress((void**)&Wvl, g_Wvl);
    cudaGetSymbolAddress((void**)&Woh, g_Woh); cudaGetSymbolAddress((void**)&Wol, g_Wol);
    cudaGetSymbolAddress((void**)&Qh, g_Qh);   cudaGetSymbolAddress((void**)&Ql, g_Ql);
    cudaGetSymbolAddress((void**)&Kh, g_Kh);   cudaGetSymbolAddress((void**)&Kl, g_Kl);
    cudaGetSymbolAddress((void**)&AOh, g_AOh); cudaGetSymbolAddress((void**)&AOl, g_AOl);
    cudaGetSymbolAddress((void**)&Phd, g_Ph);  cudaGetSymbolAddress((void**)&Pld, g_Pl);
    cudaGetSymbolAddress((void**)&Vth, g_Vth); cudaGetSymbolAddress((void**)&Vtl, g_Vtl);

    static int smem_set = 0;
    if (!smem_set) {
        cudaFuncSetAttribute(mm_hmma, cudaFuncAttributeMaxDynamicSharedMemorySize, MM_SMEM);
        cudaFuncSetAttribute(qkv_hmma, cudaFuncAttributeMaxDynamicSharedMemorySize, MM_SMEM);
        cudaFuncSetAttribute(pv_hmma, cudaFuncAttributeMaxDynamicSharedMemorySize, MM_SMEM);
        cudaFuncSetAttribute(qk_hmma, cudaFuncAttributeMaxDynamicSharedMemorySize, QK_SMEM);
        smem_set = 1;
    }

    dim3 blk(256);

    splitk<<<2048, blk>>>(x, xh, xl, Bsz * Tn * Dm);
    splitW4<<<dim3(1024, 1, 4), blk>>>(Wq, Wk, Wv, Wo, Wqh, Wql, Wkh, Wkl,
                                       Wvh, Wvl, Woh, Wol);

    qkv_hmma<<<dim3(16, 16, 3), blk, MM_SMEM>>>(xh, xl, Wqh, Wql, Wkh, Wkl, Wvh, Wvl,
                                                bq, bk, bv, Qf, Qh, Ql, Kh, Kl, Vth, Vtl);

    qk_hmma<<<dim3(16, 8, 32), blk, QK_SMEM>>>(Qh, Ql, Kh, Kl, Sd);

    qpe_kernel<<<dim3(16, 32), blk>>>(pe, Qf, QPEd);

    cope_kernel<<<dim3(1024, 32), blk>>>(Sd, QPEd, Phd, Pld);

    pv_hmma<<<dim3(8, 32), blk, MM_SMEM>>>(Phd, Pld, Vth, Vtl, AOh, AOl);

    mm_hmma<<<dim3(16, 16, 1), blk, MM_SMEM>>>(AOh, AOl, Woh, Wol, bo,
                                               out, 2048, 1024, 1024, 0, 0, 0);
}

// round 10
// speedup vs baseline: 1.1235x; 1.0099x over previous
#include <cuda_runtime.h>
#include <cuda_bf16.h>
#include <math.h>
#include <stdint.h>

#define Bsz 2
#define Tn  1024
#define Dm  1024
#define Hn  16
#define DHn 64
#define BHn (Bsz*Hn)
#define MAXP 64

// ---------------- scratch ----------------
__device__ float g_QPE[BHn*Tn*MAXP];
__device__ float g_S[(long)BHn*Tn*Tn];
__device__ __nv_bfloat16 g_Ph[(long)BHn*Tn*Tn], g_Pl[(long)BHn*Tn*Tn];
__device__ __nv_bfloat16 g_Vth[BHn*DHn*Tn], g_Vtl[BHn*DHn*Tn];
__device__ __nv_bfloat16 g_xh[Bsz*Tn*Dm],  g_xl[Bsz*Tn*Dm];
__device__ __nv_bfloat16 g_Wqh[Dm*Dm], g_Wql[Dm*Dm];
__device__ __nv_bfloat16 g_Wkh[Dm*Dm], g_Wkl[Dm*Dm];
__device__ __nv_bfloat16 g_Wvh[Dm*Dm], g_Wvl[Dm*Dm];
__device__ __nv_bfloat16 g_Woh[Dm*Dm], g_Wol[Dm*Dm];
__device__ __nv_bfloat16 g_Qh[BHn*Tn*DHn], g_Ql[BHn*Tn*DHn];
__device__ __nv_bfloat16 g_Kh[BHn*Tn*DHn], g_Kl[BHn*Tn*DHn];
__device__ __nv_bfloat16 g_AOh[Bsz*Tn*Dm], g_AOl[Bsz*Tn*Dm];

// ---------------- helpers ----------------
__device__ __forceinline__ uint32_t smem_u32(const void* p) {
    uint32_t a;
    asm("{ .reg .u64 t; cvta.to.shared.u64 t, %1; cvt.u32.u64 %0, t; }" : "=r"(a) : "l"(p));
    return a;
}
__device__ __forceinline__ void cpa16(uint32_t dst, const void* src) {
    asm volatile("cp.async.cg.shared.global [%0], [%1], 16;" :: "r"(dst), "l"(src));
}
#define CPA_COMMIT() asm volatile("cp.async.commit_group;" ::: "memory")
#define CPA_WAIT1()  asm volatile("cp.async.wait_group 1;" ::: "memory")
#define CPA_WAIT0()  asm volatile("cp.async.wait_group 0;" ::: "memory")

#define LDSM4(r, a) \
    asm volatile("ldmatrix.sync.aligned.m8n8.x4.shared.b16 {%0,%1,%2,%3}, [%4];" \
        : "=r"((r)[0]), "=r"((r)[1]), "=r"((r)[2]), "=r"((r)[3]) : "r"(a))

#define MMA_BF16(c, a, b0v, b1v) \
    asm volatile("mma.sync.aligned.m16n8k16.row.col.f32.bf16.bf16.f32 " \
        "{%0,%1,%2,%3},{%4,%5,%6,%7},{%8,%9},{%0,%1,%2,%3};" \
        : "+f"((c)[0]), "+f"((c)[1]), "+f"((c)[2]), "+f"((c)[3]) \
        : "r"((a)[0]), "r"((a)[1]), "r"((a)[2]), "r"((a)[3]), "r"(b0v), "r"(b1v))

// ---------------- split fp32 -> bf16 hi/lo ----------------
__device__ __forceinline__ void split_store4(const float* s, __nv_bfloat16* h,
                                             __nv_bfloat16* l, int i)
{
    float4 v = *(const float4*)(s + i);
    __nv_bfloat16 h0 = __float2bfloat16(v.x), h1 = __float2bfloat16(v.y);
    __nv_bfloat16 h2 = __float2bfloat16(v.z), h3 = __float2bfloat16(v.w);
    __nv_bfloat162 H0; H0.x = h0; H0.y = h1;
    __nv_bfloat162 H1; H1.x = h2; H1.y = h3;
    __nv_bfloat162 L0, L1;
    L0.x = __float2bfloat16(v.x - __bfloat162float(h0));
    L0.y = __float2bfloat16(v.y - __bfloat162float(h1));
    L1.x = __float2bfloat16(v.z - __bfloat162float(h2));
    L1.y = __float2bfloat16(v.w - __bfloat162float(h3));
    *(__nv_bfloat162*)(h + i)     = H0;
    *(__nv_bfloat162*)(h + i + 2) = H1;
    *(__nv_bfloat162*)(l + i)     = L0;
    *(__nv_bfloat162*)(l + i + 2) = L1;
}

__global__ __launch_bounds__(256) void splitk(const float* __restrict__ s,
                                              __nv_bfloat16* __restrict__ h,
                                              __nv_bfloat16* __restrict__ l, int n)
{
    int i = (blockIdx.x * 256 + threadIdx.x) * 4;
    if (i >= n) return;
    split_store4(s, h, l, i);
}

__global__ __launch_bounds__(256) void splitW4(
    const float* __restrict__ Wq, const float* __restrict__ Wk,
    const float* __restrict__ Wv, const float* __restrict__ Wo,
    __nv_bfloat16* __restrict__ Wqh, __nv_bfloat16* __restrict__ Wql,
    __nv_bfloat16* __restrict__ Wkh, __nv_bfloat16* __restrict__ Wkl,
    __nv_bfloat16* __restrict__ Wvh, __nv_bfloat16* __restrict__ Wvl,
    __nv_bfloat16* __restrict__ Woh, __nv_bfloat16* __restrict__ Wol)
{
    const int z = blockIdx.z;
    const float* s = (z == 0) ? Wq : (z == 1) ? Wk : (z == 2) ? Wv : Wo;
    __nv_bfloat16* h = (z == 0) ? Wqh : (z == 1) ? Wkh : (z == 2) ? Wvh : Woh;
    __nv_bfloat16* l = (z == 0) ? Wql : (z == 1) ? Wkl : (z == 2) ? Wvl : Wol;
    int i = (blockIdx.x * 256 + threadIdx.x) * 4;
    split_store4(s, h, l, i);
}

// ---------------- GEMM tile params: BM=128, BN=64, BK=32, 256 thr, NS=3 --------
#define PITCH 80
#define AMAT  (128*PITCH)
#define BMAT  (64*PITCH)
#define STG   (2*AMAT + 2*BMAT)
#define MM_SMEM (3*STG)

// pass-major MMA issue order: consecutive MMAs hit different accumulators
// (reuse distance 8) so fixed-latency HMMA RAW chains never stall the issue.
#define GEMM_COMPUTE(st)                                                          \
    _Pragma("unroll")                                                             \
    for (int kc = 0; kc < 2; kc++) {                                              \
        const uint32_t col = kc * 32 + lcol;                                      \
        uint32_t ah[2][4], al[2][4], bh[2][4], bl[2][4];                          \
        _Pragma("unroll")                                                         \
        for (int mt = 0; mt < 2; mt++) {                                          \
            const uint32_t ad = (st) + a_row + (uint32_t)(mt * 16 * PITCH) + col; \
            LDSM4(ah[mt], ad);                                                    \
            LDSM4(al[mt], ad + AMAT);                                             \
        }                                                                         \
        _Pragma("unroll")                                                         \
        for (int np = 0; np < 2; np++) {                                          \
            const uint32_t bd = (st) + 2*AMAT + b_row + (uint32_t)(np * 16 * PITCH) + col; \
            LDSM4(bh[np], bd);                                                    \
            LDSM4(bl[np], bd + BMAT);                                             \
        }                                                                         \
        _Pragma("unroll")                                                         \
        for (int mt = 0; mt < 2; mt++)                                            \
            _Pragma("unroll")                                                     \
            for (int nt = 0; nt < 4; nt++) {                                      \
                const int np = nt >> 1, i = nt & 1;                               \
                MMA_BF16(acc[mt][nt], ah[mt], bh[np][i], bh[np][i + 2]);          \
            }                                                                     \
        _Pragma("unroll")                                                         \
        for (int mt = 0; mt < 2; mt++)                                            \
            _Pragma("unroll")                                                     \
            for (int nt = 0; nt < 4; nt++) {                                      \
                const int np = nt >> 1, i = nt & 1;                               \
                MMA_BF16(acc[mt][nt], ah[mt], bl[np][i], bl[np][i + 2]);          \
            }                                                                     \
        _Pragma("unroll")                                                         \
        for (int mt = 0; mt < 2; mt++)                                            \
            _Pragma("unroll")                                                     \
            for (int nt = 0; nt < 4; nt++) {                                      \
                const int np = nt >> 1, i = nt & 1;                               \
                MMA_BF16(acc[mt][nt], al[mt], bh[np][i], bh[np][i + 2]);          \
            }                                                                     \
    }

// generic: C(fp32) = (Ahi+Alo)(Bhi+Blo)^T + bias
__global__ __launch_bounds__(256, 2) void mm_hmma(
    const __nv_bfloat16* __restrict__ Ahi, const __nv_bfloat16* __restrict__ Alo,
    const __nv_bfloat16* __restrict__ Bhi, const __nv_bfloat16* __restrict__ Blo,
    const float* __restrict__ bias,
    float* __restrict__ Cf,
    int M, int N, int K, long sA, long sB, long sC)
{
    extern __shared__ char dsm[];
    const uint32_t sbase = smem_u32(dsm);

    const int tid  = threadIdx.x;
    const int wid  = tid >> 5;
    const int lane = tid & 31;
    const int wm   = wid & 3;
    const int wn   = wid >> 2;
    const int z    = blockIdx.z;
    const int bm   = blockIdx.y * 128;
    const int bn   = blockIdx.x * 64;

    const __nv_bfloat16* Ah = Ahi + (long)z * sA + (long)bm * K;
    const __nv_bfloat16* Al = Alo + (long)z * sA + (long)bm * K;
    const __nv_bfloat16* Bh = Bhi + (long)z * sB + (long)bn * K;
    const __nv_bfloat16* Bl = Blo + (long)z * sB + (long)bn * K;

    float acc[2][4][4];
#pragma unroll
    for (int i = 0; i < 2; i++)
#pragma unroll
        for (int j = 0; j < 4; j++)
#pragma unroll
            for (int c = 0; c < 4; c++) acc[i][j][c] = 0.f;

    const int KS = K >> 5;

    auto load_stage = [&](int slot, int ks) {
        const uint32_t base = sbase + slot * STG;
        const int k0 = ks * 32;
#pragma unroll
        for (int c = tid; c < 512; c += 256) {
            const int r = c >> 2, seg = c & 3;
            const uint32_t d = base + r * PITCH + seg * 16;
            const long off = (long)r * K + k0 + seg * 8;
            cpa16(d,        Ah + off);
            cpa16(d + AMAT, Al + off);
        }
        {
            const int r = tid >> 2, seg = tid & 3;
            const uint32_t d = base + 2*AMAT + r * PITCH + seg * 16;
            const long off = (long)r * K + k0 + seg * 8;
            cpa16(d,        Bh + off);
            cpa16(d + BMAT, Bl + off);
        }
        CPA_COMMIT();
    };

    load_stage(0, 0);
    if (KS > 1) load_stage(1, 1);

    const uint32_t a_row = (uint32_t)(wm * 32 + (lane & 15)) * PITCH;
    const uint32_t b_row = (uint32_t)(wn * 32 + (lane & 15)) * PITCH;
    const uint32_t lcol  = (uint32_t)((lane >> 4) * 16);

    for (int k = 0; k < KS; k++) {
        if (k + 1 < KS) { CPA_WAIT1(); } else { CPA_WAIT0(); }
        __syncthreads();
        if (k + 2 < KS) load_stage((k + 2) % 3, k + 2);
        const uint32_t st = sbase + (k % 3) * STG;
        GEMM_COMPUTE(st)
    }

#pragma unroll
    for (int mt = 0; mt < 2; mt++)
#pragma unroll
        for (int nt = 0; nt < 4; nt++) {
            const int m0 = bm + wm * 32 + mt * 16 + (lane >> 2);
            const int n0 = bn + wn * 32 + nt * 8 + (lane & 3) * 2;
            float b0 = 0.f, b1 = 0.f;
            if (bias) { b0 = bias[n0]; b1 = bias[n0 + 1]; }
#pragma unroll
            for (int half = 0; half < 2; half++) {
                const int m = m0 + half * 8;
                float* cp = Cf + (long)z * sC + (long)m * N + n0;
                cp[0] = acc[mt][nt][half * 2 + 0] + b0;
                cp[1] = acc[mt][nt][half * 2 + 1] + b1;
            }
        }
}

// ---------------- QK specialized: K=64 single-stage, causal tile skip ----------
#define QPITCH 144
#define QAMAT  (128*QPITCH)
#define QBMAT  (64*QPITCH)
#define QK_SMEM (2*QAMAT + 2*QBMAT)

__global__ __launch_bounds__(256, 2) void qk_hmma(
    const __nv_bfloat16* __restrict__ Qh, const __nv_bfloat16* __restrict__ Ql,
    const __nv_bfloat16* __restrict__ Kh, const __nv_bfloat16* __restrict__ Kl,
    float* __restrict__ S)
{
    if ((int)blockIdx.x >= 2 * (int)blockIdx.y + 2) return;

    extern __shared__ char dsm[];
    const uint32_t sbase = smem_u32(dsm);

    const int tid  = threadIdx.x;
    const int wid  = tid >> 5;
    const int lane = tid & 31;
    const int wm   = wid & 3;
    const int wn   = wid >> 2;
    const int z    = blockIdx.z;
    const int bm   = blockIdx.y * 128;
    const int bn   = blockIdx.x * 64;

    const __nv_bfloat16* Ah = Qh + (long)z * Tn * DHn + (long)bm * DHn;
    const __nv_bfloat16* Al = Ql + (long)z * Tn * DHn + (long)bm * DHn;
    const __nv_bfloat16* Bh = Kh + (long)z * Tn * DHn + (long)bn * DHn;
    const __nv_bfloat16* Bl = Kl + (long)z * Tn * DHn + (long)bn * DHn;

#pragma unroll
    for (int c = tid; c < 1024; c += 256) {
        const int r = c >> 3, seg = c & 7;
        const uint32_t d = sbase + r * QPITCH + seg * 16;
        const long off = (long)r * DHn + seg * 8;
        cpa16(d,         Ah + off);
        cpa16(d + QAMAT, Al + off);
    }
#pragma unroll
    for (int c = tid; c < 512; c += 256) {
        const int r = c >> 3, seg = c & 7;
        const uint32_t d = sbase + 2*QAMAT + r * QPITCH + seg * 16;
        const long off = (long)r * DHn + seg * 8;
        cpa16(d,         Bh + off);
        cpa16(d + QBMAT, Bl + off);
    }
    CPA_COMMIT();
    CPA_WAIT0();
    __syncthreads();

    float acc[2][4][4];
#pragma unroll
    for (int i = 0; i < 2; i++)
#pragma unroll
        for (int j = 0; j < 4; j++)
#pragma unroll
            for (int c = 0; c < 4; c++) acc[i][j][c] = 0.f;

    const uint32_t a_row = (uint32_t)(wm * 32 + (lane & 15)) * QPITCH;
    const uint32_t b_row = (uint32_t)(wn * 32 + (lane & 15)) * QPITCH;
    const uint32_t lcol  = (uint32_t)((lane >> 4) * 16);

#pragma unroll
    for (int kc = 0; kc < 4; kc++) {
        const uint32_t col = kc * 32 + lcol;
        uint32_t ah[2][4], al[2][4], bh[2][4], bl[2][4];
#pragma unroll
        for (int mt = 0; mt < 2; mt++) {
            const uint32_t ad = sbase + a_row + (uint32_t)(mt * 16 * QPITCH) + col;
            LDSM4(ah[mt], ad);
            LDSM4(al[mt], ad + QAMAT);
        }
#pragma unroll
        for (int np = 0; np < 2; np++) {
            const uint32_t bd = sbase + 2*QAMAT + b_row + (uint32_t)(np * 16 * QPITCH) + col;
            LDSM4(bh[np], bd);
            LDSM4(bl[np], bd + QBMAT);
        }
        // pass-major order: no back-to-back same-acc MMAs
#pragma unroll
        for (int mt = 0; mt < 2; mt++)
#pragma unroll
            for (int nt = 0; nt < 4; nt++) {
                const int np = nt >> 1, i = nt & 1;
                MMA_BF16(acc[mt][nt], ah[mt], bh[np][i], bh[np][i + 2]);
            }
#pragma unroll
        for (int mt = 0; mt < 2; mt++)
#pragma unroll
            for (int nt = 0; nt < 4; nt++) {
                const int np = nt >> 1, i = nt & 1;
                MMA_BF16(acc[mt][nt], ah[mt], bl[np][i], bl[np][i + 2]);
            }
#pragma unroll
        for (int mt = 0; mt < 2; mt++)
#pragma unroll
            for (int nt = 0; nt < 4; nt++) {
                const int np = nt >> 1, i = nt & 1;
                MMA_BF16(acc[mt][nt], al[mt], bh[np][i], bh[np][i + 2]);
            }
    }

#pragma unroll
    for (int mt = 0; mt < 2; mt++)
#pragma unroll
        for (int nt = 0; nt < 4; nt++) {
            const int m0 = bm + wm * 32 + mt * 16 + (lane >> 2);
            const int n0 = bn + wn * 32 + nt * 8 + (lane & 3) * 2;
#pragma unroll
            for (int half = 0; half < 2; half++) {
                const int m = m0 + half * 8;
                float* cp = S + (long)z * Tn * Tn + (long)m * Tn + n0;
                cp[0] = acc[mt][nt][half * 2 + 0];
                cp[1] = acc[mt][nt][half * 2 + 1];
            }
        }
}

// ---------------- merged QKV projection (NS=3; V via coalesced smem transpose) --
#define VTP 272

__global__ __launch_bounds__(256, 2) void qkv_hmma(
    const __nv_bfloat16* __restrict__ xh, const __nv_bfloat16* __restrict__ xl,
    const __nv_bfloat16* __restrict__ Wqh, const __nv_bfloat16* __restrict__ Wql,
    const __nv_bfloat16* __restrict__ Wkh, const __nv_bfloat16* __restrict__ Wkl,
    const __nv_bfloat16* __restrict__ Wvh, const __nv_bfloat16* __restrict__ Wvl,
    const float* __restrict__ bq, const float* __restrict__ bk, const float* __restrict__ bv,
    __nv_bfloat16* __restrict__ Qh, __nv_bfloat16* __restrict__ Ql,
    __nv_bfloat16* __restrict__ Kh, __nv_bfloat16* __restrict__ Kl,
    __nv_bfloat16* __restrict__ Vth, __nv_bfloat16* __restrict__ Vtl)
{
    extern __shared__ char dsm[];
    const uint32_t sbase = smem_u32(dsm);

    const int tid  = threadIdx.x;
    const int wid  = tid >> 5;
    const int lane = tid & 31;
    const int wm   = wid & 3;
    const int wn   = wid >> 2;
    const int z    = blockIdx.z;
    const int bm   = blockIdx.y * 128;
    const int bn   = blockIdx.x * 64;
    const int K    = 1024;

    const __nv_bfloat16* Bh_ = (z == 0) ? Wqh : (z == 1) ? Wkh : Wvh;
    const __nv_bfloat16* Bl_ = (z == 0) ? Wql : (z == 1) ? Wkl : Wvl;
    const float* bias = (z == 0) ? bq : (z == 1) ? bk : bv;

    const __nv_bfloat16* Ah = xh + (long)bm * K;
    const __nv_bfloat16* Al = xl + (long)bm * K;
    const __nv_bfloat16* Bh = Bh_ + (long)bn * K;
    const __nv_bfloat16* Bl = Bl_ + (long)bn * K;

    float acc[2][4][4];
#pragma unroll
    for (int i = 0; i < 2; i++)
#pragma unroll
        for (int j = 0; j < 4; j++)
#pragma unroll
            for (int c = 0; c < 4; c++) acc[i][j][c] = 0.f;

    const int KS = K >> 5;

    auto load_stage = [&](int slot, int ks) {
        const uint32_t base = sbase + slot * STG;
        const int k0 = ks * 32;
#pragma unroll
        for (int c = tid; c < 512; c += 256) {
            const int r = c >> 2, seg = c & 3;
            const uint32_t d = base + r * PITCH + seg * 16;
            const long off = (long)r * K + k0 + seg * 8;
            cpa16(d,        Ah + off);
            cpa16(d + AMAT, Al + off);
        }
        {
            const int r = tid >> 2, seg = tid & 3;
            const uint32_t d = base + 2*AMAT + r * PITCH + seg * 16;
            const long off = (long)r * K + k0 + seg * 8;
            cpa16(d,        Bh + off);
            cpa16(d + BMAT, Bl + off);
        }
        CPA_COMMIT();
    };

    load_stage(0, 0);
    load_stage(1, 1);

    const uint32_t a_row = (uint32_t)(wm * 32 + (lane & 15)) * PITCH;
    const uint32_t b_row = (uint32_t)(wn * 32 + (lane & 15)) * PITCH;
    const uint32_t lcol  = (uint32_t)((lane >> 4) * 16);

    for (int k = 0; k < KS; k++) {
        if (k + 1 < KS) { CPA_WAIT1(); } else { CPA_WAIT0(); }
        __syncthreads();
        if (k + 2 < KS) load_stage((k + 2) % 3, k + 2);
        const uint32_t st = sbase + (k % 3) * STG;
        GEMM_COMPUTE(st)
    }

    const int h = bn >> 6;
    const int b = bm >> 10, t0 = bm & 1023;

    if (z == 2) {
        __syncthreads();
#pragma unroll
        for (int mt = 0; mt < 2; mt++)
#pragma unroll
            for (int nt = 0; nt < 4; nt++) {
                const int dh = wn * 32 + nt * 8 + (lane & 3) * 2;
                const float b0 = bias[bn + dh], b1 = bias[bn + dh + 1];
#pragma unroll
                for (int half = 0; half < 2; half++) {
                    const int tl = wm * 32 + mt * 16 + (lane >> 2) + half * 8;
                    const float v0 = acc[mt][nt][half * 2 + 0] + b0;
                    const float v1 = acc[mt][nt][half * 2 + 1] + b1;
                    __nv_bfloat16 hh0 = __float2bfloat16(v0);
                    __nv_bfloat16 hh1 = __float2bfloat16(v1);
                    __nv_bfloat16 ll0 = __float2bfloat16(v0 - __bfloat162float(hh0));
                    __nv_bfloat16 ll1 = __float2bfloat16(v1 - __bfloat162float(hh1));
                    *(__nv_bfloat16*)(dsm + dh * VTP + tl * 2)               = hh0;
                    *(__nv_bfloat16*)(dsm + (dh + 1) * VTP + tl * 2)         = hh1;
                    *(__nv_bfloat16*)(dsm + 17408 + dh * VTP + tl * 2)       = ll0;
                    *(__nv_bfloat16*)(dsm + 17408 + (dh + 1) * VTP + tl * 2) = ll1;
                }
            }
        __syncthreads();
        {
            const int dh = tid >> 2, seg = tid & 3;
            const long gb = (((long)(b * Hn + h) * DHn + dh) * Tn) + t0 + seg * 32;
            const char* srh = dsm + dh * VTP + seg * 64;
            const char* srl = dsm + 17408 + dh * VTP + seg * 64;
#pragma unroll
            for (int i = 0; i < 4; i++) {
                *(float4*)(Vth + gb + i * 8) = *(const float4*)(srh + i * 16);
                *(float4*)(Vtl + gb + i * 8) = *(const float4*)(srl + i * 16);
            }
        }
        return;
    }

#pragma unroll
    for (int mt = 0; mt < 2; mt++)
#pragma unroll
        for (int nt = 0; nt < 4; nt++) {
            const int m0 = bm + wm * 32 + mt * 16 + (lane >> 2);
            const int n0 = bn + wn * 32 + nt * 8 + (lane & 3) * 2;
            const float b0 = bias[n0], b1 = bias[n0 + 1];
            const int dh0 = n0 & 63;
#pragma unroll
            for (int half = 0; half < 2; half++) {
                const int m = m0 + half * 8;
                const float v0 = acc[mt][nt][half * 2 + 0] + b0;
                const float v1 = acc[mt][nt][half * 2 + 1] + b1;
                const int bb = m >> 10, t = m & 1023;
                __nv_bfloat16 hh0 = __float2bfloat16(v0);
                __nv_bfloat16 hh1 = __float2bfloat16(v1);
                __nv_bfloat16 ll0 = __float2bfloat16(v0 - __bfloat162float(hh0));
                __nv_bfloat16 ll1 = __float2bfloat16(v1 - __bfloat162float(hh1));
                const long base = (((long)(bb * Hn + h) * Tn + t) * DHn) + dh0;
                if (z == 0) {
                    Qh[base] = hh0; Qh[base + 1] = hh1;
                    Ql[base] = ll0; Ql[base + 1] = ll1;
                } else {
                    Kh[base] = hh0; Kh[base + 1] = hh1;
                    Kl[base] = ll0; Kl[base + 1] = ll1;
                }
            }
        }
}

// ---------------- pv: AO = P @ V (NS=3, causal KS) ----------------
__global__ __launch_bounds__(256, 2) void pv_hmma(
    const __nv_bfloat16* __restrict__ Ph, const __nv_bfloat16* __restrict__ Pl,
    const __nv_bfloat16* __restrict__ Vth, const __nv_bfloat16* __restrict__ Vtl,
    __nv_bfloat16* __restrict__ AOh, __nv_bfloat16* __restrict__ AOl)
{
    extern __shared__ char dsm[];
    const uint32_t sbase = smem_u32(dsm);

    const int tid  = threadIdx.x;
    const int wid  = tid >> 5;
    const int lane = tid & 31;
    const int wm   = wid & 3;
    const int wn   = wid >> 2;
    const int it   = blockIdx.x;
    const int bh   = blockIdx.y;
    const int b    = bh >> 4, h = bh & 15;

    const __nv_bfloat16* Ah = Ph + ((long)bh * Tn + it * 128) * Tn;
    const __nv_bfloat16* Al = Pl + ((long)bh * Tn + it * 128) * Tn;
    const __nv_bfloat16* Bh = Vth + (long)bh * DHn * Tn;
    const __nv_bfloat16* Bl = Vtl + (long)bh * DHn * Tn;

    float acc[2][4][4];
#pragma unroll
    for (int i = 0; i < 2; i++)
#pragma unroll
        for (int j = 0; j < 4; j++)
#pragma unroll
            for (int c = 0; c < 4; c++) acc[i][j][c] = 0.f;

    const int KS = 4 * (it + 1);

    auto load_stage = [&](int slot, int ks) {
        const uint32_t base = sbase + slot * STG;
        const int k0 = ks * 32;
#pragma unroll
        for (int c = tid; c < 512; c += 256) {
            const int r = c >> 2, seg = c & 3;
            const uint32_t d = base + r * PITCH + seg * 16;
            const long off = (long)r * Tn + k0 + seg * 8;
            cpa16(d,        Ah + off);
            cpa16(d + AMAT, Al + off);
        }
        {
            const int r = tid >> 2, seg = tid & 3;
            const uint32_t d = base + 2*AMAT + r * PITCH + seg * 16;
            const long off = (long)r * Tn + k0 + seg * 8;
            cpa16(d,        Bh + off);
            cpa16(d + BMAT, Bl + off);
        }
        CPA_COMMIT();
    };

    load_stage(0, 0);
    load_stage(1, 1);

    const uint32_t a_row = (uint32_t)(wm * 32 + (lane & 15)) * PITCH;
    const uint32_t b_row = (uint32_t)(wn * 32 + (lane & 15)) * PITCH;
    const uint32_t lcol  = (uint32_t)((lane >> 4) * 16);

    for (int k = 0; k < KS; k++) {
        if (k + 1 < KS) { CPA_WAIT1(); } else { CPA_WAIT0(); }
        __syncthreads();
        if (k + 2 < KS) load_stage((k + 2) % 3, k + 2);
        const uint32_t st = sbase + (k % 3) * STG;
        GEMM_COMPUTE(st)
    }

#pragma unroll
    for (int mt = 0; mt < 2; mt++)
#pragma unroll
        for (int nt = 0; nt < 4; nt++) {
            const int t0 = it * 128 + wm * 32 + mt * 16 + (lane >> 2);
            const int dh = wn * 32 + nt * 8 + (lane & 3) * 2;
#pragma unroll
            for (int half = 0; half < 2; half++) {
                const int t = t0 + half * 8;
                const float v0 = acc[mt][nt][half * 2 + 0];
                const float v1 = acc[mt][nt][half * 2 + 1];
                const long base = ((long)b * Tn + t) * Dm + h * 64 + dh;
                __nv_bfloat16 h0 = __float2bfloat16(v0);
                __nv_bfloat16 h1 = __float2bfloat16(v1);
                __nv_bfloat162 H; H.x = h0; H.y = h1;
                __nv_bfloat162 L;
                L.x = __float2bfloat16(v0 - __bfloat162float(h0));
                L.y = __float2bfloat16(v1 - __bfloat162float(h1));
                *(__nv_bfloat162*)(AOh + base) = H;
                *(__nv_bfloat162*)(AOl + base) = L;
            }
        }
}

// ---------------- qpe table (Q reconstructed from hi/lo bf16) ----------------
__global__ __launch_bounds__(256) void qpe_kernel(const float* __restrict__ PE,
                                                  const __nv_bfloat16* __restrict__ Qh,
                                                  const __nv_bfloat16* __restrict__ Ql,
                                                  float* __restrict__ QPE)
{
    const int it = blockIdx.x, bh = blockIdx.y, h = bh & (Hn - 1);
    const __nv_bfloat16* Aqh = Qh + ((long)bh * Tn + it * 64) * DHn;
    const __nv_bfloat16* Aql = Ql + ((long)bh * Tn + it * 64) * DHn;
    const float* Bp = PE + (long)h * MAXP * DHn;

    __shared__ float Qs[64][65];
    __shared__ float Ps[64][65];

    const int tid = threadIdx.x;
    const int rowb = tid >> 4, c4 = (tid & 15) << 2;
#pragma unroll
    for (int r = 0; r < 4; r++) {
        int row = rowb + r * 16;
        const long off = (long)row * DHn + c4;
        __nv_bfloat162 qh0 = *(const __nv_bfloat162*)(Aqh + off);
        __nv_bfloat162 qh1 = *(const __nv_bfloat162*)(Aqh + off + 2);
        __nv_bfloat162 ql0 = *(const __nv_bfloat162*)(Aql + off);
        __nv_bfloat162 ql1 = *(const __nv_bfloat162*)(Aql + off + 2);
        Qs[row][c4]     = __bfloat162float(qh0.x) + __bfloat162float(ql0.x);
        Qs[row][c4 + 1] = __bfloat162float(qh0.y) + __bfloat162float(ql0.y);
        Qs[row][c4 + 2] = __bfloat162float(qh1.x) + __bfloat162float(ql1.x);
        Qs[row][c4 + 3] = __bfloat162float(qh1.y) + __bfloat162float(ql1.y);
        float4 p4 = *(const float4*)(Bp + (long)row * DHn + c4);
        Ps[row][c4] = p4.x; Ps[row][c4 + 1] = p4.y;
        Ps[row][c4 + 2] = p4.z; Ps[row][c4 + 3] = p4.w;
    }
    __syncthreads();

    const int tx = tid & 15, ty = tid >> 4;
    float acc[4][4];
#pragma unroll
    for (int i = 0; i < 4; i++)
#pragma unroll
        for (int j = 0; j < 4; j++) acc[i][j] = 0.f;

#pragma unroll 16
    for (int kk = 0; kk < 64; kk++) {
        float a0 = Qs[ty * 4 + 0][kk], a1 = Qs[ty * 4 + 1][kk];
        float a2 = Qs[ty * 4 + 2][kk], a3 = Qs[ty * 4 + 3][kk];
        float b0 = Ps[tx * 4 + 0][kk], b1 = Ps[tx * 4 + 1][kk];
        float b2 = Ps[tx * 4 + 2][kk], b3 = Ps[tx * 4 + 3][kk];
        acc[0][0] = fmaf(a0, b0, acc[0][0]); acc[0][1] = fmaf(a0, b1, acc[0][1]);
        acc[0][2] = fmaf(a0, b2, acc[0][2]); acc[0][3] = fmaf(a0, b3, acc[0][3]);
        acc[1][0] = fmaf(a1, b0, acc[1][0]); acc[1][1] = fmaf(a1, b1, acc[1][1]);
        acc[1][2] = fmaf(a1, b2, acc[1][2]); acc[1][3] = fmaf(a1, b3, acc[1][3]);
        acc[2][0] = fmaf(a2, b0, acc[2][0]); acc[2][1] = fmaf(a2, b1, acc[2][1]);
        acc[2][2] = fmaf(a2, b2, acc[2][2]); acc[2][3] = fmaf(a2, b3, acc[2][3]);
        acc[3][0] = fmaf(a3, b0, acc[3][0]); acc[3][1] = fmaf(a3, b1, acc[3][1]);
        acc[3][2] = fmaf(a3, b2, acc[3][2]); acc[3][3] = fmaf(a3, b3, acc[3][3]);
    }

    float* out = QPE + ((long)bh * Tn + it * 64) * MAXP;
#pragma unroll
    for (int ii = 0; ii < 4; ii++) {
        float4 o4 = make_float4(acc[ii][0], acc[ii][1], acc[ii][2], acc[ii][3]);
        *(float4*)(out + (long)(ty * 4 + ii) * MAXP + tx * 4) = o4;
    }
}

// ---------------- CoPE (block-per-row, validated) ----------------
__global__ __launch_bounds__(256) void cope_kernel(const float* __restrict__ S,
                                                   const float* __restrict__ QPE,
                                                   __nv_bfloat16* __restrict__ Ph,
                                                   __nv_bfloat16* __restrict__ Pl)
{
    const int i = blockIdx.x, bh = blockIdx.y;
    const float* row = S + ((long)bh * Tn + i) * Tn;
    const long prow = ((long)bh * Tn + i) * Tn;
    const float* qpe = QPE + ((long)bh * Tn + i) * MAXP;
    const int blockend = ((i >> 7) + 1) << 7;

    __shared__ float qpes[64];
    __shared__ float wred[8];
    __shared__ float wred2[8];

    const int tid = threadIdx.x, lane = tid & 31, wid = tid >> 5;
    if (tid < 64) qpes[tid] = qpe[tid];

    const int j0 = tid << 2;
    float qk[4] = {0.f, 0.f, 0.f, 0.f};
    if (j0 <= i) {
        float4 s4 = *(const float4*)(row + j0);
        qk[0] = s4.x; qk[1] = s4.y; qk[2] = s4.z; qk[3] = s4.w;
    }

    float lpre[4];
    float run = 0.f;
#pragma unroll
    for (int q = 0; q < 4; q++) {
        float gg = 0.f;
        if (j0 + q <= i)
            gg = __fdividef(1.f, 1.f + __expf(-0.125f * qk[q]));
        run += gg;
        lpre[q] = run;
    }

    float v = run;
#pragma unroll
    for (int o = 1; o < 32; o <<= 1) {
        float t = __shfl_up_sync(0xffffffffu, v, o);
        if (lane >= o) v += t;
    }
    if (lane == 31) wred[wid] = v;
    __syncthreads();
    if (tid < 8) {
        float w = wred[tid];
#pragma unroll
        for (int o = 1; o < 8; o <<= 1) {
            float t = __shfl_up_sync(0x000000ffu, w, o);
            if (tid >= o) w += t;
        }
        wred[tid] = w;
    }
    __syncthreads();
    const float base  = (v - run) + (wid ? wred[wid - 1] : 0.f);
    const float total = wred[7];

    float sc[4];
    float mx = -INFINITY;
#pragma unroll
    for (int q = 0; q < 4; q++) {
        float s_ = -INFINITY;
        if (j0 + q <= i) {
            float pos = total - (base + lpre[q]);
            pos = fminf(fmaxf(pos, 0.f), 63.f);
            float pf = floorf(pos);
            int fi = (int)pf;
            float al = pos - pf;
            int ci = (fi < 63) ? fi + 1 : 63;
            float qf = qpes[fi], qc = qpes[ci];
            float qv = qf + al * (qc - qf);
            s_ = 0.125f * (qk[q] + qv);
        }
        sc[q] = s_;
        mx = fmaxf(mx, s_);
    }
#pragma unroll
    for (int o = 16; o; o >>= 1) mx = fmaxf(mx, __shfl_xor_sync(0xffffffffu, mx, o));
    if (lane == 0) wred2[wid] = mx;
    __syncthreads();
    float bmax = wred2[0];
#pragma unroll
    for (int k = 1; k < 8; k++) bmax = fmaxf(bmax, wred2[k]);

    float p[4];
    float ssum = 0.f;
#pragma unroll
    for (int q = 0; q < 4; q++) {
        float e = (j0 + q <= i) ? __expf(sc[q] - bmax) : 0.f;
        p[q] = e;
        ssum += e;
    }
#pragma unroll
    for (int o = 16; o; o >>= 1) ssum += __shfl_xor_sync(0xffffffffu, ssum, o);
    __syncthreads();
    if (lane == 0) wred2[wid] = ssum;
    __syncthreads();
    float tot = 0.f;
#pragma unroll
    for (int k = 0; k < 8; k++) tot += wred2[k];
    const float inv = __fdividef(1.f, tot);

    if (j0 < blockend) {
        float v0 = p[0] * inv, v1 = p[1] * inv, v2 = p[2] * inv, v3 = p[3] * inv;
        __nv_bfloat16 h0 = __float2bfloat16(v0), h1 = __float2bfloat16(v1);
        __nv_bfloat16 h2 = __float2bfloat16(v2), h3 = __float2bfloat16(v3);
        __nv_bfloat162 H0; H0.x = h0; H0.y = h1;
        __nv_bfloat162 H1; H1.x = h2; H1.y = h3;
        __nv_bfloat162 L0, L1;
        L0.x = __float2bfloat16(v0 - __bfloat162float(h0));
        L0.y = __float2bfloat16(v1 - __bfloat162float(h1));
        L1.x = __float2bfloat16(v2 - __bfloat162float(h2));
        L1.y = __float2bfloat16(v3 - __bfloat162float(h3));
        *(__nv_bfloat162*)(Ph + prow + j0)     = H0;
        *(__nv_bfloat162*)(Ph + prow + j0 + 2) = H1;
        *(__nv_bfloat162*)(Pl + prow + j0)     = L0;
        *(__nv_bfloat162*)(Pl + prow + j0 + 2) = L1;
    }
}

// ---------------- launcher ----------------
extern "C" void kernel_launch(void* const* d_in, const int* in_sizes, int n_in,
                              void* d_out, int out_size)
{
    (void)in_sizes; (void)n_in; (void)out_size;
    const float* x  = (const float*)d_in[0];
    const float* Wq = (const float*)d_in[1];
    const float* bq = (const float*)d_in[2];
    const float* Wk = (const float*)d_in[3];
    const float* bk = (const float*)d_in[4];
    const float* Wv = (const float*)d_in[5];
    const float* bv = (const float*)d_in[6];
    const float* Wo = (const float*)d_in[7];
    const float* bo = (const float*)d_in[8];
    const float* pe = (const float*)d_in[9];
    float* out = (float*)d_out;

    float *QPEd, *Sd;
    __nv_bfloat16 *xh, *xl, *Wqh, *Wql, *Wkh, *Wkl, *Wvh, *Wvl, *Woh, *Wol;
    __nv_bfloat16 *Qh, *Ql, *Kh, *Kl, *AOh, *AOl, *Phd, *Pld, *Vth, *Vtl;
    cudaGetSymbolAddress((void**)&QPEd, g_QPE);
    cudaGetSymbolAddress((void**)&Sd, g_S);
    cudaGetSymbolAddress((void**)&xh, g_xh);   cudaGetSymbolAddress((void**)&xl, g_xl);
    cudaGetSymbolAddress((void**)&Wqh, g_Wqh); cudaGetSymbolAddress((void**)&Wql, g_Wql);
    cudaGetSymbolAddress((void**)&Wkh, g_Wkh); cudaGetSymbolAddress((void**)&Wkl, g_Wkl);
    cudaGetSymbolAddress((void**)&Wvh, g_Wvh); cudaGetSymbolAddress((void**)&Wvl, g_Wvl);
    cudaGetSymbolAddress((void**)&Woh, g_Woh); cudaGetSymbolAddress((void**)&Wol, g_Wol);
    cudaGetSymbolAddress((void**)&Qh, g_Qh);   cudaGetSymbolAddress((void**)&Ql, g_Ql);
    cudaGetSymbolAddress((void**)&Kh, g_Kh);   cudaGetSymbolAddress((void**)&Kl, g_Kl);
    cudaGetSymbolAddress((void**)&AOh, g_AOh); cudaGetSymbolAddress((void**)&AOl, g_AOl);
    cudaGetSymbolAddress((void**)&Phd, g_Ph);  cudaGetSymbolAddress((void**)&Pld, g_Pl);
    cudaGetSymbolAddress((void**)&Vth, g_Vth); cudaGetSymbolAddress((void**)&Vtl, g_Vtl);

    static int smem_set = 0;
    if (!smem_set) {
        cudaFuncSetAttribute(mm_hmma, cudaFuncAttributeMaxDynamicSharedMemorySize, MM_SMEM);
        cudaFuncSetAttribute(qkv_hmma, cudaFuncAttributeMaxDynamicSharedMemorySize, MM_SMEM);
        cudaFuncSetAttribute(pv_hmma, cudaFuncAttributeMaxDynamicSharedMemorySize, MM_SMEM);
        cudaFuncSetAttribute(qk_hmma, cudaFuncAttributeMaxDynamicSharedMemorySize, QK_SMEM);
        smem_set = 1;
    }

    dim3 blk(256);

    splitk<<<2048, blk>>>(x, xh, xl, Bsz * Tn * Dm);
    splitW4<<<dim3(1024, 1, 4), blk>>>(Wq, Wk, Wv, Wo, Wqh, Wql, Wkh, Wkl,
                                       Wvh, Wvl, Woh, Wol);

    qkv_hmma<<<dim3(16, 16, 3), blk, MM_SMEM>>>(xh, xl, Wqh, Wql, Wkh, Wkl, Wvh, Wvl,
                                                bq, bk, bv, Qh, Ql, Kh, Kl, Vth, Vtl);

    qk_hmma<<<dim3(16, 8, 32), blk, QK_SMEM>>>(Qh, Ql, Kh, Kl, Sd);

    qpe_kernel<<<dim3(16, 32), blk>>>(pe, Qh, Ql, QPEd);

    cope_kernel<<<dim3(1024, 32), blk>>>(Sd, QPEd, Phd, Pld);

    pv_hmma<<<dim3(8, 32), blk, MM_SMEM>>>(Phd, Pld, Vth, Vtl, AOh, AOl);

    mm_hmma<<<dim3(16, 16, 1), blk, MM_SMEM>>>(AOh, AOl, Woh, Wol, bo,
                                               out, 2048, 1024, 1024, 0, 0, 0);
}

// round 11
// speedup vs baseline: 1.1315x; 1.0072x over previous
#include <cuda_runtime.h>
#include <cuda_bf16.h>
#include <math.h>
#include <stdint.h>

#define Bsz 2
#define Tn  1024
#define Dm  1024
#define Hn  16
#define DHn 64
#define BHn (Bsz*Hn)
#define MAXP 64

// ---------------- scratch ----------------
__device__ float g_QPE[BHn*Tn*MAXP];
__device__ float g_S[(long)BHn*Tn*Tn];
__device__ __nv_bfloat16 g_Ph[(long)BHn*Tn*Tn], g_Pl[(long)BHn*Tn*Tn];
__device__ __nv_bfloat16 g_Vth[BHn*DHn*Tn], g_Vtl[BHn*DHn*Tn];
__device__ __nv_bfloat16 g_xh[Bsz*Tn*Dm],  g_xl[Bsz*Tn*Dm];
__device__ __nv_bfloat16 g_Wqh[Dm*Dm], g_Wql[Dm*Dm];
__device__ __nv_bfloat16 g_Wkh[Dm*Dm], g_Wkl[Dm*Dm];
__device__ __nv_bfloat16 g_Wvh[Dm*Dm], g_Wvl[Dm*Dm];
__device__ __nv_bfloat16 g_Woh[Dm*Dm], g_Wol[Dm*Dm];
__device__ __nv_bfloat16 g_Qh[BHn*Tn*DHn], g_Ql[BHn*Tn*DHn];
__device__ __nv_bfloat16 g_Kh[BHn*Tn*DHn], g_Kl[BHn*Tn*DHn];
__device__ __nv_bfloat16 g_AOh[Bsz*Tn*Dm], g_AOl[Bsz*Tn*Dm];

// ---------------- helpers ----------------
__device__ __forceinline__ uint32_t smem_u32(const void* p) {
    uint32_t a;
    asm("{ .reg .u64 t; cvta.to.shared.u64 t, %1; cvt.u32.u64 %0, t; }" : "=r"(a) : "l"(p));
    return a;
}
__device__ __forceinline__ void cpa16(uint32_t dst, const void* src) {
    asm volatile("cp.async.cg.shared.global [%0], [%1], 16;" :: "r"(dst), "l"(src));
}
#define CPA_COMMIT() asm volatile("cp.async.commit_group;" ::: "memory")
#define CPA_WAIT1()  asm volatile("cp.async.wait_group 1;" ::: "memory")
#define CPA_WAIT0()  asm volatile("cp.async.wait_group 0;" ::: "memory")

#define LDSM4(r, a) \
    asm volatile("ldmatrix.sync.aligned.m8n8.x4.shared.b16 {%0,%1,%2,%3}, [%4];" \
        : "=r"((r)[0]), "=r"((r)[1]), "=r"((r)[2]), "=r"((r)[3]) : "r"(a))

#define MMA_BF16(c, a, b0v, b1v) \
    asm volatile("mma.sync.aligned.m16n8k16.row.col.f32.bf16.bf16.f32 " \
        "{%0,%1,%2,%3},{%4,%5,%6,%7},{%8,%9},{%0,%1,%2,%3};" \
        : "+f"((c)[0]), "+f"((c)[1]), "+f"((c)[2]), "+f"((c)[3]) \
        : "r"((a)[0]), "r"((a)[1]), "r"((a)[2]), "r"((a)[3]), "r"(b0v), "r"(b1v))

// ---------------- split fp32 -> bf16 hi/lo ----------------
__device__ __forceinline__ void split_store4(const float* s, __nv_bfloat16* h,
                                             __nv_bfloat16* l, int i)
{
    float4 v = *(const float4*)(s + i);
    __nv_bfloat16 h0 = __float2bfloat16(v.x), h1 = __float2bfloat16(v.y);
    __nv_bfloat16 h2 = __float2bfloat16(v.z), h3 = __float2bfloat16(v.w);
    __nv_bfloat162 H0; H0.x = h0; H0.y = h1;
    __nv_bfloat162 H1; H1.x = h2; H1.y = h3;
    __nv_bfloat162 L0, L1;
    L0.x = __float2bfloat16(v.x - __bfloat162float(h0));
    L0.y = __float2bfloat16(v.y - __bfloat162float(h1));
    L1.x = __float2bfloat16(v.z - __bfloat162float(h2));
    L1.y = __float2bfloat16(v.w - __bfloat162float(h3));
    *(__nv_bfloat162*)(h + i)     = H0;
    *(__nv_bfloat162*)(h + i + 2) = H1;
    *(__nv_bfloat162*)(l + i)     = L0;
    *(__nv_bfloat162*)(l + i + 2) = L1;
}

__global__ __launch_bounds__(256) void splitk(const float* __restrict__ s,
                                              __nv_bfloat16* __restrict__ h,
                                              __nv_bfloat16* __restrict__ l, int n)
{
    int i = (blockIdx.x * 256 + threadIdx.x) * 4;
    if (i >= n) return;
    split_store4(s, h, l, i);
}

__global__ __launch_bounds__(256) void splitW4(
    const float* __restrict__ Wq, const float* __restrict__ Wk,
    const float* __restrict__ Wv, const float* __restrict__ Wo,
    __nv_bfloat16* __restrict__ Wqh, __nv_bfloat16* __restrict__ Wql,
    __nv_bfloat16* __restrict__ Wkh, __nv_bfloat16* __restrict__ Wkl,
    __nv_bfloat16* __restrict__ Wvh, __nv_bfloat16* __restrict__ Wvl,
    __nv_bfloat16* __restrict__ Woh, __nv_bfloat16* __restrict__ Wol)
{
    const int z = blockIdx.z;
    const float* s = (z == 0) ? Wq : (z == 1) ? Wk : (z == 2) ? Wv : Wo;
    __nv_bfloat16* h = (z == 0) ? Wqh : (z == 1) ? Wkh : (z == 2) ? Wvh : Woh;
    __nv_bfloat16* l = (z == 0) ? Wql : (z == 1) ? Wkl : (z == 2) ? Wvl : Wol;
    int i = (blockIdx.x * 256 + threadIdx.x) * 4;
    split_store4(s, h, l, i);
}

// ---------------- GEMM tile params: BM=128, BN=64, BK=32, 256 thr, NS=2 --------
// smem stage 30720B; NS=2 -> 61440B -> 3 CTA/SM (184320 <= 228KB), regs capped 85
#define PITCH 80
#define AMAT  (128*PITCH)
#define BMAT  (64*PITCH)
#define STG   (2*AMAT + 2*BMAT)
#define MM_SMEM (2*STG)

#define GEMM_COMPUTE(st)                                                          \
    _Pragma("unroll")                                                             \
    for (int kc = 0; kc < 2; kc++) {                                              \
        const uint32_t col = kc * 32 + lcol;                                      \
        uint32_t ah[2][4], al[2][4], bh[2][4], bl[2][4];                          \
        _Pragma("unroll")                                                         \
        for (int mt = 0; mt < 2; mt++) {                                          \
            const uint32_t ad = (st) + a_row + (uint32_t)(mt * 16 * PITCH) + col; \
            LDSM4(ah[mt], ad);                                                    \
            LDSM4(al[mt], ad + AMAT);                                             \
        }                                                                         \
        _Pragma("unroll")                                                         \
        for (int np = 0; np < 2; np++) {                                          \
            const uint32_t bd = (st) + 2*AMAT + b_row + (uint32_t)(np * 16 * PITCH) + col; \
            LDSM4(bh[np], bd);                                                    \
            LDSM4(bl[np], bd + BMAT);                                             \
        }                                                                         \
        _Pragma("unroll")                                                         \
        for (int mt = 0; mt < 2; mt++)                                            \
            _Pragma("unroll")                                                     \
            for (int nt = 0; nt < 4; nt++) {                                      \
                const int np = nt >> 1, i = nt & 1;                               \
                MMA_BF16(acc[mt][nt], ah[mt], bh[np][i], bh[np][i + 2]);          \
                MMA_BF16(acc[mt][nt], ah[mt], bl[np][i], bl[np][i + 2]);          \
                MMA_BF16(acc[mt][nt], al[mt], bh[np][i], bh[np][i + 2]);          \
            }                                                                     \
    }

// generic: C(fp32) = (Ahi+Alo)(Bhi+Blo)^T + bias
__global__ __launch_bounds__(256, 3) void mm_hmma(
    const __nv_bfloat16* __restrict__ Ahi, const __nv_bfloat16* __restrict__ Alo,
    const __nv_bfloat16* __restrict__ Bhi, const __nv_bfloat16* __restrict__ Blo,
    const float* __restrict__ bias,
    float* __restrict__ Cf,
    int M, int N, int K, long sA, long sB, long sC)
{
    extern __shared__ char dsm[];
    const uint32_t sbase = smem_u32(dsm);

    const int tid  = threadIdx.x;
    const int wid  = tid >> 5;
    const int lane = tid & 31;
    const int wm   = wid & 3;
    const int wn   = wid >> 2;
    const int z    = blockIdx.z;
    const int bm   = blockIdx.y * 128;
    const int bn   = blockIdx.x * 64;

    const __nv_bfloat16* Ah = Ahi + (long)z * sA + (long)bm * K;
    const __nv_bfloat16* Al = Alo + (long)z * sA + (long)bm * K;
    const __nv_bfloat16* Bh = Bhi + (long)z * sB + (long)bn * K;
    const __nv_bfloat16* Bl = Blo + (long)z * sB + (long)bn * K;

    float acc[2][4][4];
#pragma unroll
    for (int i = 0; i < 2; i++)
#pragma unroll
        for (int j = 0; j < 4; j++)
#pragma unroll
            for (int c = 0; c < 4; c++) acc[i][j][c] = 0.f;

    const int KS = K >> 5;

    auto load_stage = [&](int slot, int ks) {
        const uint32_t base = sbase + slot * STG;
        const int k0 = ks * 32;
#pragma unroll
        for (int c = tid; c < 512; c += 256) {
            const int r = c >> 2, seg = c & 3;
            const uint32_t d = base + r * PITCH + seg * 16;
            const long off = (long)r * K + k0 + seg * 8;
            cpa16(d,        Ah + off);
            cpa16(d + AMAT, Al + off);
        }
        {
            const int r = tid >> 2, seg = tid & 3;
            const uint32_t d = base + 2*AMAT + r * PITCH + seg * 16;
            const long off = (long)r * K + k0 + seg * 8;
            cpa16(d,        Bh + off);
            cpa16(d + BMAT, Bl + off);
        }
        CPA_COMMIT();
    };

    load_stage(0, 0);

    const uint32_t a_row = (uint32_t)(wm * 32 + (lane & 15)) * PITCH;
    const uint32_t b_row = (uint32_t)(wn * 32 + (lane & 15)) * PITCH;
    const uint32_t lcol  = (uint32_t)((lane >> 4) * 16);

    for (int k = 0; k < KS; k++) {
        if (k + 1 < KS) load_stage((k + 1) & 1, k + 1);
        if (k + 1 < KS) { CPA_WAIT1(); } else { CPA_WAIT0(); }
        __syncthreads();
        const uint32_t st = sbase + (k & 1) * STG;
        GEMM_COMPUTE(st)
        __syncthreads();
    }

#pragma unroll
    for (int mt = 0; mt < 2; mt++)
#pragma unroll
        for (int nt = 0; nt < 4; nt++) {
            const int m0 = bm + wm * 32 + mt * 16 + (lane >> 2);
            const int n0 = bn + wn * 32 + nt * 8 + (lane & 3) * 2;
            float b0 = 0.f, b1 = 0.f;
            if (bias) { b0 = bias[n0]; b1 = bias[n0 + 1]; }
#pragma unroll
            for (int half = 0; half < 2; half++) {
                const int m = m0 + half * 8;
                float* cp = Cf + (long)z * sC + (long)m * N + n0;
                cp[0] = acc[mt][nt][half * 2 + 0] + b0;
                cp[1] = acc[mt][nt][half * 2 + 1] + b1;
            }
        }
}

// ---------------- QK specialized: K=64 single-stage, 4 CTAs/SM ----------
#define QPITCH 144
#define QAMAT  (128*QPITCH)
#define QBMAT  (64*QPITCH)
#define QK_SMEM (2*QAMAT + 2*QBMAT)

__global__ __launch_bounds__(256, 4) void qk_hmma(
    const __nv_bfloat16* __restrict__ Qh, const __nv_bfloat16* __restrict__ Ql,
    const __nv_bfloat16* __restrict__ Kh, const __nv_bfloat16* __restrict__ Kl,
    float* __restrict__ S)
{
    if ((int)blockIdx.x >= 2 * (int)blockIdx.y + 2) return;

    extern __shared__ char dsm[];
    const uint32_t sbase = smem_u32(dsm);

    const int tid  = threadIdx.x;
    const int wid  = tid >> 5;
    const int lane = tid & 31;
    const int wm   = wid & 3;
    const int wn   = wid >> 2;
    const int z    = blockIdx.z;
    const int bm   = blockIdx.y * 128;
    const int bn   = blockIdx.x * 64;

    const __nv_bfloat16* Ah = Qh + (long)z * Tn * DHn + (long)bm * DHn;
    const __nv_bfloat16* Al = Ql + (long)z * Tn * DHn + (long)bm * DHn;
    const __nv_bfloat16* Bh = Kh + (long)z * Tn * DHn + (long)bn * DHn;
    const __nv_bfloat16* Bl = Kl + (long)z * Tn * DHn + (long)bn * DHn;

#pragma unroll
    for (int c = tid; c < 1024; c += 256) {
        const int r = c >> 3, seg = c & 7;
        const uint32_t d = sbase + r * QPITCH + seg * 16;
        const long off = (long)r * DHn + seg * 8;
        cpa16(d,         Ah + off);
        cpa16(d + QAMAT, Al + off);
    }
#pragma unroll
    for (int c = tid; c < 512; c += 256) {
        const int r = c >> 3, seg = c & 7;
        const uint32_t d = sbase + 2*QAMAT + r * QPITCH + seg * 16;
        const long off = (long)r * DHn + seg * 8;
        cpa16(d,         Bh + off);
        cpa16(d + QBMAT, Bl + off);
    }
    CPA_COMMIT();
    CPA_WAIT0();
    __syncthreads();

    float acc[2][4][4];
#pragma unroll
    for (int i = 0; i < 2; i++)
#pragma unroll
        for (int j = 0; j < 4; j++)
#pragma unroll
            for (int c = 0; c < 4; c++) acc[i][j][c] = 0.f;

    const uint32_t a_row = (uint32_t)(wm * 32 + (lane & 15)) * QPITCH;
    const uint32_t b_row = (uint32_t)(wn * 32 + (lane & 15)) * QPITCH;
    const uint32_t lcol  = (uint32_t)((lane >> 4) * 16);

#pragma unroll
    for (int kc = 0; kc < 4; kc++) {
        const uint32_t col = kc * 32 + lcol;
        uint32_t ah[2][4], al[2][4], bh[2][4], bl[2][4];
#pragma unroll
        for (int mt = 0; mt < 2; mt++) {
            const uint32_t ad = sbase + a_row + (uint32_t)(mt * 16 * QPITCH) + col;
            LDSM4(ah[mt], ad);
            LDSM4(al[mt], ad + QAMAT);
        }
#pragma unroll
        for (int np = 0; np < 2; np++) {
            const uint32_t bd = sbase + 2*QAMAT + b_row + (uint32_t)(np * 16 * QPITCH) + col;
            LDSM4(bh[np], bd);
            LDSM4(bl[np], bd + QBMAT);
        }
#pragma unroll
        for (int mt = 0; mt < 2; mt++)
#pragma unroll
            for (int nt = 0; nt < 4; nt++) {
                const int np = nt >> 1, i = nt & 1;
                MMA_BF16(acc[mt][nt], ah[mt], bh[np][i], bh[np][i + 2]);
                MMA_BF16(acc[mt][nt], ah[mt], bl[np][i], bl[np][i + 2]);
                MMA_BF16(acc[mt][nt], al[mt], bh[np][i], bh[np][i + 2]);
            }
    }

#pragma unroll
    for (int mt = 0; mt < 2; mt++)
#pragma unroll
        for (int nt = 0; nt < 4; nt++) {
            const int m0 = bm + wm * 32 + mt * 16 + (lane >> 2);
            const int n0 = bn + wn * 32 + nt * 8 + (lane & 3) * 2;
#pragma unroll
            for (int half = 0; half < 2; half++) {
                const int m = m0 + half * 8;
                float* cp = S + (long)z * Tn * Tn + (long)m * Tn + n0;
                cp[0] = acc[mt][nt][half * 2 + 0];
                cp[1] = acc[mt][nt][half * 2 + 1];
            }
        }
}

// ---------------- merged QKV projection (NS=2, 3 CTA; V via smem transpose) --
#define VTP 272

__global__ __launch_bounds__(256, 3) void qkv_hmma(
    const __nv_bfloat16* __restrict__ xh, const __nv_bfloat16* __restrict__ xl,
    const __nv_bfloat16* __restrict__ Wqh, const __nv_bfloat16* __restrict__ Wql,
    const __nv_bfloat16* __restrict__ Wkh, const __nv_bfloat16* __restrict__ Wkl,
    const __nv_bfloat16* __restrict__ Wvh, const __nv_bfloat16* __restrict__ Wvl,
    const float* __restrict__ bq, const float* __restrict__ bk, const float* __restrict__ bv,
    __nv_bfloat16* __restrict__ Qh, __nv_bfloat16* __restrict__ Ql,
    __nv_bfloat16* __restrict__ Kh, __nv_bfloat16* __restrict__ Kl,
    __nv_bfloat16* __restrict__ Vth, __nv_bfloat16* __restrict__ Vtl)
{
    extern __shared__ char dsm[];
    const uint32_t sbase = smem_u32(dsm);

    const int tid  = threadIdx.x;
    const int wid  = tid >> 5;
    const int lane = tid & 31;
    const int wm   = wid & 3;
    const int wn   = wid >> 2;
    const int z    = blockIdx.z;
    const int bm   = blockIdx.y * 128;
    const int bn   = blockIdx.x * 64;
    const int K    = 1024;

    const __nv_bfloat16* Bh_ = (z == 0) ? Wqh : (z == 1) ? Wkh : Wvh;
    const __nv_bfloat16* Bl_ = (z == 0) ? Wql : (z == 1) ? Wkl : Wvl;
    const float* bias = (z == 0) ? bq : (z == 1) ? bk : bv;

    const __nv_bfloat16* Ah = xh + (long)bm * K;
    const __nv_bfloat16* Al = xl + (long)bm * K;
    const __nv_bfloat16* Bh = Bh_ + (long)bn * K;
    const __nv_bfloat16* Bl = Bl_ + (long)bn * K;

    float acc[2][4][4];
#pragma unroll
    for (int i = 0; i < 2; i++)
#pragma unroll
        for (int j = 0; j < 4; j++)
#pragma unroll
            for (int c = 0; c < 4; c++) acc[i][j][c] = 0.f;

    const int KS = K >> 5;

    auto load_stage = [&](int slot, int ks) {
        const uint32_t base = sbase + slot * STG;
        const int k0 = ks * 32;
#pragma unroll
        for (int c = tid; c < 512; c += 256) {
            const int r = c >> 2, seg = c & 3;
            const uint32_t d = base + r * PITCH + seg * 16;
            const long off = (long)r * K + k0 + seg * 8;
            cpa16(d,        Ah + off);
            cpa16(d + AMAT, Al + off);
        }
        {
            const int r = tid >> 2, seg = tid & 3;
            const uint32_t d = base + 2*AMAT + r * PITCH + seg * 16;
            const long off = (long)r * K + k0 + seg * 8;
            cpa16(d,        Bh + off);
            cpa16(d + BMAT, Bl + off);
        }
        CPA_COMMIT();
    };

    load_stage(0, 0);

    const uint32_t a_row = (uint32_t)(wm * 32 + (lane & 15)) * PITCH;
    const uint32_t b_row = (uint32_t)(wn * 32 + (lane & 15)) * PITCH;
    const uint32_t lcol  = (uint32_t)((lane >> 4) * 16);

    for (int k = 0; k < KS; k++) {
        if (k + 1 < KS) load_stage((k + 1) & 1, k + 1);
        if (k + 1 < KS) { CPA_WAIT1(); } else { CPA_WAIT0(); }
        __syncthreads();
        const uint32_t st = sbase + (k & 1) * STG;
        GEMM_COMPUTE(st)
        __syncthreads();
    }

    const int h = bn >> 6;
    const int b = bm >> 10, t0 = bm & 1023;

    if (z == 2) {
#pragma unroll
        for (int mt = 0; mt < 2; mt++)
#pragma unroll
            for (int nt = 0; nt < 4; nt++) {
                const int dh = wn * 32 + nt * 8 + (lane & 3) * 2;
                const float b0 = bias[bn + dh], b1 = bias[bn + dh + 1];
#pragma unroll
                for (int half = 0; half < 2; half++) {
                    const int tl = wm * 32 + mt * 16 + (lane >> 2) + half * 8;
                    const float v0 = acc[mt][nt][half * 2 + 0] + b0;
                    const float v1 = acc[mt][nt][half * 2 + 1] + b1;
                    __nv_bfloat16 hh0 = __float2bfloat16(v0);
                    __nv_bfloat16 hh1 = __float2bfloat16(v1);
                    __nv_bfloat16 ll0 = __float2bfloat16(v0 - __bfloat162float(hh0));
                    __nv_bfloat16 ll1 = __float2bfloat16(v1 - __bfloat162float(hh1));
                    *(__nv_bfloat16*)(dsm + dh * VTP + tl * 2)               = hh0;
                    *(__nv_bfloat16*)(dsm + (dh + 1) * VTP + tl * 2)         = hh1;
                    *(__nv_bfloat16*)(dsm + 17408 + dh * VTP + tl * 2)       = ll0;
                    *(__nv_bfloat16*)(dsm + 17408 + (dh + 1) * VTP + tl * 2) = ll1;
                }
            }
        __syncthreads();
        {
            const int dh = tid >> 2, seg = tid & 3;
            const long gb = (((long)(b * Hn + h) * DHn + dh) * Tn) + t0 + seg * 32;
            const char* srh = dsm + dh * VTP + seg * 64;
            const char* srl = dsm + 17408 + dh * VTP + seg * 64;
#pragma unroll
            for (int i = 0; i < 4; i++) {
                *(float4*)(Vth + gb + i * 8) = *(const float4*)(srh + i * 16);
                *(float4*)(Vtl + gb + i * 8) = *(const float4*)(srl + i * 16);
            }
        }
        return;
    }

#pragma unroll
    for (int mt = 0; mt < 2; mt++)
#pragma unroll
        for (int nt = 0; nt < 4; nt++) {
            const int m0 = bm + wm * 32 + mt * 16 + (lane >> 2);
            const int n0 = bn + wn * 32 + nt * 8 + (lane & 3) * 2;
            const float b0 = bias[n0], b1 = bias[n0 + 1];
            const int dh0 = n0 & 63;
#pragma unroll
            for (int half = 0; half < 2; half++) {
                const int m = m0 + half * 8;
                const float v0 = acc[mt][nt][half * 2 + 0] + b0;
                const float v1 = acc[mt][nt][half * 2 + 1] + b1;
                const int bb = m >> 10, t = m & 1023;
                __nv_bfloat16 hh0 = __float2bfloat16(v0);
                __nv_bfloat16 hh1 = __float2bfloat16(v1);
                __nv_bfloat16 ll0 = __float2bfloat16(v0 - __bfloat162float(hh0));
                __nv_bfloat16 ll1 = __float2bfloat16(v1 - __bfloat162float(hh1));
                const long base = (((long)(bb * Hn + h) * Tn + t) * DHn) + dh0;
                if (z == 0) {
                    Qh[base] = hh0; Qh[base + 1] = hh1;
                    Ql[base] = ll0; Ql[base + 1] = ll1;
                } else {
                    Kh[base] = hh0; Kh[base + 1] = hh1;
                    Kl[base] = ll0; Kl[base + 1] = ll1;
                }
            }
        }
}

// ---------------- pv: AO = P @ V (NS=2, 3 CTA, causal KS) ----------------
__global__ __launch_bounds__(256, 3) void pv_hmma(
    const __nv_bfloat16* __restrict__ Ph, const __nv_bfloat16* __restrict__ Pl,
    const __nv_bfloat16* __restrict__ Vth, const __nv_bfloat16* __restrict__ Vtl,
    __nv_bfloat16* __restrict__ AOh, __nv_bfloat16* __restrict__ AOl)
{
    extern __shared__ char dsm[];
    const uint32_t sbase = smem_u32(dsm);

    const int tid  = threadIdx.x;
    const int wid  = tid >> 5;
    const int lane = tid & 31;
    const int wm   = wid & 3;
    const int wn   = wid >> 2;
    const int it   = blockIdx.x;
    const int bh   = blockIdx.y;
    const int b    = bh >> 4, h = bh & 15;

    const __nv_bfloat16* Ah = Ph + ((long)bh * Tn + it * 128) * Tn;
    const __nv_bfloat16* Al = Pl + ((long)bh * Tn + it * 128) * Tn;
    const __nv_bfloat16* Bh = Vth + (long)bh * DHn * Tn;
    const __nv_bfloat16* Bl = Vtl + (long)bh * DHn * Tn;

    float acc[2][4][4];
#pragma unroll
    for (int i = 0; i < 2; i++)
#pragma unroll
        for (int j = 0; j < 4; j++)
#pragma unroll
            for (int c = 0; c < 4; c++) acc[i][j][c] = 0.f;

    const int KS = 4 * (it + 1);

    auto load_stage = [&](int slot, int ks) {
        const uint32_t base = sbase + slot * STG;
        const int k0 = ks * 32;
#pragma unroll
        for (int c = tid; c < 512; c += 256) {
            const int r = c >> 2, seg = c & 3;
            const uint32_t d = base + r * PITCH + seg * 16;
            const long off = (long)r * Tn + k0 + seg * 8;
            cpa16(d,        Ah + off);
            cpa16(d + AMAT, Al + off);
        }
        {
            const int r = tid >> 2, seg = tid & 3;
            const uint32_t d = base + 2*AMAT + r * PITCH + seg * 16;
            const long off = (long)r * Tn + k0 + seg * 8;
            cpa16(d,        Bh + off);
            cpa16(d + BMAT, Bl + off);
        }
        CPA_COMMIT();
    };

    load_stage(0, 0);

    const uint32_t a_row = (uint32_t)(wm * 32 + (lane & 15)) * PITCH;
    const uint32_t b_row = (uint32_t)(wn * 32 + (lane & 15)) * PITCH;
    const uint32_t lcol  = (uint32_t)((lane >> 4) * 16);

    for (int k = 0; k < KS; k++) {
        if (k + 1 < KS) load_stage((k + 1) & 1, k + 1);
        if (k + 1 < KS) { CPA_WAIT1(); } else { CPA_WAIT0(); }
        __syncthreads();
        const uint32_t st = sbase + (k & 1) * STG;
        GEMM_COMPUTE(st)
        __syncthreads();
    }

#pragma unroll
    for (int mt = 0; mt < 2; mt++)
#pragma unroll
        for (int nt = 0; nt < 4; nt++) {
            const int t0 = it * 128 + wm * 32 + mt * 16 + (lane >> 2);
            const int dh = wn * 32 + nt * 8 + (lane & 3) * 2;
#pragma unroll
            for (int half = 0; half < 2; half++) {
                const int t = t0 + half * 8;
                const float v0 = acc[mt][nt][half * 2 + 0];
                const float v1 = acc[mt][nt][half * 2 + 1];
                const long base = ((long)b * Tn + t) * Dm + h * 64 + dh;
                __nv_bfloat16 h0 = __float2bfloat16(v0);
                __nv_bfloat16 h1 = __float2bfloat16(v1);
                __nv_bfloat162 H; H.x = h0; H.y = h1;
                __nv_bfloat162 L;
                L.x = __float2bfloat16(v0 - __bfloat162float(h0));
                L.y = __float2bfloat16(v1 - __bfloat162float(h1));
                *(__nv_bfloat162*)(AOh + base) = H;
                *(__nv_bfloat162*)(AOl + base) = L;
            }
        }
}

// ---------------- qpe table (Q reconstructed from hi/lo bf16) ----------------
__global__ __launch_bounds__(256) void qpe_kernel(const float* __restrict__ PE,
                                                  const __nv_bfloat16* __restrict__ Qh,
                                                  const __nv_bfloat16* __restrict__ Ql,
                                                  float* __restrict__ QPE)
{
    const int it = blockIdx.x, bh = blockIdx.y, h = bh & (Hn - 1);
    const __nv_bfloat16* Aqh = Qh + ((long)bh * Tn + it * 64) * DHn;
    const __nv_bfloat16* Aql = Ql + ((long)bh * Tn + it * 64) * DHn;
    const float* Bp = PE + (long)h * MAXP * DHn;

    __shared__ float Qs[64][65];
    __shared__ float Ps[64][65];

    const int tid = threadIdx.x;
    const int rowb = tid >> 4, c4 = (tid & 15) << 2;
#pragma unroll
    for (int r = 0; r < 4; r++) {
        int row = rowb + r * 16;
        const long off = (long)row * DHn + c4;
        __nv_bfloat162 qh0 = *(const __nv_bfloat162*)(Aqh + off);
        __nv_bfloat162 qh1 = *(const __nv_bfloat162*)(Aqh + off + 2);
        __nv_bfloat162 ql0 = *(const __nv_bfloat162*)(Aql + off);
        __nv_bfloat162 ql1 = *(const __nv_bfloat162*)(Aql + off + 2);
        Qs[row][c4]     = __bfloat162float(qh0.x) + __bfloat162float(ql0.x);
        Qs[row][c4 + 1] = __bfloat162float(qh0.y) + __bfloat162float(ql0.y);
        Qs[row][c4 + 2] = __bfloat162float(qh1.x) + __bfloat162float(ql1.x);
        Qs[row][c4 + 3] = __bfloat162float(qh1.y) + __bfloat162float(ql1.y);
        float4 p4 = *(const float4*)(Bp + (long)row * DHn + c4);
        Ps[row][c4] = p4.x; Ps[row][c4 + 1] = p4.y;
        Ps[row][c4 + 2] = p4.z; Ps[row][c4 + 3] = p4.w;
    }
    __syncthreads();

    const int tx = tid & 15, ty = tid >> 4;
    float acc[4][4];
#pragma unroll
    for (int i = 0; i < 4; i++)
#pragma unroll
        for (int j = 0; j < 4; j++) acc[i][j] = 0.f;

#pragma unroll 16
    for (int kk = 0; kk < 64; kk++) {
        float a0 = Qs[ty * 4 + 0][kk], a1 = Qs[ty * 4 + 1][kk];
        float a2 = Qs[ty * 4 + 2][kk], a3 = Qs[ty * 4 + 3][kk];
        float b0 = Ps[tx * 4 + 0][kk], b1 = Ps[tx * 4 + 1][kk];
        float b2 = Ps[tx * 4 + 2][kk], b3 = Ps[tx * 4 + 3][kk];
        acc[0][0] = fmaf(a0, b0, acc[0][0]); acc[0][1] = fmaf(a0, b1, acc[0][1]);
        acc[0][2] = fmaf(a0, b2, acc[0][2]); acc[0][3] = fmaf(a0, b3, acc[0][3]);
        acc[1][0] = fmaf(a1, b0, acc[1][0]); acc[1][1] = fmaf(a1, b1, acc[1][1]);
        acc[1][2] = fmaf(a1, b2, acc[1][2]); acc[1][3] = fmaf(a1, b3, acc[1][3]);
        acc[2][0] = fmaf(a2, b0, acc[2][0]); acc[2][1] = fmaf(a2, b1, acc[2][1]);
        acc[2][2] = fmaf(a2, b2, acc[2][2]); acc[2][3] = fmaf(a2, b3, acc[2][3]);
        acc[3][0] = fmaf(a3, b0, acc[3][0]); acc[3][1] = fmaf(a3, b1, acc[3][1]);
        acc[3][2] = fmaf(a3, b2, acc[3][2]); acc[3][3] = fmaf(a3, b3, acc[3][3]);
    }

    float* out = QPE + ((long)bh * Tn + it * 64) * MAXP;
#pragma unroll
    for (int ii = 0; ii < 4; ii++) {
        float4 o4 = make_float4(acc[ii][0], acc[ii][1], acc[ii][2], acc[ii][3]);
        *(float4*)(out + (long)(ty * 4 + ii) * MAXP + tx * 4) = o4;
    }
}

// ---------------- CoPE (block-per-row, validated) ----------------
__global__ __launch_bounds__(256) void cope_kernel(const float* __restrict__ S,
                                                   const float* __restrict__ QPE,
                                                   __nv_bfloat16* __restrict__ Ph,
                                                   __nv_bfloat16* __restrict__ Pl)
{
    const int i = blockIdx.x, bh = blockIdx.y;
    const float* row = S + ((long)bh * Tn + i) * Tn;
    const long prow = ((long)bh * Tn + i) * Tn;
    const float* qpe = QPE + ((long)bh * Tn + i) * MAXP;
    const int blockend = ((i >> 7) + 1) << 7;

    __shared__ float qpes[64];
    __shared__ float wred[8];
    __shared__ float wred2[8];

    const int tid = threadIdx.x, lane = tid & 31, wid = tid >> 5;
    if (tid < 64) qpes[tid] = qpe[tid];

    const int j0 = tid << 2;
    float qk[4] = {0.f, 0.f, 0.f, 0.f};
    if (j0 <= i) {
        float4 s4 = *(const float4*)(row + j0);
        qk[0] = s4.x; qk[1] = s4.y; qk[2] = s4.z; qk[3] = s4.w;
    }

    float lpre[4];
    float run = 0.f;
#pragma unroll
    for (int q = 0; q < 4; q++) {
        float gg = 0.f;
        if (j0 + q <= i)
            gg = __fdividef(1.f, 1.f + __expf(-0.125f * qk[q]));
        run += gg;
        lpre[q] = run;
    }

    float v = run;
#pragma unroll
    for (int o = 1; o < 32; o <<= 1) {
        float t = __shfl_up_sync(0xffffffffu, v, o);
        if (lane >= o) v += t;
    }
    if (lane == 31) wred[wid] = v;
    __syncthreads();
    if (tid < 8) {
        float w = wred[tid];
#pragma unroll
        for (int o = 1; o < 8; o <<= 1) {
            float t = __shfl_up_sync(0x000000ffu, w, o);
            if (tid >= o) w += t;
        }
        wred[tid] = w;
    }
    __syncthreads();
    const float base  = (v - run) + (wid ? wred[wid - 1] : 0.f);
    const float total = wred[7];

    float sc[4];
    float mx = -INFINITY;
#pragma unroll
    for (int q = 0; q < 4; q++) {
        float s_ = -INFINITY;
        if (j0 + q <= i) {
            float pos = total - (base + lpre[q]);
            pos = fminf(fmaxf(pos, 0.f), 63.f);
            float pf = floorf(pos);
            int fi = (int)pf;
            float al = pos - pf;
            int ci = (fi < 63) ? fi + 1 : 63;
            float qf = qpes[fi], qc = qpes[ci];
            float qv = qf + al * (qc - qf);
            s_ = 0.125f * (qk[q] + qv);
        }
        sc[q] = s_;
        mx = fmaxf(mx, s_);
    }
#pragma unroll
    for (int o = 16; o; o >>= 1) mx = fmaxf(mx, __shfl_xor_sync(0xffffffffu, mx, o));
    if (lane == 0) wred2[wid] = mx;
    __syncthreads();
    float bmax = wred2[0];
#pragma unroll
    for (int k = 1; k < 8; k++) bmax = fmaxf(bmax, wred2[k]);

    float p[4];
    float ssum = 0.f;
#pragma unroll
    for (int q = 0; q < 4; q++) {
        float e = (j0 + q <= i) ? __expf(sc[q] - bmax) : 0.f;
        p[q] = e;
        ssum += e;
    }
#pragma unroll
    for (int o = 16; o; o >>= 1) ssum += __shfl_xor_sync(0xffffffffu, ssum, o);
    __syncthreads();
    if (lane == 0) wred2[wid] = ssum;
    __syncthreads();
    float tot = 0.f;
#pragma unroll
    for (int k = 0; k < 8; k++) tot += wred2[k];
    const float inv = __fdividef(1.f, tot);

    if (j0 < blockend) {
        float v0 = p[0] * inv, v1 = p[1] * inv, v2 = p[2] * inv, v3 = p[3] * inv;
        __nv_bfloat16 h0 = __float2bfloat16(v0), h1 = __float2bfloat16(v1);
        __nv_bfloat16 h2 = __float2bfloat16(v2), h3 = __float2bfloat16(v3);
        __nv_bfloat162 H0; H0.x = h0; H0.y = h1;
        __nv_bfloat162 H1; H1.x = h2; H1.y = h3;
        __nv_bfloat162 L0, L1;
        L0.x = __float2bfloat16(v0 - __bfloat162float(h0));
        L0.y = __float2bfloat16(v1 - __bfloat162float(h1));
        L1.x = __float2bfloat16(v2 - __bfloat162float(h2));
        L1.y = __float2bfloat16(v3 - __bfloat162float(h3));
        *(__nv_bfloat162*)(Ph + prow + j0)     = H0;
        *(__nv_bfloat162*)(Ph + prow + j0 + 2) = H1;
        *(__nv_bfloat162*)(Pl + prow + j0)     = L0;
        *(__nv_bfloat162*)(Pl + prow + j0 + 2) = L1;
    }
}

// ---------------- launcher ----------------
extern "C" void kernel_launch(void* const* d_in, const int* in_sizes, int n_in,
                              void* d_out, int out_size)
{
    (void)in_sizes; (void)n_in; (void)out_size;
    const float* x  = (const float*)d_in[0];
    const float* Wq = (const float*)d_in[1];
    const float* bq = (const float*)d_in[2];
    const float* Wk = (const float*)d_in[3];
    const float* bk = (const float*)d_in[4];
    const float* Wv = (const float*)d_in[5];
    const float* bv = (const float*)d_in[6];
    const float* Wo = (const float*)d_in[7];
    const float* bo = (const float*)d_in[8];
    const float* pe = (const float*)d_in[9];
    float* out = (float*)d_out;

    float *QPEd, *Sd;
    __nv_bfloat16 *xh, *xl, *Wqh, *Wql, *Wkh, *Wkl, *Wvh, *Wvl, *Woh, *Wol;
    __nv_bfloat16 *Qh, *Ql, *Kh, *Kl, *AOh, *AOl, *Phd, *Pld, *Vth, *Vtl;
    cudaGetSymbolAddress((void**)&QPEd, g_QPE);
    cudaGetSymbolAddress((void**)&Sd, g_S);
    cudaGetSymbolAddress((void**)&xh, g_xh);   cudaGetSymbolAddress((void**)&xl, g_xl);
    cudaGetSymbolAddress((void**)&Wqh, g_Wqh); cudaGetSymbolAddress((void**)&Wql, g_Wql);
    cudaGetSymbolAddress((void**)&Wkh, g_Wkh); cudaGetSymbolAddress((void**)&Wkl, g_Wkl);
    cudaGetSymbolAddress((void**)&Wvh, g_Wvh); cudaGetSymbolAddress((void**)&Wvl, g_Wvl);
    cudaGetSymbolAddress((void**)&Woh, g_Woh); cudaGetSymbolAddress((void**)&Wol, g_Wol);
    cudaGetSymbolAddress((void**)&Qh, g_Qh);   cudaGetSymbolAddress((void**)&Ql, g_Ql);
    cudaGetSymbolAddress((void**)&Kh, g_Kh);   cudaGetSymbolAddress((void**)&Kl, g_Kl);
    cudaGetSymbolAddress((void**)&AOh, g_AOh); cudaGetSymbolAddress((void**)&AOl, g_AOl);
    cudaGetSymbolAddress((void**)&Phd, g_Ph);  cudaGetSymbolAddress((void**)&Pld, g_Pl);
    cudaGetSymbolAddress((void**)&Vth, g_Vth); cudaGetSymbolAddress((void**)&Vtl, g_Vtl);

    static int smem_set = 0;
    if (!smem_set) {
        cudaFuncSetAttribute(mm_hmma, cudaFuncAttributeMaxDynamicSharedMemorySize, MM_SMEM);
        cudaFuncSetAttribute(qkv_hmma, cudaFuncAttributeMaxDynamicSharedMemorySize, MM_SMEM);
        cudaFuncSetAttribute(pv_hmma, cudaFuncAttributeMaxDynamicSharedMemorySize, MM_SMEM);
        cudaFuncSetAttribute(qk_hmma, cudaFuncAttributeMaxDynamicSharedMemorySize, QK_SMEM);
        smem_set = 1;
    }

    dim3 blk(256);

    splitk<<<2048, blk>>>(x, xh, xl, Bsz * Tn * Dm);
    splitW4<<<dim3(1024, 1, 4), blk>>>(Wq, Wk, Wv, Wo, Wqh, Wql, Wkh, Wkl,
                                       Wvh, Wvl, Woh, Wol);

    qkv_hmma<<<dim3(16, 16, 3), blk, MM_SMEM>>>(xh, xl, Wqh, Wql, Wkh, Wkl, Wvh, Wvl,
                                                bq, bk, bv, Qh, Ql, Kh, Kl, Vth, Vtl);

    qk_hmma<<<dim3(16, 8, 32), blk, QK_SMEM>>>(Qh, Ql, Kh, Kl, Sd);

    qpe_kernel<<<dim3(16, 32), blk>>>(pe, Qh, Ql, QPEd);

    cope_kernel<<<dim3(1024, 32), blk>>>(Sd, QPEd, Phd, Pld);

    pv_hmma<<<dim3(8, 32), blk, MM_SMEM>>>(Phd, Pld, Vth, Vtl, AOh, AOl);

    mm_hmma<<<dim3(16, 16, 1), blk, MM_SMEM>>>(AOh, AOl, Woh, Wol, bo,
                                               out, 2048, 1024, 1024, 0, 0, 0);
}

// round 12
// speedup vs baseline: 1.1645x; 1.0291x over previous
#include <cuda_runtime.h>
#include <cuda_bf16.h>
#include <math.h>
#include <stdint.h>

#define Bsz 2
#define Tn  1024
#define Dm  1024
#define Hn  16
#define DHn 64
#define BHn (Bsz*Hn)
#define MAXP 64

// ---------------- scratch ----------------
__device__ float g_QPE[BHn*Tn*MAXP];
__device__ float g_S[(long)BHn*Tn*Tn];
__device__ __nv_bfloat16 g_Ph[(long)BHn*Tn*Tn], g_Pl[(long)BHn*Tn*Tn];
__device__ __nv_bfloat16 g_Vth[BHn*DHn*Tn], g_Vtl[BHn*DHn*Tn];
__device__ __nv_bfloat16 g_xh[Bsz*Tn*Dm],  g_xl[Bsz*Tn*Dm];
__device__ __nv_bfloat16 g_Wqh[Dm*Dm], g_Wql[Dm*Dm];
__device__ __nv_bfloat16 g_Wkh[Dm*Dm], g_Wkl[Dm*Dm];
__device__ __nv_bfloat16 g_Wvh[Dm*Dm], g_Wvl[Dm*Dm];
__device__ __nv_bfloat16 g_Woh[Dm*Dm], g_Wol[Dm*Dm];
__device__ __nv_bfloat16 g_Qh[BHn*Tn*DHn], g_Ql[BHn*Tn*DHn];
__device__ __nv_bfloat16 g_Kh[BHn*Tn*DHn], g_Kl[BHn*Tn*DHn];
__device__ __nv_bfloat16 g_AOh[Bsz*Tn*Dm], g_AOl[Bsz*Tn*Dm];

// ---------------- helpers ----------------
__device__ __forceinline__ uint32_t smem_u32(const void* p) {
    uint32_t a;
    asm("{ .reg .u64 t; cvta.to.shared.u64 t, %1; cvt.u32.u64 %0, t; }" : "=r"(a) : "l"(p));
    return a;
}
__device__ __forceinline__ void cpa16(uint32_t dst, const void* src) {
    asm volatile("cp.async.cg.shared.global [%0], [%1], 16;" :: "r"(dst), "l"(src));
}
#define CPA_COMMIT() asm volatile("cp.async.commit_group;" ::: "memory")
#define CPA_WAIT1()  asm volatile("cp.async.wait_group 1;" ::: "memory")
#define CPA_WAIT0()  asm volatile("cp.async.wait_group 0;" ::: "memory")

#define LDSM4(r, a) \
    asm volatile("ldmatrix.sync.aligned.m8n8.x4.shared.b16 {%0,%1,%2,%3}, [%4];" \
        : "=r"((r)[0]), "=r"((r)[1]), "=r"((r)[2]), "=r"((r)[3]) : "r"(a))

#define MMA_BF16(c, a, b0v, b1v) \
    asm volatile("mma.sync.aligned.m16n8k16.row.col.f32.bf16.bf16.f32 " \
        "{%0,%1,%2,%3},{%4,%5,%6,%7},{%8,%9},{%0,%1,%2,%3};" \
        : "+f"((c)[0]), "+f"((c)[1]), "+f"((c)[2]), "+f"((c)[3]) \
        : "r"((a)[0]), "r"((a)[1]), "r"((a)[2]), "r"((a)[3]), "r"(b0v), "r"(b1v))

// ---------------- split fp32 -> bf16 hi/lo ----------------
__device__ __forceinline__ void split_store4(const float* s, __nv_bfloat16* h,
                                             __nv_bfloat16* l, int i)
{
    float4 v = *(const float4*)(s + i);
    __nv_bfloat16 h0 = __float2bfloat16(v.x), h1 = __float2bfloat16(v.y);
    __nv_bfloat16 h2 = __float2bfloat16(v.z), h3 = __float2bfloat16(v.w);
    __nv_bfloat162 H0; H0.x = h0; H0.y = h1;
    __nv_bfloat162 H1; H1.x = h2; H1.y = h3;
    __nv_bfloat162 L0, L1;
    L0.x = __float2bfloat16(v.x - __bfloat162float(h0));
    L0.y = __float2bfloat16(v.y - __bfloat162float(h1));
    L1.x = __float2bfloat16(v.z - __bfloat162float(h2));
    L1.y = __float2bfloat16(v.w - __bfloat162float(h3));
    *(__nv_bfloat162*)(h + i)     = H0;
    *(__nv_bfloat162*)(h + i + 2) = H1;
    *(__nv_bfloat162*)(l + i)     = L0;
    *(__nv_bfloat162*)(l + i + 2) = L1;
}

__global__ __launch_bounds__(256) void splitk(const float* __restrict__ s,
                                              __nv_bfloat16* __restrict__ h,
                                              __nv_bfloat16* __restrict__ l, int n)
{
    int i = (blockIdx.x * 256 + threadIdx.x) * 4;
    if (i >= n) return;
    split_store4(s, h, l, i);
}

__global__ __launch_bounds__(256) void splitW4(
    const float* __restrict__ Wq, const float* __restrict__ Wk,
    const float* __restrict__ Wv, const float* __restrict__ Wo,
    __nv_bfloat16* __restrict__ Wqh, __nv_bfloat16* __restrict__ Wql,
    __nv_bfloat16* __restrict__ Wkh, __nv_bfloat16* __restrict__ Wkl,
    __nv_bfloat16* __restrict__ Wvh, __nv_bfloat16* __restrict__ Wvl,
    __nv_bfloat16* __restrict__ Woh, __nv_bfloat16* __restrict__ Wol)
{
    const int z = blockIdx.z;
    const float* s = (z == 0) ? Wq : (z == 1) ? Wk : (z == 2) ? Wv : Wo;
    __nv_bfloat16* h = (z == 0) ? Wqh : (z == 1) ? Wkh : (z == 2) ? Wvh : Woh;
    __nv_bfloat16* l = (z == 0) ? Wql : (z == 1) ? Wkl : (z == 2) ? Wvl : Wol;
    int i = (blockIdx.x * 256 + threadIdx.x) * 4;
    split_store4(s, h, l, i);
}

// ========== 128x128 engine: warp tile 32x64, BK=32, 256 thr, NS=2 ==========
#define PITCH 80
#define AMAT  (128*PITCH)               // 10240 (A hi or lo)
#define B128M (128*PITCH)               // 10240 (B hi or lo)
#define STG128 (2*AMAT + 2*B128M)       // 40960
#define MM_SMEM (2*STG128)              // 81920 -> 2 CTA/SM

#define GEMM_COMPUTE128(st)                                                       \
    _Pragma("unroll")                                                             \
    for (int kc = 0; kc < 2; kc++) {                                              \
        const uint32_t col = kc * 32 + lcol;                                      \
        uint32_t ah[2][4], al[2][4], bh[4][4], bl[4][4];                          \
        _Pragma("unroll")                                                         \
        for (int mt = 0; mt < 2; mt++) {                                          \
            const uint32_t ad = (st) + a_row + (uint32_t)(mt * 16 * PITCH) + col; \
            LDSM4(ah[mt], ad);                                                    \
            LDSM4(al[mt], ad + AMAT);                                             \
        }                                                                         \
        _Pragma("unroll")                                                         \
        for (int np = 0; np < 4; np++) {                                          \
            const uint32_t bd = (st) + 2*AMAT + b_row + (uint32_t)(np * 16 * PITCH) + col; \
            LDSM4(bh[np], bd);                                                    \
            LDSM4(bl[np], bd + B128M);                                            \
        }                                                                         \
        _Pragma("unroll")                                                         \
        for (int mt = 0; mt < 2; mt++)                                            \
            _Pragma("unroll")                                                     \
            for (int nt = 0; nt < 8; nt++) {                                      \
                const int np = nt >> 1, i = nt & 1;                               \
                MMA_BF16(acc[mt][nt], ah[mt], bh[np][i], bh[np][i + 2]);          \
                MMA_BF16(acc[mt][nt], ah[mt], bl[np][i], bl[np][i + 2]);          \
                MMA_BF16(acc[mt][nt], al[mt], bh[np][i], bh[np][i + 2]);          \
            }                                                                     \
    }

// generic: C(fp32) = (Ahi+Alo)(Bhi+Blo)^T + bias, tiles 128x128
__global__ __launch_bounds__(256, 2) void mm_hmma(
    const __nv_bfloat16* __restrict__ Ahi, const __nv_bfloat16* __restrict__ Alo,
    const __nv_bfloat16* __restrict__ Bhi, const __nv_bfloat16* __restrict__ Blo,
    const float* __restrict__ bias,
    float* __restrict__ Cf,
    int M, int N, int K, long sA, long sB, long sC)
{
    extern __shared__ char dsm[];
    const uint32_t sbase = smem_u32(dsm);

    const int tid  = threadIdx.x;
    const int wid  = tid >> 5;
    const int lane = tid & 31;
    const int wm   = wid & 3;
    const int wn   = wid >> 2;      // 0..1, 64 cols each
    const int z    = blockIdx.z;
    const int bm   = blockIdx.y * 128;
    const int bn   = blockIdx.x * 128;

    const __nv_bfloat16* Ah = Ahi + (long)z * sA + (long)bm * K;
    const __nv_bfloat16* Al = Alo + (long)z * sA + (long)bm * K;
    const __nv_bfloat16* Bh = Bhi + (long)z * sB + (long)bn * K;
    const __nv_bfloat16* Bl = Blo + (long)z * sB + (long)bn * K;

    float acc[2][8][4];
#pragma unroll
    for (int i = 0; i < 2; i++)
#pragma unroll
        for (int j = 0; j < 8; j++)
#pragma unroll
            for (int c = 0; c < 4; c++) acc[i][j][c] = 0.f;

    const int KS = K >> 5;

    auto load_stage = [&](int slot, int ks) {
        const uint32_t base = sbase + slot * STG128;
        const int k0 = ks * 32;
#pragma unroll
        for (int c = tid; c < 512; c += 256) {
            const int r = c >> 2, seg = c & 3;
            const uint32_t d = base + r * PITCH + seg * 16;
            const long off = (long)r * K + k0 + seg * 8;
            cpa16(d,        Ah + off);
            cpa16(d + AMAT, Al + off);
        }
#pragma unroll
        for (int c = tid; c < 512; c += 256) {
            const int r = c >> 2, seg = c & 3;
            const uint32_t d = base + 2*AMAT + r * PITCH + seg * 16;
            const long off = (long)r * K + k0 + seg * 8;
            cpa16(d,         Bh + off);
            cpa16(d + B128M, Bl + off);
        }
        CPA_COMMIT();
    };

    load_stage(0, 0);

    const uint32_t a_row = (uint32_t)(wm * 32 + (lane & 15)) * PITCH;
    const uint32_t b_row = (uint32_t)(wn * 64 + (lane & 15)) * PITCH;
    const uint32_t lcol  = (uint32_t)((lane >> 4) * 16);

    for (int k = 0; k < KS; k++) {
        if (k + 1 < KS) load_stage((k + 1) & 1, k + 1);
        if (k + 1 < KS) { CPA_WAIT1(); } else { CPA_WAIT0(); }
        __syncthreads();
        const uint32_t st = sbase + (k & 1) * STG128;
        GEMM_COMPUTE128(st)
        __syncthreads();
    }

#pragma unroll
    for (int mt = 0; mt < 2; mt++)
#pragma unroll
        for (int nt = 0; nt < 8; nt++) {
            const int m0 = bm + wm * 32 + mt * 16 + (lane >> 2);
            const int n0 = bn + wn * 64 + nt * 8 + (lane & 3) * 2;
            float b0 = 0.f, b1 = 0.f;
            if (bias) { b0 = bias[n0]; b1 = bias[n0 + 1]; }
#pragma unroll
            for (int half = 0; half < 2; half++) {
                const int m = m0 + half * 8;
                float* cp = Cf + (long)z * sC + (long)m * N + n0;
                cp[0] = acc[mt][nt][half * 2 + 0] + b0;
                cp[1] = acc[mt][nt][half * 2 + 1] + b1;
            }
        }
}

// ---------------- QK: K=64 single-stage, 128x128 tiles, causal skip ----------
#define QPITCH 144
#define QMAT  (128*QPITCH)          // 18432
#define QK_SMEM (4*QMAT)            // 73728 -> 2 CTA/SM

__global__ __launch_bounds__(256, 2) void qk_hmma(
    const __nv_bfloat16* __restrict__ Qh, const __nv_bfloat16* __restrict__ Ql,
    const __nv_bfloat16* __restrict__ Kh, const __nv_bfloat16* __restrict__ Kl,
    float* __restrict__ S)
{
    if ((int)blockIdx.x > (int)blockIdx.y) return;

    extern __shared__ char dsm[];
    const uint32_t sbase = smem_u32(dsm);

    const int tid  = threadIdx.x;
    const int wid  = tid >> 5;
    const int lane = tid & 31;
    const int wm   = wid & 3;
    const int wn   = wid >> 2;
    const int z    = blockIdx.z;
    const int bm   = blockIdx.y * 128;
    const int bn   = blockIdx.x * 128;

    const __nv_bfloat16* Ah = Qh + (long)z * Tn * DHn + (long)bm * DHn;
    const __nv_bfloat16* Al = Ql + (long)z * Tn * DHn + (long)bm * DHn;
    const __nv_bfloat16* Bh = Kh + (long)z * Tn * DHn + (long)bn * DHn;
    const __nv_bfloat16* Bl = Kl + (long)z * Tn * DHn + (long)bn * DHn;

#pragma unroll
    for (int c = tid; c < 1024; c += 256) {
        const int r = c >> 3, seg = c & 7;
        const uint32_t d = sbase + r * QPITCH + seg * 16;
        const long off = (long)r * DHn + seg * 8;
        cpa16(d,        Ah + off);
        cpa16(d + QMAT, Al + off);
    }
#pragma unroll
    for (int c = tid; c < 1024; c += 256) {
        const int r = c >> 3, seg = c & 7;
        const uint32_t d = sbase + 2*QMAT + r * QPITCH + seg * 16;
        const long off = (long)r * DHn + seg * 8;
        cpa16(d,        Bh + off);
        cpa16(d + QMAT, Bl + off);
    }
    CPA_COMMIT();
    CPA_WAIT0();
    __syncthreads();

    float acc[2][8][4];
#pragma unroll
    for (int i = 0; i < 2; i++)
#pragma unroll
        for (int j = 0; j < 8; j++)
#pragma unroll
            for (int c = 0; c < 4; c++) acc[i][j][c] = 0.f;

    const uint32_t a_row = (uint32_t)(wm * 32 + (lane & 15)) * QPITCH;
    const uint32_t b_row = (uint32_t)(wn * 64 + (lane & 15)) * QPITCH;
    const uint32_t lcol  = (uint32_t)((lane >> 4) * 16);

#pragma unroll
    for (int kc = 0; kc < 4; kc++) {
        const uint32_t col = kc * 32 + lcol;
        uint32_t ah[2][4], al[2][4], bh[4][4], bl[4][4];
#pragma unroll
        for (int mt = 0; mt < 2; mt++) {
            const uint32_t ad = sbase + a_row + (uint32_t)(mt * 16 * QPITCH) + col;
            LDSM4(ah[mt], ad);
            LDSM4(al[mt], ad + QMAT);
        }
#pragma unroll
        for (int np = 0; np < 4; np++) {
            const uint32_t bd = sbase + 2*QMAT + b_row + (uint32_t)(np * 16 * QPITCH) + col;
            LDSM4(bh[np], bd);
            LDSM4(bl[np], bd + QMAT);
        }
#pragma unroll
        for (int mt = 0; mt < 2; mt++)
#pragma unroll
            for (int nt = 0; nt < 8; nt++) {
                const int np = nt >> 1, i = nt & 1;
                MMA_BF16(acc[mt][nt], ah[mt], bh[np][i], bh[np][i + 2]);
                MMA_BF16(acc[mt][nt], ah[mt], bl[np][i], bl[np][i + 2]);
                MMA_BF16(acc[mt][nt], al[mt], bh[np][i], bh[np][i + 2]);
            }
    }

#pragma unroll
    for (int mt = 0; mt < 2; mt++)
#pragma unroll
        for (int nt = 0; nt < 8; nt++) {
            const int m0 = bm + wm * 32 + mt * 16 + (lane >> 2);
            const int n0 = bn + wn * 64 + nt * 8 + (lane & 3) * 2;
#pragma unroll
            for (int half = 0; half < 2; half++) {
                const int m = m0 + half * 8;
                float* cp = S + (long)z * Tn * Tn + (long)m * Tn + n0;
                cp[0] = acc[mt][nt][half * 2 + 0];
                cp[1] = acc[mt][nt][half * 2 + 1];
            }
        }
}

// ---------------- merged QKV projection (128x128; V via smem transpose) --------
#define VTP 272
#define VHOFF (128*VTP)   // 34816

__global__ __launch_bounds__(256, 2) void qkv_hmma(
    const __nv_bfloat16* __restrict__ xh, const __nv_bfloat16* __restrict__ xl,
    const __nv_bfloat16* __restrict__ Wqh, const __nv_bfloat16* __restrict__ Wql,
    const __nv_bfloat16* __restrict__ Wkh, const __nv_bfloat16* __restrict__ Wkl,
    const __nv_bfloat16* __restrict__ Wvh, const __nv_bfloat16* __restrict__ Wvl,
    const float* __restrict__ bq, const float* __restrict__ bk, const float* __restrict__ bv,
    __nv_bfloat16* __restrict__ Qh, __nv_bfloat16* __restrict__ Ql,
    __nv_bfloat16* __restrict__ Kh, __nv_bfloat16* __restrict__ Kl,
    __nv_bfloat16* __restrict__ Vth, __nv_bfloat16* __restrict__ Vtl)
{
    extern __shared__ char dsm[];
    const uint32_t sbase = smem_u32(dsm);

    const int tid  = threadIdx.x;
    const int wid  = tid >> 5;
    const int lane = tid & 31;
    const int wm   = wid & 3;
    const int wn   = wid >> 2;
    const int z    = blockIdx.z;
    const int bm   = blockIdx.y * 128;
    const int bn   = blockIdx.x * 128;
    const int K    = 1024;

    const __nv_bfloat16* Bh_ = (z == 0) ? Wqh : (z == 1) ? Wkh : Wvh;
    const __nv_bfloat16* Bl_ = (z == 0) ? Wql : (z == 1) ? Wkl : Wvl;
    const float* bias = (z == 0) ? bq : (z == 1) ? bk : bv;

    const __nv_bfloat16* Ah = xh + (long)bm * K;
    const __nv_bfloat16* Al = xl + (long)bm * K;
    const __nv_bfloat16* Bh = Bh_ + (long)bn * K;
    const __nv_bfloat16* Bl = Bl_ + (long)bn * K;

    float acc[2][8][4];
#pragma unroll
    for (int i = 0; i < 2; i++)
#pragma unroll
        for (int j = 0; j < 8; j++)
#pragma unroll
            for (int c = 0; c < 4; c++) acc[i][j][c] = 0.f;

    const int KS = K >> 5;

    auto load_stage = [&](int slot, int ks) {
        const uint32_t base = sbase + slot * STG128;
        const int k0 = ks * 32;
#pragma unroll
        for (int c = tid; c < 512; c += 256) {
            const int r = c >> 2, seg = c & 3;
            const uint32_t d = base + r * PITCH + seg * 16;
            const long off = (long)r * K + k0 + seg * 8;
            cpa16(d,        Ah + off);
            cpa16(d + AMAT, Al + off);
        }
#pragma unroll
        for (int c = tid; c < 512; c += 256) {
            const int r = c >> 2, seg = c & 3;
            const uint32_t d = base + 2*AMAT + r * PITCH + seg * 16;
            const long off = (long)r * K + k0 + seg * 8;
            cpa16(d,         Bh + off);
            cpa16(d + B128M, Bl + off);
        }
        CPA_COMMIT();
    };

    load_stage(0, 0);

    const uint32_t a_row = (uint32_t)(wm * 32 + (lane & 15)) * PITCH;
    const uint32_t b_row = (uint32_t)(wn * 64 + (lane & 15)) * PITCH;
    const uint32_t lcol  = (uint32_t)((lane >> 4) * 16);

    for (int k = 0; k < KS; k++) {
        if (k + 1 < KS) load_stage((k + 1) & 1, k + 1);
        if (k + 1 < KS) { CPA_WAIT1(); } else { CPA_WAIT0(); }
        __syncthreads();
        const uint32_t st = sbase + (k & 1) * STG128;
        GEMM_COMPUTE128(st)
        __syncthreads();
    }

    const int b = bm >> 10, t0 = bm & 1023;

    if (z == 2) {
        // stage transposed 128dh x 128t tile in smem, then coalesced global writes
#pragma unroll
        for (int mt = 0; mt < 2; mt++)
#pragma unroll
            for (int nt = 0; nt < 8; nt++) {
                const int dh = wn * 64 + nt * 8 + (lane & 3) * 2;   // 0..127
                const float b0 = bias[bn + dh], b1 = bias[bn + dh + 1];
#pragma unroll
                for (int half = 0; half < 2; half++) {
                    const int tl = wm * 32 + mt * 16 + (lane >> 2) + half * 8;
                    const float v0 = acc[mt][nt][half * 2 + 0] + b0;
                    const float v1 = acc[mt][nt][half * 2 + 1] + b1;
                    __nv_bfloat16 hh0 = __float2bfloat16(v0);
                    __nv_bfloat16 hh1 = __float2bfloat16(v1);
                    __nv_bfloat16 ll0 = __float2bfloat16(v0 - __bfloat162float(hh0));
                    __nv_bfloat16 ll1 = __float2bfloat16(v1 - __bfloat162float(hh1));
                    *(__nv_bfloat16*)(dsm + dh * VTP + tl * 2)               = hh0;
                    *(__nv_bfloat16*)(dsm + (dh + 1) * VTP + tl * 2)         = hh1;
                    *(__nv_bfloat16*)(dsm + VHOFF + dh * VTP + tl * 2)       = ll0;
                    *(__nv_bfloat16*)(dsm + VHOFF + (dh + 1) * VTP + tl * 2) = ll1;
                }
            }
        __syncthreads();
        {
            const int dh = tid >> 1, seg = tid & 1;   // 128 rows x 2 segs of 128B
            const int h = (bn >> 6) + (dh >> 6);
            const long gb = (((long)(b * Hn + h) * DHn + (dh & 63)) * Tn) + t0 + seg * 64;
            const char* srh = dsm + dh * VTP + seg * 128;
            const char* srl = dsm + VHOFF + dh * VTP + seg * 128;
#pragma unroll
            for (int i = 0; i < 8; i++) {
                *(float4*)(Vth + gb + i * 8) = *(const float4*)(srh + i * 16);
                *(float4*)(Vtl + gb + i * 8) = *(const float4*)(srl + i * 16);
            }
        }
        return;
    }

#pragma unroll
    for (int mt = 0; mt < 2; mt++)
#pragma unroll
        for (int nt = 0; nt < 8; nt++) {
            const int m0 = bm + wm * 32 + mt * 16 + (lane >> 2);
            const int n0 = bn + wn * 64 + nt * 8 + (lane & 3) * 2;
            const float b0 = bias[n0], b1 = bias[n0 + 1];
            const int h = n0 >> 6, dh0 = n0 & 63;
#pragma unroll
            for (int half = 0; half < 2; half++) {
                const int m = m0 + half * 8;
                const float v0 = acc[mt][nt][half * 2 + 0] + b0;
                const float v1 = acc[mt][nt][half * 2 + 1] + b1;
                const int bb = m >> 10, t = m & 1023;
                __nv_bfloat16 hh0 = __float2bfloat16(v0);
                __nv_bfloat16 hh1 = __float2bfloat16(v1);
                __nv_bfloat16 ll0 = __float2bfloat16(v0 - __bfloat162float(hh0));
                __nv_bfloat16 ll1 = __float2bfloat16(v1 - __bfloat162float(hh1));
                const long base = (((long)(bb * Hn + h) * Tn + t) * DHn) + dh0;
                if (z == 0) {
                    Qh[base] = hh0; Qh[base + 1] = hh1;
                    Ql[base] = ll0; Ql[base + 1] = ll1;
                } else {
                    Kh[base] = hh0; Kh[base + 1] = hh1;
                    Kl[base] = ll0; Kl[base + 1] = ll1;
                }
            }
        }
}

// ========== 128x64 engine for pv (N=dh=64 fixed), NS=2, 3 CTA/SM ==========
#define B64M  (64*PITCH)
#define STG64 (2*AMAT + 2*B64M)        // 30720
#define PV_SMEM (2*STG64)              // 61440

__global__ __launch_bounds__(256, 3) void pv_hmma(
    const __nv_bfloat16* __restrict__ Ph, const __nv_bfloat16* __restrict__ Pl,
    const __nv_bfloat16* __restrict__ Vth, const __nv_bfloat16* __restrict__ Vtl,
    __nv_bfloat16* __restrict__ AOh, __nv_bfloat16* __restrict__ AOl)
{
    extern __shared__ char dsm[];
    const uint32_t sbase = smem_u32(dsm);

    const int tid  = threadIdx.x;
    const int wid  = tid >> 5;
    const int lane = tid & 31;
    const int wm   = wid & 3;
    const int wn   = wid >> 2;
    const int it   = blockIdx.x;
    const int bh   = blockIdx.y;
    const int b    = bh >> 4, h = bh & 15;

    const __nv_bfloat16* Ah = Ph + ((long)bh * Tn + it * 128) * Tn;
    const __nv_bfloat16* Al = Pl + ((long)bh * Tn + it * 128) * Tn;
    const __nv_bfloat16* Bh = Vth + (long)bh * DHn * Tn;
    const __nv_bfloat16* Bl = Vtl + (long)bh * DHn * Tn;

    float acc[2][4][4];
#pragma unroll
    for (int i = 0; i < 2; i++)
#pragma unroll
        for (int j = 0; j < 4; j++)
#pragma unroll
            for (int c = 0; c < 4; c++) acc[i][j][c] = 0.f;

    const int KS = 4 * (it + 1);

    auto load_stage = [&](int slot, int ks) {
        const uint32_t base = sbase + slot * STG64;
        const int k0 = ks * 32;
#pragma unroll
        for (int c = tid; c < 512; c += 256) {
            const int r = c >> 2, seg = c & 3;
            const uint32_t d = base + r * PITCH + seg * 16;
            const long off = (long)r * Tn + k0 + seg * 8;
            cpa16(d,        Ah + off);
            cpa16(d + AMAT, Al + off);
        }
        {
            const int r = tid >> 2, seg = tid & 3;
            const uint32_t d = base + 2*AMAT + r * PITCH + seg * 16;
            const long off = (long)r * Tn + k0 + seg * 8;
            cpa16(d,        Bh + off);
            cpa16(d + B64M, Bl + off);
        }
        CPA_COMMIT();
    };

    load_stage(0, 0);

    const uint32_t a_row = (uint32_t)(wm * 32 + (lane & 15)) * PITCH;
    const uint32_t b_row = (uint32_t)(wn * 32 + (lane & 15)) * PITCH;
    const uint32_t lcol  = (uint32_t)((lane >> 4) * 16);

    for (int k = 0; k < KS; k++) {
        if (k + 1 < KS) load_stage((k + 1) & 1, k + 1);
        if (k + 1 < KS) { CPA_WAIT1(); } else { CPA_WAIT0(); }
        __syncthreads();
        const uint32_t st = sbase + (k & 1) * STG64;
#pragma unroll
        for (int kc = 0; kc < 2; kc++) {
            const uint32_t col = kc * 32 + lcol;
            uint32_t ah[2][4], al[2][4], bh2[2][4], bl2[2][4];
#pragma unroll
            for (int mt = 0; mt < 2; mt++) {
                const uint32_t ad = st + a_row + (uint32_t)(mt * 16 * PITCH) + col;
                LDSM4(ah[mt], ad);
                LDSM4(al[mt], ad + AMAT);
            }
#pragma unroll
            for (int np = 0; np < 2; np++) {
                const uint32_t bd = st + 2*AMAT + b_row + (uint32_t)(np * 16 * PITCH) + col;
                LDSM4(bh2[np], bd);
                LDSM4(bl2[np], bd + B64M);
            }
#pragma unroll
            for (int mt = 0; mt < 2; mt++)
#pragma unroll
                for (int nt = 0; nt < 4; nt++) {
                    const int np = nt >> 1, i = nt & 1;
                    MMA_BF16(acc[mt][nt], ah[mt], bh2[np][i], bh2[np][i + 2]);
                    MMA_BF16(acc[mt][nt], ah[mt], bl2[np][i], bl2[np][i + 2]);
                    MMA_BF16(acc[mt][nt], al[mt], bh2[np][i], bh2[np][i + 2]);
                }
        }
        __syncthreads();
    }

#pragma unroll
    for (int mt = 0; mt < 2; mt++)
#pragma unroll
        for (int nt = 0; nt < 4; nt++) {
            const int t0 = it * 128 + wm * 32 + mt * 16 + (lane >> 2);
            const int dh = wn * 32 + nt * 8 + (lane & 3) * 2;
#pragma unroll
            for (int half = 0; half < 2; half++) {
                const int t = t0 + half * 8;
                const float v0 = acc[mt][nt][half * 2 + 0];
                const float v1 = acc[mt][nt][half * 2 + 1];
                const long base = ((long)b * Tn + t) * Dm + h * 64 + dh;
                __nv_bfloat16 h0 = __float2bfloat16(v0);
                __nv_bfloat16 h1 = __float2bfloat16(v1);
                __nv_bfloat162 H; H.x = h0; H.y = h1;
                __nv_bfloat162 L;
                L.x = __float2bfloat16(v0 - __bfloat162float(h0));
                L.y = __float2bfloat16(v1 - __bfloat162float(h1));
                *(__nv_bfloat162*)(AOh + base) = H;
                *(__nv_bfloat162*)(AOl + base) = L;
            }
        }
}

// ---------------- qpe table (Q reconstructed from hi/lo bf16) ----------------
__global__ __launch_bounds__(256) void qpe_kernel(const float* __restrict__ PE,
                                                  const __nv_bfloat16* __restrict__ Qh,
                                                  const __nv_bfloat16* __restrict__ Ql,
                                                  float* __restrict__ QPE)
{
    const int it = blockIdx.x, bh = blockIdx.y, h = bh & (Hn - 1);
    const __nv_bfloat16* Aqh = Qh + ((long)bh * Tn + it * 64) * DHn;
    const __nv_bfloat16* Aql = Ql + ((long)bh * Tn + it * 64) * DHn;
    const float* Bp = PE + (long)h * MAXP * DHn;

    __shared__ float Qs[64][65];
    __shared__ float Ps[64][65];

    const int tid = threadIdx.x;
    const int rowb = tid >> 4, c4 = (tid & 15) << 2;
#pragma unroll
    for (int r = 0; r < 4; r++) {
        int row = rowb + r * 16;
        const long off = (long)row * DHn + c4;
        __nv_bfloat162 qh0 = *(const __nv_bfloat162*)(Aqh + off);
        __nv_bfloat162 qh1 = *(const __nv_bfloat162*)(Aqh + off + 2);
        __nv_bfloat162 ql0 = *(const __nv_bfloat162*)(Aql + off);
        __nv_bfloat162 ql1 = *(const __nv_bfloat162*)(Aql + off + 2);
        Qs[row][c4]     = __bfloat162float(qh0.x) + __bfloat162float(ql0.x);
        Qs[row][c4 + 1] = __bfloat162float(qh0.y) + __bfloat162float(ql0.y);
        Qs[row][c4 + 2] = __bfloat162float(qh1.x) + __bfloat162float(ql1.x);
        Qs[row][c4 + 3] = __bfloat162float(qh1.y) + __bfloat162float(ql1.y);
        float4 p4 = *(const float4*)(Bp + (long)row * DHn + c4);
        Ps[row][c4] = p4.x; Ps[row][c4 + 1] = p4.y;
        Ps[row][c4 + 2] = p4.z; Ps[row][c4 + 3] = p4.w;
    }
    __syncthreads();

    const int tx = tid & 15, ty = tid >> 4;
    float acc[4][4];
#pragma unroll
    for (int i = 0; i < 4; i++)
#pragma unroll
        for (int j = 0; j < 4; j++) acc[i][j] = 0.f;

#pragma unroll 16
    for (int kk = 0; kk < 64; kk++) {
        float a0 = Qs[ty * 4 + 0][kk], a1 = Qs[ty * 4 + 1][kk];
        float a2 = Qs[ty * 4 + 2][kk], a3 = Qs[ty * 4 + 3][kk];
        float b0 = Ps[tx * 4 + 0][kk], b1 = Ps[tx * 4 + 1][kk];
        float b2 = Ps[tx * 4 + 2][kk], b3 = Ps[tx * 4 + 3][kk];
        acc[0][0] = fmaf(a0, b0, acc[0][0]); acc[0][1] = fmaf(a0, b1, acc[0][1]);
        acc[0][2] = fmaf(a0, b2, acc[0][2]); acc[0][3] = fmaf(a0, b3, acc[0][3]);
        acc[1][0] = fmaf(a1, b0, acc[1][0]); acc[1][1] = fmaf(a1, b1, acc[1][1]);
        acc[1][2] = fmaf(a1, b2, acc[1][2]); acc[1][3] = fmaf(a1, b3, acc[1][3]);
        acc[2][0] = fmaf(a2, b0, acc[2][0]); acc[2][1] = fmaf(a2, b1, acc[2][1]);
        acc[2][2] = fmaf(a2, b2, acc[2][2]); acc[2][3] = fmaf(a2, b3, acc[2][3]);
        acc[3][0] = fmaf(a3, b0, acc[3][0]); acc[3][1] = fmaf(a3, b1, acc[3][1]);
        acc[3][2] = fmaf(a3, b2, acc[3][2]); acc[3][3] = fmaf(a3, b3, acc[3][3]);
    }

    float* out = QPE + ((long)bh * Tn + it * 64) * MAXP;
#pragma unroll
    for (int ii = 0; ii < 4; ii++) {
        float4 o4 = make_float4(acc[ii][0], acc[ii][1], acc[ii][2], acc[ii][3]);
        *(float4*)(out + (long)(ty * 4 + ii) * MAXP + tx * 4) = o4;
    }
}

// ---------------- CoPE (block-per-row, validated) ----------------
__global__ __launch_bounds__(256) void cope_kernel(const float* __restrict__ S,
                                                   const float* __restrict__ QPE,
                                                   __nv_bfloat16* __restrict__ Ph,
                                                   __nv_bfloat16* __restrict__ Pl)
{
    const int i = blockIdx.x, bh = blockIdx.y;
    const float* row = S + ((long)bh * Tn + i) * Tn;
    const long prow = ((long)bh * Tn + i) * Tn;
    const float* qpe = QPE + ((long)bh * Tn + i) * MAXP;
    const int blockend = ((i >> 7) + 1) << 7;

    __shared__ float qpes[64];
    __shared__ float wred[8];
    __shared__ float wred2[8];

    const int tid = threadIdx.x, lane = tid & 31, wid = tid >> 5;
    if (tid < 64) qpes[tid] = qpe[tid];

    const int j0 = tid << 2;
    float qk[4] = {0.f, 0.f, 0.f, 0.f};
    if (j0 <= i) {
        float4 s4 = *(const float4*)(row + j0);
        qk[0] = s4.x; qk[1] = s4.y; qk[2] = s4.z; qk[3] = s4.w;
    }

    float lpre[4];
    float run = 0.f;
#pragma unroll
    for (int q = 0; q < 4; q++) {
        float gg = 0.f;
        if (j0 + q <= i)
            gg = __fdividef(1.f, 1.f + __expf(-0.125f * qk[q]));
        run += gg;
        lpre[q] = run;
    }

    float v = run;
#pragma unroll
    for (int o = 1; o < 32; o <<= 1) {
        float t = __shfl_up_sync(0xffffffffu, v, o);
        if (lane >= o) v += t;
    }
    if (lane == 31) wred[wid] = v;
    __syncthreads();
    if (tid < 8) {
        float w = wred[tid];
#pragma unroll
        for (int o = 1; o < 8; o <<= 1) {
            float t = __shfl_up_sync(0x000000ffu, w, o);
            if (tid >= o) w += t;
        }
        wred[tid] = w;
    }
    __syncthreads();
    const float base  = (v - run) + (wid ? wred[wid - 1] : 0.f);
    const float total = wred[7];

    float sc[4];
    float mx = -INFINITY;
#pragma unroll
    for (int q = 0; q < 4; q++) {
        float s_ = -INFINITY;
        if (j0 + q <= i) {
            float pos = total - (base + lpre[q]);
            pos = fminf(fmaxf(pos, 0.f), 63.f);
            float pf = floorf(pos);
            int fi = (int)pf;
            float al = pos - pf;
            int ci = (fi < 63) ? fi + 1 : 63;
            float qf = qpes[fi], qc = qpes[ci];
            float qv = qf + al * (qc - qf);
            s_ = 0.125f * (qk[q] + qv);
        }
        sc[q] = s_;
        mx = fmaxf(mx, s_);
    }
#pragma unroll
    for (int o = 16; o; o >>= 1) mx = fmaxf(mx, __shfl_xor_sync(0xffffffffu, mx, o));
    if (lane == 0) wred2[wid] = mx;
    __syncthreads();
    float bmax = wred2[0];
#pragma unroll
    for (int k = 1; k < 8; k++) bmax = fmaxf(bmax, wred2[k]);

    float p[4];
    float ssum = 0.f;
#pragma unroll
    for (int q = 0; q < 4; q++) {
        float e = (j0 + q <= i) ? __expf(sc[q] - bmax) : 0.f;
        p[q] = e;
        ssum += e;
    }
#pragma unroll
    for (int o = 16; o; o >>= 1) ssum += __shfl_xor_sync(0xffffffffu, ssum, o);
    __syncthreads();
    if (lane == 0) wred2[wid] = ssum;
    __syncthreads();
    float tot = 0.f;
#pragma unroll
    for (int k = 0; k < 8; k++) tot += wred2[k];
    const float inv = __fdividef(1.f, tot);

    if (j0 < blockend) {
        float v0 = p[0] * inv, v1 = p[1] * inv, v2 = p[2] * inv, v3 = p[3] * inv;
        __nv_bfloat16 h0 = __float2bfloat16(v0), h1 = __float2bfloat16(v1);
        __nv_bfloat16 h2 = __float2bfloat16(v2), h3 = __float2bfloat16(v3);
        __nv_bfloat162 H0; H0.x = h0; H0.y = h1;
        __nv_bfloat162 H1; H1.x = h2; H1.y = h3;
        __nv_bfloat162 L0, L1;
        L0.x = __float2bfloat16(v0 - __bfloat162float(h0));
        L0.y = __float2bfloat16(v1 - __bfloat162float(h1));
        L1.x = __float2bfloat16(v2 - __bfloat162float(h2));
        L1.y = __float2bfloat16(v3 - __bfloat162float(h3));
        *(__nv_bfloat162*)(Ph + prow + j0)     = H0;
        *(__nv_bfloat162*)(Ph + prow + j0 + 2) = H1;
        *(__nv_bfloat162*)(Pl + prow + j0)     = L0;
        *(__nv_bfloat162*)(Pl + prow + j0 + 2) = L1;
    }
}

// ---------------- launcher ----------------
extern "C" void kernel_launch(void* const* d_in, const int* in_sizes, int n_in,
                              void* d_out, int out_size)
{
    (void)in_sizes; (void)n_in; (void)out_size;
    const float* x  = (const float*)d_in[0];
    const float* Wq = (const float*)d_in[1];
    const float* bq = (const float*)d_in[2];
    const float* Wk = (const float*)d_in[3];
    const float* bk = (const float*)d_in[4];
    const float* Wv = (const float*)d_in[5];
    const float* bv = (const float*)d_in[6];
    const float* Wo = (const float*)d_in[7];
    const float* bo = (const float*)d_in[8];
    const float* pe = (const float*)d_in[9];
    float* out = (float*)d_out;

    float *QPEd, *Sd;
    __nv_bfloat16 *xh, *xl, *Wqh, *Wql, *Wkh, *Wkl, *Wvh, *Wvl, *Woh, *Wol;
    __nv_bfloat16 *Qh, *Ql, *Kh, *Kl, *AOh, *AOl, *Phd, *Pld, *Vth, *Vtl;
    cudaGetSymbolAddress((void**)&QPEd, g_QPE);
    cudaGetSymbolAddress((void**)&Sd, g_S);
    cudaGetSymbolAddress((void**)&xh, g_xh);   cudaGetSymbolAddress((void**)&xl, g_xl);
    cudaGetSymbolAddress((void**)&Wqh, g_Wqh); cudaGetSymbolAddress((void**)&Wql, g_Wql);
    cudaGetSymbolAddress((void**)&Wkh, g_Wkh); cudaGetSymbolAddress((void**)&Wkl, g_Wkl);
    cudaGetSymbolAddress((void**)&Wvh, g_Wvh); cudaGetSymbolAddress((void**)&Wvl, g_Wvl);
    cudaGetSymbolAddress((void**)&Woh, g_Woh); cudaGetSymbolAddress((void**)&Wol, g_Wol);
    cudaGetSymbolAddress((void**)&Qh, g_Qh);   cudaGetSymbolAddress((void**)&Ql, g_Ql);
    cudaGetSymbolAddress((void**)&Kh, g_Kh);   cudaGetSymbolAddress((void**)&Kl, g_Kl);
    cudaGetSymbolAddress((void**)&AOh, g_AOh); cudaGetSymbolAddress((void**)&AOl, g_AOl);
    cudaGetSymbolAddress((void**)&Phd, g_Ph);  cudaGetSymbolAddress((void**)&Pld, g_Pl);
    cudaGetSymbolAddress((void**)&Vth, g_Vth); cudaGetSymbolAddress((void**)&Vtl, g_Vtl);

    static int smem_set = 0;
    if (!smem_set) {
        cudaFuncSetAttribute(mm_hmma, cudaFuncAttributeMaxDynamicSharedMemorySize, MM_SMEM);
        cudaFuncSetAttribute(qkv_hmma, cudaFuncAttributeMaxDynamicSharedMemorySize, MM_SMEM);
        cudaFuncSetAttribute(pv_hmma, cudaFuncAttributeMaxDynamicSharedMemorySize, PV_SMEM);
        cudaFuncSetAttribute(qk_hmma, cudaFuncAttributeMaxDynamicSharedMemorySize, QK_SMEM);
        smem_set = 1;
    }

    dim3 blk(256);

    splitk<<<2048, blk>>>(x, xh, xl, Bsz * Tn * Dm);
    splitW4<<<dim3(1024, 1, 4), blk>>>(Wq, Wk, Wv, Wo, Wqh, Wql, Wkh, Wkl,
                                       Wvh, Wvl, Woh, Wol);

    qkv_hmma<<<dim3(8, 16, 3), blk, MM_SMEM>>>(xh, xl, Wqh, Wql, Wkh, Wkl, Wvh, Wvl,
                                               bq, bk, bv, Qh, Ql, Kh, Kl, Vth, Vtl);

    qk_hmma<<<dim3(8, 8, 32), blk, QK_SMEM>>>(Qh, Ql, Kh, Kl, Sd);

    qpe_kernel<<<dim3(16, 32), blk>>>(pe, Qh, Ql, QPEd);

    cope_kernel<<<dim3(1024, 32), blk>>>(Sd, QPEd, Phd, Pld);

    pv_hmma<<<dim3(8, 32), blk, PV_SMEM>>>(Phd, Pld, Vth, Vtl, AOh, AOl);

    mm_hmma<<<dim3(8, 16, 1), blk, MM_SMEM>>>(AOh, AOl, Woh, Wol, bo,
                                              out, 2048, 1024, 1024, 0, 0, 0);
}

// round 14
// speedup vs baseline: 1.3444x; 1.1545x over previous
#include <cuda_runtime.h>
#include <cuda_bf16.h>
#include <cuda_fp16.h>
#include <math.h>
#include <stdint.h>

#define Bsz 2
#define Tn  1024
#define Dm  1024
#define Hn  16
#define DHn 64
#define BHn (Bsz*Hn)
#define MAXP 64

// ---------------- scratch ----------------
__device__ float g_QPE[BHn*Tn*MAXP];
__device__ float g_S[(long)BHn*Tn*Tn];
__device__ __nv_bfloat16 g_Ph[(long)BHn*Tn*Tn], g_Pl[(long)BHn*Tn*Tn];
__device__ __nv_bfloat16 g_Vth[BHn*DHn*Tn], g_Vtl[BHn*DHn*Tn];
__device__ __half g_xh[Bsz*Tn*Dm], g_xl[Bsz*Tn*Dm];          // fp16 activation split
__device__ __half g_Wqh[Dm*Dm], g_Wkh[Dm*Dm], g_Wvh[Dm*Dm], g_Woh[Dm*Dm]; // fp16 hi only
__device__ __nv_bfloat16 g_Qh[BHn*Tn*DHn], g_Ql[BHn*Tn*DHn];
__device__ __nv_bfloat16 g_Kh[BHn*Tn*DHn], g_Kl[BHn*Tn*DHn];
__device__ __half g_AOh[Bsz*Tn*Dm], g_AOl[Bsz*Tn*Dm];        // fp16 split of AO

// ---------------- helpers ----------------
__device__ __forceinline__ uint32_t smem_u32(const void* p) {
    uint32_t a;
    asm("{ .reg .u64 t; cvta.to.shared.u64 t, %1; cvt.u32.u64 %0, t; }" : "=r"(a) : "l"(p));
    return a;
}
__device__ __forceinline__ void cpa16(uint32_t dst, const void* src) {
    asm volatile("cp.async.cg.shared.global [%0], [%1], 16;" :: "r"(dst), "l"(src));
}
#define CPA_COMMIT() asm volatile("cp.async.commit_group;" ::: "memory")
#define CPA_WAIT1()  asm volatile("cp.async.wait_group 1;" ::: "memory")
#define CPA_WAIT0()  asm volatile("cp.async.wait_group 0;" ::: "memory")

#define LDSM4(r, a) \
    asm volatile("ldmatrix.sync.aligned.m8n8.x4.shared.b16 {%0,%1,%2,%3}, [%4];" \
        : "=r"((r)[0]), "=r"((r)[1]), "=r"((r)[2]), "=r"((r)[3]) : "r"(a))

#define MMA_BF16(c, a, b0v, b1v) \
    asm volatile("mma.sync.aligned.m16n8k16.row.col.f32.bf16.bf16.f32 " \
        "{%0,%1,%2,%3},{%4,%5,%6,%7},{%8,%9},{%0,%1,%2,%3};" \
        : "+f"((c)[0]), "+f"((c)[1]), "+f"((c)[2]), "+f"((c)[3]) \
        : "r"((a)[0]), "r"((a)[1]), "r"((a)[2]), "r"((a)[3]), "r"(b0v), "r"(b1v))

#define MMA_F16(c, a, b0v, b1v) \
    asm volatile("mma.sync.aligned.m16n8k16.row.col.f32.f16.f16.f32 " \
        "{%0,%1,%2,%3},{%4,%5,%6,%7},{%8,%9},{%0,%1,%2,%3};" \
        : "+f"((c)[0]), "+f"((c)[1]), "+f"((c)[2]), "+f"((c)[3]) \
        : "r"((a)[0]), "r"((a)[1]), "r"((a)[2]), "r"((a)[3]), "r"(b0v), "r"(b1v))

// ---------------- splits ----------------
__global__ __launch_bounds__(256) void splitx_h(const float* __restrict__ s,
                                                __half* __restrict__ h,
                                                __half* __restrict__ l, int n)
{
    int i = (blockIdx.x * 256 + threadIdx.x) * 4;
    if (i >= n) return;
    float4 v = *(const float4*)(s + i);
    __half h0 = __float2half(v.x), h1 = __float2half(v.y);
    __half h2 = __float2half(v.z), h3 = __float2half(v.w);
    __half2 H0; H0.x = h0; H0.y = h1;
    __half2 H1; H1.x = h2; H1.y = h3;
    __half2 L0, L1;
    L0.x = __float2half(v.x - __half2float(h0));
    L0.y = __float2half(v.y - __half2float(h1));
    L1.x = __float2half(v.z - __half2float(h2));
    L1.y = __float2half(v.w - __half2float(h3));
    *(__half2*)(h + i)     = H0;
    *(__half2*)(h + i + 2) = H1;
    *(__half2*)(l + i)     = L0;
    *(__half2*)(l + i + 2) = L1;
}

__global__ __launch_bounds__(256) void splitW4h(
    const float* __restrict__ Wq, const float* __restrict__ Wk,
    const float* __restrict__ Wv, const float* __restrict__ Wo,
    __half* __restrict__ Wqh, __half* __restrict__ Wkh,
    __half* __restrict__ Wvh, __half* __restrict__ Woh)
{
    const int z = blockIdx.z;
    const float* s = (z == 0) ? Wq : (z == 1) ? Wk : (z == 2) ? Wv : Wo;
    __half* h = (z == 0) ? Wqh : (z == 1) ? Wkh : (z == 2) ? Wvh : Woh;
    int i = (blockIdx.x * 256 + threadIdx.x) * 4;
    float4 v = *(const float4*)(s + i);
    __half2 H0, H1;
    H0.x = __float2half(v.x); H0.y = __float2half(v.y);
    H1.x = __float2half(v.z); H1.y = __float2half(v.w);
    *(__half2*)(h + i)     = H0;
    *(__half2*)(h + i + 2) = H1;
}

// ========== fp16 2-pass 128x128 engine (projections): C = (Ah+Al)·Bh^T ==========
#define PITCH 80
#define AMAT  (128*PITCH)
#define B128M (128*PITCH)
#define STG2  (2*AMAT + B128M)      // 30720: [Ah][Al][Bh]
#define MM2_SMEM (2*STG2)           // 61440

#define GEMM2_COMPUTE128(st)                                                      \
    _Pragma("unroll")                                                             \
    for (int kc = 0; kc < 2; kc++) {                                              \
        const uint32_t col = kc * 32 + lcol;                                      \
        uint32_t ah[2][4], al[2][4], bh[4][4];                                    \
        _Pragma("unroll")                                                         \
        for (int mt = 0; mt < 2; mt++) {                                          \
            const uint32_t ad = (st) + a_row + (uint32_t)(mt * 16 * PITCH) + col; \
            LDSM4(ah[mt], ad);                                                    \
            LDSM4(al[mt], ad + AMAT);                                             \
        }                                                                         \
        _Pragma("unroll")                                                         \
        for (int np = 0; np < 4; np++) {                                          \
            const uint32_t bd = (st) + 2*AMAT + b_row + (uint32_t)(np * 16 * PITCH) + col; \
            LDSM4(bh[np], bd);                                                    \
        }                                                                         \
        _Pragma("unroll")                                                         \
        for (int mt = 0; mt < 2; mt++)                                            \
            _Pragma("unroll")                                                     \
            for (int nt = 0; nt < 8; nt++) {                                      \
                const int np = nt >> 1, i = nt & 1;                               \
                MMA_F16(acc[mt][nt], ah[mt], bh[np][i], bh[np][i + 2]);           \
                MMA_F16(acc[mt][nt], al[mt], bh[np][i], bh[np][i + 2]);           \
            }                                                                     \
    }

// out-projection: out(fp32) = (AOh+AOl)·Woh^T + bias
__global__ __launch_bounds__(256, 2) void mm2_hmma(
    const __half* __restrict__ Ahi, const __half* __restrict__ Alo,
    const __half* __restrict__ Bhh,
    const float* __restrict__ bias, float* __restrict__ Cf, int N, int K)
{
    extern __shared__ char dsm[];
    const uint32_t sbase = smem_u32(dsm);

    const int tid  = threadIdx.x;
    const int wid  = tid >> 5;
    const int lane = tid & 31;
    const int wm   = wid & 3;
    const int wn   = wid >> 2;
    const int bm   = blockIdx.y * 128;
    const int bn   = blockIdx.x * 128;

    const __half* Ah = Ahi + (long)bm * K;
    const __half* Al = Alo + (long)bm * K;
    const __half* Bh = Bhh + (long)bn * K;

    float acc[2][8][4];
#pragma unroll
    for (int i = 0; i < 2; i++)
#pragma unroll
        for (int j = 0; j < 8; j++)
#pragma unroll
            for (int c = 0; c < 4; c++) acc[i][j][c] = 0.f;

    const int KS = K >> 5;

    auto load_stage = [&](int slot, int ks) {
        const uint32_t base = sbase + slot * STG2;
        const int k0 = ks * 32;
#pragma unroll
        for (int c = tid; c < 512; c += 256) {
            const int r = c >> 2, seg = c & 3;
            const uint32_t d = base + r * PITCH + seg * 16;
            const long off = (long)r * K + k0 + seg * 8;
            cpa16(d,        Ah + off);
            cpa16(d + AMAT, Al + off);
        }
#pragma unroll
        for (int c = tid; c < 512; c += 256) {
            const int r = c >> 2, seg = c & 3;
            const uint32_t d = base + 2*AMAT + r * PITCH + seg * 16;
            const long off = (long)r * K + k0 + seg * 8;
            cpa16(d, Bh + off);
        }
        CPA_COMMIT();
    };

    load_stage(0, 0);

    const uint32_t a_row = (uint32_t)(wm * 32 + (lane & 15)) * PITCH;
    const uint32_t b_row = (uint32_t)(wn * 64 + (lane & 15)) * PITCH;
    const uint32_t lcol  = (uint32_t)((lane >> 4) * 16);

    for (int k = 0; k < KS; k++) {
        if (k + 1 < KS) load_stage((k + 1) & 1, k + 1);
        if (k + 1 < KS) { CPA_WAIT1(); } else { CPA_WAIT0(); }
        __syncthreads();
        const uint32_t st = sbase + (k & 1) * STG2;
        GEMM2_COMPUTE128(st)
        __syncthreads();
    }

#pragma unroll
    for (int mt = 0; mt < 2; mt++)
#pragma unroll
        for (int nt = 0; nt < 8; nt++) {
            const int m0 = bm + wm * 32 + mt * 16 + (lane >> 2);
            const int n0 = bn + wn * 64 + nt * 8 + (lane & 3) * 2;
            const float b0 = bias[n0], b1 = bias[n0 + 1];
#pragma unroll
            for (int half = 0; half < 2; half++) {
                const int m = m0 + half * 8;
                float* cp = Cf + (long)m * N + n0;
                cp[0] = acc[mt][nt][half * 2 + 0] + b0;
                cp[1] = acc[mt][nt][half * 2 + 1] + b1;
            }
        }
}

// ---------------- merged QKV projection: fp16 2-pass, scatter epilogue --------
#define VTP 272
#define VHOFF (128*VTP)              // 34816
#define QKV_SMEM (2*VHOFF)           // 69632 >= 2*STG2 (61440); epilogue needs it

__global__ __launch_bounds__(256, 2) void qkv_hmma(
    const __half* __restrict__ xh, const __half* __restrict__ xl,
    const __half* __restrict__ Wqh, const __half* __restrict__ Wkh,
    const __half* __restrict__ Wvh,
    const float* __restrict__ bq, const float* __restrict__ bk, const float* __restrict__ bv,
    __nv_bfloat16* __restrict__ Qh, __nv_bfloat16* __restrict__ Ql,
    __nv_bfloat16* __restrict__ Kh, __nv_bfloat16* __restrict__ Kl,
    __nv_bfloat16* __restrict__ Vth, __nv_bfloat16* __restrict__ Vtl)
{
    extern __shared__ char dsm[];
    const uint32_t sbase = smem_u32(dsm);

    const int tid  = threadIdx.x;
    const int wid  = tid >> 5;
    const int lane = tid & 31;
    const int wm   = wid & 3;
    const int wn   = wid >> 2;
    const int z    = blockIdx.z;
    const int bm   = blockIdx.y * 128;
    const int bn   = blockIdx.x * 128;
    const int K    = 1024;

    const __half* Bh_ = (z == 0) ? Wqh : (z == 1) ? Wkh : Wvh;
    const float* bias = (z == 0) ? bq : (z == 1) ? bk : bv;

    const __half* Ah = xh + (long)bm * K;
    const __half* Al = xl + (long)bm * K;
    const __half* Bh = Bh_ + (long)bn * K;

    float acc[2][8][4];
#pragma unroll
    for (int i = 0; i < 2; i++)
#pragma unroll
        for (int j = 0; j < 8; j++)
#pragma unroll
            for (int c = 0; c < 4; c++) acc[i][j][c] = 0.f;

    const int KS = K >> 5;

    auto load_stage = [&](int slot, int ks) {
        const uint32_t base = sbase + slot * STG2;
        const int k0 = ks * 32;
#pragma unroll
        for (int c = tid; c < 512; c += 256) {
            const int r = c >> 2, seg = c & 3;
            const uint32_t d = base + r * PITCH + seg * 16;
            const long off = (long)r * K + k0 + seg * 8;
            cpa16(d,        Ah + off);
            cpa16(d + AMAT, Al + off);
        }
#pragma unroll
        for (int c = tid; c < 512; c += 256) {
            const int r = c >> 2, seg = c & 3;
            const uint32_t d = base + 2*AMAT + r * PITCH + seg * 16;
            const long off = (long)r * K + k0 + seg * 8;
            cpa16(d, Bh + off);
        }
        CPA_COMMIT();
    };

    load_stage(0, 0);

    const uint32_t a_row = (uint32_t)(wm * 32 + (lane & 15)) * PITCH;
    const uint32_t b_row = (uint32_t)(wn * 64 + (lane & 15)) * PITCH;
    const uint32_t lcol  = (uint32_t)((lane >> 4) * 16);

    for (int k = 0; k < KS; k++) {
        if (k + 1 < KS) load_stage((k + 1) & 1, k + 1);
        if (k + 1 < KS) { CPA_WAIT1(); } else { CPA_WAIT0(); }
        __syncthreads();
        const uint32_t st = sbase + (k & 1) * STG2;
        GEMM2_COMPUTE128(st)
        __syncthreads();
    }

    const int b = bm >> 10, t0 = bm & 1023;

    if (z == 2) {
        // stage transposed 128dh x 128t tile in smem (fits QKV_SMEM), coalesced writes
#pragma unroll
        for (int mt = 0; mt < 2; mt++)
#pragma unroll
            for (int nt = 0; nt < 8; nt++) {
                const int dh = wn * 64 + nt * 8 + (lane & 3) * 2;
                const float b0 = bias[bn + dh], b1 = bias[bn + dh + 1];
#pragma unroll
                for (int half = 0; half < 2; half++) {
                    const int tl = wm * 32 + mt * 16 + (lane >> 2) + half * 8;
                    const float v0 = acc[mt][nt][half * 2 + 0] + b0;
                    const float v1 = acc[mt][nt][half * 2 + 1] + b1;
                    __nv_bfloat16 hh0 = __float2bfloat16(v0);
                    __nv_bfloat16 hh1 = __float2bfloat16(v1);
                    __nv_bfloat16 ll0 = __float2bfloat16(v0 - __bfloat162float(hh0));
                    __nv_bfloat16 ll1 = __float2bfloat16(v1 - __bfloat162float(hh1));
                    *(__nv_bfloat16*)(dsm + dh * VTP + tl * 2)               = hh0;
                    *(__nv_bfloat16*)(dsm + (dh + 1) * VTP + tl * 2)         = hh1;
                    *(__nv_bfloat16*)(dsm + VHOFF + dh * VTP + tl * 2)       = ll0;
                    *(__nv_bfloat16*)(dsm + VHOFF + (dh + 1) * VTP + tl * 2) = ll1;
                }
            }
        __syncthreads();
        {
            const int dh = tid >> 1, seg = tid & 1;
            const int h = (bn >> 6) + (dh >> 6);
            const long gb = (((long)(b * Hn + h) * DHn + (dh & 63)) * Tn) + t0 + seg * 64;
            const char* srh = dsm + dh * VTP + seg * 128;
            const char* srl = dsm + VHOFF + dh * VTP + seg * 128;
#pragma unroll
            for (int i = 0; i < 8; i++) {
                *(float4*)(Vth + gb + i * 8) = *(const float4*)(srh + i * 16);
                *(float4*)(Vtl + gb + i * 8) = *(const float4*)(srl + i * 16);
            }
        }
        return;
    }

#pragma unroll
    for (int mt = 0; mt < 2; mt++)
#pragma unroll
        for (int nt = 0; nt < 8; nt++) {
            const int m0 = bm + wm * 32 + mt * 16 + (lane >> 2);
            const int n0 = bn + wn * 64 + nt * 8 + (lane & 3) * 2;
            const float b0 = bias[n0], b1 = bias[n0 + 1];
            const int h = n0 >> 6, dh0 = n0 & 63;
#pragma unroll
            for (int half = 0; half < 2; half++) {
                const int m = m0 + half * 8;
                const float v0 = acc[mt][nt][half * 2 + 0] + b0;
                const float v1 = acc[mt][nt][half * 2 + 1] + b1;
                const int bb = m >> 10, t = m & 1023;
                __nv_bfloat16 hh0 = __float2bfloat16(v0);
                __nv_bfloat16 hh1 = __float2bfloat16(v1);
                __nv_bfloat16 ll0 = __float2bfloat16(v0 - __bfloat162float(hh0));
                __nv_bfloat16 ll1 = __float2bfloat16(v1 - __bfloat162float(hh1));
                const long base = (((long)(bb * Hn + h) * Tn + t) * DHn) + dh0;
                if (z == 0) {
                    Qh[base] = hh0; Qh[base + 1] = hh1;
                    Ql[base] = ll0; Ql[base + 1] = ll1;
                } else {
                    Kh[base] = hh0; Kh[base + 1] = hh1;
                    Kl[base] = ll0; Kl[base + 1] = ll1;
                }
            }
        }
}

// ---------------- QK: bf16 3-pass, K=64 single-stage, 128x128, causal skip ----------
#define QPITCH 144
#define QMAT  (128*QPITCH)
#define QK_SMEM (4*QMAT)

__global__ __launch_bounds__(256, 2) void qk_hmma(
    const __nv_bfloat16* __restrict__ Qh, const __nv_bfloat16* __restrict__ Ql,
    const __nv_bfloat16* __restrict__ Kh, const __nv_bfloat16* __restrict__ Kl,
    float* __restrict__ S)
{
    if ((int)blockIdx.x > (int)blockIdx.y) return;

    extern __shared__ char dsm[];
    const uint32_t sbase = smem_u32(dsm);

    const int tid  = threadIdx.x;
    const int wid  = tid >> 5;
    const int lane = tid & 31;
    const int wm   = wid & 3;
    const int wn   = wid >> 2;
    const int z    = blockIdx.z;
    const int bm   = blockIdx.y * 128;
    const int bn   = blockIdx.x * 128;

    const __nv_bfloat16* Ah = Qh + (long)z * Tn * DHn + (long)bm * DHn;
    const __nv_bfloat16* Al = Ql + (long)z * Tn * DHn + (long)bm * DHn;
    const __nv_bfloat16* Bh = Kh + (long)z * Tn * DHn + (long)bn * DHn;
    const __nv_bfloat16* Bl = Kl + (long)z * Tn * DHn + (long)bn * DHn;

#pragma unroll
    for (int c = tid; c < 1024; c += 256) {
        const int r = c >> 3, seg = c & 7;
        const uint32_t d = sbase + r * QPITCH + seg * 16;
        const long off = (long)r * DHn + seg * 8;
        cpa16(d,        Ah + off);
        cpa16(d + QMAT, Al + off);
    }
#pragma unroll
    for (int c = tid; c < 1024; c += 256) {
        const int r = c >> 3, seg = c & 7;
        const uint32_t d = sbase + 2*QMAT + r * QPITCH + seg * 16;
        const long off = (long)r * DHn + seg * 8;
        cpa16(d,        Bh + off);
        cpa16(d + QMAT, Bl + off);
    }
    CPA_COMMIT();
    CPA_WAIT0();
    __syncthreads();

    float acc[2][8][4];
#pragma unroll
    for (int i = 0; i < 2; i++)
#pragma unroll
        for (int j = 0; j < 8; j++)
#pragma unroll
            for (int c = 0; c < 4; c++) acc[i][j][c] = 0.f;

    const uint32_t a_row = (uint32_t)(wm * 32 + (lane & 15)) * QPITCH;
    const uint32_t b_row = (uint32_t)(wn * 64 + (lane & 15)) * QPITCH;
    const uint32_t lcol  = (uint32_t)((lane >> 4) * 16);

#pragma unroll
    for (int kc = 0; kc < 4; kc++) {
        const uint32_t col = kc * 32 + lcol;
        uint32_t ah[2][4], al[2][4], bh[4][4], bl[4][4];
#pragma unroll
        for (int mt = 0; mt < 2; mt++) {
            const uint32_t ad = sbase + a_row + (uint32_t)(mt * 16 * QPITCH) + col;
            LDSM4(ah[mt], ad);
            LDSM4(al[mt], ad + QMAT);
        }
#pragma unroll
        for (int np = 0; np < 4; np++) {
            const uint32_t bd = sbase + 2*QMAT + b_row + (uint32_t)(np * 16 * QPITCH) + col;
            LDSM4(bh[np], bd);
            LDSM4(bl[np], bd + QMAT);
        }
#pragma unroll
        for (int mt = 0; mt < 2; mt++)
#pragma unroll
            for (int nt = 0; nt < 8; nt++) {
                const int np = nt >> 1, i = nt & 1;
                MMA_BF16(acc[mt][nt], ah[mt], bh[np][i], bh[np][i + 2]);
                MMA_BF16(acc[mt][nt], ah[mt], bl[np][i], bl[np][i + 2]);
                MMA_BF16(acc[mt][nt], al[mt], bh[np][i], bh[np][i + 2]);
            }
    }

#pragma unroll
    for (int mt = 0; mt < 2; mt++)
#pragma unroll
        for (int nt = 0; nt < 8; nt++) {
            const int m0 = bm + wm * 32 + mt * 16 + (lane >> 2);
            const int n0 = bn + wn * 64 + nt * 8 + (lane & 3) * 2;
#pragma unroll
            for (int half = 0; half < 2; half++) {
                const int m = m0 + half * 8;
                float* cp = S + (long)z * Tn * Tn + (long)m * Tn + n0;
                cp[0] = acc[mt][nt][half * 2 + 0];
                cp[1] = acc[mt][nt][half * 2 + 1];
            }
        }
}

// ========== pv: bf16 3-pass 128x64, NS=2, 3 CTA/SM; epilogue -> fp16 AO ==========
#define B64M  (64*PITCH)
#define STG64 (2*AMAT + 2*B64M)
#define PV_SMEM (2*STG64)

__global__ __launch_bounds__(256, 3) void pv_hmma(
    const __nv_bfloat16* __restrict__ Ph, const __nv_bfloat16* __restrict__ Pl,
    const __nv_bfloat16* __restrict__ Vth, const __nv_bfloat16* __restrict__ Vtl,
    __half* __restrict__ AOh, __half* __restrict__ AOl)
{
    extern __shared__ char dsm[];
    const uint32_t sbase = smem_u32(dsm);

    const int tid  = threadIdx.x;
    const int wid  = tid >> 5;
    const int lane = tid & 31;
    const int wm   = wid & 3;
    const int wn   = wid >> 2;
    const int it   = blockIdx.x;
    const int bh   = blockIdx.y;
    const int b    = bh >> 4, h = bh & 15;

    const __nv_bfloat16* Ah = Ph + ((long)bh * Tn + it * 128) * Tn;
    const __nv_bfloat16* Al = Pl + ((long)bh * Tn + it * 128) * Tn;
    const __nv_bfloat16* Bh = Vth + (long)bh * DHn * Tn;
    const __nv_bfloat16* Bl = Vtl + (long)bh * DHn * Tn;

    float acc[2][4][4];
#pragma unroll
    for (int i = 0; i < 2; i++)
#pragma unroll
        for (int j = 0; j < 4; j++)
#pragma unroll
            for (int c = 0; c < 4; c++) acc[i][j][c] = 0.f;

    const int KS = 4 * (it + 1);

    auto load_stage = [&](int slot, int ks) {
        const uint32_t base = sbase + slot * STG64;
        const int k0 = ks * 32;
#pragma unroll
        for (int c = tid; c < 512; c += 256) {
            const int r = c >> 2, seg = c & 3;
            const uint32_t d = base + r * PITCH + seg * 16;
            const long off = (long)r * Tn + k0 + seg * 8;
            cpa16(d,        Ah + off);
            cpa16(d + AMAT, Al + off);
        }
        {
            const int r = tid >> 2, seg = tid & 3;
            const uint32_t d = base + 2*AMAT + r * PITCH + seg * 16;
            const long off = (long)r * Tn + k0 + seg * 8;
            cpa16(d,        Bh + off);
            cpa16(d + B64M, Bl + off);
        }
        CPA_COMMIT();
    };

    load_stage(0, 0);

    const uint32_t a_row = (uint32_t)(wm * 32 + (lane & 15)) * PITCH;
    const uint32_t b_row = (uint32_t)(wn * 32 + (lane & 15)) * PITCH;
    const uint32_t lcol  = (uint32_t)((lane >> 4) * 16);

    for (int k = 0; k < KS; k++) {
        if (k + 1 < KS) load_stage((k + 1) & 1, k + 1);
        if (k + 1 < KS) { CPA_WAIT1(); } else { CPA_WAIT0(); }
        __syncthreads();
        const uint32_t st = sbase + (k & 1) * STG64;
#pragma unroll
        for (int kc = 0; kc < 2; kc++) {
            const uint32_t col = kc * 32 + lcol;
            uint32_t ah[2][4], al[2][4], bh2[2][4], bl2[2][4];
#pragma unroll
            for (int mt = 0; mt < 2; mt++) {
                const uint32_t ad = st + a_row + (uint32_t)(mt * 16 * PITCH) + col;
                LDSM4(ah[mt], ad);
                LDSM4(al[mt], ad + AMAT);
            }
#pragma unroll
            for (int np = 0; np < 2; np++) {
                const uint32_t bd = st + 2*AMAT + b_row + (uint32_t)(np * 16 * PITCH) + col;
                LDSM4(bh2[np], bd);
                LDSM4(bl2[np], bd + B64M);
            }
#pragma unroll
            for (int mt = 0; mt < 2; mt++)
#pragma unroll
                for (int nt = 0; nt < 4; nt++) {
                    const int np = nt >> 1, i = nt & 1;
                    MMA_BF16(acc[mt][nt], ah[mt], bh2[np][i], bh2[np][i + 2]);
                    MMA_BF16(acc[mt][nt], ah[mt], bl2[np][i], bl2[np][i + 2]);
                    MMA_BF16(acc[mt][nt], al[mt], bh2[np][i], bh2[np][i + 2]);
                }
        }
        __syncthreads();
    }

#pragma unroll
    for (int mt = 0; mt < 2; mt++)
#pragma unroll
        for (int nt = 0; nt < 4; nt++) {
            const int t0 = it * 128 + wm * 32 + mt * 16 + (lane >> 2);
            const int dh = wn * 32 + nt * 8 + (lane & 3) * 2;
#pragma unroll
            for (int half = 0; half < 2; half++) {
                const int t = t0 + half * 8;
                const float v0 = acc[mt][nt][half * 2 + 0];
                const float v1 = acc[mt][nt][half * 2 + 1];
                const long base = ((long)b * Tn + t) * Dm + h * 64 + dh;
                __half h0 = __float2half(v0);
                __half h1 = __float2half(v1);
                __half2 H; H.x = h0; H.y = h1;
                __half2 L;
                L.x = __float2half(v0 - __half2float(h0));
                L.y = __float2half(v1 - __half2float(h1));
                *(__half2*)(AOh + base) = H;
                *(__half2*)(AOl + base) = L;
            }
        }
}

// ---------------- qpe table (Q reconstructed from hi/lo bf16) ----------------
__global__ __launch_bounds__(256) void qpe_kernel(const float* __restrict__ PE,
                                                  const __nv_bfloat16* __restrict__ Qh,
                                                  const __nv_bfloat16* __restrict__ Ql,
                                                  float* __restrict__ QPE)
{
    const int it = blockIdx.x, bh = blockIdx.y, h = bh & (Hn - 1);
    const __nv_bfloat16* Aqh = Qh + ((long)bh * Tn + it * 64) * DHn;
    const __nv_bfloat16* Aql = Ql + ((long)bh * Tn + it * 64) * DHn;
    const float* Bp = PE + (long)h * MAXP * DHn;

    __shared__ float Qs[64][65];
    __shared__ float Ps[64][65];

    const int tid = threadIdx.x;
    const int rowb = tid >> 4, c4 = (tid & 15) << 2;
#pragma unroll
    for (int r = 0; r < 4; r++) {
        int row = rowb + r * 16;
        const long off = (long)row * DHn + c4;
        __nv_bfloat162 qh0 = *(const __nv_bfloat162*)(Aqh + off);
        __nv_bfloat162 qh1 = *(const __nv_bfloat162*)(Aqh + off + 2);
        __nv_bfloat162 ql0 = *(const __nv_bfloat162*)(Aql + off);
        __nv_bfloat162 ql1 = *(const __nv_bfloat162*)(Aql + off + 2);
        Qs[row][c4]     = __bfloat162float(qh0.x) + __bfloat162float(ql0.x);
        Qs[row][c4 + 1] = __bfloat162float(qh0.y) + __bfloat162float(ql0.y);
        Qs[row][c4 + 2] = __bfloat162float(qh1.x) + __bfloat162float(ql1.x);
        Qs[row][c4 + 3] = __bfloat162float(qh1.y) + __bfloat162float(ql1.y);
        float4 p4 = *(const float4*)(Bp + (long)row * DHn + c4);
        Ps[row][c4] = p4.x; Ps[row][c4 + 1] = p4.y;
        Ps[row][c4 + 2] = p4.z; Ps[row][c4 + 3] = p4.w;
    }
    __syncthreads();

    const int tx = tid & 15, ty = tid >> 4;
    float acc[4][4];
#pragma unroll
    for (int i = 0; i < 4; i++)
#pragma unroll
        for (int j = 0; j < 4; j++) acc[i][j] = 0.f;

#pragma unroll 16
    for (int kk = 0; kk < 64; kk++) {
        float a0 = Qs[ty * 4 + 0][kk], a1 = Qs[ty * 4 + 1][kk];
        float a2 = Qs[ty * 4 + 2][kk], a3 = Qs[ty * 4 + 3][kk];
        float b0 = Ps[tx * 4 + 0][kk], b1 = Ps[tx * 4 + 1][kk];
        float b2 = Ps[tx * 4 + 2][kk], b3 = Ps[tx * 4 + 3][kk];
        acc[0][0] = fmaf(a0, b0, acc[0][0]); acc[0][1] = fmaf(a0, b1, acc[0][1]);
        acc[0][2] = fmaf(a0, b2, acc[0][2]); acc[0][3] = fmaf(a0, b3, acc[0][3]);
        acc[1][0] = fmaf(a1, b0, acc[1][0]); acc[1][1] = fmaf(a1, b1, acc[1][1]);
        acc[1][2] = fmaf(a1, b2, acc[1][2]); acc[1][3] = fmaf(a1, b3, acc[1][3]);
        acc[2][0] = fmaf(a2, b0, acc[2][0]); acc[2][1] = fmaf(a2, b1, acc[2][1]);
        acc[2][2] = fmaf(a2, b2, acc[2][2]); acc[2][3] = fmaf(a2, b3, acc[2][3]);
        acc[3][0] = fmaf(a3, b0, acc[3][0]); acc[3][1] = fmaf(a3, b1, acc[3][1]);
        acc[3][2] = fmaf(a3, b2, acc[3][2]); acc[3][3] = fmaf(a3, b3, acc[3][3]);
    }

    float* out = QPE + ((long)bh * Tn + it * 64) * MAXP;
#pragma unroll
    for (int ii = 0; ii < 4; ii++) {
        float4 o4 = make_float4(acc[ii][0], acc[ii][1], acc[ii][2], acc[ii][3]);
        *(float4*)(out + (long)(ty * 4 + ii) * MAXP + tx * 4) = o4;
    }
}

// ---------------- CoPE (block-per-row, validated) ----------------
__global__ __launch_bounds__(256) void cope_kernel(const float* __restrict__ S,
                                                   const float* __restrict__ QPE,
                                                   __nv_bfloat16* __restrict__ Ph,
                                                   __nv_bfloat16* __restrict__ Pl)
{
    const int i = blockIdx.x, bh = blockIdx.y;
    const float* row = S + ((long)bh * Tn + i) * Tn;
    const long prow = ((long)bh * Tn + i) * Tn;
    const float* qpe = QPE + ((long)bh * Tn + i) * MAXP;
    const int blockend = ((i >> 7) + 1) << 7;

    __shared__ float qpes[64];
    __shared__ float wred[8];
    __shared__ float wred2[8];

    const int tid = threadIdx.x, lane = tid & 31, wid = tid >> 5;
    if (tid < 64) qpes[tid] = qpe[tid];

    const int j0 = tid << 2;
    float qk[4] = {0.f, 0.f, 0.f, 0.f};
    if (j0 <= i) {
        float4 s4 = *(const float4*)(row + j0);
        qk[0] = s4.x; qk[1] = s4.y; qk[2] = s4.z; qk[3] = s4.w;
    }

    float lpre[4];
    float run = 0.f;
#pragma unroll
    for (int q = 0; q < 4; q++) {
        float gg = 0.f;
        if (j0 + q <= i)
            gg = __fdividef(1.f, 1.f + __expf(-0.125f * qk[q]));
        run += gg;
        lpre[q] = run;
    }

    float v = run;
#pragma unroll
    for (int o = 1; o < 32; o <<= 1) {
        float t = __shfl_up_sync(0xffffffffu, v, o);
        if (lane >= o) v += t;
    }
    if (lane == 31) wred[wid] = v;
    __syncthreads();
    if (tid < 8) {
        float w = wred[tid];
#pragma unroll
        for (int o = 1; o < 8; o <<= 1) {
            float t = __shfl_up_sync(0x000000ffu, w, o);
            if (tid >= o) w += t;
        }
        wred[tid] = w;
    }
    __syncthreads();
    const float base  = (v - run) + (wid ? wred[wid - 1] : 0.f);
    const float total = wred[7];

    float sc[4];
    float mx = -INFINITY;
#pragma unroll
    for (int q = 0; q < 4; q++) {
        float s_ = -INFINITY;
        if (j0 + q <= i) {
            float pos = total - (base + lpre[q]);
            pos = fminf(fmaxf(pos, 0.f), 63.f);
            float pf = floorf(pos);
            int fi = (int)pf;
            float al = pos - pf;
            int ci = (fi < 63) ? fi + 1 : 63;
            float qf = qpes[fi], qc = qpes[ci];
            float qv = qf + al * (qc - qf);
            s_ = 0.125f * (qk[q] + qv);
        }
        sc[q] = s_;
        mx = fmaxf(mx, s_);
    }
#pragma unroll
    for (int o = 16; o; o >>= 1) mx = fmaxf(mx, __shfl_xor_sync(0xffffffffu, mx, o));
    if (lane == 0) wred2[wid] = mx;
    __syncthreads();
    float bmax = wred2[0];
#pragma unroll
    for (int k = 1; k < 8; k++) bmax = fmaxf(bmax, wred2[k]);

    float p[4];
    float ssum = 0.f;
#pragma unroll
    for (int q = 0; q < 4; q++) {
        float e = (j0 + q <= i) ? __expf(sc[q] - bmax) : 0.f;
        p[q] = e;
        ssum += e;
    }
#pragma unroll
    for (int o = 16; o; o >>= 1) ssum += __shfl_xor_sync(0xffffffffu, ssum, o);
    __syncthreads();
    if (lane == 0) wred2[wid] = ssum;
    __syncthreads();
    float tot = 0.f;
#pragma unroll
    for (int k = 0; k < 8; k++) tot += wred2[k];
    const float inv = __fdividef(1.f, tot);

    if (j0 < blockend) {
        float v0 = p[0] * inv, v1 = p[1] * inv, v2 = p[2] * inv, v3 = p[3] * inv;
        __nv_bfloat16 h0 = __float2bfloat16(v0), h1 = __float2bfloat16(v1);
        __nv_bfloat16 h2 = __float2bfloat16(v2), h3 = __float2bfloat16(v3);
        __nv_bfloat162 H0; H0.x = h0; H0.y = h1;
        __nv_bfloat162 H1; H1.x = h2; H1.y = h3;
        __nv_bfloat162 L0, L1;
        L0.x = __float2bfloat16(v0 - __bfloat162float(h0));
        L0.y = __float2bfloat16(v1 - __bfloat162float(h1));
        L1.x = __float2bfloat16(v2 - __bfloat162float(h2));
        L1.y = __float2bfloat16(v3 - __bfloat162float(h3));
        *(__nv_bfloat162*)(Ph + prow + j0)     = H0;
        *(__nv_bfloat162*)(Ph + prow + j0 + 2) = H1;
        *(__nv_bfloat162*)(Pl + prow + j0)     = L0;
        *(__nv_bfloat162*)(Pl + prow + j0 + 2) = L1;
    }
}

// ---------------- launcher ----------------
extern "C" void kernel_launch(void* const* d_in, const int* in_sizes, int n_in,
                              void* d_out, int out_size)
{
    (void)in_sizes; (void)n_in; (void)out_size;
    const float* x  = (const float*)d_in[0];
    const float* Wq = (const float*)d_in[1];
    const float* bq = (const float*)d_in[2];
    const float* Wk = (const float*)d_in[3];
    const float* bk = (const float*)d_in[4];
    const float* Wv = (const float*)d_in[5];
    const float* bv = (const float*)d_in[6];
    const float* Wo = (const float*)d_in[7];
    const float* bo = (const float*)d_in[8];
    const float* pe = (const float*)d_in[9];
    float* out = (float*)d_out;

    float *QPEd, *Sd;
    __half *xh, *xl, *Wqh, *Wkh, *Wvh, *Woh, *AOh, *AOl;
    __nv_bfloat16 *Qh, *Ql, *Kh, *Kl, *Phd, *Pld, *Vth, *Vtl;
    cudaGetSymbolAddress((void**)&QPEd, g_QPE);
    cudaGetSymbolAddress((void**)&Sd, g_S);
    cudaGetSymbolAddress((void**)&xh, g_xh);   cudaGetSymbolAddress((void**)&xl, g_xl);
    cudaGetSymbolAddress((void**)&Wqh, g_Wqh); cudaGetSymbolAddress((void**)&Wkh, g_Wkh);
    cudaGetSymbolAddress((void**)&Wvh, g_Wvh); cudaGetSymbolAddress((void**)&Woh, g_Woh);
    cudaGetSymbolAddress((void**)&Qh, g_Qh);   cudaGetSymbolAddress((void**)&Ql, g_Ql);
    cudaGetSymbolAddress((void**)&Kh, g_Kh);   cudaGetSymbolAddress((void**)&Kl, g_Kl);
    cudaGetSymbolAddress((void**)&AOh, g_AOh); cudaGetSymbolAddress((void**)&AOl, g_AOl);
    cudaGetSymbolAddress((void**)&Phd, g_Ph);  cudaGetSymbolAddress((void**)&Pld, g_Pl);
    cudaGetSymbolAddress((void**)&Vth, g_Vth); cudaGetSymbolAddress((void**)&Vtl, g_Vtl);

    static int smem_set = 0;
    if (!smem_set) {
        cudaFuncSetAttribute(mm2_hmma, cudaFuncAttributeMaxDynamicSharedMemorySize, MM2_SMEM);
        cudaFuncSetAttribute(qkv_hmma, cudaFuncAttributeMaxDynamicSharedMemorySize, QKV_SMEM);
        cudaFuncSetAttribute(pv_hmma, cudaFuncAttributeMaxDynamicSharedMemorySize, PV_SMEM);
        cudaFuncSetAttribute(qk_hmma, cudaFuncAttributeMaxDynamicSharedMemorySize, QK_SMEM);
        smem_set = 1;
    }

    dim3 blk(256);

    splitx_h<<<2048, blk>>>(x, xh, xl, Bsz * Tn * Dm);
    splitW4h<<<dim3(1024, 1, 4), blk>>>(Wq, Wk, Wv, Wo, Wqh, Wkh, Wvh, Woh);

    qkv_hmma<<<dim3(8, 16, 3), blk, QKV_SMEM>>>(xh, xl, Wqh, Wkh, Wvh,
                                                bq, bk, bv, Qh, Ql, Kh, Kl, Vth, Vtl);

    qk_hmma<<<dim3(8, 8, 32), blk, QK_SMEM>>>(Qh, Ql, Kh, Kl, Sd);

    qpe_kernel<<<dim3(16, 32), blk>>>(pe, Qh, Ql, QPEd);

    cope_kernel<<<dim3(1024, 32), blk>>>(Sd, QPEd, Phd, Pld);

    pv_hmma<<<dim3(8, 32), blk, PV_SMEM>>>(Phd, Pld, Vth, Vtl, AOh, AOl);

    mm2_hmma<<<dim3(8, 16, 1), blk, MM2_SMEM>>>(AOh, AOl, Woh, bo, out, 1024, 1024);
}

// round 15
// speedup vs baseline: 1.5124x; 1.1250x over previous
#include <cuda_runtime.h>
#include <cuda_bf16.h>
#include <cuda_fp16.h>
#include <math.h>
#include <stdint.h>

#define Bsz 2
#define Tn  1024
#define Dm  1024
#define Hn  16
#define DHn 64
#define BHn (Bsz*Hn)
#define MAXP 64

// ---------------- scratch ----------------
__device__ float g_QPE[BHn*Tn*MAXP];
__device__ float g_S[(long)BHn*Tn*Tn];
__device__ __nv_bfloat16 g_Ph[(long)BHn*Tn*Tn], g_Pl[(long)BHn*Tn*Tn];
__device__ __nv_bfloat16 g_Vth[BHn*DHn*Tn], g_Vtl[BHn*DHn*Tn];
__device__ __half g_xh[Bsz*Tn*Dm];                            // fp16 activation (hi only)
__device__ __half g_Wqh[Dm*Dm], g_Wkh[Dm*Dm], g_Wvh[Dm*Dm], g_Woh[Dm*Dm]; // fp16 W
__device__ __nv_bfloat16 g_Qh[BHn*Tn*DHn], g_Ql[BHn*Tn*DHn];
__device__ __nv_bfloat16 g_Kh[BHn*Tn*DHn], g_Kl[BHn*Tn*DHn];
__device__ __half g_AOh[Bsz*Tn*Dm], g_AOl[Bsz*Tn*Dm];        // fp16 split of AO

// ---------------- helpers ----------------
__device__ __forceinline__ uint32_t smem_u32(const void* p) {
    uint32_t a;
    asm("{ .reg .u64 t; cvta.to.shared.u64 t, %1; cvt.u32.u64 %0, t; }" : "=r"(a) : "l"(p));
    return a;
}
__device__ __forceinline__ void cpa16(uint32_t dst, const void* src) {
    asm volatile("cp.async.cg.shared.global [%0], [%1], 16;" :: "r"(dst), "l"(src));
}
#define CPA_COMMIT() asm volatile("cp.async.commit_group;" ::: "memory")
#define CPA_WAIT1()  asm volatile("cp.async.wait_group 1;" ::: "memory")
#define CPA_WAIT0()  asm volatile("cp.async.wait_group 0;" ::: "memory")

#define LDSM4(r, a) \
    asm volatile("ldmatrix.sync.aligned.m8n8.x4.shared.b16 {%0,%1,%2,%3}, [%4];" \
        : "=r"((r)[0]), "=r"((r)[1]), "=r"((r)[2]), "=r"((r)[3]) : "r"(a))

#define MMA_BF16(c, a, b0v, b1v) \
    asm volatile("mma.sync.aligned.m16n8k16.row.col.f32.bf16.bf16.f32 " \
        "{%0,%1,%2,%3},{%4,%5,%6,%7},{%8,%9},{%0,%1,%2,%3};" \
        : "+f"((c)[0]), "+f"((c)[1]), "+f"((c)[2]), "+f"((c)[3]) \
        : "r"((a)[0]), "r"((a)[1]), "r"((a)[2]), "r"((a)[3]), "r"(b0v), "r"(b1v))

#define MMA_F16(c, a, b0v, b1v) \
    asm volatile("mma.sync.aligned.m16n8k16.row.col.f32.f16.f16.f32 " \
        "{%0,%1,%2,%3},{%4,%5,%6,%7},{%8,%9},{%0,%1,%2,%3};" \
        : "+f"((c)[0]), "+f"((c)[1]), "+f"((c)[2]), "+f"((c)[3]) \
        : "r"((a)[0]), "r"((a)[1]), "r"((a)[2]), "r"((a)[3]), "r"(b0v), "r"(b1v))

// ---------------- conversions ----------------
__global__ __launch_bounds__(256) void cvtx_h(const float* __restrict__ s,
                                              __half* __restrict__ h, int n)
{
    int i = (blockIdx.x * 256 + threadIdx.x) * 4;
    if (i >= n) return;
    float4 v = *(const float4*)(s + i);
    __half2 H0, H1;
    H0.x = __float2half(v.x); H0.y = __float2half(v.y);
    H1.x = __float2half(v.z); H1.y = __float2half(v.w);
    *(__half2*)(h + i)     = H0;
    *(__half2*)(h + i + 2) = H1;
}

__global__ __launch_bounds__(256) void splitW4h(
    const float* __restrict__ Wq, const float* __restrict__ Wk,
    const float* __restrict__ Wv, const float* __restrict__ Wo,
    __half* __restrict__ Wqh, __half* __restrict__ Wkh,
    __half* __restrict__ Wvh, __half* __restrict__ Woh)
{
    const int z = blockIdx.z;
    const float* s = (z == 0) ? Wq : (z == 1) ? Wk : (z == 2) ? Wv : Wo;
    __half* h = (z == 0) ? Wqh : (z == 1) ? Wkh : (z == 2) ? Wvh : Woh;
    int i = (blockIdx.x * 256 + threadIdx.x) * 4;
    float4 v = *(const float4*)(s + i);
    __half2 H0, H1;
    H0.x = __float2half(v.x); H0.y = __float2half(v.y);
    H1.x = __float2half(v.z); H1.y = __float2half(v.w);
    *(__half2*)(h + i)     = H0;
    *(__half2*)(h + i + 2) = H1;
}

// ---------------- common tile params ----------------
#define PITCH 80
#define AMAT  (128*PITCH)
#define B128M (128*PITCH)

// ========== fp16 2-pass engine (out-proj): C = (Ah+Al)·Bh^T ==========
#define STG2  (2*AMAT + B128M)      // 30720: [Ah][Al][Bh]
#define MM2_SMEM (2*STG2)           // 61440

__global__ __launch_bounds__(256, 2) void mm2_hmma(
    const __half* __restrict__ Ahi, const __half* __restrict__ Alo,
    const __half* __restrict__ Bhh,
    const float* __restrict__ bias, float* __restrict__ Cf, int N, int K)
{
    extern __shared__ char dsm[];
    const uint32_t sbase = smem_u32(dsm);

    const int tid  = threadIdx.x;
    const int wid  = tid >> 5;
    const int lane = tid & 31;
    const int wm   = wid & 3;
    const int wn   = wid >> 2;
    const int bm   = blockIdx.y * 128;
    const int bn   = blockIdx.x * 128;

    const __half* Ah = Ahi + (long)bm * K;
    const __half* Al = Alo + (long)bm * K;
    const __half* Bh = Bhh + (long)bn * K;

    float acc[2][8][4];
#pragma unroll
    for (int i = 0; i < 2; i++)
#pragma unroll
        for (int j = 0; j < 8; j++)
#pragma unroll
            for (int c = 0; c < 4; c++) acc[i][j][c] = 0.f;

    const int KS = K >> 5;

    auto load_stage = [&](int slot, int ks) {
        const uint32_t base = sbase + slot * STG2;
        const int k0 = ks * 32;
#pragma unroll
        for (int c = tid; c < 512; c += 256) {
            const int r = c >> 2, seg = c & 3;
            const uint32_t d = base + r * PITCH + seg * 16;
            const long off = (long)r * K + k0 + seg * 8;
            cpa16(d,        Ah + off);
            cpa16(d + AMAT, Al + off);
        }
#pragma unroll
        for (int c = tid; c < 512; c += 256) {
            const int r = c >> 2, seg = c & 3;
            const uint32_t d = base + 2*AMAT + r * PITCH + seg * 16;
            const long off = (long)r * K + k0 + seg * 8;
            cpa16(d, Bh + off);
        }
        CPA_COMMIT();
    };

    load_stage(0, 0);

    const uint32_t a_row = (uint32_t)(wm * 32 + (lane & 15)) * PITCH;
    const uint32_t b_row = (uint32_t)(wn * 64 + (lane & 15)) * PITCH;
    const uint32_t lcol  = (uint32_t)((lane >> 4) * 16);

    for (int k = 0; k < KS; k++) {
        if (k + 1 < KS) load_stage((k + 1) & 1, k + 1);
        if (k + 1 < KS) { CPA_WAIT1(); } else { CPA_WAIT0(); }
        __syncthreads();
        const uint32_t st = sbase + (k & 1) * STG2;
#pragma unroll
        for (int kc = 0; kc < 2; kc++) {
            const uint32_t col = kc * 32 + lcol;
            uint32_t ah[2][4], al[2][4], bh[4][4];
#pragma unroll
            for (int mt = 0; mt < 2; mt++) {
                const uint32_t ad = st + a_row + (uint32_t)(mt * 16 * PITCH) + col;
                LDSM4(ah[mt], ad);
                LDSM4(al[mt], ad + AMAT);
            }
#pragma unroll
            for (int np = 0; np < 4; np++) {
                const uint32_t bd = st + 2*AMAT + b_row + (uint32_t)(np * 16 * PITCH) + col;
                LDSM4(bh[np], bd);
            }
#pragma unroll
            for (int mt = 0; mt < 2; mt++)
#pragma unroll
                for (int nt = 0; nt < 8; nt++) {
                    const int np = nt >> 1, i = nt & 1;
                    MMA_F16(acc[mt][nt], ah[mt], bh[np][i], bh[np][i + 2]);
                    MMA_F16(acc[mt][nt], al[mt], bh[np][i], bh[np][i + 2]);
                }
        }
        __syncthreads();
    }

#pragma unroll
    for (int mt = 0; mt < 2; mt++)
#pragma unroll
        for (int nt = 0; nt < 8; nt++) {
            const int m0 = bm + wm * 32 + mt * 16 + (lane >> 2);
            const int n0 = bn + wn * 64 + nt * 8 + (lane & 3) * 2;
            const float b0 = bias[n0], b1 = bias[n0 + 1];
#pragma unroll
            for (int half = 0; half < 2; half++) {
                const int m = m0 + half * 8;
                float* cp = Cf + (long)m * N + n0;
                cp[0] = acc[mt][nt][half * 2 + 0] + b0;
                cp[1] = acc[mt][nt][half * 2 + 1] + b1;
            }
        }
}

// ---------------- merged QKV projection: fp16 1-PASS, scatter epilogue --------
#define STG1  (AMAT + B128M)         // 20480: [Ah][Bh]
#define VTP 272
#define VHOFF (128*VTP)              // 34816
#define QKV_SMEM (2*VHOFF)           // 69632 (>= 2*STG1; epilogue transpose buffer)

__global__ __launch_bounds__(256, 2) void qkv_hmma(
    const __half* __restrict__ xh,
    const __half* __restrict__ Wqh, const __half* __restrict__ Wkh,
    const __half* __restrict__ Wvh,
    const float* __restrict__ bq, const float* __restrict__ bk, const float* __restrict__ bv,
    __nv_bfloat16* __restrict__ Qh, __nv_bfloat16* __restrict__ Ql,
    __nv_bfloat16* __restrict__ Kh, __nv_bfloat16* __restrict__ Kl,
    __nv_bfloat16* __restrict__ Vth, __nv_bfloat16* __restrict__ Vtl)
{
    extern __shared__ char dsm[];
    const uint32_t sbase = smem_u32(dsm);

    const int tid  = threadIdx.x;
    const int wid  = tid >> 5;
    const int lane = tid & 31;
    const int wm   = wid & 3;
    const int wn   = wid >> 2;
    const int z    = blockIdx.z;
    const int bm   = blockIdx.y * 128;
    const int bn   = blockIdx.x * 128;
    const int K    = 1024;

    const __half* Bh_ = (z == 0) ? Wqh : (z == 1) ? Wkh : Wvh;
    const float* bias = (z == 0) ? bq : (z == 1) ? bk : bv;

    const __half* Ah = xh + (long)bm * K;
    const __half* Bh = Bh_ + (long)bn * K;

    float acc[2][8][4];
#pragma unroll
    for (int i = 0; i < 2; i++)
#pragma unroll
        for (int j = 0; j < 8; j++)
#pragma unroll
            for (int c = 0; c < 4; c++) acc[i][j][c] = 0.f;

    const int KS = K >> 5;

    auto load_stage = [&](int slot, int ks) {
        const uint32_t base = sbase + slot * STG1;
        const int k0 = ks * 32;
#pragma unroll
        for (int c = tid; c < 512; c += 256) {
            const int r = c >> 2, seg = c & 3;
            const uint32_t d = base + r * PITCH + seg * 16;
            const long off = (long)r * K + k0 + seg * 8;
            cpa16(d, Ah + off);
        }
#pragma unroll
        for (int c = tid; c < 512; c += 256) {
            const int r = c >> 2, seg = c & 3;
            const uint32_t d = base + AMAT + r * PITCH + seg * 16;
            const long off = (long)r * K + k0 + seg * 8;
            cpa16(d, Bh + off);
        }
        CPA_COMMIT();
    };

    load_stage(0, 0);

    const uint32_t a_row = (uint32_t)(wm * 32 + (lane & 15)) * PITCH;
    const uint32_t b_row = (uint32_t)(wn * 64 + (lane & 15)) * PITCH;
    const uint32_t lcol  = (uint32_t)((lane >> 4) * 16);

    for (int k = 0; k < KS; k++) {
        if (k + 1 < KS) load_stage((k + 1) & 1, k + 1);
        if (k + 1 < KS) { CPA_WAIT1(); } else { CPA_WAIT0(); }
        __syncthreads();
        const uint32_t st = sbase + (k & 1) * STG1;
#pragma unroll
        for (int kc = 0; kc < 2; kc++) {
            const uint32_t col = kc * 32 + lcol;
            uint32_t ah[2][4], bh[4][4];
#pragma unroll
            for (int mt = 0; mt < 2; mt++) {
                const uint32_t ad = st + a_row + (uint32_t)(mt * 16 * PITCH) + col;
                LDSM4(ah[mt], ad);
            }
#pragma unroll
            for (int np = 0; np < 4; np++) {
                const uint32_t bd = st + AMAT + b_row + (uint32_t)(np * 16 * PITCH) + col;
                LDSM4(bh[np], bd);
            }
#pragma unroll
            for (int mt = 0; mt < 2; mt++)
#pragma unroll
                for (int nt = 0; nt < 8; nt++) {
                    const int np = nt >> 1, i = nt & 1;
                    MMA_F16(acc[mt][nt], ah[mt], bh[np][i], bh[np][i + 2]);
                }
        }
        __syncthreads();
    }

    const int b = bm >> 10, t0 = bm & 1023;

    if (z == 2) {
        // stage transposed 128dh x 128t tile in smem, coalesced global writes
#pragma unroll
        for (int mt = 0; mt < 2; mt++)
#pragma unroll
            for (int nt = 0; nt < 8; nt++) {
                const int dh = wn * 64 + nt * 8 + (lane & 3) * 2;
                const float b0 = bias[bn + dh], b1 = bias[bn + dh + 1];
#pragma unroll
                for (int half = 0; half < 2; half++) {
                    const int tl = wm * 32 + mt * 16 + (lane >> 2) + half * 8;
                    const float v0 = acc[mt][nt][half * 2 + 0] + b0;
                    const float v1 = acc[mt][nt][half * 2 + 1] + b1;
                    __nv_bfloat16 hh0 = __float2bfloat16(v0);
                    __nv_bfloat16 hh1 = __float2bfloat16(v1);
                    __nv_bfloat16 ll0 = __float2bfloat16(v0 - __bfloat162float(hh0));
                    __nv_bfloat16 ll1 = __float2bfloat16(v1 - __bfloat162float(hh1));
                    *(__nv_bfloat16*)(dsm + dh * VTP + tl * 2)               = hh0;
                    *(__nv_bfloat16*)(dsm + (dh + 1) * VTP + tl * 2)         = hh1;
                    *(__nv_bfloat16*)(dsm + VHOFF + dh * VTP + tl * 2)       = ll0;
                    *(__nv_bfloat16*)(dsm + VHOFF + (dh + 1) * VTP + tl * 2) = ll1;
                }
            }
        __syncthreads();
        {
            const int dh = tid >> 1, seg = tid & 1;
            const int h = (bn >> 6) + (dh >> 6);
            const long gb = (((long)(b * Hn + h) * DHn + (dh & 63)) * Tn) + t0 + seg * 64;
            const char* srh = dsm + dh * VTP + seg * 128;
            const char* srl = dsm + VHOFF + dh * VTP + seg * 128;
#pragma unroll
            for (int i = 0; i < 8; i++) {
                *(float4*)(Vth + gb + i * 8) = *(const float4*)(srh + i * 16);
                *(float4*)(Vtl + gb + i * 8) = *(const float4*)(srl + i * 16);
            }
        }
        return;
    }

#pragma unroll
    for (int mt = 0; mt < 2; mt++)
#pragma unroll
        for (int nt = 0; nt < 8; nt++) {
            const int m0 = bm + wm * 32 + mt * 16 + (lane >> 2);
            const int n0 = bn + wn * 64 + nt * 8 + (lane & 3) * 2;
            const float b0 = bias[n0], b1 = bias[n0 + 1];
            const int h = n0 >> 6, dh0 = n0 & 63;
#pragma unroll
            for (int half = 0; half < 2; half++) {
                const int m = m0 + half * 8;
                const float v0 = acc[mt][nt][half * 2 + 0] + b0;
                const float v1 = acc[mt][nt][half * 2 + 1] + b1;
                const int bb = m >> 10, t = m & 1023;
                __nv_bfloat16 hh0 = __float2bfloat16(v0);
                __nv_bfloat16 hh1 = __float2bfloat16(v1);
                __nv_bfloat16 ll0 = __float2bfloat16(v0 - __bfloat162float(hh0));
                __nv_bfloat16 ll1 = __float2bfloat16(v1 - __bfloat162float(hh1));
                const long base = (((long)(bb * Hn + h) * Tn + t) * DHn) + dh0;
                if (z == 0) {
                    Qh[base] = hh0; Qh[base + 1] = hh1;
                    Ql[base] = ll0; Ql[base + 1] = ll1;
                } else {
                    Kh[base] = hh0; Kh[base + 1] = hh1;
                    Kl[base] = ll0; Kl[base + 1] = ll1;
                }
            }
        }
}

// ---------------- QK: bf16 3-pass, K=64 single-stage, 128x128, causal skip ----------
#define QPITCH 144
#define QMAT  (128*QPITCH)
#define QK_SMEM (4*QMAT)

__global__ __launch_bounds__(256, 2) void qk_hmma(
    const __nv_bfloat16* __restrict__ Qh, const __nv_bfloat16* __restrict__ Ql,
    const __nv_bfloat16* __restrict__ Kh, const __nv_bfloat16* __restrict__ Kl,
    float* __restrict__ S)
{
    if ((int)blockIdx.x > (int)blockIdx.y) return;

    extern __shared__ char dsm[];
    const uint32_t sbase = smem_u32(dsm);

    const int tid  = threadIdx.x;
    const int wid  = tid >> 5;
    const int lane = tid & 31;
    const int wm   = wid & 3;
    const int wn   = wid >> 2;
    const int z    = blockIdx.z;
    const int bm   = blockIdx.y * 128;
    const int bn   = blockIdx.x * 128;

    const __nv_bfloat16* Ah = Qh + (long)z * Tn * DHn + (long)bm * DHn;
    const __nv_bfloat16* Al = Ql + (long)z * Tn * DHn + (long)bm * DHn;
    const __nv_bfloat16* Bh = Kh + (long)z * Tn * DHn + (long)bn * DHn;
    const __nv_bfloat16* Bl = Kl + (long)z * Tn * DHn + (long)bn * DHn;

#pragma unroll
    for (int c = tid; c < 1024; c += 256) {
        const int r = c >> 3, seg = c & 7;
        const uint32_t d = sbase + r * QPITCH + seg * 16;
        const long off = (long)r * DHn + seg * 8;
        cpa16(d,        Ah + off);
        cpa16(d + QMAT, Al + off);
    }
#pragma unroll
    for (int c = tid; c < 1024; c += 256) {
        const int r = c >> 3, seg = c & 7;
        const uint32_t d = sbase + 2*QMAT + r * QPITCH + seg * 16;
        const long off = (long)r * DHn + seg * 8;
        cpa16(d,        Bh + off);
        cpa16(d + QMAT, Bl + off);
    }
    CPA_COMMIT();
    CPA_WAIT0();
    __syncthreads();

    float acc[2][8][4];
#pragma unroll
    for (int i = 0; i < 2; i++)
#pragma unroll
        for (int j = 0; j < 8; j++)
#pragma unroll
            for (int c = 0; c < 4; c++) acc[i][j][c] = 0.f;

    const uint32_t a_row = (uint32_t)(wm * 32 + (lane & 15)) * QPITCH;
    const uint32_t b_row = (uint32_t)(wn * 64 + (lane & 15)) * QPITCH;
    const uint32_t lcol  = (uint32_t)((lane >> 4) * 16);

#pragma unroll
    for (int kc = 0; kc < 4; kc++) {
        const uint32_t col = kc * 32 + lcol;
        uint32_t ah[2][4], al[2][4], bh[4][4], bl[4][4];
#pragma unroll
        for (int mt = 0; mt < 2; mt++) {
            const uint32_t ad = sbase + a_row + (uint32_t)(mt * 16 * QPITCH) + col;
            LDSM4(ah[mt], ad);
            LDSM4(al[mt], ad + QMAT);
        }
#pragma unroll
        for (int np = 0; np < 4; np++) {
            const uint32_t bd = sbase + 2*QMAT + b_row + (uint32_t)(np * 16 * QPITCH) + col;
            LDSM4(bh[np], bd);
            LDSM4(bl[np], bd + QMAT);
        }
#pragma unroll
        for (int mt = 0; mt < 2; mt++)
#pragma unroll
            for (int nt = 0; nt < 8; nt++) {
                const int np = nt >> 1, i = nt & 1;
                MMA_BF16(acc[mt][nt], ah[mt], bh[np][i], bh[np][i + 2]);
                MMA_BF16(acc[mt][nt], ah[mt], bl[np][i], bl[np][i + 2]);
                MMA_BF16(acc[mt][nt], al[mt], bh[np][i], bh[np][i + 2]);
            }
    }

#pragma unroll
    for (int mt = 0; mt < 2; mt++)
#pragma unroll
        for (int nt = 0; nt < 8; nt++) {
            const int m0 = bm + wm * 32 + mt * 16 + (lane >> 2);
            const int n0 = bn + wn * 64 + nt * 8 + (lane & 3) * 2;
#pragma unroll
            for (int half = 0; half < 2; half++) {
                const int m = m0 + half * 8;
                float* cp = S + (long)z * Tn * Tn + (long)m * Tn + n0;
                cp[0] = acc[mt][nt][half * 2 + 0];
                cp[1] = acc[mt][nt][half * 2 + 1];
            }
        }
}

// ========== pv: bf16 3-pass 128x64, NS=2, 3 CTA/SM; epilogue -> fp16 AO ==========
#define B64M  (64*PITCH)
#define STG64 (2*AMAT + 2*B64M)
#define PV_SMEM (2*STG64)

__global__ __launch_bounds__(256, 3) void pv_hmma(
    const __nv_bfloat16* __restrict__ Ph, const __nv_bfloat16* __restrict__ Pl,
    const __nv_bfloat16* __restrict__ Vth, const __nv_bfloat16* __restrict__ Vtl,
    __half* __restrict__ AOh, __half* __restrict__ AOl)
{
    extern __shared__ char dsm[];
    const uint32_t sbase = smem_u32(dsm);

    const int tid  = threadIdx.x;
    const int wid  = tid >> 5;
    const int lane = tid & 31;
    const int wm   = wid & 3;
    const int wn   = wid >> 2;
    const int it   = blockIdx.x;
    const int bh   = blockIdx.y;
    const int b    = bh >> 4, h = bh & 15;

    const __nv_bfloat16* Ah = Ph + ((long)bh * Tn + it * 128) * Tn;
    const __nv_bfloat16* Al = Pl + ((long)bh * Tn + it * 128) * Tn;
    const __nv_bfloat16* Bh = Vth + (long)bh * DHn * Tn;
    const __nv_bfloat16* Bl = Vtl + (long)bh * DHn * Tn;

    float acc[2][4][4];
#pragma unroll
    for (int i = 0; i < 2; i++)
#pragma unroll
        for (int j = 0; j < 4; j++)
#pragma unroll
            for (int c = 0; c < 4; c++) acc[i][j][c] = 0.f;

    const int KS = 4 * (it + 1);

    auto load_stage = [&](int slot, int ks) {
        const uint32_t base = sbase + slot * STG64;
        const int k0 = ks * 32;
#pragma unroll
        for (int c = tid; c < 512; c += 256) {
            const int r = c >> 2, seg = c & 3;
            const uint32_t d = base + r * PITCH + seg * 16;
            const long off = (long)r * Tn + k0 + seg * 8;
            cpa16(d,        Ah + off);
            cpa16(d + AMAT, Al + off);
        }
        {
            const int r = tid >> 2, seg = tid & 3;
            const uint32_t d = base + 2*AMAT + r * PITCH + seg * 16;
            const long off = (long)r * Tn + k0 + seg * 8;
            cpa16(d,        Bh + off);
            cpa16(d + B64M, Bl + off);
        }
        CPA_COMMIT();
    };

    load_stage(0, 0);

    const uint32_t a_row = (uint32_t)(wm * 32 + (lane & 15)) * PITCH;
    const uint32_t b_row = (uint32_t)(wn * 32 + (lane & 15)) * PITCH;
    const uint32_t lcol  = (uint32_t)((lane >> 4) * 16);

    for (int k = 0; k < KS; k++) {
        if (k + 1 < KS) load_stage((k + 1) & 1, k + 1);
        if (k + 1 < KS) { CPA_WAIT1(); } else { CPA_WAIT0(); }
        __syncthreads();
        const uint32_t st = sbase + (k & 1) * STG64;
#pragma unroll
        for (int kc = 0; kc < 2; kc++) {
            const uint32_t col = kc * 32 + lcol;
            uint32_t ah[2][4], al[2][4], bh2[2][4], bl2[2][4];
#pragma unroll
            for (int mt = 0; mt < 2; mt++) {
                const uint32_t ad = st + a_row + (uint32_t)(mt * 16 * PITCH) + col;
                LDSM4(ah[mt], ad);
                LDSM4(al[mt], ad + AMAT);
            }
#pragma unroll
            for (int np = 0; np < 2; np++) {
                const uint32_t bd = st + 2*AMAT + b_row + (uint32_t)(np * 16 * PITCH) + col;
                LDSM4(bh2[np], bd);
                LDSM4(bl2[np], bd + B64M);
            }
#pragma unroll
            for (int mt = 0; mt < 2; mt++)
#pragma unroll
                for (int nt = 0; nt < 4; nt++) {
                    const int np = nt >> 1, i = nt & 1;
                    MMA_BF16(acc[mt][nt], ah[mt], bh2[np][i], bh2[np][i + 2]);
                    MMA_BF16(acc[mt][nt], ah[mt], bl2[np][i], bl2[np][i + 2]);
                    MMA_BF16(acc[mt][nt], al[mt], bh2[np][i], bh2[np][i + 2]);
                }
        }
        __syncthreads();
    }

#pragma unroll
    for (int mt = 0; mt < 2; mt++)
#pragma unroll
        for (int nt = 0; nt < 4; nt++) {
            const int t0 = it * 128 + wm * 32 + mt * 16 + (lane >> 2);
            const int dh = wn * 32 + nt * 8 + (lane & 3) * 2;
#pragma unroll
            for (int half = 0; half < 2; half++) {
                const int t = t0 + half * 8;
                const float v0 = acc[mt][nt][half * 2 + 0];
                const float v1 = acc[mt][nt][half * 2 + 1];
                const long base = ((long)b * Tn + t) * Dm + h * 64 + dh;
                __half h0 = __float2half(v0);
                __half h1 = __float2half(v1);
                __half2 H; H.x = h0; H.y = h1;
                __half2 L;
                L.x = __float2half(v0 - __half2float(h0));
                L.y = __float2half(v1 - __half2float(h1));
                *(__half2*)(AOh + base) = H;
                *(__half2*)(AOl + base) = L;
            }
        }
}

// ---------------- qpe table (Q reconstructed from hi/lo bf16) ----------------
__global__ __launch_bounds__(256) void qpe_kernel(const float* __restrict__ PE,
                                                  const __nv_bfloat16* __restrict__ Qh,
                                                  const __nv_bfloat16* __restrict__ Ql,
                                                  float* __restrict__ QPE)
{
    const int it = blockIdx.x, bh = blockIdx.y, h = bh & (Hn - 1);
    const __nv_bfloat16* Aqh = Qh + ((long)bh * Tn + it * 64) * DHn;
    const __nv_bfloat16* Aql = Ql + ((long)bh * Tn + it * 64) * DHn;
    const float* Bp = PE + (long)h * MAXP * DHn;

    __shared__ float Qs[64][65];
    __shared__ float Ps[64][65];

    const int tid = threadIdx.x;
    const int rowb = tid >> 4, c4 = (tid & 15) << 2;
#pragma unroll
    for (int r = 0; r < 4; r++) {
        int row = rowb + r * 16;
        const long off = (long)row * DHn + c4;
        __nv_bfloat162 qh0 = *(const __nv_bfloat162*)(Aqh + off);
        __nv_bfloat162 qh1 = *(const __nv_bfloat162*)(Aqh + off + 2);
        __nv_bfloat162 ql0 = *(const __nv_bfloat162*)(Aql + off);
        __nv_bfloat162 ql1 = *(const __nv_bfloat162*)(Aql + off + 2);
        Qs[row][c4]     = __bfloat162float(qh0.x) + __bfloat162float(ql0.x);
        Qs[row][c4 + 1] = __bfloat162float(qh0.y) + __bfloat162float(ql0.y);
        Qs[row][c4 + 2] = __bfloat162float(qh1.x) + __bfloat162float(ql1.x);
        Qs[row][c4 + 3] = __bfloat162float(qh1.y) + __bfloat162float(ql1.y);
        float4 p4 = *(const float4*)(Bp + (long)row * DHn + c4);
        Ps[row][c4] = p4.x; Ps[row][c4 + 1] = p4.y;
        Ps[row][c4 + 2] = p4.z; Ps[row][c4 + 3] = p4.w;
    }
    __syncthreads();

    const int tx = tid & 15, ty = tid >> 4;
    float acc[4][4];
#pragma unroll
    for (int i = 0; i < 4; i++)
#pragma unroll
        for (int j = 0; j < 4; j++) acc[i][j] = 0.f;

#pragma unroll 16
    for (int kk = 0; kk < 64; kk++) {
        float a0 = Qs[ty * 4 + 0][kk], a1 = Qs[ty * 4 + 1][kk];
        float a2 = Qs[ty * 4 + 2][kk], a3 = Qs[ty * 4 + 3][kk];
        float b0 = Ps[tx * 4 + 0][kk], b1 = Ps[tx * 4 + 1][kk];
        float b2 = Ps[tx * 4 + 2][kk], b3 = Ps[tx * 4 + 3][kk];
        acc[0][0] = fmaf(a0, b0, acc[0][0]); acc[0][1] = fmaf(a0, b1, acc[0][1]);
        acc[0][2] = fmaf(a0, b2, acc[0][2]); acc[0][3] = fmaf(a0, b3, acc[0][3]);
        acc[1][0] = fmaf(a1, b0, acc[1][0]); acc[1][1] = fmaf(a1, b1, acc[1][1]);
        acc[1][2] = fmaf(a1, b2, acc[1][2]); acc[1][3] = fmaf(a1, b3, acc[1][3]);
        acc[2][0] = fmaf(a2, b0, acc[2][0]); acc[2][1] = fmaf(a2, b1, acc[2][1]);
        acc[2][2] = fmaf(a2, b2, acc[2][2]); acc[2][3] = fmaf(a2, b3, acc[2][3]);
        acc[3][0] = fmaf(a3, b0, acc[3][0]); acc[3][1] = fmaf(a3, b1, acc[3][1]);
        acc[3][2] = fmaf(a3, b2, acc[3][2]); acc[3][3] = fmaf(a3, b3, acc[3][3]);
    }

    float* out = QPE + ((long)bh * Tn + it * 64) * MAXP;
#pragma unroll
    for (int ii = 0; ii < 4; ii++) {
        float4 o4 = make_float4(acc[ii][0], acc[ii][1], acc[ii][2], acc[ii][3]);
        *(float4*)(out + (long)(ty * 4 + ii) * MAXP + tx * 4) = o4;
    }
}

// ---------------- CoPE (block-per-row, validated) ----------------
__global__ __launch_bounds__(256) void cope_kernel(const float* __restrict__ S,
                                                   const float* __restrict__ QPE,
                                                   __nv_bfloat16* __restrict__ Ph,
                                                   __nv_bfloat16* __restrict__ Pl)
{
    const int i = blockIdx.x, bh = blockIdx.y;
    const float* row = S + ((long)bh * Tn + i) * Tn;
    const long prow = ((long)bh * Tn + i) * Tn;
    const float* qpe = QPE + ((long)bh * Tn + i) * MAXP;
    const int blockend = ((i >> 7) + 1) << 7;

    __shared__ float qpes[64];
    __shared__ float wred[8];
    __shared__ float wred2[8];

    const int tid = threadIdx.x, lane = tid & 31, wid = tid >> 5;
    if (tid < 64) qpes[tid] = qpe[tid];

    const int j0 = tid << 2;
    float qk[4] = {0.f, 0.f, 0.f, 0.f};
    if (j0 <= i) {
        float4 s4 = *(const float4*)(row + j0);
        qk[0] = s4.x; qk[1] = s4.y; qk[2] = s4.z; qk[3] = s4.w;
    }

    float lpre[4];
    float run = 0.f;
#pragma unroll
    for (int q = 0; q < 4; q++) {
        float gg = 0.f;
        if (j0 + q <= i)
            gg = __fdividef(1.f, 1.f + __expf(-0.125f * qk[q]));
        run += gg;
        lpre[q] = run;
    }

    float v = run;
#pragma unroll
    for (int o = 1; o < 32; o <<= 1) {
        float t = __shfl_up_sync(0xffffffffu, v, o);
        if (lane >= o) v += t;
    }
    if (lane == 31) wred[wid] = v;
    __syncthreads();
    if (tid < 8) {
        float w = wred[tid];
#pragma unroll
        for (int o = 1; o < 8; o <<= 1) {
            float t = __shfl_up_sync(0x000000ffu, w, o);
            if (tid >= o) w += t;
        }
        wred[tid] = w;
    }
    __syncthreads();
    const float base  = (v - run) + (wid ? wred[wid - 1] : 0.f);
    const float total = wred[7];

    float sc[4];
    float mx = -INFINITY;
#pragma unroll
    for (int q = 0; q < 4; q++) {
        float s_ = -INFINITY;
        if (j0 + q <= i) {
            float pos = total - (base + lpre[q]);
            pos = fminf(fmaxf(pos, 0.f), 63.f);
            float pf = floorf(pos);
            int fi = (int)pf;
            float al = pos - pf;
            int ci = (fi < 63) ? fi + 1 : 63;
            float qf = qpes[fi], qc = qpes[ci];
            float qv = qf + al * (qc - qf);
            s_ = 0.125f * (qk[q] + qv);
        }
        sc[q] = s_;
        mx = fmaxf(mx, s_);
    }
#pragma unroll
    for (int o = 16; o; o >>= 1) mx = fmaxf(mx, __shfl_xor_sync(0xffffffffu, mx, o));
    if (lane == 0) wred2[wid] = mx;
    __syncthreads();
    float bmax = wred2[0];
#pragma unroll
    for (int k = 1; k < 8; k++) bmax = fmaxf(bmax, wred2[k]);

    float p[4];
    float ssum = 0.f;
#pragma unroll
    for (int q = 0; q < 4; q++) {
        float e = (j0 + q <= i) ? __expf(sc[q] - bmax) : 0.f;
        p[q] = e;
        ssum += e;
    }
#pragma unroll
    for (int o = 16; o; o >>= 1) ssum += __shfl_xor_sync(0xffffffffu, ssum, o);
    __syncthreads();
    if (lane == 0) wred2[wid] = ssum;
    __syncthreads();
    float tot = 0.f;
#pragma unroll
    for (int k = 0; k < 8; k++) tot += wred2[k];
    const float inv = __fdividef(1.f, tot);

    if (j0 < blockend) {
        float v0 = p[0] * inv, v1 = p[1] * inv, v2 = p[2] * inv, v3 = p[3] * inv;
        __nv_bfloat16 h0 = __float2bfloat16(v0), h1 = __float2bfloat16(v1);
        __nv_bfloat16 h2 = __float2bfloat16(v2), h3 = __float2bfloat16(v3);
        __nv_bfloat162 H0; H0.x = h0; H0.y = h1;
        __nv_bfloat162 H1; H1.x = h2; H1.y = h3;
        __nv_bfloat162 L0, L1;
        L0.x = __float2bfloat16(v0 - __bfloat162float(h0));
        L0.y = __float2bfloat16(v1 - __bfloat162float(h1));
        L1.x = __float2bfloat16(v2 - __bfloat162float(h2));
        L1.y = __float2bfloat16(v3 - __bfloat162float(h3));
        *(__nv_bfloat162*)(Ph + prow + j0)     = H0;
        *(__nv_bfloat162*)(Ph + prow + j0 + 2) = H1;
        *(__nv_bfloat162*)(Pl + prow + j0)     = L0;
        *(__nv_bfloat162*)(Pl + prow + j0 + 2) = L1;
    }
}

// ---------------- launcher ----------------
extern "C" void kernel_launch(void* const* d_in, const int* in_sizes, int n_in,
                              void* d_out, int out_size)
{
    (void)in_sizes; (void)n_in; (void)out_size;
    const float* x  = (const float*)d_in[0];
    const float* Wq = (const float*)d_in[1];
    const float* bq = (const float*)d_in[2];
    const float* Wk = (const float*)d_in[3];
    const float* bk = (const float*)d_in[4];
    const float* Wv = (const float*)d_in[5];
    const float* bv = (const float*)d_in[6];
    const float* Wo = (const float*)d_in[7];
    const float* bo = (const float*)d_in[8];
    const float* pe = (const float*)d_in[9];
    float* out = (float*)d_out;

    float *QPEd, *Sd;
    __half *xh, *Wqh, *Wkh, *Wvh, *Woh, *AOh, *AOl;
    __nv_bfloat16 *Qh, *Ql, *Kh, *Kl, *Phd, *Pld, *Vth, *Vtl;
    cudaGetSymbolAddress((void**)&QPEd, g_QPE);
    cudaGetSymbolAddress((void**)&Sd, g_S);
    cudaGetSymbolAddress((void**)&xh, g_xh);
    cudaGetSymbolAddress((void**)&Wqh, g_Wqh); cudaGetSymbolAddress((void**)&Wkh, g_Wkh);
    cudaGetSymbolAddress((void**)&Wvh, g_Wvh); cudaGetSymbolAddress((void**)&Woh, g_Woh);
    cudaGetSymbolAddress((void**)&Qh, g_Qh);   cudaGetSymbolAddress((void**)&Ql, g_Ql);
    cudaGetSymbolAddress((void**)&Kh, g_Kh);   cudaGetSymbolAddress((void**)&Kl, g_Kl);
    cudaGetSymbolAddress((void**)&AOh, g_AOh); cudaGetSymbolAddress((void**)&AOl, g_AOl);
    cudaGetSymbolAddress((void**)&Phd, g_Ph);  cudaGetSymbolAddress((void**)&Pld, g_Pl);
    cudaGetSymbolAddress((void**)&Vth, g_Vth); cudaGetSymbolAddress((void**)&Vtl, g_Vtl);

    static int smem_set = 0;
    if (!smem_set) {
        cudaFuncSetAttribute(mm2_hmma, cudaFuncAttributeMaxDynamicSharedMemorySize, MM2_SMEM);
        cudaFuncSetAttribute(qkv_hmma, cudaFuncAttributeMaxDynamicSharedMemorySize, QKV_SMEM);
        cudaFuncSetAttribute(pv_hmma, cudaFuncAttributeMaxDynamicSharedMemorySize, PV_SMEM);
        cudaFuncSetAttribute(qk_hmma, cudaFuncAttributeMaxDynamicSharedMemorySize, QK_SMEM);
        smem_set = 1;
    }

    dim3 blk(256);

    cvtx_h<<<2048, blk>>>(x, xh, Bsz * Tn * Dm);
    splitW4h<<<dim3(1024, 1, 4), blk>>>(Wq, Wk, Wv, Wo, Wqh, Wkh, Wvh, Woh);

    qkv_hmma<<<dim3(8, 16, 3), blk, QKV_SMEM>>>(xh, Wqh, Wkh, Wvh,
                                                bq, bk, bv, Qh, Ql, Kh, Kl, Vth, Vtl);

    qk_hmma<<<dim3(8, 8, 32), blk, QK_SMEM>>>(Qh, Ql, Kh, Kl, Sd);

    qpe_kernel<<<dim3(16, 32), blk>>>(pe, Qh, Ql, QPEd);

    cope_kernel<<<dim3(1024, 32), blk>>>(Sd, QPEd, Phd, Pld);

    pv_hmma<<<dim3(8, 32), blk, PV_SMEM>>>(Phd, Pld, Vth, Vtl, AOh, AOl);

    mm2_hmma<<<dim3(8, 16, 1), blk, MM2_SMEM>>>(AOh, AOl, Woh, bo, out, 1024, 1024);
}

// round 16
// speedup vs baseline: 1.6450x; 1.0877x over previous
#include <cuda_runtime.h>
#include <cuda_fp16.h>
#include <math.h>
#include <stdint.h>

#define Bsz 2
#define Tn  1024
#define Dm  1024
#define Hn  16
#define DHn 64
#define BHn (Bsz*Hn)
#define MAXP 64

// ---------------- scratch ----------------
__device__ float g_QPE[BHn*Tn*MAXP];
__device__ float g_S[(long)BHn*Tn*Tn];
__device__ __half g_Ph[(long)BHn*Tn*Tn], g_Pl[(long)BHn*Tn*Tn];  // probs hi/lo fp16
__device__ __half g_Vth[BHn*DHn*Tn];                             // V^T fp16 (hi only)
__device__ __half g_xh[Bsz*Tn*Dm];                               // fp16 activation
__device__ __half g_Wqh[Dm*Dm], g_Wkh[Dm*Dm], g_Wvh[Dm*Dm], g_Woh[Dm*Dm];
__device__ __half g_Qh[BHn*Tn*DHn], g_Ql[BHn*Tn*DHn];            // Q hi/lo fp16
__device__ __half g_Kh[BHn*Tn*DHn];                              // K fp16 (hi only)
__device__ __half g_AOh[Bsz*Tn*Dm], g_AOl[Bsz*Tn*Dm];

// ---------------- helpers ----------------
__device__ __forceinline__ uint32_t smem_u32(const void* p) {
    uint32_t a;
    asm("{ .reg .u64 t; cvta.to.shared.u64 t, %1; cvt.u32.u64 %0, t; }" : "=r"(a) : "l"(p));
    return a;
}
__device__ __forceinline__ void cpa16(uint32_t dst, const void* src) {
    asm volatile("cp.async.cg.shared.global [%0], [%1], 16;" :: "r"(dst), "l"(src));
}
#define CPA_COMMIT() asm volatile("cp.async.commit_group;" ::: "memory")
#define CPA_WAIT1()  asm volatile("cp.async.wait_group 1;" ::: "memory")
#define CPA_WAIT0()  asm volatile("cp.async.wait_group 0;" ::: "memory")

#define LDSM4(r, a) \
    asm volatile("ldmatrix.sync.aligned.m8n8.x4.shared.b16 {%0,%1,%2,%3}, [%4];" \
        : "=r"((r)[0]), "=r"((r)[1]), "=r"((r)[2]), "=r"((r)[3]) : "r"(a))

#define MMA_F16(c, a, b0v, b1v) \
    asm volatile("mma.sync.aligned.m16n8k16.row.col.f32.f16.f16.f32 " \
        "{%0,%1,%2,%3},{%4,%5,%6,%7},{%8,%9},{%0,%1,%2,%3};" \
        : "+f"((c)[0]), "+f"((c)[1]), "+f"((c)[2]), "+f"((c)[3]) \
        : "r"((a)[0]), "r"((a)[1]), "r"((a)[2]), "r"((a)[3]), "r"(b0v), "r"(b1v))

// ---------------- conversions ----------------
__global__ __launch_bounds__(256) void cvtx_h(const float* __restrict__ s,
                                              __half* __restrict__ h, int n)
{
    int i = (blockIdx.x * 256 + threadIdx.x) * 4;
    if (i >= n) return;
    float4 v = *(const float4*)(s + i);
    __half2 H0, H1;
    H0.x = __float2half(v.x); H0.y = __float2half(v.y);
    H1.x = __float2half(v.z); H1.y = __float2half(v.w);
    *(__half2*)(h + i)     = H0;
    *(__half2*)(h + i + 2) = H1;
}

__global__ __launch_bounds__(256) void splitW4h(
    const float* __restrict__ Wq, const float* __restrict__ Wk,
    const float* __restrict__ Wv, const float* __restrict__ Wo,
    __half* __restrict__ Wqh, __half* __restrict__ Wkh,
    __half* __restrict__ Wvh, __half* __restrict__ Woh)
{
    const int z = blockIdx.z;
    const float* s = (z == 0) ? Wq : (z == 1) ? Wk : (z == 2) ? Wv : Wo;
    __half* h = (z == 0) ? Wqh : (z == 1) ? Wkh : (z == 2) ? Wvh : Woh;
    int i = (blockIdx.x * 256 + threadIdx.x) * 4;
    float4 v = *(const float4*)(s + i);
    __half2 H0, H1;
    H0.x = __float2half(v.x); H0.y = __float2half(v.y);
    H1.x = __float2half(v.z); H1.y = __float2half(v.w);
    *(__half2*)(h + i)     = H0;
    *(__half2*)(h + i + 2) = H1;
}

// ---------------- common tile params ----------------
#define PITCH 80
#define AMAT  (128*PITCH)
#define B128M (128*PITCH)

// ========== fp16 2-pass engine (out-proj): C = (Ah+Al)·Bh^T ==========
#define STG2  (2*AMAT + B128M)      // 30720
#define MM2_SMEM (2*STG2)

__global__ __launch_bounds__(256, 2) void mm2_hmma(
    const __half* __restrict__ Ahi, const __half* __restrict__ Alo,
    const __half* __restrict__ Bhh,
    const float* __restrict__ bias, float* __restrict__ Cf, int N, int K)
{
    extern __shared__ char dsm[];
    const uint32_t sbase = smem_u32(dsm);

    const int tid  = threadIdx.x;
    const int wid  = tid >> 5;
    const int lane = tid & 31;
    const int wm   = wid & 3;
    const int wn   = wid >> 2;
    const int bm   = blockIdx.y * 128;
    const int bn   = blockIdx.x * 128;

    const __half* Ah = Ahi + (long)bm * K;
    const __half* Al = Alo + (long)bm * K;
    const __half* Bh = Bhh + (long)bn * K;

    float acc[2][8][4];
#pragma unroll
    for (int i = 0; i < 2; i++)
#pragma unroll
        for (int j = 0; j < 8; j++)
#pragma unroll
            for (int c = 0; c < 4; c++) acc[i][j][c] = 0.f;

    const int KS = K >> 5;

    auto load_stage = [&](int slot, int ks) {
        const uint32_t base = sbase + slot * STG2;
        const int k0 = ks * 32;
#pragma unroll
        for (int c = tid; c < 512; c += 256) {
            const int r = c >> 2, seg = c & 3;
            const uint32_t d = base + r * PITCH + seg * 16;
            const long off = (long)r * K + k0 + seg * 8;
            cpa16(d,        Ah + off);
            cpa16(d + AMAT, Al + off);
        }
#pragma unroll
        for (int c = tid; c < 512; c += 256) {
            const int r = c >> 2, seg = c & 3;
            const uint32_t d = base + 2*AMAT + r * PITCH + seg * 16;
            const long off = (long)r * K + k0 + seg * 8;
            cpa16(d, Bh + off);
        }
        CPA_COMMIT();
    };

    load_stage(0, 0);

    const uint32_t a_row = (uint32_t)(wm * 32 + (lane & 15)) * PITCH;
    const uint32_t b_row = (uint32_t)(wn * 64 + (lane & 15)) * PITCH;
    const uint32_t lcol  = (uint32_t)((lane >> 4) * 16);

    for (int k = 0; k < KS; k++) {
        if (k + 1 < KS) load_stage((k + 1) & 1, k + 1);
        if (k + 1 < KS) { CPA_WAIT1(); } else { CPA_WAIT0(); }
        __syncthreads();
        const uint32_t st = sbase + (k & 1) * STG2;
#pragma unroll
        for (int kc = 0; kc < 2; kc++) {
            const uint32_t col = kc * 32 + lcol;
            uint32_t ah[2][4], al[2][4], bh[4][4];
#pragma unroll
            for (int mt = 0; mt < 2; mt++) {
                const uint32_t ad = st + a_row + (uint32_t)(mt * 16 * PITCH) + col;
                LDSM4(ah[mt], ad);
                LDSM4(al[mt], ad + AMAT);
            }
#pragma unroll
            for (int np = 0; np < 4; np++) {
                const uint32_t bd = st + 2*AMAT + b_row + (uint32_t)(np * 16 * PITCH) + col;
                LDSM4(bh[np], bd);
            }
#pragma unroll
            for (int mt = 0; mt < 2; mt++)
#pragma unroll
                for (int nt = 0; nt < 8; nt++) {
                    const int np = nt >> 1, i = nt & 1;
                    MMA_F16(acc[mt][nt], ah[mt], bh[np][i], bh[np][i + 2]);
                    MMA_F16(acc[mt][nt], al[mt], bh[np][i], bh[np][i + 2]);
                }
        }
        __syncthreads();
    }

#pragma unroll
    for (int mt = 0; mt < 2; mt++)
#pragma unroll
        for (int nt = 0; nt < 8; nt++) {
            const int m0 = bm + wm * 32 + mt * 16 + (lane >> 2);
            const int n0 = bn + wn * 64 + nt * 8 + (lane & 3) * 2;
            const float b0 = bias[n0], b1 = bias[n0 + 1];
#pragma unroll
            for (int half = 0; half < 2; half++) {
                const int m = m0 + half * 8;
                float* cp = Cf + (long)m * N + n0;
                cp[0] = acc[mt][nt][half * 2 + 0] + b0;
                cp[1] = acc[mt][nt][half * 2 + 1] + b1;
            }
        }
}

// ---------------- merged QKV projection: fp16 1-pass, scatter epilogue --------
#define STG1  (AMAT + B128M)         // 20480
#define VTP 272
#define QKV_SMEM (2*STG1)            // 40960 (epilogue hi-only buffer = 34816 fits)

__global__ __launch_bounds__(256, 2) void qkv_hmma(
    const __half* __restrict__ xh,
    const __half* __restrict__ Wqh, const __half* __restrict__ Wkh,
    const __half* __restrict__ Wvh,
    const float* __restrict__ bq, const float* __restrict__ bk, const float* __restrict__ bv,
    __half* __restrict__ Qh, __half* __restrict__ Ql,
    __half* __restrict__ Kh, __half* __restrict__ Vth)
{
    extern __shared__ char dsm[];
    const uint32_t sbase = smem_u32(dsm);

    const int tid  = threadIdx.x;
    const int wid  = tid >> 5;
    const int lane = tid & 31;
    const int wm   = wid & 3;
    const int wn   = wid >> 2;
    const int z    = blockIdx.z;
    const int bm   = blockIdx.y * 128;
    const int bn   = blockIdx.x * 128;
    const int K    = 1024;

    const __half* Bh_ = (z == 0) ? Wqh : (z == 1) ? Wkh : Wvh;
    const float* bias = (z == 0) ? bq : (z == 1) ? bk : bv;

    const __half* Ah = xh + (long)bm * K;
    const __half* Bh = Bh_ + (long)bn * K;

    float acc[2][8][4];
#pragma unroll
    for (int i = 0; i < 2; i++)
#pragma unroll
        for (int j = 0; j < 8; j++)
#pragma unroll
            for (int c = 0; c < 4; c++) acc[i][j][c] = 0.f;

    const int KS = K >> 5;

    auto load_stage = [&](int slot, int ks) {
        const uint32_t base = sbase + slot * STG1;
        const int k0 = ks * 32;
#pragma unroll
        for (int c = tid; c < 512; c += 256) {
            const int r = c >> 2, seg = c & 3;
            const uint32_t d = base + r * PITCH + seg * 16;
            const long off = (long)r * K + k0 + seg * 8;
            cpa16(d, Ah + off);
        }
#pragma unroll
        for (int c = tid; c < 512; c += 256) {
            const int r = c >> 2, seg = c & 3;
            const uint32_t d = base + AMAT + r * PITCH + seg * 16;
            const long off = (long)r * K + k0 + seg * 8;
            cpa16(d, Bh + off);
        }
        CPA_COMMIT();
    };

    load_stage(0, 0);

    const uint32_t a_row = (uint32_t)(wm * 32 + (lane & 15)) * PITCH;
    const uint32_t b_row = (uint32_t)(wn * 64 + (lane & 15)) * PITCH;
    const uint32_t lcol  = (uint32_t)((lane >> 4) * 16);

    for (int k = 0; k < KS; k++) {
        if (k + 1 < KS) load_stage((k + 1) & 1, k + 1);
        if (k + 1 < KS) { CPA_WAIT1(); } else { CPA_WAIT0(); }
        __syncthreads();
        const uint32_t st = sbase + (k & 1) * STG1;
#pragma unroll
        for (int kc = 0; kc < 2; kc++) {
            const uint32_t col = kc * 32 + lcol;
            uint32_t ah[2][4], bh[4][4];
#pragma unroll
            for (int mt = 0; mt < 2; mt++) {
                const uint32_t ad = st + a_row + (uint32_t)(mt * 16 * PITCH) + col;
                LDSM4(ah[mt], ad);
            }
#pragma unroll
            for (int np = 0; np < 4; np++) {
                const uint32_t bd = st + AMAT + b_row + (uint32_t)(np * 16 * PITCH) + col;
                LDSM4(bh[np], bd);
            }
#pragma unroll
            for (int mt = 0; mt < 2; mt++)
#pragma unroll
                for (int nt = 0; nt < 8; nt++) {
                    const int np = nt >> 1, i = nt & 1;
                    MMA_F16(acc[mt][nt], ah[mt], bh[np][i], bh[np][i + 2]);
                }
        }
        __syncthreads();
    }

    const int b = bm >> 10, t0 = bm & 1023;

    if (z == 2) {
        // stage transposed 128dh x 128t fp16 tile (hi only), coalesced writes
#pragma unroll
        for (int mt = 0; mt < 2; mt++)
#pragma unroll
            for (int nt = 0; nt < 8; nt++) {
                const int dh = wn * 64 + nt * 8 + (lane & 3) * 2;
                const float b0 = bias[bn + dh], b1 = bias[bn + dh + 1];
#pragma unroll
                for (int half = 0; half < 2; half++) {
                    const int tl = wm * 32 + mt * 16 + (lane >> 2) + half * 8;
                    const float v0 = acc[mt][nt][half * 2 + 0] + b0;
                    const float v1 = acc[mt][nt][half * 2 + 1] + b1;
                    *(__half*)(dsm + dh * VTP + tl * 2)       = __float2half(v0);
                    *(__half*)(dsm + (dh + 1) * VTP + tl * 2) = __float2half(v1);
                }
            }
        __syncthreads();
        {
            const int dh = tid >> 1, seg = tid & 1;
            const int h = (bn >> 6) + (dh >> 6);
            const long gb = (((long)(b * Hn + h) * DHn + (dh & 63)) * Tn) + t0 + seg * 64;
            const char* srh = dsm + dh * VTP + seg * 128;
#pragma unroll
            for (int i = 0; i < 8; i++)
                *(float4*)(Vth + gb + i * 8) = *(const float4*)(srh + i * 16);
        }
        return;
    }

#pragma unroll
    for (int mt = 0; mt < 2; mt++)
#pragma unroll
        for (int nt = 0; nt < 8; nt++) {
            const int m0 = bm + wm * 32 + mt * 16 + (lane >> 2);
            const int n0 = bn + wn * 64 + nt * 8 + (lane & 3) * 2;
            const float b0 = bias[n0], b1 = bias[n0 + 1];
            const int h = n0 >> 6, dh0 = n0 & 63;
#pragma unroll
            for (int half = 0; half < 2; half++) {
                const int m = m0 + half * 8;
                const float v0 = acc[mt][nt][half * 2 + 0] + b0;
                const float v1 = acc[mt][nt][half * 2 + 1] + b1;
                const int bb = m >> 10, t = m & 1023;
                const long base = (((long)(bb * Hn + h) * Tn + t) * DHn) + dh0;
                __half hh0 = __float2half(v0);
                __half hh1 = __float2half(v1);
                if (z == 0) {
                    Qh[base] = hh0; Qh[base + 1] = hh1;
                    Ql[base]     = __float2half(v0 - __half2float(hh0));
                    Ql[base + 1] = __float2half(v1 - __half2float(hh1));
                } else {
                    Kh[base] = hh0; Kh[base + 1] = hh1;
                }
            }
        }
}

// ---------------- QK: fp16 2-pass (Q hi/lo, K hi), K=64 single-stage, causal ----
#define QPITCH 144
#define QMAT  (128*QPITCH)
#define QK_SMEM (3*QMAT)     // 55296: [Qh][Ql][Kh]

__global__ __launch_bounds__(256, 2) void qk_hmma(
    const __half* __restrict__ Qh, const __half* __restrict__ Ql,
    const __half* __restrict__ Kh,
    float* __restrict__ S)
{
    if ((int)blockIdx.x > (int)blockIdx.y) return;

    extern __shared__ char dsm[];
    const uint32_t sbase = smem_u32(dsm);

    const int tid  = threadIdx.x;
    const int wid  = tid >> 5;
    const int lane = tid & 31;
    const int wm   = wid & 3;
    const int wn   = wid >> 2;
    const int z    = blockIdx.z;
    const int bm   = blockIdx.y * 128;
    const int bn   = blockIdx.x * 128;

    const __half* Ah = Qh + (long)z * Tn * DHn + (long)bm * DHn;
    const __half* Al = Ql + (long)z * Tn * DHn + (long)bm * DHn;
    const __half* Bh = Kh + (long)z * Tn * DHn + (long)bn * DHn;

#pragma unroll
    for (int c = tid; c < 1024; c += 256) {
        const int r = c >> 3, seg = c & 7;
        const uint32_t d = sbase + r * QPITCH + seg * 16;
        const long off = (long)r * DHn + seg * 8;
        cpa16(d,        Ah + off);
        cpa16(d + QMAT, Al + off);
    }
#pragma unroll
    for (int c = tid; c < 1024; c += 256) {
        const int r = c >> 3, seg = c & 7;
        const uint32_t d = sbase + 2*QMAT + r * QPITCH + seg * 16;
        const long off = (long)r * DHn + seg * 8;
        cpa16(d, Bh + off);
    }
    CPA_COMMIT();
    CPA_WAIT0();
    __syncthreads();

    float acc[2][8][4];
#pragma unroll
    for (int i = 0; i < 2; i++)
#pragma unroll
        for (int j = 0; j < 8; j++)
#pragma unroll
            for (int c = 0; c < 4; c++) acc[i][j][c] = 0.f;

    const uint32_t a_row = (uint32_t)(wm * 32 + (lane & 15)) * QPITCH;
    const uint32_t b_row = (uint32_t)(wn * 64 + (lane & 15)) * QPITCH;
    const uint32_t lcol  = (uint32_t)((lane >> 4) * 16);

#pragma unroll
    for (int kc = 0; kc < 4; kc++) {
        const uint32_t col = kc * 32 + lcol;
        uint32_t ah[2][4], al[2][4], bh[4][4];
#pragma unroll
        for (int mt = 0; mt < 2; mt++) {
            const uint32_t ad = sbase + a_row + (uint32_t)(mt * 16 * QPITCH) + col;
            LDSM4(ah[mt], ad);
            LDSM4(al[mt], ad + QMAT);
        }
#pragma unroll
        for (int np = 0; np < 4; np++) {
            const uint32_t bd = sbase + 2*QMAT + b_row + (uint32_t)(np * 16 * QPITCH) + col;
            LDSM4(bh[np], bd);
        }
#pragma unroll
        for (int mt = 0; mt < 2; mt++)
#pragma unroll
            for (int nt = 0; nt < 8; nt++) {
                const int np = nt >> 1, i = nt & 1;
                MMA_F16(acc[mt][nt], ah[mt], bh[np][i], bh[np][i + 2]);
                MMA_F16(acc[mt][nt], al[mt], bh[np][i], bh[np][i + 2]);
            }
    }

#pragma unroll
    for (int mt = 0; mt < 2; mt++)
#pragma unroll
        for (int nt = 0; nt < 8; nt++) {
            const int m0 = bm + wm * 32 + mt * 16 + (lane >> 2);
            const int n0 = bn + wn * 64 + nt * 8 + (lane & 3) * 2;
#pragma unroll
            for (int half = 0; half < 2; half++) {
                const int m = m0 + half * 8;
                float* cp = S + (long)z * Tn * Tn + (long)m * Tn + n0;
                cp[0] = acc[mt][nt][half * 2 + 0];
                cp[1] = acc[mt][nt][half * 2 + 1];
            }
        }
}

// ========== pv: fp16 2-pass (P hi/lo, V hi), 128x64, NS=2, 3 CTA/SM ==========
#define B64M  (64*PITCH)
#define STG64 (2*AMAT + B64M)     // 25600: [Ph][Pl][Vh]
#define PV_SMEM (2*STG64)         // 51200

__global__ __launch_bounds__(256, 3) void pv_hmma(
    const __half* __restrict__ Ph, const __half* __restrict__ Pl,
    const __half* __restrict__ Vth,
    __half* __restrict__ AOh, __half* __restrict__ AOl)
{
    extern __shared__ char dsm[];
    const uint32_t sbase = smem_u32(dsm);

    const int tid  = threadIdx.x;
    const int wid  = tid >> 5;
    const int lane = tid & 31;
    const int wm   = wid & 3;
    const int wn   = wid >> 2;
    const int it   = blockIdx.x;
    const int bh   = blockIdx.y;
    const int b    = bh >> 4, h = bh & 15;

    const __half* Ah = Ph + ((long)bh * Tn + it * 128) * Tn;
    const __half* Al = Pl + ((long)bh * Tn + it * 128) * Tn;
    const __half* Bh = Vth + (long)bh * DHn * Tn;

    float acc[2][4][4];
#pragma unroll
    for (int i = 0; i < 2; i++)
#pragma unroll
        for (int j = 0; j < 4; j++)
#pragma unroll
            for (int c = 0; c < 4; c++) acc[i][j][c] = 0.f;

    const int KS = 4 * (it + 1);

    auto load_stage = [&](int slot, int ks) {
        const uint32_t base = sbase + slot * STG64;
        const int k0 = ks * 32;
#pragma unroll
        for (int c = tid; c < 512; c += 256) {
            const int r = c >> 2, seg = c & 3;
            const uint32_t d = base + r * PITCH + seg * 16;
            const long off = (long)r * Tn + k0 + seg * 8;
            cpa16(d,        Ah + off);
            cpa16(d + AMAT, Al + off);
        }
        {
            const int r = tid >> 2, seg = tid & 3;
            const uint32_t d = base + 2*AMAT + r * PITCH + seg * 16;
            const long off = (long)r * Tn + k0 + seg * 8;
            cpa16(d, Bh + off);
        }
        CPA_COMMIT();
    };

    load_stage(0, 0);

    const uint32_t a_row = (uint32_t)(wm * 32 + (lane & 15)) * PITCH;
    const uint32_t b_row = (uint32_t)(wn * 32 + (lane & 15)) * PITCH;
    const uint32_t lcol  = (uint32_t)((lane >> 4) * 16);

    for (int k = 0; k < KS; k++) {
        if (k + 1 < KS) load_stage((k + 1) & 1, k + 1);
        if (k + 1 < KS) { CPA_WAIT1(); } else { CPA_WAIT0(); }
        __syncthreads();
        const uint32_t st = sbase + (k & 1) * STG64;
#pragma unroll
        for (int kc = 0; kc < 2; kc++) {
            const uint32_t col = kc * 32 + lcol;
            uint32_t ah[2][4], al[2][4], bh2[2][4];
#pragma unroll
            for (int mt = 0; mt < 2; mt++) {
                const uint32_t ad = st + a_row + (uint32_t)(mt * 16 * PITCH) + col;
                LDSM4(ah[mt], ad);
                LDSM4(al[mt], ad + AMAT);
            }
#pragma unroll
            for (int np = 0; np < 2; np++) {
                const uint32_t bd = st + 2*AMAT + b_row + (uint32_t)(np * 16 * PITCH) + col;
                LDSM4(bh2[np], bd);
            }
#pragma unroll
            for (int mt = 0; mt < 2; mt++)
#pragma unroll
                for (int nt = 0; nt < 4; nt++) {
                    const int np = nt >> 1, i = nt & 1;
                    MMA_F16(acc[mt][nt], ah[mt], bh2[np][i], bh2[np][i + 2]);
                    MMA_F16(acc[mt][nt], al[mt], bh2[np][i], bh2[np][i + 2]);
                }
        }
        __syncthreads();
    }

#pragma unroll
    for (int mt = 0; mt < 2; mt++)
#pragma unroll
        for (int nt = 0; nt < 4; nt++) {
            const int t0 = it * 128 + wm * 32 + mt * 16 + (lane >> 2);
            const int dh = wn * 32 + nt * 8 + (lane & 3) * 2;
#pragma unroll
            for (int half = 0; half < 2; half++) {
                const int t = t0 + half * 8;
                const float v0 = acc[mt][nt][half * 2 + 0];
                const float v1 = acc[mt][nt][half * 2 + 1];
                const long base = ((long)b * Tn + t) * Dm + h * 64 + dh;
                __half h0 = __float2half(v0);
                __half h1 = __float2half(v1);
                __half2 H; H.x = h0; H.y = h1;
                __half2 L;
                L.x = __float2half(v0 - __half2float(h0));
                L.y = __float2half(v1 - __half2float(h1));
                *(__half2*)(AOh + base) = H;
                *(__half2*)(AOl + base) = L;
            }
        }
}

// ---------------- qpe table (Q reconstructed from fp16 hi/lo) ----------------
__global__ __launch_bounds__(256) void qpe_kernel(const float* __restrict__ PE,
                                                  const __half* __restrict__ Qh,
                                                  const __half* __restrict__ Ql,
                                                  float* __restrict__ QPE)
{
    const int it = blockIdx.x, bh = blockIdx.y, h = bh & (Hn - 1);
    const __half* Aqh = Qh + ((long)bh * Tn + it * 64) * DHn;
    const __half* Aql = Ql + ((long)bh * Tn + it * 64) * DHn;
    const float* Bp = PE + (long)h * MAXP * DHn;

    __shared__ float Qs[64][65];
    __shared__ float Ps[64][65];

    const int tid = threadIdx.x;
    const int rowb = tid >> 4, c4 = (tid & 15) << 2;
#pragma unroll
    for (int r = 0; r < 4; r++) {
        int row = rowb + r * 16;
        const long off = (long)row * DHn + c4;
        __half2 qh0 = *(const __half2*)(Aqh + off);
        __half2 qh1 = *(const __half2*)(Aqh + off + 2);
        __half2 ql0 = *(const __half2*)(Aql + off);
        __half2 ql1 = *(const __half2*)(Aql + off + 2);
        Qs[row][c4]     = __half2float(qh0.x) + __half2float(ql0.x);
        Qs[row][c4 + 1] = __half2float(qh0.y) + __half2float(ql0.y);
        Qs[row][c4 + 2] = __half2float(qh1.x) + __half2float(ql1.x);
        Qs[row][c4 + 3] = __half2float(qh1.y) + __half2float(ql1.y);
        float4 p4 = *(const float4*)(Bp + (long)row * DHn + c4);
        Ps[row][c4] = p4.x; Ps[row][c4 + 1] = p4.y;
        Ps[row][c4 + 2] = p4.z; Ps[row][c4 + 3] = p4.w;
    }
    __syncthreads();

    const int tx = tid & 15, ty = tid >> 4;
    float acc[4][4];
#pragma unroll
    for (int i = 0; i < 4; i++)
#pragma unroll
        for (int j = 0; j < 4; j++) acc[i][j] = 0.f;

#pragma unroll 16
    for (int kk = 0; kk < 64; kk++) {
        float a0 = Qs[ty * 4 + 0][kk], a1 = Qs[ty * 4 + 1][kk];
        float a2 = Qs[ty * 4 + 2][kk], a3 = Qs[ty * 4 + 3][kk];
        float b0 = Ps[tx * 4 + 0][kk], b1 = Ps[tx * 4 + 1][kk];
        float b2 = Ps[tx * 4 + 2][kk], b3 = Ps[tx * 4 + 3][kk];
        acc[0][0] = fmaf(a0, b0, acc[0][0]); acc[0][1] = fmaf(a0, b1, acc[0][1]);
        acc[0][2] = fmaf(a0, b2, acc[0][2]); acc[0][3] = fmaf(a0, b3, acc[0][3]);
        acc[1][0] = fmaf(a1, b0, acc[1][0]); acc[1][1] = fmaf(a1, b1, acc[1][1]);
        acc[1][2] = fmaf(a1, b2, acc[1][2]); acc[1][3] = fmaf(a1, b3, acc[1][3]);
        acc[2][0] = fmaf(a2, b0, acc[2][0]); acc[2][1] = fmaf(a2, b1, acc[2][1]);
        acc[2][2] = fmaf(a2, b2, acc[2][2]); acc[2][3] = fmaf(a2, b3, acc[2][3]);
        acc[3][0] = fmaf(a3, b0, acc[3][0]); acc[3][1] = fmaf(a3, b1, acc[3][1]);
        acc[3][2] = fmaf(a3, b2, acc[3][2]); acc[3][3] = fmaf(a3, b3, acc[3][3]);
    }

    float* out = QPE + ((long)bh * Tn + it * 64) * MAXP;
#pragma unroll
    for (int ii = 0; ii < 4; ii++) {
        float4 o4 = make_float4(acc[ii][0], acc[ii][1], acc[ii][2], acc[ii][3]);
        *(float4*)(out + (long)(ty * 4 + ii) * MAXP + tx * 4) = o4;
    }
}

// ---------------- CoPE (block-per-row; fp16 hi/lo prob output) ----------------
__global__ __launch_bounds__(256) void cope_kernel(const float* __restrict__ S,
                                                   const float* __restrict__ QPE,
                                                   __half* __restrict__ Ph,
                                                   __half* __restrict__ Pl)
{
    const int i = blockIdx.x, bh = blockIdx.y;
    const float* row = S + ((long)bh * Tn + i) * Tn;
    const long prow = ((long)bh * Tn + i) * Tn;
    const float* qpe = QPE + ((long)bh * Tn + i) * MAXP;
    const int blockend = ((i >> 7) + 1) << 7;

    __shared__ float qpes[64];
    __shared__ float wred[8];
    __shared__ float wred2[8];

    const int tid = threadIdx.x, lane = tid & 31, wid = tid >> 5;
    if (tid < 64) qpes[tid] = qpe[tid];

    const int j0 = tid << 2;
    float qk[4] = {0.f, 0.f, 0.f, 0.f};
    if (j0 <= i) {
        float4 s4 = *(const float4*)(row + j0);
        qk[0] = s4.x; qk[1] = s4.y; qk[2] = s4.z; qk[3] = s4.w;
    }

    float lpre[4];
    float run = 0.f;
#pragma unroll
    for (int q = 0; q < 4; q++) {
        float gg = 0.f;
        if (j0 + q <= i)
            gg = __fdividef(1.f, 1.f + __expf(-0.125f * qk[q]));
        run += gg;
        lpre[q] = run;
    }

    float v = run;
#pragma unroll
    for (int o = 1; o < 32; o <<= 1) {
        float t = __shfl_up_sync(0xffffffffu, v, o);
        if (lane >= o) v += t;
    }
    if (lane == 31) wred[wid] = v;
    __syncthreads();
    if (tid < 8) {
        float w = wred[tid];
#pragma unroll
        for (int o = 1; o < 8; o <<= 1) {
            float t = __shfl_up_sync(0x000000ffu, w, o);
            if (tid >= o) w += t;
        }
        wred[tid] = w;
    }
    __syncthreads();
    const float base  = (v - run) + (wid ? wred[wid - 1] : 0.f);
    const float total = wred[7];

    float sc[4];
    float mx = -INFINITY;
#pragma unroll
    for (int q = 0; q < 4; q++) {
        float s_ = -INFINITY;
        if (j0 + q <= i) {
            float pos = total - (base + lpre[q]);
            pos = fminf(fmaxf(pos, 0.f), 63.f);
            float pf = floorf(pos);
            int fi = (int)pf;
            float al = pos - pf;
            int ci = (fi < 63) ? fi + 1 : 63;
            float qf = qpes[fi], qc = qpes[ci];
            float qv = qf + al * (qc - qf);
            s_ = 0.125f * (qk[q] + qv);
        }
        sc[q] = s_;
        mx = fmaxf(mx, s_);
    }
#pragma unroll
    for (int o = 16; o; o >>= 1) mx = fmaxf(mx, __shfl_xor_sync(0xffffffffu, mx, o));
    if (lane == 0) wred2[wid] = mx;
    __syncthreads();
    float bmax = wred2[0];
#pragma unroll
    for (int k = 1; k < 8; k++) bmax = fmaxf(bmax, wred2[k]);

    float p[4];
    float ssum = 0.f;
#pragma unroll
    for (int q = 0; q < 4; q++) {
        float e = (j0 + q <= i) ? __expf(sc[q] - bmax) : 0.f;
        p[q] = e;
        ssum += e;
    }
#pragma unroll
    for (int o = 16; o; o >>= 1) ssum += __shfl_xor_sync(0xffffffffu, ssum, o);
    __syncthreads();
    if (lane == 0) wred2[wid] = ssum;
    __syncthreads();
    float tot = 0.f;
#pragma unroll
    for (int k = 0; k < 8; k++) tot += wred2[k];
    const float inv = __fdividef(1.f, tot);

    if (j0 < blockend) {
        float v0 = p[0] * inv, v1 = p[1] * inv, v2 = p[2] * inv, v3 = p[3] * inv;
        __half h0 = __float2half(v0), h1 = __float2half(v1);
        __half h2 = __float2half(v2), h3 = __float2half(v3);
        __half2 H0; H0.x = h0; H0.y = h1;
        __half2 H1; H1.x = h2; H1.y = h3;
        __half2 L0, L1;
        L0.x = __float2half(v0 - __half2float(h0));
        L0.y = __float2half(v1 - __half2float(h1));
        L1.x = __float2half(v2 - __half2float(h2));
        L1.y = __float2half(v3 - __half2float(h3));
        *(__half2*)(Ph + prow + j0)     = H0;
        *(__half2*)(Ph + prow + j0 + 2) = H1;
        *(__half2*)(Pl + prow + j0)     = L0;
        *(__half2*)(Pl + prow + j0 + 2) = L1;
    }
}

// ---------------- launcher ----------------
extern "C" void kernel_launch(void* const* d_in, const int* in_sizes, int n_in,
                              void* d_out, int out_size)
{
    (void)in_sizes; (void)n_in; (void)out_size;
    const float* x  = (const float*)d_in[0];
    const float* Wq = (const float*)d_in[1];
    const float* bq = (const float*)d_in[2];
    const float* Wk = (const float*)d_in[3];
    const float* bk = (const float*)d_in[4];
    const float* Wv = (const float*)d_in[5];
    const float* bv = (const float*)d_in[6];
    const float* Wo = (const float*)d_in[7];
    const float* bo = (const float*)d_in[8];
    const float* pe = (const float*)d_in[9];
    float* out = (float*)d_out;

    float *QPEd, *Sd;
    __half *xh, *Wqh, *Wkh, *Wvh, *Woh, *AOh, *AOl;
    __half *Qh, *Ql, *Kh, *Phd, *Pld, *Vth;
    cudaGetSymbolAddress((void**)&QPEd, g_QPE);
    cudaGetSymbolAddress((void**)&Sd, g_S);
    cudaGetSymbolAddress((void**)&xh, g_xh);
    cudaGetSymbolAddress((void**)&Wqh, g_Wqh); cudaGetSymbolAddress((void**)&Wkh, g_Wkh);
    cudaGetSymbolAddress((void**)&Wvh, g_Wvh); cudaGetSymbolAddress((void**)&Woh, g_Woh);
    cudaGetSymbolAddress((void**)&Qh, g_Qh);   cudaGetSymbolAddress((void**)&Ql, g_Ql);
    cudaGetSymbolAddress((void**)&Kh, g_Kh);
    cudaGetSymbolAddress((void**)&AOh, g_AOh); cudaGetSymbolAddress((void**)&AOl, g_AOl);
    cudaGetSymbolAddress((void**)&Phd, g_Ph);  cudaGetSymbolAddress((void**)&Pld, g_Pl);
    cudaGetSymbolAddress((void**)&Vth, g_Vth);

    static int smem_set = 0;
    if (!smem_set) {
        cudaFuncSetAttribute(mm2_hmma, cudaFuncAttributeMaxDynamicSharedMemorySize, MM2_SMEM);
        cudaFuncSetAttribute(qkv_hmma, cudaFuncAttributeMaxDynamicSharedMemorySize, QKV_SMEM);
        cudaFuncSetAttribute(pv_hmma, cudaFuncAttributeMaxDynamicSharedMemorySize, PV_SMEM);
        cudaFuncSetAttribute(qk_hmma, cudaFuncAttributeMaxDynamicSharedMemorySize, QK_SMEM);
        smem_set = 1;
    }

    dim3 blk(256);

    cvtx_h<<<2048, blk>>>(x, xh, Bsz * Tn * Dm);
    splitW4h<<<dim3(1024, 1, 4), blk>>>(Wq, Wk, Wv, Wo, Wqh, Wkh, Wvh, Woh);

    qkv_hmma<<<dim3(8, 16, 3), blk, QKV_SMEM>>>(xh, Wqh, Wkh, Wvh,
                                                bq, bk, bv, Qh, Ql, Kh, Vth);

    qk_hmma<<<dim3(8, 8, 32), blk, QK_SMEM>>>(Qh, Ql, Kh, Sd);

    qpe_kernel<<<dim3(16, 32), blk>>>(pe, Qh, Ql, QPEd);

    cope_kernel<<<dim3(1024, 32), blk>>>(Sd, QPEd, Phd, Pld);

    pv_hmma<<<dim3(8, 32), blk, PV_SMEM>>>(Phd, Pld, Vth, AOh, AOl);

    mm2_hmma<<<dim3(8, 16, 1), blk, MM2_SMEM>>>(AOh, AOl, Woh, bo, out, 1024, 1024);
}

// round 17
// speedup vs baseline: 1.8776x; 1.1414x over previous
#include <cuda_runtime.h>
#include <cuda_fp16.h>
#include <math.h>
#include <stdint.h>

#define Bsz 2
#define Tn  1024
#define Dm  1024
#define Hn  16
#define DHn 64
#define BHn (Bsz*Hn)
#define MAXP 64

// ---------------- scratch ----------------
__device__ float g_QPE[BHn*Tn*MAXP];
__device__ float g_S[(long)BHn*Tn*Tn];
__device__ __half g_Ph[(long)BHn*Tn*Tn];                         // probs fp16 (hi only)
__device__ __half g_Vth[BHn*DHn*Tn];                             // V^T fp16 (hi only)
__device__ __half g_xh[Bsz*Tn*Dm];                               // fp16 activation
__device__ __half g_Wqh[Dm*Dm], g_Wkh[Dm*Dm], g_Wvh[Dm*Dm], g_Woh[Dm*Dm];
__device__ __half g_Qh[BHn*Tn*DHn], g_Ql[BHn*Tn*DHn];            // Q hi/lo fp16
__device__ __half g_Kh[BHn*Tn*DHn];                              // K fp16 (hi only)
__device__ __half g_AOh[Bsz*Tn*Dm];                              // AO fp16 (hi only)

// ---------------- helpers ----------------
__device__ __forceinline__ uint32_t smem_u32(const void* p) {
    uint32_t a;
    asm("{ .reg .u64 t; cvta.to.shared.u64 t, %1; cvt.u32.u64 %0, t; }" : "=r"(a) : "l"(p));
    return a;
}
__device__ __forceinline__ void cpa16(uint32_t dst, const void* src) {
    asm volatile("cp.async.cg.shared.global [%0], [%1], 16;" :: "r"(dst), "l"(src));
}
#define CPA_COMMIT() asm volatile("cp.async.commit_group;" ::: "memory")
#define CPA_WAIT1()  asm volatile("cp.async.wait_group 1;" ::: "memory")
#define CPA_WAIT0()  asm volatile("cp.async.wait_group 0;" ::: "memory")

#define LDSM4(r, a) \
    asm volatile("ldmatrix.sync.aligned.m8n8.x4.shared.b16 {%0,%1,%2,%3}, [%4];" \
        : "=r"((r)[0]), "=r"((r)[1]), "=r"((r)[2]), "=r"((r)[3]) : "r"(a))

#define MMA_F16(c, a, b0v, b1v) \
    asm volatile("mma.sync.aligned.m16n8k16.row.col.f32.f16.f16.f32 " \
        "{%0,%1,%2,%3},{%4,%5,%6,%7},{%8,%9},{%0,%1,%2,%3};" \
        : "+f"((c)[0]), "+f"((c)[1]), "+f"((c)[2]), "+f"((c)[3]) \
        : "r"((a)[0]), "r"((a)[1]), "r"((a)[2]), "r"((a)[3]), "r"(b0v), "r"(b1v))

// ---------------- conversions ----------------
__global__ __launch_bounds__(256) void cvtx_h(const float* __restrict__ s,
                                              __half* __restrict__ h, int n)
{
    int i = (blockIdx.x * 256 + threadIdx.x) * 4;
    if (i >= n) return;
    float4 v = *(const float4*)(s + i);
    __half2 H0, H1;
    H0.x = __float2half(v.x); H0.y = __float2half(v.y);
    H1.x = __float2half(v.z); H1.y = __float2half(v.w);
    *(__half2*)(h + i)     = H0;
    *(__half2*)(h + i + 2) = H1;
}

__global__ __launch_bounds__(256) void splitW4h(
    const float* __restrict__ Wq, const float* __restrict__ Wk,
    const float* __restrict__ Wv, const float* __restrict__ Wo,
    __half* __restrict__ Wqh, __half* __restrict__ Wkh,
    __half* __restrict__ Wvh, __half* __restrict__ Woh)
{
    const int z = blockIdx.z;
    const float* s = (z == 0) ? Wq : (z == 1) ? Wk : (z == 2) ? Wv : Wo;
    __half* h = (z == 0) ? Wqh : (z == 1) ? Wkh : (z == 2) ? Wvh : Woh;
    int i = (blockIdx.x * 256 + threadIdx.x) * 4;
    float4 v = *(const float4*)(s + i);
    __half2 H0, H1;
    H0.x = __float2half(v.x); H0.y = __float2half(v.y);
    H1.x = __float2half(v.z); H1.y = __float2half(v.w);
    *(__half2*)(h + i)     = H0;
    *(__half2*)(h + i + 2) = H1;
}

// ---------------- common tile params ----------------
#define PITCH 80
#define AMAT  (128*PITCH)
#define B128M (128*PITCH)

// ========== fp16 1-pass engine (out-proj): out = AOh·Woh^T + bias ==========
#define STGO  (AMAT + B128M)        // 20480: [Ah][Bh]
#define MM1_SMEM (2*STGO)           // 40960

__global__ __launch_bounds__(256, 2) void mm1_hmma(
    const __half* __restrict__ Ahi, const __half* __restrict__ Bhh,
    const float* __restrict__ bias, float* __restrict__ Cf, int N, int K)
{
    extern __shared__ char dsm[];
    const uint32_t sbase = smem_u32(dsm);

    const int tid  = threadIdx.x;
    const int wid  = tid >> 5;
    const int lane = tid & 31;
    const int wm   = wid & 3;
    const int wn   = wid >> 2;
    const int bm   = blockIdx.y * 128;
    const int bn   = blockIdx.x * 128;

    const __half* Ah = Ahi + (long)bm * K;
    const __half* Bh = Bhh + (long)bn * K;

    float acc[2][8][4];
#pragma unroll
    for (int i = 0; i < 2; i++)
#pragma unroll
        for (int j = 0; j < 8; j++)
#pragma unroll
            for (int c = 0; c < 4; c++) acc[i][j][c] = 0.f;

    const int KS = K >> 5;

    auto load_stage = [&](int slot, int ks) {
        const uint32_t base = sbase + slot * STGO;
        const int k0 = ks * 32;
#pragma unroll
        for (int c = tid; c < 512; c += 256) {
            const int r = c >> 2, seg = c & 3;
            const uint32_t d = base + r * PITCH + seg * 16;
            const long off = (long)r * K + k0 + seg * 8;
            cpa16(d, Ah + off);
        }
#pragma unroll
        for (int c = tid; c < 512; c += 256) {
            const int r = c >> 2, seg = c & 3;
            const uint32_t d = base + AMAT + r * PITCH + seg * 16;
            const long off = (long)r * K + k0 + seg * 8;
            cpa16(d, Bh + off);
        }
        CPA_COMMIT();
    };

    load_stage(0, 0);

    const uint32_t a_row = (uint32_t)(wm * 32 + (lane & 15)) * PITCH;
    const uint32_t b_row = (uint32_t)(wn * 64 + (lane & 15)) * PITCH;
    const uint32_t lcol  = (uint32_t)((lane >> 4) * 16);

    for (int k = 0; k < KS; k++) {
        if (k + 1 < KS) load_stage((k + 1) & 1, k + 1);
        if (k + 1 < KS) { CPA_WAIT1(); } else { CPA_WAIT0(); }
        __syncthreads();
        const uint32_t st = sbase + (k & 1) * STGO;
#pragma unroll
        for (int kc = 0; kc < 2; kc++) {
            const uint32_t col = kc * 32 + lcol;
            uint32_t ah[2][4], bh[4][4];
#pragma unroll
            for (int mt = 0; mt < 2; mt++) {
                const uint32_t ad = st + a_row + (uint32_t)(mt * 16 * PITCH) + col;
                LDSM4(ah[mt], ad);
            }
#pragma unroll
            for (int np = 0; np < 4; np++) {
                const uint32_t bd = st + AMAT + b_row + (uint32_t)(np * 16 * PITCH) + col;
                LDSM4(bh[np], bd);
            }
#pragma unroll
            for (int mt = 0; mt < 2; mt++)
#pragma unroll
                for (int nt = 0; nt < 8; nt++) {
                    const int np = nt >> 1, i = nt & 1;
                    MMA_F16(acc[mt][nt], ah[mt], bh[np][i], bh[np][i + 2]);
                }
        }
        __syncthreads();
    }

#pragma unroll
    for (int mt = 0; mt < 2; mt++)
#pragma unroll
        for (int nt = 0; nt < 8; nt++) {
            const int m0 = bm + wm * 32 + mt * 16 + (lane >> 2);
            const int n0 = bn + wn * 64 + nt * 8 + (lane & 3) * 2;
            const float b0 = bias[n0], b1 = bias[n0 + 1];
#pragma unroll
            for (int half = 0; half < 2; half++) {
                const int m = m0 + half * 8;
                float* cp = Cf + (long)m * N + n0;
                cp[0] = acc[mt][nt][half * 2 + 0] + b0;
                cp[1] = acc[mt][nt][half * 2 + 1] + b1;
            }
        }
}

// ---------------- merged QKV projection: fp16 1-pass, scatter epilogue --------
#define STG1  (AMAT + B128M)         // 20480
#define VTP 272
#define QKV_SMEM (2*STG1)            // 40960 (epilogue hi-only buffer = 34816 fits)

__global__ __launch_bounds__(256, 2) void qkv_hmma(
    const __half* __restrict__ xh,
    const __half* __restrict__ Wqh, const __half* __restrict__ Wkh,
    const __half* __restrict__ Wvh,
    const float* __restrict__ bq, const float* __restrict__ bk, const float* __restrict__ bv,
    __half* __restrict__ Qh, __half* __restrict__ Ql,
    __half* __restrict__ Kh, __half* __restrict__ Vth)
{
    extern __shared__ char dsm[];
    const uint32_t sbase = smem_u32(dsm);

    const int tid  = threadIdx.x;
    const int wid  = tid >> 5;
    const int lane = tid & 31;
    const int wm   = wid & 3;
    const int wn   = wid >> 2;
    const int z    = blockIdx.z;
    const int bm   = blockIdx.y * 128;
    const int bn   = blockIdx.x * 128;
    const int K    = 1024;

    const __half* Bh_ = (z == 0) ? Wqh : (z == 1) ? Wkh : Wvh;
    const float* bias = (z == 0) ? bq : (z == 1) ? bk : bv;

    const __half* Ah = xh + (long)bm * K;
    const __half* Bh = Bh_ + (long)bn * K;

    float acc[2][8][4];
#pragma unroll
    for (int i = 0; i < 2; i++)
#pragma unroll
        for (int j = 0; j < 8; j++)
#pragma unroll
            for (int c = 0; c < 4; c++) acc[i][j][c] = 0.f;

    const int KS = K >> 5;

    auto load_stage = [&](int slot, int ks) {
        const uint32_t base = sbase + slot * STG1;
        const int k0 = ks * 32;
#pragma unroll
        for (int c = tid; c < 512; c += 256) {
            const int r = c >> 2, seg = c & 3;
            const uint32_t d = base + r * PITCH + seg * 16;
            const long off = (long)r * K + k0 + seg * 8;
            cpa16(d, Ah + off);
        }
#pragma unroll
        for (int c = tid; c < 512; c += 256) {
            const int r = c >> 2, seg = c & 3;
            const uint32_t d = base + AMAT + r * PITCH + seg * 16;
            const long off = (long)r * K + k0 + seg * 8;
            cpa16(d, Bh + off);
        }
        CPA_COMMIT();
    };

    load_stage(0, 0);

    const uint32_t a_row = (uint32_t)(wm * 32 + (lane & 15)) * PITCH;
    const uint32_t b_row = (uint32_t)(wn * 64 + (lane & 15)) * PITCH;
    const uint32_t lcol  = (uint32_t)((lane >> 4) * 16);

    for (int k = 0; k < KS; k++) {
        if (k + 1 < KS) load_stage((k + 1) & 1, k + 1);
        if (k + 1 < KS) { CPA_WAIT1(); } else { CPA_WAIT0(); }
        __syncthreads();
        const uint32_t st = sbase + (k & 1) * STG1;
#pragma unroll
        for (int kc = 0; kc < 2; kc++) {
            const uint32_t col = kc * 32 + lcol;
            uint32_t ah[2][4], bh[4][4];
#pragma unroll
            for (int mt = 0; mt < 2; mt++) {
                const uint32_t ad = st + a_row + (uint32_t)(mt * 16 * PITCH) + col;
                LDSM4(ah[mt], ad);
            }
#pragma unroll
            for (int np = 0; np < 4; np++) {
                const uint32_t bd = st + AMAT + b_row + (uint32_t)(np * 16 * PITCH) + col;
                LDSM4(bh[np], bd);
            }
#pragma unroll
            for (int mt = 0; mt < 2; mt++)
#pragma unroll
                for (int nt = 0; nt < 8; nt++) {
                    const int np = nt >> 1, i = nt & 1;
                    MMA_F16(acc[mt][nt], ah[mt], bh[np][i], bh[np][i + 2]);
                }
        }
        __syncthreads();
    }

    const int b = bm >> 10, t0 = bm & 1023;

    if (z == 2) {
        // stage transposed 128dh x 128t fp16 tile (hi only), coalesced writes
#pragma unroll
        for (int mt = 0; mt < 2; mt++)
#pragma unroll
            for (int nt = 0; nt < 8; nt++) {
                const int dh = wn * 64 + nt * 8 + (lane & 3) * 2;
                const float b0 = bias[bn + dh], b1 = bias[bn + dh + 1];
#pragma unroll
                for (int half = 0; half < 2; half++) {
                    const int tl = wm * 32 + mt * 16 + (lane >> 2) + half * 8;
                    const float v0 = acc[mt][nt][half * 2 + 0] + b0;
                    const float v1 = acc[mt][nt][half * 2 + 1] + b1;
                    *(__half*)(dsm + dh * VTP + tl * 2)       = __float2half(v0);
                    *(__half*)(dsm + (dh + 1) * VTP + tl * 2) = __float2half(v1);
                }
            }
        __syncthreads();
        {
            const int dh = tid >> 1, seg = tid & 1;
            const int h = (bn >> 6) + (dh >> 6);
            const long gb = (((long)(b * Hn + h) * DHn + (dh & 63)) * Tn) + t0 + seg * 64;
            const char* srh = dsm + dh * VTP + seg * 128;
#pragma unroll
            for (int i = 0; i < 8; i++)
                *(float4*)(Vth + gb + i * 8) = *(const float4*)(srh + i * 16);
        }
        return;
    }

#pragma unroll
    for (int mt = 0; mt < 2; mt++)
#pragma unroll
        for (int nt = 0; nt < 8; nt++) {
            const int m0 = bm + wm * 32 + mt * 16 + (lane >> 2);
            const int n0 = bn + wn * 64 + nt * 8 + (lane & 3) * 2;
            const float b0 = bias[n0], b1 = bias[n0 + 1];
            const int h = n0 >> 6, dh0 = n0 & 63;
#pragma unroll
            for (int half = 0; half < 2; half++) {
                const int m = m0 + half * 8;
                const float v0 = acc[mt][nt][half * 2 + 0] + b0;
                const float v1 = acc[mt][nt][half * 2 + 1] + b1;
                const int bb = m >> 10, t = m & 1023;
                const long base = (((long)(bb * Hn + h) * Tn + t) * DHn) + dh0;
                __half hh0 = __float2half(v0);
                __half hh1 = __float2half(v1);
                if (z == 0) {
                    Qh[base] = hh0; Qh[base + 1] = hh1;
                    Ql[base]     = __float2half(v0 - __half2float(hh0));
                    Ql[base + 1] = __float2half(v1 - __half2float(hh1));
                } else {
                    Kh[base] = hh0; Kh[base + 1] = hh1;
                }
            }
        }
}

// ---------------- QK: fp16 2-pass (Q hi/lo, K hi), K=64 single-stage, causal ----
#define QPITCH 144
#define QMAT  (128*QPITCH)
#define QK_SMEM (3*QMAT)     // 55296

__global__ __launch_bounds__(256, 2) void qk_hmma(
    const __half* __restrict__ Qh, const __half* __restrict__ Ql,
    const __half* __restrict__ Kh,
    float* __restrict__ S)
{
    if ((int)blockIdx.x > (int)blockIdx.y) return;

    extern __shared__ char dsm[];
    const uint32_t sbase = smem_u32(dsm);

    const int tid  = threadIdx.x;
    const int wid  = tid >> 5;
    const int lane = tid & 31;
    const int wm   = wid & 3;
    const int wn   = wid >> 2;
    const int z    = blockIdx.z;
    const int bm   = blockIdx.y * 128;
    const int bn   = blockIdx.x * 128;

    const __half* Ah = Qh + (long)z * Tn * DHn + (long)bm * DHn;
    const __half* Al = Ql + (long)z * Tn * DHn + (long)bm * DHn;
    const __half* Bh = Kh + (long)z * Tn * DHn + (long)bn * DHn;

#pragma unroll
    for (int c = tid; c < 1024; c += 256) {
        const int r = c >> 3, seg = c & 7;
        const uint32_t d = sbase + r * QPITCH + seg * 16;
        const long off = (long)r * DHn + seg * 8;
        cpa16(d,        Ah + off);
        cpa16(d + QMAT, Al + off);
    }
#pragma unroll
    for (int c = tid; c < 1024; c += 256) {
        const int r = c >> 3, seg = c & 7;
        const uint32_t d = sbase + 2*QMAT + r * QPITCH + seg * 16;
        const long off = (long)r * DHn + seg * 8;
        cpa16(d, Bh + off);
    }
    CPA_COMMIT();
    CPA_WAIT0();
    __syncthreads();

    float acc[2][8][4];
#pragma unroll
    for (int i = 0; i < 2; i++)
#pragma unroll
        for (int j = 0; j < 8; j++)
#pragma unroll
            for (int c = 0; c < 4; c++) acc[i][j][c] = 0.f;

    const uint32_t a_row = (uint32_t)(wm * 32 + (lane & 15)) * QPITCH;
    const uint32_t b_row = (uint32_t)(wn * 64 + (lane & 15)) * QPITCH;
    const uint32_t lcol  = (uint32_t)((lane >> 4) * 16);

#pragma unroll
    for (int kc = 0; kc < 4; kc++) {
        const uint32_t col = kc * 32 + lcol;
        uint32_t ah[2][4], al[2][4], bh[4][4];
#pragma unroll
        for (int mt = 0; mt < 2; mt++) {
            const uint32_t ad = sbase + a_row + (uint32_t)(mt * 16 * QPITCH) + col;
            LDSM4(ah[mt], ad);
            LDSM4(al[mt], ad + QMAT);
        }
#pragma unroll
        for (int np = 0; np < 4; np++) {
            const uint32_t bd = sbase + 2*QMAT + b_row + (uint32_t)(np * 16 * QPITCH) + col;
            LDSM4(bh[np], bd);
        }
#pragma unroll
        for (int mt = 0; mt < 2; mt++)
#pragma unroll
            for (int nt = 0; nt < 8; nt++) {
                const int np = nt >> 1, i = nt & 1;
                MMA_F16(acc[mt][nt], ah[mt], bh[np][i], bh[np][i + 2]);
                MMA_F16(acc[mt][nt], al[mt], bh[np][i], bh[np][i + 2]);
            }
    }

#pragma unroll
    for (int mt = 0; mt < 2; mt++)
#pragma unroll
        for (int nt = 0; nt < 8; nt++) {
            const int m0 = bm + wm * 32 + mt * 16 + (lane >> 2);
            const int n0 = bn + wn * 64 + nt * 8 + (lane & 3) * 2;
#pragma unroll
            for (int half = 0; half < 2; half++) {
                const int m = m0 + half * 8;
                float* cp = S + (long)z * Tn * Tn + (long)m * Tn + n0;
                cp[0] = acc[mt][nt][half * 2 + 0];
                cp[1] = acc[mt][nt][half * 2 + 1];
            }
        }
}

// ========== pv: fp16 1-pass (P hi, V hi), 128x64, NS=2, 3 CTA/SM ==========
#define B64M  (64*PITCH)
#define STG64 (AMAT + B64M)       // 15360: [Ph][Vh]
#define PV_SMEM (2*STG64)         // 30720

__global__ __launch_bounds__(256, 3) void pv_hmma(
    const __half* __restrict__ Ph, const __half* __restrict__ Vth,
    __half* __restrict__ AOh)
{
    extern __shared__ char dsm[];
    const uint32_t sbase = smem_u32(dsm);

    const int tid  = threadIdx.x;
    const int wid  = tid >> 5;
    const int lane = tid & 31;
    const int wm   = wid & 3;
    const int wn   = wid >> 2;
    const int it   = blockIdx.x;
    const int bh   = blockIdx.y;
    const int b    = bh >> 4, h = bh & 15;

    const __half* Ah = Ph + ((long)bh * Tn + it * 128) * Tn;
    const __half* Bh = Vth + (long)bh * DHn * Tn;

    float acc[2][4][4];
#pragma unroll
    for (int i = 0; i < 2; i++)
#pragma unroll
        for (int j = 0; j < 4; j++)
#pragma unroll
            for (int c = 0; c < 4; c++) acc[i][j][c] = 0.f;

    const int KS = 4 * (it + 1);

    auto load_stage = [&](int slot, int ks) {
        const uint32_t base = sbase + slot * STG64;
        const int k0 = ks * 32;
#pragma unroll
        for (int c = tid; c < 512; c += 256) {
            const int r = c >> 2, seg = c & 3;
            const uint32_t d = base + r * PITCH + seg * 16;
            const long off = (long)r * Tn + k0 + seg * 8;
            cpa16(d, Ah + off);
        }
        {
            const int r = tid >> 2, seg = tid & 3;
            const uint32_t d = base + AMAT + r * PITCH + seg * 16;
            const long off = (long)r * Tn + k0 + seg * 8;
            cpa16(d, Bh + off);
        }
        CPA_COMMIT();
    };

    load_stage(0, 0);

    const uint32_t a_row = (uint32_t)(wm * 32 + (lane & 15)) * PITCH;
    const uint32_t b_row = (uint32_t)(wn * 32 + (lane & 15)) * PITCH;
    const uint32_t lcol  = (uint32_t)((lane >> 4) * 16);

    for (int k = 0; k < KS; k++) {
        if (k + 1 < KS) load_stage((k + 1) & 1, k + 1);
        if (k + 1 < KS) { CPA_WAIT1(); } else { CPA_WAIT0(); }
        __syncthreads();
        const uint32_t st = sbase + (k & 1) * STG64;
#pragma unroll
        for (int kc = 0; kc < 2; kc++) {
            const uint32_t col = kc * 32 + lcol;
            uint32_t ah[2][4], bh2[2][4];
#pragma unroll
            for (int mt = 0; mt < 2; mt++) {
                const uint32_t ad = st + a_row + (uint32_t)(mt * 16 * PITCH) + col;
                LDSM4(ah[mt], ad);
            }
#pragma unroll
            for (int np = 0; np < 2; np++) {
                const uint32_t bd = st + AMAT + b_row + (uint32_t)(np * 16 * PITCH) + col;
                LDSM4(bh2[np], bd);
            }
#pragma unroll
            for (int mt = 0; mt < 2; mt++)
#pragma unroll
                for (int nt = 0; nt < 4; nt++) {
                    const int np = nt >> 1, i = nt & 1;
                    MMA_F16(acc[mt][nt], ah[mt], bh2[np][i], bh2[np][i + 2]);
                }
        }
        __syncthreads();
    }

#pragma unroll
    for (int mt = 0; mt < 2; mt++)
#pragma unroll
        for (int nt = 0; nt < 4; nt++) {
            const int t0 = it * 128 + wm * 32 + mt * 16 + (lane >> 2);
            const int dh = wn * 32 + nt * 8 + (lane & 3) * 2;
#pragma unroll
            for (int half = 0; half < 2; half++) {
                const int t = t0 + half * 8;
                const float v0 = acc[mt][nt][half * 2 + 0];
                const float v1 = acc[mt][nt][half * 2 + 1];
                const long base = ((long)b * Tn + t) * Dm + h * 64 + dh;
                __half2 H;
                H.x = __float2half(v0);
                H.y = __float2half(v1);
                *(__half2*)(AOh + base) = H;
            }
        }
}

// ---------------- qpe table (Q reconstructed from fp16 hi/lo) ----------------
__global__ __launch_bounds__(256) void qpe_kernel(const float* __restrict__ PE,
                                                  const __half* __restrict__ Qh,
                                                  const __half* __restrict__ Ql,
                                                  float* __restrict__ QPE)
{
    const int it = blockIdx.x, bh = blockIdx.y, h = bh & (Hn - 1);
    const __half* Aqh = Qh + ((long)bh * Tn + it * 64) * DHn;
    const __half* Aql = Ql + ((long)bh * Tn + it * 64) * DHn;
    const float* Bp = PE + (long)h * MAXP * DHn;

    __shared__ float Qs[64][65];
    __shared__ float Ps[64][65];

    const int tid = threadIdx.x;
    const int rowb = tid >> 4, c4 = (tid & 15) << 2;
#pragma unroll
    for (int r = 0; r < 4; r++) {
        int row = rowb + r * 16;
        const long off = (long)row * DHn + c4;
        __half2 qh0 = *(const __half2*)(Aqh + off);
        __half2 qh1 = *(const __half2*)(Aqh + off + 2);
        __half2 ql0 = *(const __half2*)(Aql + off);
        __half2 ql1 = *(const __half2*)(Aql + off + 2);
        Qs[row][c4]     = __half2float(qh0.x) + __half2float(ql0.x);
        Qs[row][c4 + 1] = __half2float(qh0.y) + __half2float(ql0.y);
        Qs[row][c4 + 2] = __half2float(qh1.x) + __half2float(ql1.x);
        Qs[row][c4 + 3] = __half2float(qh1.y) + __half2float(ql1.y);
        float4 p4 = *(const float4*)(Bp + (long)row * DHn + c4);
        Ps[row][c4] = p4.x; Ps[row][c4 + 1] = p4.y;
        Ps[row][c4 + 2] = p4.z; Ps[row][c4 + 3] = p4.w;
    }
    __syncthreads();

    const int tx = tid & 15, ty = tid >> 4;
    float acc[4][4];
#pragma unroll
    for (int i = 0; i < 4; i++)
#pragma unroll
        for (int j = 0; j < 4; j++) acc[i][j] = 0.f;

#pragma unroll 16
    for (int kk = 0; kk < 64; kk++) {
        float a0 = Qs[ty * 4 + 0][kk], a1 = Qs[ty * 4 + 1][kk];
        float a2 = Qs[ty * 4 + 2][kk], a3 = Qs[ty * 4 + 3][kk];
        float b0 = Ps[tx * 4 + 0][kk], b1 = Ps[tx * 4 + 1][kk];
        float b2 = Ps[tx * 4 + 2][kk], b3 = Ps[tx * 4 + 3][kk];
        acc[0][0] = fmaf(a0, b0, acc[0][0]); acc[0][1] = fmaf(a0, b1, acc[0][1]);
        acc[0][2] = fmaf(a0, b2, acc[0][2]); acc[0][3] = fmaf(a0, b3, acc[0][3]);
        acc[1][0] = fmaf(a1, b0, acc[1][0]); acc[1][1] = fmaf(a1, b1, acc[1][1]);
        acc[1][2] = fmaf(a1, b2, acc[1][2]); acc[1][3] = fmaf(a1, b3, acc[1][3]);
        acc[2][0] = fmaf(a2, b0, acc[2][0]); acc[2][1] = fmaf(a2, b1, acc[2][1]);
        acc[2][2] = fmaf(a2, b2, acc[2][2]); acc[2][3] = fmaf(a2, b3, acc[2][3]);
        acc[3][0] = fmaf(a3, b0, acc[3][0]); acc[3][1] = fmaf(a3, b1, acc[3][1]);
        acc[3][2] = fmaf(a3, b2, acc[3][2]); acc[3][3] = fmaf(a3, b3, acc[3][3]);
    }

    float* out = QPE + ((long)bh * Tn + it * 64) * MAXP;
#pragma unroll
    for (int ii = 0; ii < 4; ii++) {
        float4 o4 = make_float4(acc[ii][0], acc[ii][1], acc[ii][2], acc[ii][3]);
        *(float4*)(out + (long)(ty * 4 + ii) * MAXP + tx * 4) = o4;
    }
}

// ---------------- CoPE (block-per-row; fp16 hi-only prob output) ----------------
__global__ __launch_bounds__(256) void cope_kernel(const float* __restrict__ S,
                                                   const float* __restrict__ QPE,
                                                   __half* __restrict__ Ph)
{
    const int i = blockIdx.x, bh = blockIdx.y;
    const float* row = S + ((long)bh * Tn + i) * Tn;
    const long prow = ((long)bh * Tn + i) * Tn;
    const float* qpe = QPE + ((long)bh * Tn + i) * MAXP;
    const int blockend = ((i >> 7) + 1) << 7;

    __shared__ float qpes[64];
    __shared__ float wred[8];
    __shared__ float wred2[8];

    const int tid = threadIdx.x, lane = tid & 31, wid = tid >> 5;
    if (tid < 64) qpes[tid] = qpe[tid];

    const int j0 = tid << 2;
    float qk[4] = {0.f, 0.f, 0.f, 0.f};
    if (j0 <= i) {
        float4 s4 = *(const float4*)(row + j0);
        qk[0] = s4.x; qk[1] = s4.y; qk[2] = s4.z; qk[3] = s4.w;
    }

    float lpre[4];
    float run = 0.f;
#pragma unroll
    for (int q = 0; q < 4; q++) {
        float gg = 0.f;
        if (j0 + q <= i)
            gg = __fdividef(1.f, 1.f + __expf(-0.125f * qk[q]));
        run += gg;
        lpre[q] = run;
    }

    float v = run;
#pragma unroll
    for (int o = 1; o < 32; o <<= 1) {
        float t = __shfl_up_sync(0xffffffffu, v, o);
        if (lane >= o) v += t;
    }
    if (lane == 31) wred[wid] = v;
    __syncthreads();
    if (tid < 8) {
        float w = wred[tid];
#pragma unroll
        for (int o = 1; o < 8; o <<= 1) {
            float t = __shfl_up_sync(0x000000ffu, w, o);
            if (tid >= o) w += t;
        }
        wred[tid] = w;
    }
    __syncthreads();
    const float base  = (v - run) + (wid ? wred[wid - 1] : 0.f);
    const float total = wred[7];

    float sc[4];
    float mx = -INFINITY;
#pragma unroll
    for (int q = 0; q < 4; q++) {
        float s_ = -INFINITY;
        if (j0 + q <= i) {
            float pos = total - (base + lpre[q]);
            pos = fminf(fmaxf(pos, 0.f), 63.f);
            float pf = floorf(pos);
            int fi = (int)pf;
            float al = pos - pf;
            int ci = (fi < 63) ? fi + 1 : 63;
            float qf = qpes[fi], qc = qpes[ci];
            float qv = qf + al * (qc - qf);
            s_ = 0.125f * (qk[q] + qv);
        }
        sc[q] = s_;
        mx = fmaxf(mx, s_);
    }
#pragma unroll
    for (int o = 16; o; o >>= 1) mx = fmaxf(mx, __shfl_xor_sync(0xffffffffu, mx, o));
    if (lane == 0) wred2[wid] = mx;
    __syncthreads();
    float bmax = wred2[0];
#pragma unroll
    for (int k = 1; k < 8; k++) bmax = fmaxf(bmax, wred2[k]);

    float p[4];
    float ssum = 0.f;
#pragma unroll
    for (int q = 0; q < 4; q++) {
        float e = (j0 + q <= i) ? __expf(sc[q] - bmax) : 0.f;
        p[q] = e;
        ssum += e;
    }
#pragma unroll
    for (int o = 16; o; o >>= 1) ssum += __shfl_xor_sync(0xffffffffu, ssum, o);
    __syncthreads();
    if (lane == 0) wred2[wid] = ssum;
    __syncthreads();
    float tot = 0.f;
#pragma unroll
    for (int k = 0; k < 8; k++) tot += wred2[k];
    const float inv = __fdividef(1.f, tot);

    if (j0 < blockend) {
        __half2 H0, H1;
        H0.x = __float2half(p[0] * inv);
        H0.y = __float2half(p[1] * inv);
        H1.x = __float2half(p[2] * inv);
        H1.y = __float2half(p[3] * inv);
        *(__half2*)(Ph + prow + j0)     = H0;
        *(__half2*)(Ph + prow + j0 + 2) = H1;
    }
}

// ---------------- launcher ----------------
extern "C" void kernel_launch(void* const* d_in, const int* in_sizes, int n_in,
                              void* d_out, int out_size)
{
    (void)in_sizes; (void)n_in; (void)out_size;
    const float* x  = (const float*)d_in[0];
    const float* Wq = (const float*)d_in[1];
    const float* bq = (const float*)d_in[2];
    const float* Wk = (const float*)d_in[3];
    const float* bk = (const float*)d_in[4];
    const float* Wv = (const float*)d_in[5];
    const float* bv = (const float*)d_in[6];
    const float* Wo = (const float*)d_in[7];
    const float* bo = (const float*)d_in[8];
    const float* pe = (const float*)d_in[9];
    float* out = (float*)d_out;

    float *QPEd, *Sd;
    __half *xh, *Wqh, *Wkh, *Wvh, *Woh, *AOh;
    __half *Qh, *Ql, *Kh, *Phd, *Vth;
    cudaGetSymbolAddress((void**)&QPEd, g_QPE);
    cudaGetSymbolAddress((void**)&Sd, g_S);
    cudaGetSymbolAddress((void**)&xh, g_xh);
    cudaGetSymbolAddress((void**)&Wqh, g_Wqh); cudaGetSymbolAddress((void**)&Wkh, g_Wkh);
    cudaGetSymbolAddress((void**)&Wvh, g_Wvh); cudaGetSymbolAddress((void**)&Woh, g_Woh);
    cudaGetSymbolAddress((void**)&Qh, g_Qh);   cudaGetSymbolAddress((void**)&Ql, g_Ql);
    cudaGetSymbolAddress((void**)&Kh, g_Kh);
    cudaGetSymbolAddress((void**)&AOh, g_AOh);
    cudaGetSymbolAddress((void**)&Phd, g_Ph);
    cudaGetSymbolAddress((void**)&Vth, g_Vth);

    static int smem_set = 0;
    if (!smem_set) {
        cudaFuncSetAttribute(mm1_hmma, cudaFuncAttributeMaxDynamicSharedMemorySize, MM1_SMEM);
        cudaFuncSetAttribute(qkv_hmma, cudaFuncAttributeMaxDynamicSharedMemorySize, QKV_SMEM);
        cudaFuncSetAttribute(pv_hmma, cudaFuncAttributeMaxDynamicSharedMemorySize, PV_SMEM);
        cudaFuncSetAttribute(qk_hmma, cudaFuncAttributeMaxDynamicSharedMemorySize, QK_SMEM);
        smem_set = 1;
    }

    dim3 blk(256);

    cvtx_h<<<2048, blk>>>(x, xh, Bsz * Tn * Dm);
    splitW4h<<<dim3(1024, 1, 4), blk>>>(Wq, Wk, Wv, Wo, Wqh, Wkh, Wvh, Woh);

    qkv_hmma<<<dim3(8, 16, 3), blk, QKV_SMEM>>>(xh, Wqh, Wkh, Wvh,
                                                bq, bk, bv, Qh, Ql, Kh, Vth);

    qk_hmma<<<dim3(8, 8, 32), blk, QK_SMEM>>>(Qh, Ql, Kh, Sd);

    qpe_kernel<<<dim3(16, 32), blk>>>(pe, Qh, Ql, QPEd);

    cope_kernel<<<dim3(1024, 32), blk>>>(Sd, QPEd, Phd);

    pv_hmma<<<dim3(8, 32), blk, PV_SMEM>>>(Phd, Vth, AOh);

    mm1_hmma<<<dim3(8, 16, 1), blk, MM1_SMEM>>>(AOh, Woh, bo, out, 1024, 1024);
}